// round 1
// baseline (speedup 1.0000x reference)
#include <cuda_runtime.h>
#include <cuda_bf16.h>
#include <math.h>

// Problem constants
#define B_  2
#define L_  1024
#define DM  1024
#define DI  2048
#define NS  16
#define RR  64
#define KC  4
#define MTOT (B_ * L_)      // 2048
#define EPS 1e-5f

// ---------------------------------------------------------------------------
// Scratch buffers (device globals; no allocation allowed)
// ---------------------------------------------------------------------------
__device__ float g_xz_a[MTOT * (2 * DI)];   // a @ Wi^T  (x | z)
__device__ float g_xz_b[MTOT * DI];         // flip(b) @ Wi[:DI]^T (x only)
__device__ float g_u_f[MTOT * DI];          // silu(conv(x_f))
__device__ float g_u_b[MTOT * DI];
__device__ float g_dbl_f[MTOT * (RR + 2 * NS)];  // u @ Wx^T (dt|B|C), 96 cols
__device__ float g_dbl_b[MTOT * (RR + 2 * NS)];
__device__ float g_delta_f[MTOT * DI];
__device__ float g_delta_b[MTOT * DI];
__device__ float g_y_f[MTOT * DI];
__device__ float g_y_b[MTOT * DI];          // in flipped time
__device__ float g_g[MTOT * DI];            // gated + rmsnorm

// ---------------------------------------------------------------------------
// Tiled SGEMM:  C[m,n] = act( sum_k A'[m,k] * W[n,k] + biasScale*bias[n] )
//   A row-major with row stride lda; A' = optionally L-flipped rows within batch
//   W row-major [Nn, Kd] (row stride == Kd)
//   C row-major [M, Nn]
// ---------------------------------------------------------------------------
#define BM 128
#define BN 128
#define BK 16
#define TM 8
#define TN 8

__global__ __launch_bounds__(256, 2)
void linear_kernel(const float* __restrict__ A, int lda,
                   const float* __restrict__ W,
                   const float* __restrict__ bias, float biasScale,
                   float* __restrict__ C,
                   int M, int Nn, int Kd, int flip, int act)
{
    __shared__ float As[BK][BM];
    __shared__ float Ws[BK][BN];

    const int tid  = threadIdx.x;
    const int row0 = blockIdx.y * BM;
    const int col0 = blockIdx.x * BN;

    const int ty = tid >> 4;       // 0..15
    const int tx = tid & 15;       // 0..15

    const int lrow  = tid >> 2;          // 0..63
    const int lcol4 = (tid & 3) << 2;    // 0,4,8,12

    float acc[TM][TN];
#pragma unroll
    for (int i = 0; i < TM; i++)
#pragma unroll
        for (int j = 0; j < TN; j++) acc[i][j] = 0.f;

    for (int k0 = 0; k0 < Kd; k0 += BK) {
        // ---- load A tile (BM x BK), transposed into As[k][m]
#pragma unroll
        for (int rr = 0; rr < 2; rr++) {
            int r    = lrow + rr * 64;
            int grow = row0 + r;
            int srow = grow;
            if (flip) {
                int bb = grow >> 10;           // L_ = 1024
                int l  = grow & 1023;
                srow = (bb << 10) + (1023 - l);
            }
            float4 v = *(const float4*)(A + (size_t)srow * lda + k0 + lcol4);
            As[lcol4 + 0][r] = v.x;
            As[lcol4 + 1][r] = v.y;
            As[lcol4 + 2][r] = v.z;
            As[lcol4 + 3][r] = v.w;
        }
        // ---- load W tile (BN x BK), transposed into Ws[k][n]
#pragma unroll
        for (int rr = 0; rr < 2; rr++) {
            int n  = lrow + rr * 64;
            int gn = col0 + n;
            float4 v = make_float4(0.f, 0.f, 0.f, 0.f);
            if (gn < Nn) v = *(const float4*)(W + (size_t)gn * Kd + k0 + lcol4);
            Ws[lcol4 + 0][n] = v.x;
            Ws[lcol4 + 1][n] = v.y;
            Ws[lcol4 + 2][n] = v.z;
            Ws[lcol4 + 3][n] = v.w;
        }
        __syncthreads();

#pragma unroll
        for (int kk = 0; kk < BK; kk++) {
            float ra[TM], rb[TN];
#pragma unroll
            for (int i = 0; i < TM; i++) ra[i] = As[kk][ty * TM + i];
#pragma unroll
            for (int j = 0; j < TN; j++) rb[j] = Ws[kk][tx * TN + j];
#pragma unroll
            for (int i = 0; i < TM; i++)
#pragma unroll
                for (int j = 0; j < TN; j++)
                    acc[i][j] = fmaf(ra[i], rb[j], acc[i][j]);
        }
        __syncthreads();
    }

    // ---- epilogue
#pragma unroll
    for (int i = 0; i < TM; i++) {
        int grow = row0 + ty * TM + i;
#pragma unroll
        for (int j = 0; j < TN; j++) {
            int gcol = col0 + tx * TN + j;
            if (gcol < Nn) {
                float v = acc[i][j];
                if (bias) v += biasScale * bias[gcol];
                if (act == 1) {  // softplus
                    v = (v > 20.f) ? v : log1pf(expf(v));
                }
                C[(size_t)grow * Nn + gcol] = v;
            }
        }
    }
}

// ---------------------------------------------------------------------------
// Depthwise causal conv1d (K=4) + bias + SiLU
//   x: [MTOT, ldx] (we read columns [0, DI)), u: [MTOT, DI]
// ---------------------------------------------------------------------------
__global__ void conv_silu_kernel(const float* __restrict__ x, int ldx,
                                 const float* __restrict__ w,
                                 const float* __restrict__ bias,
                                 float* __restrict__ u)
{
    int idx = blockIdx.x * blockDim.x + threadIdx.x;
    if (idx >= MTOT * DI) return;
    int d   = idx % DI;
    int row = idx / DI;
    int l   = row & (L_ - 1);

    float acc = bias[d];
#pragma unroll
    for (int k = 0; k < KC; k++) {
        int ls = l + k - (KC - 1);
        if (ls >= 0) {
            acc = fmaf(x[(size_t)(row + k - (KC - 1)) * ldx + d], w[d * KC + k], acc);
        }
    }
    // silu
    float s = 1.f / (1.f + __expf(-acc));
    u[idx] = acc * s;
}

// ---------------------------------------------------------------------------
// Selective scan, both branches in one launch (blockIdx.y selects branch)
//   thread = one (batch, d); 16 states in registers; 16-step smem-staged chunks
// ---------------------------------------------------------------------------
#define SCAN_TPB 128
#define SCAN_CH  16

__global__ __launch_bounds__(SCAN_TPB, 1)
void scan_kernel(const float* __restrict__ u_f, const float* __restrict__ del_f,
                 const float* __restrict__ dbl_f,
                 const float* __restrict__ u_b, const float* __restrict__ del_b,
                 const float* __restrict__ dbl_b,
                 const float* __restrict__ A_log_f, const float* __restrict__ D_f,
                 const float* __restrict__ A_log_b, const float* __restrict__ D_b,
                 float* __restrict__ y_f, float* __restrict__ y_b)
{
    const int br = blockIdx.y;
    const float* __restrict__ u    = br ? u_b   : u_f;
    const float* __restrict__ del  = br ? del_b : del_f;
    const float* __restrict__ dbl  = br ? dbl_b : dbl_f;
    const float* __restrict__ Alog = br ? A_log_b : A_log_f;
    const float* __restrict__ Dv_p = br ? D_b  : D_f;
    float* __restrict__ yout       = br ? y_b  : y_f;

    const int tid   = threadIdx.x;
    const int dpart = blockIdx.x % (DI / SCAN_TPB);   // 0..15
    const int bb    = blockIdx.x / (DI / SCAN_TPB);   // 0..1
    const int d     = dpart * SCAN_TPB + tid;
    const int dbase = dpart * SCAN_TPB;

    float a[NS];
    bool fast = true;
#pragma unroll
    for (int n = 0; n < NS; n++) {
        a[n] = expf(Alog[(size_t)d * NS + n]);
        fast = fast && (fabsf(a[n] - (float)(n + 1)) < 1e-4f * (float)(n + 1));
    }
    const float Dv = Dv_p[d];

    float h[NS];
#pragma unroll
    for (int n = 0; n < NS; n++) h[n] = 0.f;

    __shared__ float  s_del[SCAN_CH][SCAN_TPB];
    __shared__ float  s_u[SCAN_CH][SCAN_TPB];
    __shared__ float4 s_bc[SCAN_CH][8];   // 32 floats per step: B[0..15], C[0..15]

    for (int c0 = 0; c0 < L_; c0 += SCAN_CH) {
        __syncthreads();
        // stage chunk: delta + u (coalesced), B/C via float4
#pragma unroll
        for (int k = 0; k < SCAN_CH; k++) {
            size_t off = (size_t)(bb * L_ + c0 + k) * DI + dbase + tid;
            s_del[k][tid] = del[off];
            s_u[k][tid]   = u[off];
        }
        {
            int k = tid >> 3;        // 0..15
            int q = tid & 7;         // 0..7
            size_t off = (size_t)(bb * L_ + c0 + k) * (RR + 2 * NS) + RR + q * 4;
            s_bc[k][q] = *(const float4*)(dbl + off);
        }
        __syncthreads();

        if (fast) {
#pragma unroll 4
            for (int k = 0; k < SCAN_CH; k++) {
                float dl = s_del[k][tid];
                float uu = s_u[k][tid];
                float du = dl * uu;
                float e  = __expf(-dl);
                float p  = e;
                float yv = 0.f;
                const float* bc = (const float*)s_bc[k];
#pragma unroll
                for (int n = 0; n < NS; n++) {
                    h[n] = fmaf(p, h[n], du * bc[n]);
                    yv   = fmaf(h[n], bc[NS + n], yv);
                    p   *= e;
                }
                yv = fmaf(uu, Dv, yv);
                yout[(size_t)(bb * L_ + c0 + k) * DI + d] = yv;
            }
        } else {
            for (int k = 0; k < SCAN_CH; k++) {
                float dl = s_del[k][tid];
                float uu = s_u[k][tid];
                float du = dl * uu;
                float yv = 0.f;
                const float* bc = (const float*)s_bc[k];
#pragma unroll
                for (int n = 0; n < NS; n++) {
                    float dA = __expf(-dl * a[n]);
                    h[n] = fmaf(dA, h[n], du * bc[n]);
                    yv   = fmaf(h[n], bc[NS + n], yv);
                }
                yv = fmaf(uu, Dv, yv);
                yout[(size_t)(bb * L_ + c0 + k) * DI + d] = yv;
            }
        }
    }
}

// ---------------------------------------------------------------------------
// Gate (y * silu(z)) + RMSNorm * norm_w, one block per row
//   y = y_f[row] + y_b[flipped row]; z = xz_a[row, DI + d]
// ---------------------------------------------------------------------------
__global__ __launch_bounds__(256)
void gate_rms_kernel(const float* __restrict__ yf, const float* __restrict__ yb,
                     const float* __restrict__ xz, const float* __restrict__ nw,
                     float* __restrict__ g)
{
    const int row = blockIdx.x;
    const int l   = row & (L_ - 1);
    const int bb  = row >> 10;
    const int frow = (bb << 10) + (L_ - 1 - l);
    const int tid = threadIdx.x;

    __shared__ float sg[DI];
    __shared__ float red[8];

    float ss = 0.f;
    for (int d = tid; d < DI; d += 256) {
        float y  = yf[(size_t)row * DI + d] + yb[(size_t)frow * DI + d];
        float z  = xz[(size_t)row * (2 * DI) + DI + d];
        float sz = z / (1.f + __expf(-z));
        float gg = y * sz;
        sg[d] = gg;
        ss = fmaf(gg, gg, ss);
    }
#pragma unroll
    for (int o = 16; o; o >>= 1) ss += __shfl_xor_sync(0xFFFFFFFFu, ss, o);
    if ((tid & 31) == 0) red[tid >> 5] = ss;
    __syncthreads();
    float total = red[0] + red[1] + red[2] + red[3] + red[4] + red[5] + red[6] + red[7];
    float scale = rsqrtf(total / (float)DI + EPS);

    for (int d = tid; d < DI; d += 256) {
        g[(size_t)row * DI + d] = sg[d] * scale * nw[d];
    }
}

// ---------------------------------------------------------------------------
// Launch
// ---------------------------------------------------------------------------
extern "C" void kernel_launch(void* const* d_in, const int* in_sizes, int n_in,
                              void* d_out, int out_size)
{
    (void)in_sizes; (void)n_in; (void)out_size;
    const float* a       = (const float*)d_in[0];
    const float* b       = (const float*)d_in[1];
    const float* Wi      = (const float*)d_in[2];
    const float* conv_w  = (const float*)d_in[3];
    const float* conv_b  = (const float*)d_in[4];
    const float* Wx      = (const float*)d_in[5];
    const float* Wdt     = (const float*)d_in[6];
    const float* bdt     = (const float*)d_in[7];
    const float* A_log   = (const float*)d_in[8];
    const float* D       = (const float*)d_in[9];
    const float* conv_w_b = (const float*)d_in[10];
    const float* conv_b_b = (const float*)d_in[11];
    const float* Wx_b    = (const float*)d_in[12];
    const float* Wdt_b   = (const float*)d_in[13];
    const float* bdt_b   = (const float*)d_in[14];
    const float* A_log_b = (const float*)d_in[15];
    const float* D_b     = (const float*)d_in[16];
    const float* Wo      = (const float*)d_in[17];
    const float* norm_w  = (const float*)d_in[18];
    float* out = (float*)d_out;

    float *p_xz_a, *p_xz_b, *p_u_f, *p_u_b, *p_dbl_f, *p_dbl_b;
    float *p_delta_f, *p_delta_b, *p_y_f, *p_y_b, *p_g;
    cudaGetSymbolAddress((void**)&p_xz_a, g_xz_a);
    cudaGetSymbolAddress((void**)&p_xz_b, g_xz_b);
    cudaGetSymbolAddress((void**)&p_u_f, g_u_f);
    cudaGetSymbolAddress((void**)&p_u_b, g_u_b);
    cudaGetSymbolAddress((void**)&p_dbl_f, g_dbl_f);
    cudaGetSymbolAddress((void**)&p_dbl_b, g_dbl_b);
    cudaGetSymbolAddress((void**)&p_delta_f, g_delta_f);
    cudaGetSymbolAddress((void**)&p_delta_b, g_delta_b);
    cudaGetSymbolAddress((void**)&p_y_f, g_y_f);
    cudaGetSymbolAddress((void**)&p_y_b, g_y_b);
    cudaGetSymbolAddress((void**)&p_g, g_g);

    const int TPB = 256;
    const int DBL = RR + 2 * NS;  // 96

    // 1. xz_a = a @ Wi^T                     [2048, 4096]
    linear_kernel<<<dim3((2 * DI) / BN, MTOT / BM), TPB>>>(
        a, DM, Wi, nullptr, 0.f, p_xz_a, MTOT, 2 * DI, DM, 0, 0);

    // 2. xz_b = flip(b) @ Wi[:DI]^T          [2048, 2048]
    linear_kernel<<<dim3(DI / BN, MTOT / BM), TPB>>>(
        b, DM, Wi, nullptr, 0.f, p_xz_b, MTOT, DI, DM, 1, 0);

    // 3/4. conv + silu
    conv_silu_kernel<<<(MTOT * DI + TPB - 1) / TPB, TPB>>>(p_xz_a, 2 * DI, conv_w, conv_b, p_u_f);
    conv_silu_kernel<<<(MTOT * DI + TPB - 1) / TPB, TPB>>>(p_xz_b, DI, conv_w_b, conv_b_b, p_u_b);

    // 5/6. dbl = u @ Wx^T                    [2048, 96]
    linear_kernel<<<dim3(1, MTOT / BM), TPB>>>(
        p_u_f, DI, Wx, nullptr, 0.f, p_dbl_f, MTOT, DBL, DI, 0, 0);
    linear_kernel<<<dim3(1, MTOT / BM), TPB>>>(
        p_u_b, DI, Wx_b, nullptr, 0.f, p_dbl_b, MTOT, DBL, DI, 0, 0);

    // 7. delta = softplus(dt @ Wdt^T + 2*bdt)   [2048, 2048]
    linear_kernel<<<dim3(DI / BN, MTOT / BM), TPB>>>(
        p_dbl_f, DBL, Wdt, bdt, 2.f, p_delta_f, MTOT, DI, RR, 0, 1);
    linear_kernel<<<dim3(DI / BN, MTOT / BM), TPB>>>(
        p_dbl_b, DBL, Wdt_b, bdt_b, 2.f, p_delta_b, MTOT, DI, RR, 0, 1);

    // 8. selective scans (both branches)
    scan_kernel<<<dim3(B_ * DI / SCAN_TPB, 2), SCAN_TPB>>>(
        p_u_f, p_delta_f, p_dbl_f,
        p_u_b, p_delta_b, p_dbl_b,
        A_log, D, A_log_b, D_b,
        p_y_f, p_y_b);

    // 9. gate + rmsnorm
    gate_rms_kernel<<<MTOT, TPB>>>(p_y_f, p_y_b, p_xz_a, norm_w, p_g);

    // 10. out = g @ Wo^T                     [2048, 1024]
    linear_kernel<<<dim3(DM / BN, MTOT / BM), TPB>>>(
        p_g, DI, Wo, nullptr, 0.f, out, MTOT, DM, DI, 0, 0);
}

// round 2
// speedup vs baseline: 2.0934x; 2.0934x over previous
#include <cuda_runtime.h>
#include <cuda_bf16.h>
#include <math.h>
#include <stdint.h>

// Problem constants
#define B_  2
#define L_  1024
#define DM  1024
#define DI  2048
#define NS  16
#define RR  64
#define KC  4
#define MTOT (B_ * L_)      // 2048
#define EPS 1e-5f

// ---------------------------------------------------------------------------
// Scratch buffers (device globals; no allocation allowed)
// ---------------------------------------------------------------------------
__device__ float g_xz_a[MTOT * (2 * DI)];   // a @ Wi^T  (x | z)
__device__ float g_xz_b[MTOT * DI];         // flip(b) @ Wi[:DI]^T (x only)
__device__ float g_u_f[MTOT * DI];          // silu(conv(x_f))
__device__ float g_u_b[MTOT * DI];
__device__ float g_dbl_f[MTOT * (RR + 2 * NS)];  // u @ Wx^T (dt|B|C), 96 cols
__device__ float g_dbl_b[MTOT * (RR + 2 * NS)];
__device__ float g_delta_f[MTOT * DI];
__device__ float g_delta_b[MTOT * DI];
__device__ float g_y_f[MTOT * DI];
__device__ float g_y_b[MTOT * DI];          // in flipped time
__device__ float g_g[MTOT * DI];            // gated + rmsnorm

// ---------------------------------------------------------------------------
// TF32 tensor-core GEMM:
//   C[m,n] = act( sum_k A'[m,k] * W[n,k] + biasScale*bias[n] )
//   A row-major (row stride lda); A' = optionally L-flipped rows within batch
//   W row-major [Nn, Kd]; C row-major [M, Nn]
//   Block tile 128x64, BK=16, 256 threads, warp tile 32x32 (m16n8k8 frags)
// ---------------------------------------------------------------------------
#define BM 128
#define BN 64
#define BK 16

__device__ __forceinline__ uint32_t f2tf32(float x) {
    uint32_t r;
    asm("cvt.rna.tf32.f32 %0, %1;" : "=r"(r) : "f"(x));
    return r;
}

__device__ __forceinline__ void mma_tf32(float c[4], const uint32_t a[4],
                                         const uint32_t b[2]) {
    asm volatile(
        "mma.sync.aligned.m16n8k8.row.col.f32.tf32.tf32.f32 "
        "{%0,%1,%2,%3}, {%4,%5,%6,%7}, {%8,%9}, {%0,%1,%2,%3};"
        : "+f"(c[0]), "+f"(c[1]), "+f"(c[2]), "+f"(c[3])
        : "r"(a[0]), "r"(a[1]), "r"(a[2]), "r"(a[3]), "r"(b[0]), "r"(b[1]));
}

__global__ __launch_bounds__(256)
void tf32_linear_kernel(const float* __restrict__ A, int lda,
                        const float* __restrict__ W,
                        const float* __restrict__ bias, float biasScale,
                        float* __restrict__ C,
                        int M, int Nn, int Kd, int flip, int act)
{
    __shared__ uint32_t As[2][BK][BM + 8];
    __shared__ uint32_t Bs[2][BK][BN + 8];

    const int tid  = threadIdx.x;
    const int lane = tid & 31;
    const int warp = tid >> 5;
    const int g    = lane >> 2;
    const int tg   = lane & 3;
    const int warpM = (warp & 3) * 32;
    const int warpN = (warp >> 2) * 32;
    const int row0 = blockIdx.y * BM;
    const int col0 = blockIdx.x * BN;

    // per-thread gmem-load coordinates
    const int a_r0  = tid >> 2;              // A vec 0 row (0..63), vec1: +64
    const int ld_c4 = (tid & 3) << 2;        // k-subcol 0,4,8,12
    const int b_r   = tid >> 2;              // B row 0..63

    float acc[2][4][4];
#pragma unroll
    for (int mi = 0; mi < 2; mi++)
#pragma unroll
        for (int ni = 0; ni < 4; ni++)
#pragma unroll
            for (int q = 0; q < 4; q++) acc[mi][ni][q] = 0.f;

    const int ntiles = Kd / BK;

    float4 ra[2], rb;

    // ---- prologue: load tile 0 into gmem-staging regs, store to smem[0]
    {
        const int k0 = 0;
#pragma unroll
        for (int i = 0; i < 2; i++) {
            int grow = row0 + a_r0 + i * 64;
            if (flip) { int bb = grow >> 10; int l = grow & 1023; grow = (bb << 10) + (1023 - l); }
            ra[i] = *(const float4*)(A + (size_t)grow * lda + k0 + ld_c4);
        }
        {
            int gn = col0 + b_r;
            rb = (gn < Nn) ? *(const float4*)(W + (size_t)gn * Kd + k0 + ld_c4)
                           : make_float4(0.f, 0.f, 0.f, 0.f);
        }
#pragma unroll
        for (int i = 0; i < 2; i++) {
            int r = a_r0 + i * 64;
            As[0][ld_c4 + 0][r] = f2tf32(ra[i].x);
            As[0][ld_c4 + 1][r] = f2tf32(ra[i].y);
            As[0][ld_c4 + 2][r] = f2tf32(ra[i].z);
            As[0][ld_c4 + 3][r] = f2tf32(ra[i].w);
        }
        Bs[0][ld_c4 + 0][b_r] = f2tf32(rb.x);
        Bs[0][ld_c4 + 1][b_r] = f2tf32(rb.y);
        Bs[0][ld_c4 + 2][b_r] = f2tf32(rb.z);
        Bs[0][ld_c4 + 3][b_r] = f2tf32(rb.w);
    }
    __syncthreads();

    int cur = 0;
    for (int t = 0; t < ntiles; t++) {
        const bool has_next = (t + 1 < ntiles);
        if (has_next) {
            const int k0 = (t + 1) * BK;
#pragma unroll
            for (int i = 0; i < 2; i++) {
                int grow = row0 + a_r0 + i * 64;
                if (flip) { int bb = grow >> 10; int l = grow & 1023; grow = (bb << 10) + (1023 - l); }
                ra[i] = *(const float4*)(A + (size_t)grow * lda + k0 + ld_c4);
            }
            {
                int gn = col0 + b_r;
                rb = (gn < Nn) ? *(const float4*)(W + (size_t)gn * Kd + k0 + ld_c4)
                               : make_float4(0.f, 0.f, 0.f, 0.f);
            }
        }

        // ---- compute on smem[cur]
#pragma unroll
        for (int kk = 0; kk < BK; kk += 8) {
            uint32_t af[2][4], bf[4][2];
#pragma unroll
            for (int mi = 0; mi < 2; mi++) {
                int m0 = warpM + mi * 16 + g;
                af[mi][0] = As[cur][kk + tg    ][m0];
                af[mi][1] = As[cur][kk + tg    ][m0 + 8];
                af[mi][2] = As[cur][kk + tg + 4][m0];
                af[mi][3] = As[cur][kk + tg + 4][m0 + 8];
            }
#pragma unroll
            for (int ni = 0; ni < 4; ni++) {
                int n0 = warpN + ni * 8 + g;
                bf[ni][0] = Bs[cur][kk + tg    ][n0];
                bf[ni][1] = Bs[cur][kk + tg + 4][n0];
            }
#pragma unroll
            for (int mi = 0; mi < 2; mi++)
#pragma unroll
                for (int ni = 0; ni < 4; ni++)
                    mma_tf32(acc[mi][ni], af[mi], bf[ni]);
        }

        if (has_next) {
            const int nxt = cur ^ 1;
#pragma unroll
            for (int i = 0; i < 2; i++) {
                int r = a_r0 + i * 64;
                As[nxt][ld_c4 + 0][r] = f2tf32(ra[i].x);
                As[nxt][ld_c4 + 1][r] = f2tf32(ra[i].y);
                As[nxt][ld_c4 + 2][r] = f2tf32(ra[i].z);
                As[nxt][ld_c4 + 3][r] = f2tf32(ra[i].w);
            }
            Bs[nxt][ld_c4 + 0][b_r] = f2tf32(rb.x);
            Bs[nxt][ld_c4 + 1][b_r] = f2tf32(rb.y);
            Bs[nxt][ld_c4 + 2][b_r] = f2tf32(rb.z);
            Bs[nxt][ld_c4 + 3][b_r] = f2tf32(rb.w);
            __syncthreads();
            cur = nxt;
        }
    }

    // ---- epilogue
#pragma unroll
    for (int mi = 0; mi < 2; mi++) {
        int r0 = row0 + warpM + mi * 16 + g;
#pragma unroll
        for (int ni = 0; ni < 4; ni++) {
            int cb = col0 + warpN + ni * 8 + 2 * tg;
            if (cb < Nn) {
                float v00 = acc[mi][ni][0], v01 = acc[mi][ni][1];
                float v10 = acc[mi][ni][2], v11 = acc[mi][ni][3];
                if (bias) {
                    float b0 = biasScale * bias[cb];
                    float b1 = biasScale * bias[cb + 1];
                    v00 += b0; v01 += b1; v10 += b0; v11 += b1;
                }
                if (act == 1) {  // softplus
                    v00 = (v00 > 20.f) ? v00 : log1pf(expf(v00));
                    v01 = (v01 > 20.f) ? v01 : log1pf(expf(v01));
                    v10 = (v10 > 20.f) ? v10 : log1pf(expf(v10));
                    v11 = (v11 > 20.f) ? v11 : log1pf(expf(v11));
                }
                *(float2*)(C + (size_t)r0 * Nn + cb)       = make_float2(v00, v01);
                *(float2*)(C + (size_t)(r0 + 8) * Nn + cb) = make_float2(v10, v11);
            }
        }
    }
}

// ---------------------------------------------------------------------------
// Depthwise causal conv1d (K=4) + bias + SiLU
// ---------------------------------------------------------------------------
__global__ void conv_silu_kernel(const float* __restrict__ x, int ldx,
                                 const float* __restrict__ w,
                                 const float* __restrict__ bias,
                                 float* __restrict__ u)
{
    int idx = blockIdx.x * blockDim.x + threadIdx.x;
    if (idx >= MTOT * DI) return;
    int d   = idx % DI;
    int row = idx / DI;
    int l   = row & (L_ - 1);

    float acc = bias[d];
#pragma unroll
    for (int k = 0; k < KC; k++) {
        int ls = l + k - (KC - 1);
        if (ls >= 0) {
            acc = fmaf(x[(size_t)(row + k - (KC - 1)) * ldx + d], w[d * KC + k], acc);
        }
    }
    float s = 1.f / (1.f + __expf(-acc));
    u[idx] = acc * s;
}

// ---------------------------------------------------------------------------
// Selective scan, both branches in one launch (blockIdx.y selects branch)
// ---------------------------------------------------------------------------
#define SCAN_TPB 128
#define SCAN_CH  16

__global__ __launch_bounds__(SCAN_TPB, 1)
void scan_kernel(const float* __restrict__ u_f, const float* __restrict__ del_f,
                 const float* __restrict__ dbl_f,
                 const float* __restrict__ u_b, const float* __restrict__ del_b,
                 const float* __restrict__ dbl_b,
                 const float* __restrict__ A_log_f, const float* __restrict__ D_f,
                 const float* __restrict__ A_log_b, const float* __restrict__ D_b,
                 float* __restrict__ y_f, float* __restrict__ y_b)
{
    const int br = blockIdx.y;
    const float* __restrict__ u    = br ? u_b   : u_f;
    const float* __restrict__ del  = br ? del_b : del_f;
    const float* __restrict__ dbl  = br ? dbl_b : dbl_f;
    const float* __restrict__ Alog = br ? A_log_b : A_log_f;
    const float* __restrict__ Dv_p = br ? D_b  : D_f;
    float* __restrict__ yout       = br ? y_b  : y_f;

    const int tid   = threadIdx.x;
    const int dpart = blockIdx.x % (DI / SCAN_TPB);   // 0..15
    const int bb    = blockIdx.x / (DI / SCAN_TPB);   // 0..1
    const int d     = dpart * SCAN_TPB + tid;
    const int dbase = dpart * SCAN_TPB;

    float a[NS];
    bool fast = true;
#pragma unroll
    for (int n = 0; n < NS; n++) {
        a[n] = expf(Alog[(size_t)d * NS + n]);
        fast = fast && (fabsf(a[n] - (float)(n + 1)) < 1e-4f * (float)(n + 1));
    }
    const float Dv = Dv_p[d];

    float h[NS];
#pragma unroll
    for (int n = 0; n < NS; n++) h[n] = 0.f;

    __shared__ float  s_del[SCAN_CH][SCAN_TPB];
    __shared__ float  s_u[SCAN_CH][SCAN_TPB];
    __shared__ float4 s_bc[SCAN_CH][8];

    for (int c0 = 0; c0 < L_; c0 += SCAN_CH) {
        __syncthreads();
#pragma unroll
        for (int k = 0; k < SCAN_CH; k++) {
            size_t off = (size_t)(bb * L_ + c0 + k) * DI + dbase + tid;
            s_del[k][tid] = del[off];
            s_u[k][tid]   = u[off];
        }
        {
            int k = tid >> 3;
            int q = tid & 7;
            size_t off = (size_t)(bb * L_ + c0 + k) * (RR + 2 * NS) + RR + q * 4;
            s_bc[k][q] = *(const float4*)(dbl + off);
        }
        __syncthreads();

        if (fast) {
#pragma unroll 4
            for (int k = 0; k < SCAN_CH; k++) {
                float dl = s_del[k][tid];
                float uu = s_u[k][tid];
                float du = dl * uu;
                float e  = __expf(-dl);
                float p  = e;
                float yv = 0.f;
                const float* bc = (const float*)s_bc[k];
#pragma unroll
                for (int n = 0; n < NS; n++) {
                    h[n] = fmaf(p, h[n], du * bc[n]);
                    yv   = fmaf(h[n], bc[NS + n], yv);
                    p   *= e;
                }
                yv = fmaf(uu, Dv, yv);
                yout[(size_t)(bb * L_ + c0 + k) * DI + d] = yv;
            }
        } else {
            for (int k = 0; k < SCAN_CH; k++) {
                float dl = s_del[k][tid];
                float uu = s_u[k][tid];
                float du = dl * uu;
                float yv = 0.f;
                const float* bc = (const float*)s_bc[k];
#pragma unroll
                for (int n = 0; n < NS; n++) {
                    float dA = __expf(-dl * a[n]);
                    h[n] = fmaf(dA, h[n], du * bc[n]);
                    yv   = fmaf(h[n], bc[NS + n], yv);
                }
                yv = fmaf(uu, Dv, yv);
                yout[(size_t)(bb * L_ + c0 + k) * DI + d] = yv;
            }
        }
    }
}

// ---------------------------------------------------------------------------
// Gate (y * silu(z)) + RMSNorm * norm_w, one block per row
// ---------------------------------------------------------------------------
__global__ __launch_bounds__(256)
void gate_rms_kernel(const float* __restrict__ yf, const float* __restrict__ yb,
                     const float* __restrict__ xz, const float* __restrict__ nw,
                     float* __restrict__ g)
{
    const int row = blockIdx.x;
    const int l   = row & (L_ - 1);
    const int bb  = row >> 10;
    const int frow = (bb << 10) + (L_ - 1 - l);
    const int tid = threadIdx.x;

    __shared__ float sg[DI];
    __shared__ float red[8];

    float ss = 0.f;
    for (int d = tid; d < DI; d += 256) {
        float y  = yf[(size_t)row * DI + d] + yb[(size_t)frow * DI + d];
        float z  = xz[(size_t)row * (2 * DI) + DI + d];
        float sz = z / (1.f + __expf(-z));
        float gg = y * sz;
        sg[d] = gg;
        ss = fmaf(gg, gg, ss);
    }
#pragma unroll
    for (int o = 16; o; o >>= 1) ss += __shfl_xor_sync(0xFFFFFFFFu, ss, o);
    if ((tid & 31) == 0) red[tid >> 5] = ss;
    __syncthreads();
    float total = red[0] + red[1] + red[2] + red[3] + red[4] + red[5] + red[6] + red[7];
    float scale = rsqrtf(total / (float)DI + EPS);

    for (int d = tid; d < DI; d += 256) {
        g[(size_t)row * DI + d] = sg[d] * scale * nw[d];
    }
}

// ---------------------------------------------------------------------------
// Launch
// ---------------------------------------------------------------------------
extern "C" void kernel_launch(void* const* d_in, const int* in_sizes, int n_in,
                              void* d_out, int out_size)
{
    (void)in_sizes; (void)n_in; (void)out_size;
    const float* a       = (const float*)d_in[0];
    const float* b       = (const float*)d_in[1];
    const float* Wi      = (const float*)d_in[2];
    const float* conv_w  = (const float*)d_in[3];
    const float* conv_b  = (const float*)d_in[4];
    const float* Wx      = (const float*)d_in[5];
    const float* Wdt     = (const float*)d_in[6];
    const float* bdt     = (const float*)d_in[7];
    const float* A_log   = (const float*)d_in[8];
    const float* D       = (const float*)d_in[9];
    const float* conv_w_b = (const float*)d_in[10];
    const float* conv_b_b = (const float*)d_in[11];
    const float* Wx_b    = (const float*)d_in[12];
    const float* Wdt_b   = (const float*)d_in[13];
    const float* bdt_b   = (const float*)d_in[14];
    const float* A_log_b = (const float*)d_in[15];
    const float* D_b     = (const float*)d_in[16];
    const float* Wo      = (const float*)d_in[17];
    const float* norm_w  = (const float*)d_in[18];
    float* out = (float*)d_out;

    float *p_xz_a, *p_xz_b, *p_u_f, *p_u_b, *p_dbl_f, *p_dbl_b;
    float *p_delta_f, *p_delta_b, *p_y_f, *p_y_b, *p_g;
    cudaGetSymbolAddress((void**)&p_xz_a, g_xz_a);
    cudaGetSymbolAddress((void**)&p_xz_b, g_xz_b);
    cudaGetSymbolAddress((void**)&p_u_f, g_u_f);
    cudaGetSymbolAddress((void**)&p_u_b, g_u_b);
    cudaGetSymbolAddress((void**)&p_dbl_f, g_dbl_f);
    cudaGetSymbolAddress((void**)&p_dbl_b, g_dbl_b);
    cudaGetSymbolAddress((void**)&p_delta_f, g_delta_f);
    cudaGetSymbolAddress((void**)&p_delta_b, g_delta_b);
    cudaGetSymbolAddress((void**)&p_y_f, g_y_f);
    cudaGetSymbolAddress((void**)&p_y_b, g_y_b);
    cudaGetSymbolAddress((void**)&p_g, g_g);

    const int TPB = 256;
    const int DBL = RR + 2 * NS;  // 96

    // 1. xz_a = a @ Wi^T                     [2048, 4096]
    tf32_linear_kernel<<<dim3((2 * DI) / BN, MTOT / BM), TPB>>>(
        a, DM, Wi, nullptr, 0.f, p_xz_a, MTOT, 2 * DI, DM, 0, 0);

    // 2. xz_b = flip(b) @ Wi[:DI]^T          [2048, 2048]
    tf32_linear_kernel<<<dim3(DI / BN, MTOT / BM), TPB>>>(
        b, DM, Wi, nullptr, 0.f, p_xz_b, MTOT, DI, DM, 1, 0);

    // 3/4. conv + silu
    conv_silu_kernel<<<(MTOT * DI + TPB - 1) / TPB, TPB>>>(p_xz_a, 2 * DI, conv_w, conv_b, p_u_f);
    conv_silu_kernel<<<(MTOT * DI + TPB - 1) / TPB, TPB>>>(p_xz_b, DI, conv_w_b, conv_b_b, p_u_b);

    // 5/6. dbl = u @ Wx^T                    [2048, 96]
    tf32_linear_kernel<<<dim3((DBL + BN - 1) / BN, MTOT / BM), TPB>>>(
        p_u_f, DI, Wx, nullptr, 0.f, p_dbl_f, MTOT, DBL, DI, 0, 0);
    tf32_linear_kernel<<<dim3((DBL + BN - 1) / BN, MTOT / BM), TPB>>>(
        p_u_b, DI, Wx_b, nullptr, 0.f, p_dbl_b, MTOT, DBL, DI, 0, 0);

    // 7. delta = softplus(dt @ Wdt^T + 2*bdt)   [2048, 2048]
    tf32_linear_kernel<<<dim3(DI / BN, MTOT / BM), TPB>>>(
        p_dbl_f, DBL, Wdt, bdt, 2.f, p_delta_f, MTOT, DI, RR, 0, 1);
    tf32_linear_kernel<<<dim3(DI / BN, MTOT / BM), TPB>>>(
        p_dbl_b, DBL, Wdt_b, bdt_b, 2.f, p_delta_b, MTOT, DI, RR, 0, 1);

    // 8. selective scans (both branches)
    scan_kernel<<<dim3(B_ * DI / SCAN_TPB, 2), SCAN_TPB>>>(
        p_u_f, p_delta_f, p_dbl_f,
        p_u_b, p_delta_b, p_dbl_b,
        A_log, D, A_log_b, D_b,
        p_y_f, p_y_b);

    // 9. gate + rmsnorm
    gate_rms_kernel<<<MTOT, TPB>>>(p_y_f, p_y_b, p_xz_a, norm_w, p_g);

    // 10. out = g @ Wo^T                     [2048, 1024]
    tf32_linear_kernel<<<dim3(DM / BN, MTOT / BM), TPB>>>(
        p_g, DI, Wo, nullptr, 0.f, out, MTOT, DM, DI, 0, 0);
}

// round 3
// speedup vs baseline: 2.1252x; 1.0152x over previous
#include <cuda_runtime.h>
#include <cuda_bf16.h>
#include <math.h>
#include <stdint.h>

// Problem constants
#define B_  2
#define L_  1024
#define DM  1024
#define DI  2048
#define NS  16
#define RR  64
#define KC  4
#define MTOT (B_ * L_)      // 2048
#define EPS 1e-5f

// ---------------------------------------------------------------------------
// Scratch buffers (device globals; no allocation allowed)
// ---------------------------------------------------------------------------
__device__ float g_xz_a[MTOT * (2 * DI)];   // a @ Wi^T  (x | z)
__device__ float g_xz_b[MTOT * DI];         // flip(b) @ Wi[:DI]^T (x only)
__device__ float g_u_f[MTOT * DI];          // silu(conv(x_f))
__device__ float g_u_b[MTOT * DI];
__device__ float g_dbl_f[MTOT * (RR + 2 * NS)];  // u @ Wx^T (dt|B|C), 96 cols
__device__ float g_dbl_b[MTOT * (RR + 2 * NS)];
__device__ float g_delta_f[MTOT * DI];
__device__ float g_delta_b[MTOT * DI];
__device__ float g_y_f[MTOT * DI];
__device__ float g_y_b[MTOT * DI];          // in flipped time
__device__ float g_g[MTOT * DI];            // gated + rmsnorm

// ---------------------------------------------------------------------------
// TF32 tensor-core GEMM:
//   C[m,n] = act( sum_k A'[m,k] * W[n,k] + biasScale*bias[n] )
//   A row-major (row stride lda); A' = optionally L-flipped rows within batch
//   W row-major [Nn, Kd]; C row-major [M, Nn]
//   Block tile 128x128, BK=16, 256 threads, warp tile 32x64 (m16n8k8 frags)
// ---------------------------------------------------------------------------
#define BM 128
#define BN 128
#define BK 16
#define PAD 8

__device__ __forceinline__ uint32_t f2tf32(float x) {
    uint32_t r;
    asm("cvt.rna.tf32.f32 %0, %1;" : "=r"(r) : "f"(x));
    return r;
}

__device__ __forceinline__ void mma_tf32(float c[4], const uint32_t a[4],
                                         const uint32_t b[2]) {
    asm volatile(
        "mma.sync.aligned.m16n8k8.row.col.f32.tf32.tf32.f32 "
        "{%0,%1,%2,%3}, {%4,%5,%6,%7}, {%8,%9}, {%0,%1,%2,%3};"
        : "+f"(c[0]), "+f"(c[1]), "+f"(c[2]), "+f"(c[3])
        : "r"(a[0]), "r"(a[1]), "r"(a[2]), "r"(a[3]), "r"(b[0]), "r"(b[1]));
}

__global__ __launch_bounds__(256)
void tf32_linear_kernel(const float* __restrict__ A, int lda,
                        const float* __restrict__ W,
                        const float* __restrict__ bias, float biasScale,
                        float* __restrict__ C,
                        int M, int Nn, int Kd, int flip, int act)
{
    __shared__ uint32_t As[2][BK][BM + PAD];
    __shared__ uint32_t Bs[2][BK][BN + PAD];

    const int tid  = threadIdx.x;
    const int lane = tid & 31;
    const int warp = tid >> 5;
    const int g    = lane >> 2;          // 0..7
    const int tg   = lane & 3;           // 0..3
    const int warpM = (warp & 3) * 32;
    const int warpN = (warp >> 2) * 64;
    const int row0 = blockIdx.y * BM;
    const int col0 = blockIdx.x * BN;

    // per-thread gmem-load coordinates (two float4 per matrix per tile)
    const int ld_r  = tid >> 2;              // 0..63 (second: +64)
    const int ld_c4 = (tid & 3) << 2;        // k-subcol 0,4,8,12

    float acc[2][8][4];
#pragma unroll
    for (int mi = 0; mi < 2; mi++)
#pragma unroll
        for (int ni = 0; ni < 8; ni++)
#pragma unroll
            for (int q = 0; q < 4; q++) acc[mi][ni][q] = 0.f;

    const int ntiles = Kd / BK;

    float4 ra[2], rb[2];

    // precomputed source rows for A (flip applied once)
    int arow[2];
#pragma unroll
    for (int i = 0; i < 2; i++) {
        int grow = row0 + ld_r + i * 64;
        if (flip) { int bb = grow >> 10; int l = grow & 1023; grow = (bb << 10) + (1023 - l); }
        arow[i] = grow;
    }
    int wrow[2];
    bool wok[2];
#pragma unroll
    for (int i = 0; i < 2; i++) {
        int gn = col0 + ld_r + i * 64;
        wrow[i] = gn;
        wok[i]  = (gn < Nn);
    }

    // ---- prologue: tile 0
    {
#pragma unroll
        for (int i = 0; i < 2; i++)
            ra[i] = *(const float4*)(A + (size_t)arow[i] * lda + ld_c4);
#pragma unroll
        for (int i = 0; i < 2; i++)
            rb[i] = wok[i] ? *(const float4*)(W + (size_t)wrow[i] * Kd + ld_c4)
                           : make_float4(0.f, 0.f, 0.f, 0.f);
#pragma unroll
        for (int i = 0; i < 2; i++) {
            int r = ld_r + i * 64;
            As[0][ld_c4 + 0][r] = f2tf32(ra[i].x);
            As[0][ld_c4 + 1][r] = f2tf32(ra[i].y);
            As[0][ld_c4 + 2][r] = f2tf32(ra[i].z);
            As[0][ld_c4 + 3][r] = f2tf32(ra[i].w);
            Bs[0][ld_c4 + 0][r] = f2tf32(rb[i].x);
            Bs[0][ld_c4 + 1][r] = f2tf32(rb[i].y);
            Bs[0][ld_c4 + 2][r] = f2tf32(rb[i].z);
            Bs[0][ld_c4 + 3][r] = f2tf32(rb[i].w);
        }
    }
    __syncthreads();

    int cur = 0;
    for (int t = 0; t < ntiles; t++) {
        const bool has_next = (t + 1 < ntiles);
        if (has_next) {
            const int k0 = (t + 1) * BK;
#pragma unroll
            for (int i = 0; i < 2; i++)
                ra[i] = *(const float4*)(A + (size_t)arow[i] * lda + k0 + ld_c4);
#pragma unroll
            for (int i = 0; i < 2; i++)
                rb[i] = wok[i] ? *(const float4*)(W + (size_t)wrow[i] * Kd + k0 + ld_c4)
                               : make_float4(0.f, 0.f, 0.f, 0.f);
        }

        // ---- compute on smem[cur]
#pragma unroll
        for (int kk = 0; kk < BK; kk += 8) {
            uint32_t af[2][4], bf[8][2];
#pragma unroll
            for (int mi = 0; mi < 2; mi++) {
                int m0 = warpM + mi * 16 + g;
                af[mi][0] = As[cur][kk + tg    ][m0];
                af[mi][1] = As[cur][kk + tg    ][m0 + 8];
                af[mi][2] = As[cur][kk + tg + 4][m0];
                af[mi][3] = As[cur][kk + tg + 4][m0 + 8];
            }
#pragma unroll
            for (int ni = 0; ni < 8; ni++) {
                int n0 = warpN + ni * 8 + g;
                bf[ni][0] = Bs[cur][kk + tg    ][n0];
                bf[ni][1] = Bs[cur][kk + tg + 4][n0];
            }
#pragma unroll
            for (int mi = 0; mi < 2; mi++)
#pragma unroll
                for (int ni = 0; ni < 8; ni++)
                    mma_tf32(acc[mi][ni], af[mi], bf[ni]);
        }

        if (has_next) {
            const int nxt = cur ^ 1;
#pragma unroll
            for (int i = 0; i < 2; i++) {
                int r = ld_r + i * 64;
                As[nxt][ld_c4 + 0][r] = f2tf32(ra[i].x);
                As[nxt][ld_c4 + 1][r] = f2tf32(ra[i].y);
                As[nxt][ld_c4 + 2][r] = f2tf32(ra[i].z);
                As[nxt][ld_c4 + 3][r] = f2tf32(ra[i].w);
                Bs[nxt][ld_c4 + 0][r] = f2tf32(rb[i].x);
                Bs[nxt][ld_c4 + 1][r] = f2tf32(rb[i].y);
                Bs[nxt][ld_c4 + 2][r] = f2tf32(rb[i].z);
                Bs[nxt][ld_c4 + 3][r] = f2tf32(rb[i].w);
            }
            __syncthreads();
            cur = nxt;
        }
    }

    // ---- epilogue
#pragma unroll
    for (int mi = 0; mi < 2; mi++) {
        int r0 = row0 + warpM + mi * 16 + g;
#pragma unroll
        for (int ni = 0; ni < 8; ni++) {
            int cb = col0 + warpN + ni * 8 + 2 * tg;
            if (cb < Nn) {
                float v00 = acc[mi][ni][0], v01 = acc[mi][ni][1];
                float v10 = acc[mi][ni][2], v11 = acc[mi][ni][3];
                if (bias) {
                    float b0 = biasScale * bias[cb];
                    float b1 = biasScale * bias[cb + 1];
                    v00 += b0; v01 += b1; v10 += b0; v11 += b1;
                }
                if (act == 1) {  // softplus
                    v00 = (v00 > 20.f) ? v00 : log1pf(expf(v00));
                    v01 = (v01 > 20.f) ? v01 : log1pf(expf(v01));
                    v10 = (v10 > 20.f) ? v10 : log1pf(expf(v10));
                    v11 = (v11 > 20.f) ? v11 : log1pf(expf(v11));
                }
                *(float2*)(C + (size_t)r0 * Nn + cb)       = make_float2(v00, v01);
                *(float2*)(C + (size_t)(r0 + 8) * Nn + cb) = make_float2(v10, v11);
            }
        }
    }
}

// ---------------------------------------------------------------------------
// Depthwise causal conv1d (K=4) + bias + SiLU; both branches (blockIdx.z)
// ---------------------------------------------------------------------------
__global__ void conv_silu_kernel(const float* __restrict__ x0, int ld0,
                                 const float* __restrict__ w0,
                                 const float* __restrict__ b0,
                                 float* __restrict__ u0,
                                 const float* __restrict__ x1, int ld1,
                                 const float* __restrict__ w1,
                                 const float* __restrict__ b1,
                                 float* __restrict__ u1)
{
    const int br = blockIdx.z;
    const float* __restrict__ x = br ? x1 : x0;
    const float* __restrict__ w = br ? w1 : w0;
    const float* __restrict__ bi = br ? b1 : b0;
    float* __restrict__ u = br ? u1 : u0;
    const int ldx = br ? ld1 : ld0;

    int idx = blockIdx.x * blockDim.x + threadIdx.x;
    if (idx >= MTOT * DI) return;
    int d   = idx % DI;
    int row = idx / DI;
    int l   = row & (L_ - 1);

    float acc = bi[d];
#pragma unroll
    for (int k = 0; k < KC; k++) {
        int ls = l + k - (KC - 1);
        if (ls >= 0) {
            acc = fmaf(x[(size_t)(row + k - (KC - 1)) * ldx + d], w[d * KC + k], acc);
        }
    }
    float s = 1.f / (1.f + __expf(-acc));
    u[idx] = acc * s;
}

// ---------------------------------------------------------------------------
// Selective scan, both branches in one launch (blockIdx.y selects branch)
// ---------------------------------------------------------------------------
#define SCAN_TPB 128
#define SCAN_CH  16

__global__ __launch_bounds__(SCAN_TPB, 1)
void scan_kernel(const float* __restrict__ u_f, const float* __restrict__ del_f,
                 const float* __restrict__ dbl_f,
                 const float* __restrict__ u_b, const float* __restrict__ del_b,
                 const float* __restrict__ dbl_b,
                 const float* __restrict__ A_log_f, const float* __restrict__ D_f,
                 const float* __restrict__ A_log_b, const float* __restrict__ D_b,
                 float* __restrict__ y_f, float* __restrict__ y_b)
{
    const int br = blockIdx.y;
    const float* __restrict__ u    = br ? u_b   : u_f;
    const float* __restrict__ del  = br ? del_b : del_f;
    const float* __restrict__ dbl  = br ? dbl_b : dbl_f;
    const float* __restrict__ Alog = br ? A_log_b : A_log_f;
    const float* __restrict__ Dv_p = br ? D_b  : D_f;
    float* __restrict__ yout       = br ? y_b  : y_f;

    const int tid   = threadIdx.x;
    const int dpart = blockIdx.x % (DI / SCAN_TPB);   // 0..15
    const int bb    = blockIdx.x / (DI / SCAN_TPB);   // 0..1
    const int d     = dpart * SCAN_TPB + tid;
    const int dbase = dpart * SCAN_TPB;

    float a[NS];
    bool fast = true;
#pragma unroll
    for (int n = 0; n < NS; n++) {
        a[n] = expf(Alog[(size_t)d * NS + n]);
        fast = fast && (fabsf(a[n] - (float)(n + 1)) < 1e-4f * (float)(n + 1));
    }
    const float Dv = Dv_p[d];

    float h[NS];
#pragma unroll
    for (int n = 0; n < NS; n++) h[n] = 0.f;

    __shared__ float  s_del[SCAN_CH][SCAN_TPB];
    __shared__ float  s_u[SCAN_CH][SCAN_TPB];
    __shared__ float4 s_bc[SCAN_CH][8];

    for (int c0 = 0; c0 < L_; c0 += SCAN_CH) {
        __syncthreads();
#pragma unroll
        for (int k = 0; k < SCAN_CH; k++) {
            size_t off = (size_t)(bb * L_ + c0 + k) * DI + dbase + tid;
            s_del[k][tid] = del[off];
            s_u[k][tid]   = u[off];
        }
        {
            int k = tid >> 3;
            int q = tid & 7;
            size_t off = (size_t)(bb * L_ + c0 + k) * (RR + 2 * NS) + RR + q * 4;
            s_bc[k][q] = *(const float4*)(dbl + off);
        }
        __syncthreads();

        if (fast) {
#pragma unroll 2
            for (int k = 0; k < SCAN_CH; k++) {
                float dl = s_del[k][tid];
                float uu = s_u[k][tid];
                float du = dl * uu;
                float e  = __expf(-dl);
                // vector-load B/C (8x LDS.128, broadcast)
                float4 V0 = s_bc[k][0], V1 = s_bc[k][1], V2 = s_bc[k][2], V3 = s_bc[k][3];
                float4 W0 = s_bc[k][4], W1 = s_bc[k][5], W2 = s_bc[k][6], W3 = s_bc[k][7];
                float Bv[NS] = {V0.x,V0.y,V0.z,V0.w, V1.x,V1.y,V1.z,V1.w,
                                V2.x,V2.y,V2.z,V2.w, V3.x,V3.y,V3.z,V3.w};
                float Cv[NS] = {W0.x,W0.y,W0.z,W0.w, W1.x,W1.y,W1.z,W1.w,
                                W2.x,W2.y,W2.z,W2.w, W3.x,W3.y,W3.z,W3.w};
                float p  = e;
                float yv0 = 0.f, yv1 = 0.f;
#pragma unroll
                for (int n = 0; n < NS; n++) {
                    h[n] = fmaf(p, h[n], du * Bv[n]);
                    if (n & 1) yv1 = fmaf(h[n], Cv[n], yv1);
                    else       yv0 = fmaf(h[n], Cv[n], yv0);
                    p   *= e;
                }
                float yv = fmaf(uu, Dv, yv0 + yv1);
                yout[(size_t)(bb * L_ + c0 + k) * DI + d] = yv;
            }
        } else {
            for (int k = 0; k < SCAN_CH; k++) {
                float dl = s_del[k][tid];
                float uu = s_u[k][tid];
                float du = dl * uu;
                float yv = 0.f;
                const float* bc = (const float*)s_bc[k];
#pragma unroll
                for (int n = 0; n < NS; n++) {
                    float dA = __expf(-dl * a[n]);
                    h[n] = fmaf(dA, h[n], du * bc[n]);
                    yv   = fmaf(h[n], bc[NS + n], yv);
                }
                yv = fmaf(uu, Dv, yv);
                yout[(size_t)(bb * L_ + c0 + k) * DI + d] = yv;
            }
        }
    }
}

// ---------------------------------------------------------------------------
// Gate (y * silu(z)) + RMSNorm * norm_w, one block per row
// ---------------------------------------------------------------------------
__global__ __launch_bounds__(256)
void gate_rms_kernel(const float* __restrict__ yf, const float* __restrict__ yb,
                     const float* __restrict__ xz, const float* __restrict__ nw,
                     float* __restrict__ g)
{
    const int row = blockIdx.x;
    const int l   = row & (L_ - 1);
    const int bb  = row >> 10;
    const int frow = (bb << 10) + (L_ - 1 - l);
    const int tid = threadIdx.x;

    __shared__ float sg[DI];
    __shared__ float red[8];

    float ss = 0.f;
    for (int d = tid; d < DI; d += 256) {
        float y  = yf[(size_t)row * DI + d] + yb[(size_t)frow * DI + d];
        float z  = xz[(size_t)row * (2 * DI) + DI + d];
        float sz = z / (1.f + __expf(-z));
        float gg = y * sz;
        sg[d] = gg;
        ss = fmaf(gg, gg, ss);
    }
#pragma unroll
    for (int o = 16; o; o >>= 1) ss += __shfl_xor_sync(0xFFFFFFFFu, ss, o);
    if ((tid & 31) == 0) red[tid >> 5] = ss;
    __syncthreads();
    float total = red[0] + red[1] + red[2] + red[3] + red[4] + red[5] + red[6] + red[7];
    float scale = rsqrtf(total / (float)DI + EPS);

    for (int d = tid; d < DI; d += 256) {
        g[(size_t)row * DI + d] = sg[d] * scale * nw[d];
    }
}

// ---------------------------------------------------------------------------
// Launch
// ---------------------------------------------------------------------------
extern "C" void kernel_launch(void* const* d_in, const int* in_sizes, int n_in,
                              void* d_out, int out_size)
{
    (void)in_sizes; (void)n_in; (void)out_size;
    const float* a       = (const float*)d_in[0];
    const float* b       = (const float*)d_in[1];
    const float* Wi      = (const float*)d_in[2];
    const float* conv_w  = (const float*)d_in[3];
    const float* conv_b  = (const float*)d_in[4];
    const float* Wx      = (const float*)d_in[5];
    const float* Wdt     = (const float*)d_in[6];
    const float* bdt     = (const float*)d_in[7];
    const float* A_log   = (const float*)d_in[8];
    const float* D       = (const float*)d_in[9];
    const float* conv_w_b = (const float*)d_in[10];
    const float* conv_b_b = (const float*)d_in[11];
    const float* Wx_b    = (const float*)d_in[12];
    const float* Wdt_b   = (const float*)d_in[13];
    const float* bdt_b   = (const float*)d_in[14];
    const float* A_log_b = (const float*)d_in[15];
    const float* D_b     = (const float*)d_in[16];
    const float* Wo      = (const float*)d_in[17];
    const float* norm_w  = (const float*)d_in[18];
    float* out = (float*)d_out;

    float *p_xz_a, *p_xz_b, *p_u_f, *p_u_b, *p_dbl_f, *p_dbl_b;
    float *p_delta_f, *p_delta_b, *p_y_f, *p_y_b, *p_g;
    cudaGetSymbolAddress((void**)&p_xz_a, g_xz_a);
    cudaGetSymbolAddress((void**)&p_xz_b, g_xz_b);
    cudaGetSymbolAddress((void**)&p_u_f, g_u_f);
    cudaGetSymbolAddress((void**)&p_u_b, g_u_b);
    cudaGetSymbolAddress((void**)&p_dbl_f, g_dbl_f);
    cudaGetSymbolAddress((void**)&p_dbl_b, g_dbl_b);
    cudaGetSymbolAddress((void**)&p_delta_f, g_delta_f);
    cudaGetSymbolAddress((void**)&p_delta_b, g_delta_b);
    cudaGetSymbolAddress((void**)&p_y_f, g_y_f);
    cudaGetSymbolAddress((void**)&p_y_b, g_y_b);
    cudaGetSymbolAddress((void**)&p_g, g_g);

    const int TPB = 256;
    const int DBL = RR + 2 * NS;  // 96

    // 1. xz_a = a @ Wi^T                     [2048, 4096]
    tf32_linear_kernel<<<dim3((2 * DI) / BN, MTOT / BM), TPB>>>(
        a, DM, Wi, nullptr, 0.f, p_xz_a, MTOT, 2 * DI, DM, 0, 0);

    // 2. xz_b = flip(b) @ Wi[:DI]^T          [2048, 2048]
    tf32_linear_kernel<<<dim3(DI / BN, MTOT / BM), TPB>>>(
        b, DM, Wi, nullptr, 0.f, p_xz_b, MTOT, DI, DM, 1, 0);

    // 3. conv + silu (both branches, z-dim)
    conv_silu_kernel<<<dim3((MTOT * DI + TPB - 1) / TPB, 1, 2), TPB>>>(
        p_xz_a, 2 * DI, conv_w, conv_b, p_u_f,
        p_xz_b, DI, conv_w_b, conv_b_b, p_u_b);

    // 5/6. dbl = u @ Wx^T                    [2048, 96]
    tf32_linear_kernel<<<dim3(1, MTOT / BM), TPB>>>(
        p_u_f, DI, Wx, nullptr, 0.f, p_dbl_f, MTOT, DBL, DI, 0, 0);
    tf32_linear_kernel<<<dim3(1, MTOT / BM), TPB>>>(
        p_u_b, DI, Wx_b, nullptr, 0.f, p_dbl_b, MTOT, DBL, DI, 0, 0);

    // 7. delta = softplus(dt @ Wdt^T + 2*bdt)   [2048, 2048]
    tf32_linear_kernel<<<dim3(DI / BN, MTOT / BM), TPB>>>(
        p_dbl_f, DBL, Wdt, bdt, 2.f, p_delta_f, MTOT, DI, RR, 0, 1);
    tf32_linear_kernel<<<dim3(DI / BN, MTOT / BM), TPB>>>(
        p_dbl_b, DBL, Wdt_b, bdt_b, 2.f, p_delta_b, MTOT, DI, RR, 0, 1);

    // 8. selective scans (both branches)
    scan_kernel<<<dim3(B_ * DI / SCAN_TPB, 2), SCAN_TPB>>>(
        p_u_f, p_delta_f, p_dbl_f,
        p_u_b, p_delta_b, p_dbl_b,
        A_log, D, A_log_b, D_b,
        p_y_f, p_y_b);

    // 9. gate + rmsnorm
    gate_rms_kernel<<<MTOT, TPB>>>(p_y_f, p_y_b, p_xz_a, norm_w, p_g);

    // 10. out = g @ Wo^T                     [2048, 1024]
    tf32_linear_kernel<<<dim3(DM / BN, MTOT / BM), TPB>>>(
        p_g, DI, Wo, nullptr, 0.f, out, MTOT, DM, DI, 0, 0);
}

// round 4
// speedup vs baseline: 2.7574x; 1.2974x over previous
#include <cuda_runtime.h>
#include <cuda_bf16.h>
#include <math.h>
#include <stdint.h>

// Problem constants
#define B_  2
#define L_  1024
#define DM  1024
#define DI  2048
#define NS  16
#define RR  64
#define KC  4
#define MTOT (B_ * L_)      // 2048
#define EPS 1e-5f

#define DBLC (RR + 2 * NS)  // 96
#define SPLITK 8
#define KCHUNK (DI / SPLITK)  // 256

// ---------------------------------------------------------------------------
// Scratch buffers (device globals; no allocation allowed)
// ---------------------------------------------------------------------------
__device__ float g_xz_a[MTOT * (2 * DI)];   // a @ Wi^T  (x | z)
__device__ float g_xz_b[MTOT * DI];         // flip(b) @ Wi[:DI]^T (x only)
__device__ float g_u_f[MTOT * DI];          // silu(conv(x_f))
__device__ float g_u_b[MTOT * DI];
__device__ float g_dblp[2 * SPLITK * MTOT * DBLC];  // split-K partials
__device__ float g_dbl_f[MTOT * DBLC];      // u @ Wx^T (dt|B|C), 96 cols
__device__ float g_dbl_b[MTOT * DBLC];
__device__ float g_delta_f[MTOT * DI];
__device__ float g_delta_b[MTOT * DI];
__device__ float g_y_f[MTOT * DI];
__device__ float g_y_b[MTOT * DI];          // in flipped time
__device__ float g_g[MTOT * DI];            // gated + rmsnorm

// ---------------------------------------------------------------------------
// TF32 tensor-core GEMM:
//   C[m,n] = act( sum_{k in chunk} A'[m,k] * W[n,k] + biasScale*bias[n] )
//   A row-major (row stride lda); A' = optionally L-flipped rows within batch
//   W row-major [Nn, Kd]; C row-major [M, Nn]
//   kchunk > 0: split-K mode; blockIdx.z picks chunk, C offset by z*M*Nn
//   Block tile 128x128, BK=16, 256 threads, warp tile 32x64 (m16n8k8 frags)
// ---------------------------------------------------------------------------
#define BM 128
#define BN 128
#define BK 16
#define PAD 8

__device__ __forceinline__ uint32_t f2tf32(float x) {
    uint32_t r;
    asm("cvt.rna.tf32.f32 %0, %1;" : "=r"(r) : "f"(x));
    return r;
}

__device__ __forceinline__ void mma_tf32(float c[4], const uint32_t a[4],
                                         const uint32_t b[2]) {
    asm volatile(
        "mma.sync.aligned.m16n8k8.row.col.f32.tf32.tf32.f32 "
        "{%0,%1,%2,%3}, {%4,%5,%6,%7}, {%8,%9}, {%0,%1,%2,%3};"
        : "+f"(c[0]), "+f"(c[1]), "+f"(c[2]), "+f"(c[3])
        : "r"(a[0]), "r"(a[1]), "r"(a[2]), "r"(a[3]), "r"(b[0]), "r"(b[1]));
}

__global__ __launch_bounds__(256)
void tf32_linear_kernel(const float* __restrict__ A, int lda,
                        const float* __restrict__ W,
                        const float* __restrict__ bias, float biasScale,
                        float* __restrict__ C,
                        int M, int Nn, int Kd, int flip, int act, int kchunk)
{
    __shared__ uint32_t As[2][BK][BM + PAD];
    __shared__ uint32_t Bs[2][BK][BN + PAD];

    const int tid  = threadIdx.x;
    const int lane = tid & 31;
    const int warp = tid >> 5;
    const int g    = lane >> 2;          // 0..7
    const int tg   = lane & 3;           // 0..3
    const int warpM = (warp & 3) * 32;
    const int warpN = (warp >> 2) * 64;
    const int row0 = blockIdx.y * BM;
    const int col0 = blockIdx.x * BN;

    int kb = 0, klen = Kd;
    if (kchunk > 0) {
        kb   = blockIdx.z * kchunk;
        klen = kchunk;
        C   += (size_t)blockIdx.z * M * Nn;
    }

    // per-thread gmem-load coordinates (two float4 per matrix per tile)
    const int ld_r  = tid >> 2;              // 0..63 (second: +64)
    const int ld_c4 = (tid & 3) << 2;        // k-subcol 0,4,8,12

    float acc[2][8][4];
#pragma unroll
    for (int mi = 0; mi < 2; mi++)
#pragma unroll
        for (int ni = 0; ni < 8; ni++)
#pragma unroll
            for (int q = 0; q < 4; q++) acc[mi][ni][q] = 0.f;

    const int ntiles = klen / BK;

    float4 ra[2], rb[2];

    // precomputed source rows for A (flip applied once)
    int arow[2];
#pragma unroll
    for (int i = 0; i < 2; i++) {
        int grow = row0 + ld_r + i * 64;
        if (flip) { int bb = grow >> 10; int l = grow & 1023; grow = (bb << 10) + (1023 - l); }
        arow[i] = grow;
    }
    int wrow[2];
    bool wok[2];
#pragma unroll
    for (int i = 0; i < 2; i++) {
        int gn = col0 + ld_r + i * 64;
        wrow[i] = gn;
        wok[i]  = (gn < Nn);
    }

    // ---- prologue: tile 0
    {
#pragma unroll
        for (int i = 0; i < 2; i++)
            ra[i] = *(const float4*)(A + (size_t)arow[i] * lda + kb + ld_c4);
#pragma unroll
        for (int i = 0; i < 2; i++)
            rb[i] = wok[i] ? *(const float4*)(W + (size_t)wrow[i] * Kd + kb + ld_c4)
                           : make_float4(0.f, 0.f, 0.f, 0.f);
#pragma unroll
        for (int i = 0; i < 2; i++) {
            int r = ld_r + i * 64;
            As[0][ld_c4 + 0][r] = f2tf32(ra[i].x);
            As[0][ld_c4 + 1][r] = f2tf32(ra[i].y);
            As[0][ld_c4 + 2][r] = f2tf32(ra[i].z);
            As[0][ld_c4 + 3][r] = f2tf32(ra[i].w);
            Bs[0][ld_c4 + 0][r] = f2tf32(rb[i].x);
            Bs[0][ld_c4 + 1][r] = f2tf32(rb[i].y);
            Bs[0][ld_c4 + 2][r] = f2tf32(rb[i].z);
            Bs[0][ld_c4 + 3][r] = f2tf32(rb[i].w);
        }
    }
    __syncthreads();

    int cur = 0;
    for (int t = 0; t < ntiles; t++) {
        const bool has_next = (t + 1 < ntiles);
        if (has_next) {
            const int k0 = kb + (t + 1) * BK;
#pragma unroll
            for (int i = 0; i < 2; i++)
                ra[i] = *(const float4*)(A + (size_t)arow[i] * lda + k0 + ld_c4);
#pragma unroll
            for (int i = 0; i < 2; i++)
                rb[i] = wok[i] ? *(const float4*)(W + (size_t)wrow[i] * Kd + k0 + ld_c4)
                               : make_float4(0.f, 0.f, 0.f, 0.f);
        }

        // ---- compute on smem[cur]
#pragma unroll
        for (int kk = 0; kk < BK; kk += 8) {
            uint32_t af[2][4], bf[8][2];
#pragma unroll
            for (int mi = 0; mi < 2; mi++) {
                int m0 = warpM + mi * 16 + g;
                af[mi][0] = As[cur][kk + tg    ][m0];
                af[mi][1] = As[cur][kk + tg    ][m0 + 8];
                af[mi][2] = As[cur][kk + tg + 4][m0];
                af[mi][3] = As[cur][kk + tg + 4][m0 + 8];
            }
#pragma unroll
            for (int ni = 0; ni < 8; ni++) {
                int n0 = warpN + ni * 8 + g;
                bf[ni][0] = Bs[cur][kk + tg    ][n0];
                bf[ni][1] = Bs[cur][kk + tg + 4][n0];
            }
#pragma unroll
            for (int mi = 0; mi < 2; mi++)
#pragma unroll
                for (int ni = 0; ni < 8; ni++)
                    mma_tf32(acc[mi][ni], af[mi], bf[ni]);
        }

        if (has_next) {
            const int nxt = cur ^ 1;
#pragma unroll
            for (int i = 0; i < 2; i++) {
                int r = ld_r + i * 64;
                As[nxt][ld_c4 + 0][r] = f2tf32(ra[i].x);
                As[nxt][ld_c4 + 1][r] = f2tf32(ra[i].y);
                As[nxt][ld_c4 + 2][r] = f2tf32(ra[i].z);
                As[nxt][ld_c4 + 3][r] = f2tf32(ra[i].w);
                Bs[nxt][ld_c4 + 0][r] = f2tf32(rb[i].x);
                Bs[nxt][ld_c4 + 1][r] = f2tf32(rb[i].y);
                Bs[nxt][ld_c4 + 2][r] = f2tf32(rb[i].z);
                Bs[nxt][ld_c4 + 3][r] = f2tf32(rb[i].w);
            }
            __syncthreads();
            cur = nxt;
        }
    }

    // ---- epilogue
#pragma unroll
    for (int mi = 0; mi < 2; mi++) {
        int r0 = row0 + warpM + mi * 16 + g;
#pragma unroll
        for (int ni = 0; ni < 8; ni++) {
            int cb = col0 + warpN + ni * 8 + 2 * tg;
            if (cb < Nn) {
                float v00 = acc[mi][ni][0], v01 = acc[mi][ni][1];
                float v10 = acc[mi][ni][2], v11 = acc[mi][ni][3];
                if (bias) {
                    float b0 = biasScale * bias[cb];
                    float b1 = biasScale * bias[cb + 1];
                    v00 += b0; v01 += b1; v10 += b0; v11 += b1;
                }
                if (act == 1) {  // softplus
                    v00 = (v00 > 20.f) ? v00 : log1pf(expf(v00));
                    v01 = (v01 > 20.f) ? v01 : log1pf(expf(v01));
                    v10 = (v10 > 20.f) ? v10 : log1pf(expf(v10));
                    v11 = (v11 > 20.f) ? v11 : log1pf(expf(v11));
                }
                *(float2*)(C + (size_t)r0 * Nn + cb)       = make_float2(v00, v01);
                *(float2*)(C + (size_t)(r0 + 8) * Nn + cb) = make_float2(v10, v11);
            }
        }
    }
}

// ---------------------------------------------------------------------------
// Reduce split-K partials: out[br][j] = sum_s part[br][s][j]
// ---------------------------------------------------------------------------
__global__ void reduce_dbl_kernel(const float* __restrict__ part,
                                  float* __restrict__ of,
                                  float* __restrict__ ob)
{
    const int NV = MTOT * DBLC / 4;   // float4 per branch
    int i = blockIdx.x * blockDim.x + threadIdx.x;
    if (i >= 2 * NV) return;
    int br = (i >= NV);
    int j  = i - br * NV;
    const float4* p = (const float4*)part + (size_t)br * SPLITK * NV + j;
    float4 s = make_float4(0.f, 0.f, 0.f, 0.f);
#pragma unroll
    for (int k = 0; k < SPLITK; k++) {
        float4 v = p[(size_t)k * NV];
        s.x += v.x; s.y += v.y; s.z += v.z; s.w += v.w;
    }
    ((float4*)(br ? ob : of))[j] = s;
}

// ---------------------------------------------------------------------------
// Depthwise causal conv1d (K=4) + bias + SiLU; both branches (blockIdx.z)
// ---------------------------------------------------------------------------
__global__ void conv_silu_kernel(const float* __restrict__ x0, int ld0,
                                 const float* __restrict__ w0,
                                 const float* __restrict__ b0,
                                 float* __restrict__ u0,
                                 const float* __restrict__ x1, int ld1,
                                 const float* __restrict__ w1,
                                 const float* __restrict__ b1,
                                 float* __restrict__ u1)
{
    const int br = blockIdx.z;
    const float* __restrict__ x = br ? x1 : x0;
    const float* __restrict__ w = br ? w1 : w0;
    const float* __restrict__ bi = br ? b1 : b0;
    float* __restrict__ u = br ? u1 : u0;
    const int ldx = br ? ld1 : ld0;

    int idx = blockIdx.x * blockDim.x + threadIdx.x;
    if (idx >= MTOT * DI) return;
    int d   = idx % DI;
    int row = idx / DI;
    int l   = row & (L_ - 1);

    float acc = bi[d];
#pragma unroll
    for (int k = 0; k < KC; k++) {
        int ls = l + k - (KC - 1);
        if (ls >= 0) {
            acc = fmaf(x[(size_t)(row + k - (KC - 1)) * ldx + d], w[d * KC + k], acc);
        }
    }
    float s = 1.f / (1.f + __expf(-acc));
    u[idx] = acc * s;
}

// ---------------------------------------------------------------------------
// Selective scan, both branches in one launch (blockIdx.y selects branch)
// ---------------------------------------------------------------------------
#define SCAN_TPB 128
#define SCAN_CH  16

__global__ __launch_bounds__(SCAN_TPB, 1)
void scan_kernel(const float* __restrict__ u_f, const float* __restrict__ del_f,
                 const float* __restrict__ dbl_f,
                 const float* __restrict__ u_b, const float* __restrict__ del_b,
                 const float* __restrict__ dbl_b,
                 const float* __restrict__ A_log_f, const float* __restrict__ D_f,
                 const float* __restrict__ A_log_b, const float* __restrict__ D_b,
                 float* __restrict__ y_f, float* __restrict__ y_b)
{
    const int br = blockIdx.y;
    const float* __restrict__ u    = br ? u_b   : u_f;
    const float* __restrict__ del  = br ? del_b : del_f;
    const float* __restrict__ dbl  = br ? dbl_b : dbl_f;
    const float* __restrict__ Alog = br ? A_log_b : A_log_f;
    const float* __restrict__ Dv_p = br ? D_b  : D_f;
    float* __restrict__ yout       = br ? y_b  : y_f;

    const int tid   = threadIdx.x;
    const int dpart = blockIdx.x % (DI / SCAN_TPB);   // 0..15
    const int bb    = blockIdx.x / (DI / SCAN_TPB);   // 0..1
    const int d     = dpart * SCAN_TPB + tid;
    const int dbase = dpart * SCAN_TPB;

    float a[NS];
    bool fast = true;
#pragma unroll
    for (int n = 0; n < NS; n++) {
        a[n] = expf(Alog[(size_t)d * NS + n]);
        fast = fast && (fabsf(a[n] - (float)(n + 1)) < 1e-4f * (float)(n + 1));
    }
    const float Dv = Dv_p[d];

    float h[NS];
#pragma unroll
    for (int n = 0; n < NS; n++) h[n] = 0.f;

    __shared__ float  s_del[SCAN_CH][SCAN_TPB];
    __shared__ float  s_u[SCAN_CH][SCAN_TPB];
    __shared__ float4 s_bc[SCAN_CH][8];

    for (int c0 = 0; c0 < L_; c0 += SCAN_CH) {
        __syncthreads();
#pragma unroll
        for (int k = 0; k < SCAN_CH; k++) {
            size_t off = (size_t)(bb * L_ + c0 + k) * DI + dbase + tid;
            s_del[k][tid] = del[off];
            s_u[k][tid]   = u[off];
        }
        {
            int k = tid >> 3;
            int q = tid & 7;
            size_t off = (size_t)(bb * L_ + c0 + k) * DBLC + RR + q * 4;
            s_bc[k][q] = *(const float4*)(dbl + off);
        }
        __syncthreads();

        if (fast) {
#pragma unroll 2
            for (int k = 0; k < SCAN_CH; k++) {
                float dl = s_del[k][tid];
                float uu = s_u[k][tid];
                float du = dl * uu;
                float e  = __expf(-dl);
                float4 V0 = s_bc[k][0], V1 = s_bc[k][1], V2 = s_bc[k][2], V3 = s_bc[k][3];
                float4 W0 = s_bc[k][4], W1 = s_bc[k][5], W2 = s_bc[k][6], W3 = s_bc[k][7];
                float Bv[NS] = {V0.x,V0.y,V0.z,V0.w, V1.x,V1.y,V1.z,V1.w,
                                V2.x,V2.y,V2.z,V2.w, V3.x,V3.y,V3.z,V3.w};
                float Cv[NS] = {W0.x,W0.y,W0.z,W0.w, W1.x,W1.y,W1.z,W1.w,
                                W2.x,W2.y,W2.z,W2.w, W3.x,W3.y,W3.z,W3.w};
                float p  = e;
                float yv0 = 0.f, yv1 = 0.f;
#pragma unroll
                for (int n = 0; n < NS; n++) {
                    h[n] = fmaf(p, h[n], du * Bv[n]);
                    if (n & 1) yv1 = fmaf(h[n], Cv[n], yv1);
                    else       yv0 = fmaf(h[n], Cv[n], yv0);
                    p   *= e;
                }
                float yv = fmaf(uu, Dv, yv0 + yv1);
                yout[(size_t)(bb * L_ + c0 + k) * DI + d] = yv;
            }
        } else {
            for (int k = 0; k < SCAN_CH; k++) {
                float dl = s_del[k][tid];
                float uu = s_u[k][tid];
                float du = dl * uu;
                float yv = 0.f;
                const float* bc = (const float*)s_bc[k];
#pragma unroll
                for (int n = 0; n < NS; n++) {
                    float dA = __expf(-dl * a[n]);
                    h[n] = fmaf(dA, h[n], du * bc[n]);
                    yv   = fmaf(h[n], bc[NS + n], yv);
                }
                yv = fmaf(uu, Dv, yv);
                yout[(size_t)(bb * L_ + c0 + k) * DI + d] = yv;
            }
        }
    }
}

// ---------------------------------------------------------------------------
// Gate (y * silu(z)) + RMSNorm * norm_w, one block per row
// ---------------------------------------------------------------------------
__global__ __launch_bounds__(256)
void gate_rms_kernel(const float* __restrict__ yf, const float* __restrict__ yb,
                     const float* __restrict__ xz, const float* __restrict__ nw,
                     float* __restrict__ g)
{
    const int row = blockIdx.x;
    const int l   = row & (L_ - 1);
    const int bb  = row >> 10;
    const int frow = (bb << 10) + (L_ - 1 - l);
    const int tid = threadIdx.x;

    __shared__ float sg[DI];
    __shared__ float red[8];

    float ss = 0.f;
    for (int d = tid; d < DI; d += 256) {
        float y  = yf[(size_t)row * DI + d] + yb[(size_t)frow * DI + d];
        float z  = xz[(size_t)row * (2 * DI) + DI + d];
        float sz = z / (1.f + __expf(-z));
        float gg = y * sz;
        sg[d] = gg;
        ss = fmaf(gg, gg, ss);
    }
#pragma unroll
    for (int o = 16; o; o >>= 1) ss += __shfl_xor_sync(0xFFFFFFFFu, ss, o);
    if ((tid & 31) == 0) red[tid >> 5] = ss;
    __syncthreads();
    float total = red[0] + red[1] + red[2] + red[3] + red[4] + red[5] + red[6] + red[7];
    float scale = rsqrtf(total / (float)DI + EPS);

    for (int d = tid; d < DI; d += 256) {
        g[(size_t)row * DI + d] = sg[d] * scale * nw[d];
    }
}

// ---------------------------------------------------------------------------
// Launch
// ---------------------------------------------------------------------------
extern "C" void kernel_launch(void* const* d_in, const int* in_sizes, int n_in,
                              void* d_out, int out_size)
{
    (void)in_sizes; (void)n_in; (void)out_size;
    const float* a       = (const float*)d_in[0];
    const float* b       = (const float*)d_in[1];
    const float* Wi      = (const float*)d_in[2];
    const float* conv_w  = (const float*)d_in[3];
    const float* conv_b  = (const float*)d_in[4];
    const float* Wx      = (const float*)d_in[5];
    const float* Wdt     = (const float*)d_in[6];
    const float* bdt     = (const float*)d_in[7];
    const float* A_log   = (const float*)d_in[8];
    const float* D       = (const float*)d_in[9];
    const float* conv_w_b = (const float*)d_in[10];
    const float* conv_b_b = (const float*)d_in[11];
    const float* Wx_b    = (const float*)d_in[12];
    const float* Wdt_b   = (const float*)d_in[13];
    const float* bdt_b   = (const float*)d_in[14];
    const float* A_log_b = (const float*)d_in[15];
    const float* D_b     = (const float*)d_in[16];
    const float* Wo      = (const float*)d_in[17];
    const float* norm_w  = (const float*)d_in[18];
    float* out = (float*)d_out;

    float *p_xz_a, *p_xz_b, *p_u_f, *p_u_b, *p_dblp, *p_dbl_f, *p_dbl_b;
    float *p_delta_f, *p_delta_b, *p_y_f, *p_y_b, *p_g;
    cudaGetSymbolAddress((void**)&p_xz_a, g_xz_a);
    cudaGetSymbolAddress((void**)&p_xz_b, g_xz_b);
    cudaGetSymbolAddress((void**)&p_u_f, g_u_f);
    cudaGetSymbolAddress((void**)&p_u_b, g_u_b);
    cudaGetSymbolAddress((void**)&p_dblp, g_dblp);
    cudaGetSymbolAddress((void**)&p_dbl_f, g_dbl_f);
    cudaGetSymbolAddress((void**)&p_dbl_b, g_dbl_b);
    cudaGetSymbolAddress((void**)&p_delta_f, g_delta_f);
    cudaGetSymbolAddress((void**)&p_delta_b, g_delta_b);
    cudaGetSymbolAddress((void**)&p_y_f, g_y_f);
    cudaGetSymbolAddress((void**)&p_y_b, g_y_b);
    cudaGetSymbolAddress((void**)&p_g, g_g);

    const int TPB = 256;

    // 1. xz_a = a @ Wi^T                     [2048, 4096]
    tf32_linear_kernel<<<dim3((2 * DI) / BN, MTOT / BM), TPB>>>(
        a, DM, Wi, nullptr, 0.f, p_xz_a, MTOT, 2 * DI, DM, 0, 0, 0);

    // 2. xz_b = flip(b) @ Wi[:DI]^T          [2048, 2048]
    tf32_linear_kernel<<<dim3(DI / BN, MTOT / BM), TPB>>>(
        b, DM, Wi, nullptr, 0.f, p_xz_b, MTOT, DI, DM, 1, 0, 0);

    // 3. conv + silu (both branches, z-dim)
    conv_silu_kernel<<<dim3((MTOT * DI + TPB - 1) / TPB, 1, 2), TPB>>>(
        p_xz_a, 2 * DI, conv_w, conv_b, p_u_f,
        p_xz_b, DI, conv_w_b, conv_b_b, p_u_b);

    // 4/5. dbl = u @ Wx^T  [2048, 96], split-K (SPLITK chunks of 256)
    tf32_linear_kernel<<<dim3(1, MTOT / BM, SPLITK), TPB>>>(
        p_u_f, DI, Wx, nullptr, 0.f, p_dblp, MTOT, DBLC, DI, 0, 0, KCHUNK);
    tf32_linear_kernel<<<dim3(1, MTOT / BM, SPLITK), TPB>>>(
        p_u_b, DI, Wx_b, nullptr, 0.f, p_dblp + (size_t)SPLITK * MTOT * DBLC,
        MTOT, DBLC, DI, 0, 0, KCHUNK);

    // 6. reduce partials -> dbl_f, dbl_b
    {
        int nthreads = 2 * MTOT * DBLC / 4;
        reduce_dbl_kernel<<<(nthreads + TPB - 1) / TPB, TPB>>>(p_dblp, p_dbl_f, p_dbl_b);
    }

    // 7. delta = softplus(dt @ Wdt^T + 2*bdt)   [2048, 2048]
    tf32_linear_kernel<<<dim3(DI / BN, MTOT / BM), TPB>>>(
        p_dbl_f, DBLC, Wdt, bdt, 2.f, p_delta_f, MTOT, DI, RR, 0, 1, 0);
    tf32_linear_kernel<<<dim3(DI / BN, MTOT / BM), TPB>>>(
        p_dbl_b, DBLC, Wdt_b, bdt_b, 2.f, p_delta_b, MTOT, DI, RR, 0, 1, 0);

    // 8. selective scans (both branches)
    scan_kernel<<<dim3(B_ * DI / SCAN_TPB, 2), SCAN_TPB>>>(
        p_u_f, p_delta_f, p_dbl_f,
        p_u_b, p_delta_b, p_dbl_b,
        A_log, D, A_log_b, D_b,
        p_y_f, p_y_b);

    // 9. gate + rmsnorm
    gate_rms_kernel<<<MTOT, TPB>>>(p_y_f, p_y_b, p_xz_a, norm_w, p_g);

    // 10. out = g @ Wo^T                     [2048, 1024]
    tf32_linear_kernel<<<dim3(DM / BN, MTOT / BM), TPB>>>(
        p_g, DI, Wo, nullptr, 0.f, out, MTOT, DM, DI, 0, 0, 0);
}

// round 6
// speedup vs baseline: 3.2922x; 1.1940x over previous
#include <cuda_runtime.h>
#include <cuda_bf16.h>
#include <cuda_fp16.h>
#include <math.h>
#include <stdint.h>

// Problem constants
#define B_  2
#define L_  1024
#define DM  1024
#define DI  2048
#define NS  16
#define RR  64
#define KC  4
#define MTOT (B_ * L_)      // 2048
#define EPS 1e-5f

#define DBLC (RR + 2 * NS)  // 96
#define SPLITK 8
#define KCHUNK (DI / SPLITK)  // 256

// ---------------------------------------------------------------------------
// Scratch buffers (device globals; no allocation allowed)
// ---------------------------------------------------------------------------
__device__ float g_xz_a[MTOT * (2 * DI)];   // a @ Wi^T  (x | z)
__device__ float g_xz_b[MTOT * DI];         // flip(b) @ Wi[:DI]^T (x only)
__device__ float g_u_f[MTOT * DI];          // silu(conv(x_f))
__device__ float g_u_b[MTOT * DI];
__device__ float g_dblp[2 * SPLITK * MTOT * DBLC];  // split-K partials
__device__ float g_dbl_f[MTOT * DBLC];      // u @ Wx^T (dt|B|C), 96 cols
__device__ float g_dbl_b[MTOT * DBLC];
__device__ float g_delta_f[MTOT * DI];
__device__ float g_delta_b[MTOT * DI];
__device__ float g_y_f[MTOT * DI];
__device__ float g_y_b[MTOT * DI];          // in flipped time
__device__ float g_g[MTOT * DI];            // gated + rmsnorm

// ---------------------------------------------------------------------------
// fp16 tensor-core GEMM (mma.sync m16n8k16, fp32 accumulate):
//   C[m,n] = act( sum_{k in chunk} A'[m,k] * W[n,k] + biasScale*bias[n] )
//   A row-major fp32 (row stride lda); f32->f16 converted inline on load.
//   A' = optionally L-flipped rows within batch of 1024.
//   W row-major fp32 [Nn, Kd]; C row-major fp32 [M, Nn].
//   kchunk > 0: split-K; blockIdx.z picks chunk, C offset by z*M*Nn.
//   Block tile 128x128, BK=32, 256 threads, warp tile 32x64.
// ---------------------------------------------------------------------------
#define BM 128
#define BN 128
#define BK 32
#define BKP 40   // padded row length in halves (80B stride: ldmatrix conflict-free)

__device__ __forceinline__ uint32_t smem_u32(const void* p) {
    uint32_t a;
    asm("{ .reg .u64 t; cvta.to.shared.u64 t, %1; cvt.u32.u64 %0, t; }"
        : "=r"(a) : "l"(p));
    return a;
}

__device__ __forceinline__ void ldsm4(uint32_t& r0, uint32_t& r1,
                                      uint32_t& r2, uint32_t& r3, uint32_t addr) {
    asm volatile("ldmatrix.sync.aligned.m8n8.x4.shared.b16 {%0,%1,%2,%3}, [%4];"
                 : "=r"(r0), "=r"(r1), "=r"(r2), "=r"(r3) : "r"(addr));
}

__device__ __forceinline__ void mma_f16(float c[4], const uint32_t a[4],
                                        const uint32_t b[2]) {
    asm volatile(
        "mma.sync.aligned.m16n8k16.row.col.f32.f16.f16.f32 "
        "{%0,%1,%2,%3}, {%4,%5,%6,%7}, {%8,%9}, {%0,%1,%2,%3};"
        : "+f"(c[0]), "+f"(c[1]), "+f"(c[2]), "+f"(c[3])
        : "r"(a[0]), "r"(a[1]), "r"(a[2]), "r"(a[3]), "r"(b[0]), "r"(b[1]));
}

// load 16 consecutive fp32, convert to 16 halves (8 packed half2)
__device__ __forceinline__ void ld_cvt16(const float* gp, uint32_t h[8]) {
#pragma unroll
    for (int q = 0; q < 4; q++) {
        float4 v = *(const float4*)(gp + 4 * q);
        __half2 p0 = __floats2half2_rn(v.x, v.y);
        __half2 p1 = __floats2half2_rn(v.z, v.w);
        h[2 * q]     = *(uint32_t*)&p0;
        h[2 * q + 1] = *(uint32_t*)&p1;
    }
}

__global__ __launch_bounds__(256, 2)
void h_linear_kernel(const float* __restrict__ A, int lda,
                     const float* __restrict__ W,
                     const float* __restrict__ bias, float biasScale,
                     float* __restrict__ C,
                     int M, int Nn, int Kd, int flip, int act, int kchunk)
{
    __shared__ uint16_t As[2][BM][BKP];
    __shared__ uint16_t Bs[2][BN][BKP];

    const int tid  = threadIdx.x;
    const int lane = tid & 31;
    const int warp = tid >> 5;
    const int g    = lane >> 2;
    const int tg   = lane & 3;
    const int warpM = (warp & 3) * 32;
    const int warpN = (warp >> 2) * 64;
    const int row0 = blockIdx.y * BM;
    const int col0 = blockIdx.x * BN;

    int kb = 0, klen = Kd;
    if (kchunk > 0) {
        kb   = blockIdx.z * kchunk;
        klen = kchunk;
        C   += (size_t)blockIdx.z * M * Nn;
    }

    // gmem-load coords: each thread loads 16 floats of A and 16 of B per tile
    const int ld_r = tid >> 1;            // 0..127
    const int ld_s = (tid & 1) * 16;      // k segment 0 / 16

    // ldmatrix lane decomposition
    const int tquad = lane >> 3;
    const int trow  = lane & 7;
    const int a_m = ((tquad & 1) << 3) + trow;   // A: tiles (m8, k8) ordered m-first
    const int a_k = (tquad >> 1) << 3;
    const int b_n = ((tquad >> 1) << 3) + trow;  // B: tiles ordered k-first
    const int b_k = (tquad & 1) << 3;

    float acc[2][8][4];
#pragma unroll
    for (int mi = 0; mi < 2; mi++)
#pragma unroll
        for (int ni = 0; ni < 8; ni++)
#pragma unroll
            for (int q = 0; q < 4; q++) acc[mi][ni][q] = 0.f;

    const int ntiles = klen / BK;

    int arow;
    {
        int grow = row0 + ld_r;
        if (flip) { int bb = grow >> 10; int l = grow & 1023; grow = (bb << 10) + (1023 - l); }
        arow = grow;
    }
    const int wrow = col0 + ld_r;
    const bool wok = (wrow < Nn);

    const uint32_t sA = smem_u32(&As[0][0][0]);
    const uint32_t sB = smem_u32(&Bs[0][0][0]);
    constexpr uint32_t STG = BM * BKP * 2;   // bytes per stage

    uint32_t ha[8], hb[8];

    // ---- prologue: tile 0
    {
        ld_cvt16(A + (size_t)arow * lda + kb + ld_s, ha);
        if (wok) ld_cvt16(W + (size_t)wrow * Kd + kb + ld_s, hb);
        else {
#pragma unroll
            for (int q = 0; q < 8; q++) hb[q] = 0u;
        }
        *(uint4*)&As[0][ld_r][ld_s]     = make_uint4(ha[0], ha[1], ha[2], ha[3]);
        *(uint4*)&As[0][ld_r][ld_s + 8] = make_uint4(ha[4], ha[5], ha[6], ha[7]);
        *(uint4*)&Bs[0][ld_r][ld_s]     = make_uint4(hb[0], hb[1], hb[2], hb[3]);
        *(uint4*)&Bs[0][ld_r][ld_s + 8] = make_uint4(hb[4], hb[5], hb[6], hb[7]);
    }
    __syncthreads();

    int cur = 0;
    for (int t = 0; t < ntiles; t++) {
        const bool has_next = (t + 1 < ntiles);
        if (has_next) {
            const int k0 = kb + (t + 1) * BK;
            ld_cvt16(A + (size_t)arow * lda + k0 + ld_s, ha);
            if (wok) ld_cvt16(W + (size_t)wrow * Kd + k0 + ld_s, hb);
        }

        // ---- compute on stage cur: two k16 steps
#pragma unroll
        for (int kk = 0; kk < 2; kk++) {
            const uint32_t kbyte = (uint32_t)(kk * 16) * 2;
            uint32_t af[2][4], bf[8][2];
#pragma unroll
            for (int mi = 0; mi < 2; mi++) {
                uint32_t addr = sA + cur * STG
                              + (uint32_t)(warpM + mi * 16 + a_m) * (BKP * 2)
                              + kbyte + (uint32_t)a_k * 2;
                ldsm4(af[mi][0], af[mi][1], af[mi][2], af[mi][3], addr);
            }
#pragma unroll
            for (int nj = 0; nj < 4; nj++) {
                uint32_t addr = sB + cur * STG
                              + (uint32_t)(warpN + nj * 16 + b_n) * (BKP * 2)
                              + kbyte + (uint32_t)b_k * 2;
                ldsm4(bf[2 * nj][0], bf[2 * nj][1], bf[2 * nj + 1][0], bf[2 * nj + 1][1], addr);
            }
#pragma unroll
            for (int mi = 0; mi < 2; mi++)
#pragma unroll
                for (int ni = 0; ni < 8; ni++)
                    mma_f16(acc[mi][ni], af[mi], bf[ni]);
        }

        if (has_next) {
            const int nxt = cur ^ 1;
            if (!wok) {
#pragma unroll
                for (int q = 0; q < 8; q++) hb[q] = 0u;
            }
            __syncthreads();
            *(uint4*)&As[nxt][ld_r][ld_s]     = make_uint4(ha[0], ha[1], ha[2], ha[3]);
            *(uint4*)&As[nxt][ld_r][ld_s + 8] = make_uint4(ha[4], ha[5], ha[6], ha[7]);
            *(uint4*)&Bs[nxt][ld_r][ld_s]     = make_uint4(hb[0], hb[1], hb[2], hb[3]);
            *(uint4*)&Bs[nxt][ld_r][ld_s + 8] = make_uint4(hb[4], hb[5], hb[6], hb[7]);
            __syncthreads();
            cur = nxt;
        }
    }

    // ---- epilogue
#pragma unroll
    for (int mi = 0; mi < 2; mi++) {
        int r0 = row0 + warpM + mi * 16 + g;
#pragma unroll
        for (int ni = 0; ni < 8; ni++) {
            int cb = col0 + warpN + ni * 8 + 2 * tg;
            if (cb < Nn) {
                float v00 = acc[mi][ni][0], v01 = acc[mi][ni][1];
                float v10 = acc[mi][ni][2], v11 = acc[mi][ni][3];
                if (bias) {
                    float b0 = biasScale * bias[cb];
                    float b1 = biasScale * bias[cb + 1];
                    v00 += b0; v01 += b1; v10 += b0; v11 += b1;
                }
                if (act == 1) {  // softplus
                    v00 = (v00 > 20.f) ? v00 : log1pf(expf(v00));
                    v01 = (v01 > 20.f) ? v01 : log1pf(expf(v01));
                    v10 = (v10 > 20.f) ? v10 : log1pf(expf(v10));
                    v11 = (v11 > 20.f) ? v11 : log1pf(expf(v11));
                }
                *(float2*)(C + (size_t)r0 * Nn + cb)       = make_float2(v00, v01);
                *(float2*)(C + (size_t)(r0 + 8) * Nn + cb) = make_float2(v10, v11);
            }
        }
    }
}

// ---------------------------------------------------------------------------
// Reduce split-K partials
// ---------------------------------------------------------------------------
__global__ void reduce_dbl_kernel(const float* __restrict__ part,
                                  float* __restrict__ of,
                                  float* __restrict__ ob)
{
    const int NV = MTOT * DBLC / 4;
    int i = blockIdx.x * blockDim.x + threadIdx.x;
    if (i >= 2 * NV) return;
    int br = (i >= NV);
    int j  = i - br * NV;
    const float4* p = (const float4*)part + (size_t)br * SPLITK * NV + j;
    float4 s = make_float4(0.f, 0.f, 0.f, 0.f);
#pragma unroll
    for (int k = 0; k < SPLITK; k++) {
        float4 v = p[(size_t)k * NV];
        s.x += v.x; s.y += v.y; s.z += v.z; s.w += v.w;
    }
    ((float4*)(br ? ob : of))[j] = s;
}

// ---------------------------------------------------------------------------
// Depthwise causal conv1d (K=4) + bias + SiLU; both branches (blockIdx.z)
// ---------------------------------------------------------------------------
__global__ void conv_silu_kernel(const float* __restrict__ x0, int ld0,
                                 const float* __restrict__ w0,
                                 const float* __restrict__ b0,
                                 float* __restrict__ u0,
                                 const float* __restrict__ x1, int ld1,
                                 const float* __restrict__ w1,
                                 const float* __restrict__ b1,
                                 float* __restrict__ u1)
{
    const int br = blockIdx.z;
    const float* __restrict__ x = br ? x1 : x0;
    const float* __restrict__ w = br ? w1 : w0;
    const float* __restrict__ bi = br ? b1 : b0;
    float* __restrict__ u = br ? u1 : u0;
    const int ldx = br ? ld1 : ld0;

    int idx = blockIdx.x * blockDim.x + threadIdx.x;
    if (idx >= MTOT * DI) return;
    int d   = idx % DI;
    int row = idx / DI;
    int l   = row & (L_ - 1);

    float acc = bi[d];
#pragma unroll
    for (int k = 0; k < KC; k++) {
        int ls = l + k - (KC - 1);
        if (ls >= 0) {
            acc = fmaf(x[(size_t)(row + k - (KC - 1)) * ldx + d], w[d * KC + k], acc);
        }
    }
    float s = 1.f / (1.f + __expf(-acc));
    u[idx] = acc * s;
}

// ---------------------------------------------------------------------------
// Selective scan, both branches in one launch (blockIdx.y selects branch)
// ---------------------------------------------------------------------------
#define SCAN_TPB 128
#define SCAN_CH  16

__global__ __launch_bounds__(SCAN_TPB, 1)
void scan_kernel(const float* __restrict__ u_f, const float* __restrict__ del_f,
                 const float* __restrict__ dbl_f,
                 const float* __restrict__ u_b, const float* __restrict__ del_b,
                 const float* __restrict__ dbl_b,
                 const float* __restrict__ A_log_f, const float* __restrict__ D_f,
                 const float* __restrict__ A_log_b, const float* __restrict__ D_b,
                 float* __restrict__ y_f, float* __restrict__ y_b)
{
    const int br = blockIdx.y;
    const float* __restrict__ u    = br ? u_b   : u_f;
    const float* __restrict__ del  = br ? del_b : del_f;
    const float* __restrict__ dbl  = br ? dbl_b : dbl_f;
    const float* __restrict__ Alog = br ? A_log_b : A_log_f;
    const float* __restrict__ Dv_p = br ? D_b  : D_f;
    float* __restrict__ yout       = br ? y_b  : y_f;

    const int tid   = threadIdx.x;
    const int dpart = blockIdx.x % (DI / SCAN_TPB);
    const int bb    = blockIdx.x / (DI / SCAN_TPB);
    const int d     = dpart * SCAN_TPB + tid;
    const int dbase = dpart * SCAN_TPB;

    float a[NS];
    bool fast = true;
#pragma unroll
    for (int n = 0; n < NS; n++) {
        a[n] = expf(Alog[(size_t)d * NS + n]);
        fast = fast && (fabsf(a[n] - (float)(n + 1)) < 1e-4f * (float)(n + 1));
    }
    const float Dv = Dv_p[d];

    float h[NS];
#pragma unroll
    for (int n = 0; n < NS; n++) h[n] = 0.f;

    __shared__ float  s_del[SCAN_CH][SCAN_TPB];
    __shared__ float  s_u[SCAN_CH][SCAN_TPB];
    __shared__ float4 s_bc[SCAN_CH][8];

    for (int c0 = 0; c0 < L_; c0 += SCAN_CH) {
        __syncthreads();
#pragma unroll
        for (int k = 0; k < SCAN_CH; k++) {
            size_t off = (size_t)(bb * L_ + c0 + k) * DI + dbase + tid;
            s_del[k][tid] = del[off];
            s_u[k][tid]   = u[off];
        }
        {
            int k = tid >> 3;
            int q = tid & 7;
            size_t off = (size_t)(bb * L_ + c0 + k) * DBLC + RR + q * 4;
            s_bc[k][q] = *(const float4*)(dbl + off);
        }
        __syncthreads();

        if (fast) {
#pragma unroll 2
            for (int k = 0; k < SCAN_CH; k++) {
                float dl = s_del[k][tid];
                float uu = s_u[k][tid];
                float du = dl * uu;
                float e  = __expf(-dl);
                float4 V0 = s_bc[k][0], V1 = s_bc[k][1], V2 = s_bc[k][2], V3 = s_bc[k][3];
                float4 W0 = s_bc[k][4], W1 = s_bc[k][5], W2 = s_bc[k][6], W3 = s_bc[k][7];
                float Bv[NS] = {V0.x,V0.y,V0.z,V0.w, V1.x,V1.y,V1.z,V1.w,
                                V2.x,V2.y,V2.z,V2.w, V3.x,V3.y,V3.z,V3.w};
                float Cv[NS] = {W0.x,W0.y,W0.z,W0.w, W1.x,W1.y,W1.z,W1.w,
                                W2.x,W2.y,W2.z,W2.w, W3.x,W3.y,W3.z,W3.w};
                float p  = e;
                float yv0 = 0.f, yv1 = 0.f;
#pragma unroll
                for (int n = 0; n < NS; n++) {
                    h[n] = fmaf(p, h[n], du * Bv[n]);
                    if (n & 1) yv1 = fmaf(h[n], Cv[n], yv1);
                    else       yv0 = fmaf(h[n], Cv[n], yv0);
                    p   *= e;
                }
                float yv = fmaf(uu, Dv, yv0 + yv1);
                yout[(size_t)(bb * L_ + c0 + k) * DI + d] = yv;
            }
        } else {
            for (int k = 0; k < SCAN_CH; k++) {
                float dl = s_del[k][tid];
                float uu = s_u[k][tid];
                float du = dl * uu;
                float yv = 0.f;
                const float* bc = (const float*)s_bc[k];
#pragma unroll
                for (int n = 0; n < NS; n++) {
                    float dA = __expf(-dl * a[n]);
                    h[n] = fmaf(dA, h[n], du * bc[n]);
                    yv   = fmaf(h[n], bc[NS + n], yv);
                }
                yv = fmaf(uu, Dv, yv);
                yout[(size_t)(bb * L_ + c0 + k) * DI + d] = yv;
            }
        }
    }
}

// ---------------------------------------------------------------------------
// Gate (y * silu(z)) + RMSNorm * norm_w, one block per row
// ---------------------------------------------------------------------------
__global__ __launch_bounds__(256)
void gate_rms_kernel(const float* __restrict__ yf, const float* __restrict__ yb,
                     const float* __restrict__ xz, const float* __restrict__ nw,
                     float* __restrict__ g)
{
    const int row = blockIdx.x;
    const int l   = row & (L_ - 1);
    const int bb  = row >> 10;
    const int frow = (bb << 10) + (L_ - 1 - l);
    const int tid = threadIdx.x;

    __shared__ float sg[DI];
    __shared__ float red[8];

    float ss = 0.f;
    for (int d = tid; d < DI; d += 256) {
        float y  = yf[(size_t)row * DI + d] + yb[(size_t)frow * DI + d];
        float z  = xz[(size_t)row * (2 * DI) + DI + d];
        float sz = z / (1.f + __expf(-z));
        float gg = y * sz;
        sg[d] = gg;
        ss = fmaf(gg, gg, ss);
    }
#pragma unroll
    for (int o = 16; o; o >>= 1) ss += __shfl_xor_sync(0xFFFFFFFFu, ss, o);
    if ((tid & 31) == 0) red[tid >> 5] = ss;
    __syncthreads();
    float total = red[0] + red[1] + red[2] + red[3] + red[4] + red[5] + red[6] + red[7];
    float scale = rsqrtf(total / (float)DI + EPS);

    for (int d = tid; d < DI; d += 256) {
        g[(size_t)row * DI + d] = sg[d] * scale * nw[d];
    }
}

// ---------------------------------------------------------------------------
// Launch
// ---------------------------------------------------------------------------
extern "C" void kernel_launch(void* const* d_in, const int* in_sizes, int n_in,
                              void* d_out, int out_size)
{
    (void)in_sizes; (void)n_in; (void)out_size;
    const float* a       = (const float*)d_in[0];
    const float* b       = (const float*)d_in[1];
    const float* Wi      = (const float*)d_in[2];
    const float* conv_w  = (const float*)d_in[3];
    const float* conv_b  = (const float*)d_in[4];
    const float* Wx      = (const float*)d_in[5];
    const float* Wdt     = (const float*)d_in[6];
    const float* bdt     = (const float*)d_in[7];
    const float* A_log   = (const float*)d_in[8];
    const float* D       = (const float*)d_in[9];
    const float* conv_w_b = (const float*)d_in[10];
    const float* conv_b_b = (const float*)d_in[11];
    const float* Wx_b    = (const float*)d_in[12];
    const float* Wdt_b   = (const float*)d_in[13];
    const float* bdt_b   = (const float*)d_in[14];
    const float* A_log_b = (const float*)d_in[15];
    const float* D_b     = (const float*)d_in[16];
    const float* Wo      = (const float*)d_in[17];
    const float* norm_w  = (const float*)d_in[18];
    float* out = (float*)d_out;

    float *p_xz_a, *p_xz_b, *p_u_f, *p_u_b, *p_dblp, *p_dbl_f, *p_dbl_b;
    float *p_delta_f, *p_delta_b, *p_y_f, *p_y_b, *p_g;
    cudaGetSymbolAddress((void**)&p_xz_a, g_xz_a);
    cudaGetSymbolAddress((void**)&p_xz_b, g_xz_b);
    cudaGetSymbolAddress((void**)&p_u_f, g_u_f);
    cudaGetSymbolAddress((void**)&p_u_b, g_u_b);
    cudaGetSymbolAddress((void**)&p_dblp, g_dblp);
    cudaGetSymbolAddress((void**)&p_dbl_f, g_dbl_f);
    cudaGetSymbolAddress((void**)&p_dbl_b, g_dbl_b);
    cudaGetSymbolAddress((void**)&p_delta_f, g_delta_f);
    cudaGetSymbolAddress((void**)&p_delta_b, g_delta_b);
    cudaGetSymbolAddress((void**)&p_y_f, g_y_f);
    cudaGetSymbolAddress((void**)&p_y_b, g_y_b);
    cudaGetSymbolAddress((void**)&p_g, g_g);

    const int TPB = 256;

    // 1. xz_a = a @ Wi^T                     [2048, 4096]
    h_linear_kernel<<<dim3((2 * DI) / BN, MTOT / BM), TPB>>>(
        a, DM, Wi, nullptr, 0.f, p_xz_a, MTOT, 2 * DI, DM, 0, 0, 0);

    // 2. xz_b = flip(b) @ Wi[:DI]^T          [2048, 2048]
    h_linear_kernel<<<dim3(DI / BN, MTOT / BM), TPB>>>(
        b, DM, Wi, nullptr, 0.f, p_xz_b, MTOT, DI, DM, 1, 0, 0);

    // 3. conv + silu (both branches, z-dim)
    conv_silu_kernel<<<dim3((MTOT * DI + TPB - 1) / TPB, 1, 2), TPB>>>(
        p_xz_a, 2 * DI, conv_w, conv_b, p_u_f,
        p_xz_b, DI, conv_w_b, conv_b_b, p_u_b);

    // 4/5. dbl = u @ Wx^T  [2048, 96], split-K
    h_linear_kernel<<<dim3(1, MTOT / BM, SPLITK), TPB>>>(
        p_u_f, DI, Wx, nullptr, 0.f, p_dblp, MTOT, DBLC, DI, 0, 0, KCHUNK);
    h_linear_kernel<<<dim3(1, MTOT / BM, SPLITK), TPB>>>(
        p_u_b, DI, Wx_b, nullptr, 0.f, p_dblp + (size_t)SPLITK * MTOT * DBLC,
        MTOT, DBLC, DI, 0, 0, KCHUNK);

    // 6. reduce partials -> dbl_f, dbl_b
    {
        int nthreads = 2 * MTOT * DBLC / 4;
        reduce_dbl_kernel<<<(nthreads + TPB - 1) / TPB, TPB>>>(p_dblp, p_dbl_f, p_dbl_b);
    }

    // 7. delta = softplus(dt @ Wdt^T + 2*bdt)   [2048, 2048]
    h_linear_kernel<<<dim3(DI / BN, MTOT / BM), TPB>>>(
        p_dbl_f, DBLC, Wdt, bdt, 2.f, p_delta_f, MTOT, DI, RR, 0, 1, 0);
    h_linear_kernel<<<dim3(DI / BN, MTOT / BM), TPB>>>(
        p_dbl_b, DBLC, Wdt_b, bdt_b, 2.f, p_delta_b, MTOT, DI, RR, 0, 1, 0);

    // 8. selective scans (both branches)
    scan_kernel<<<dim3(B_ * DI / SCAN_TPB, 2), SCAN_TPB>>>(
        p_u_f, p_delta_f, p_dbl_f,
        p_u_b, p_delta_b, p_dbl_b,
        A_log, D, A_log_b, D_b,
        p_y_f, p_y_b);

    // 9. gate + rmsnorm
    gate_rms_kernel<<<MTOT, TPB>>>(p_y_f, p_y_b, p_xz_a, norm_w, p_g);

    // 10. out = g @ Wo^T                     [2048, 1024]
    h_linear_kernel<<<dim3(DM / BN, MTOT / BM), TPB>>>(
        p_g, DI, Wo, nullptr, 0.f, out, MTOT, DM, DI, 0, 0, 0);
}

// round 7
// speedup vs baseline: 4.7068x; 1.4297x over previous
#include <cuda_runtime.h>
#include <cuda_bf16.h>
#include <cuda_fp16.h>
#include <math.h>
#include <stdint.h>

// Problem constants
#define B_  2
#define L_  1024
#define DM  1024
#define DI  2048
#define NS  16
#define RR  64
#define KC  4
#define MTOT (B_ * L_)      // 2048
#define EPS 1e-5f

#define DBLC (RR + 2 * NS)  // 96
#define SPLITK 8
#define KCHUNK (DI / SPLITK)  // 256

// ---------------------------------------------------------------------------
// Scratch buffers (device globals; no allocation allowed)
// ---------------------------------------------------------------------------
__device__ __half g_ha[MTOT * DM];          // fp16 a
__device__ __half g_hb[MTOT * DM];          // fp16 b
__device__ __half g_hWi[(2 * DI) * DM];     // fp16 Wi
__device__ __half g_hWo[DM * DI];           // fp16 Wo
__device__ __half g_hWx[DBLC * DI];         // fp16 Wx
__device__ __half g_hWx_b[DBLC * DI];
__device__ __half g_hWdt[DI * RR];          // fp16 Wdt
__device__ __half g_hWdt_b[DI * RR];
__device__ __half g_hu_f[MTOT * DI];        // fp16 u (GEMM operand)
__device__ __half g_hu_b[MTOT * DI];
__device__ __half g_hdbl_f[MTOT * DBLC];    // fp16 dbl (delta GEMM operand)
__device__ __half g_hdbl_b[MTOT * DBLC];
__device__ __half g_hg[MTOT * DI];          // fp16 g (out GEMM operand)

__device__ float g_xz_a[MTOT * (2 * DI)];   // a @ Wi^T  (x | z)
__device__ float g_xz_b[MTOT * DI];         // flip(b) @ Wi[:DI]^T (x only)
__device__ float g_u_f[MTOT * DI];          // silu(conv(x_f))  (f32 for scan)
__device__ float g_u_b[MTOT * DI];
__device__ float g_dblp[2 * SPLITK * MTOT * DBLC];  // split-K partials
__device__ float g_dbl_f[MTOT * DBLC];      // f32 dbl (scan reads B/C)
__device__ float g_dbl_b[MTOT * DBLC];
__device__ float g_delta_f[MTOT * DI];
__device__ float g_delta_b[MTOT * DI];
__device__ float g_y_f[MTOT * DI];
__device__ float g_y_b[MTOT * DI];          // in flipped time

// ---------------------------------------------------------------------------
// fp16 tensor-core GEMM, cp.async 4-stage pipeline:
//   C[m,n] = act( sum_{k chunk} A'[m,k] * W[n,k] + biasScale*bias[n] )
//   A, W fp16 row-major; C fp32 row-major.
//   flip: A rows L-reversed within batch of 1024.
//   kchunk > 0: split-K; blockIdx.z picks chunk, C offset by z*M*Nn.
//   Block tile 128x128, BK=32, 256 threads, warp tile 32x64.
// ---------------------------------------------------------------------------
#define BM 128
#define BN 128
#define BK 32
#define BKP 40   // padded row in halves (80B stride: ldmatrix conflict-free)
#define STAGES 4
#define STG_BYTES ((BM + BN) * BKP * 2)      // 20480 per stage
#define SMEM_TOTAL (STAGES * STG_BYTES)      // 81920

__device__ __forceinline__ uint32_t smem_u32(const void* p) {
    uint32_t a;
    asm("{ .reg .u64 t; cvta.to.shared.u64 t, %1; cvt.u32.u64 %0, t; }"
        : "=r"(a) : "l"(p));
    return a;
}

__device__ __forceinline__ void ldsm4(uint32_t& r0, uint32_t& r1,
                                      uint32_t& r2, uint32_t& r3, uint32_t addr) {
    asm volatile("ldmatrix.sync.aligned.m8n8.x4.shared.b16 {%0,%1,%2,%3}, [%4];"
                 : "=r"(r0), "=r"(r1), "=r"(r2), "=r"(r3) : "r"(addr));
}

__device__ __forceinline__ void mma_f16(float c[4], const uint32_t a[4],
                                        const uint32_t b[2]) {
    asm volatile(
        "mma.sync.aligned.m16n8k16.row.col.f32.f16.f16.f32 "
        "{%0,%1,%2,%3}, {%4,%5,%6,%7}, {%8,%9}, {%0,%1,%2,%3};"
        : "+f"(c[0]), "+f"(c[1]), "+f"(c[2]), "+f"(c[3])
        : "r"(a[0]), "r"(a[1]), "r"(a[2]), "r"(a[3]), "r"(b[0]), "r"(b[1]));
}

#define CP_ASYNC16(dst, src, sz) \
    asm volatile("cp.async.cg.shared.global [%0], [%1], 16, %2;" \
                 :: "r"(dst), "l"(src), "r"(sz) : "memory")
#define CP_COMMIT() asm volatile("cp.async.commit_group;" ::: "memory")
#define CP_WAIT2()  asm volatile("cp.async.wait_group 2;" ::: "memory")

__global__ __launch_bounds__(256, 2)
void ha_linear_kernel(const __half* __restrict__ A, int lda,
                      const __half* __restrict__ W, int ldw,
                      const float* __restrict__ bias, float biasScale,
                      float* __restrict__ C,
                      int M, int Nn, int Kd, int flip, int act, int kchunk)
{
    extern __shared__ __align__(16) char dsm[];
    const uint32_t sbase = smem_u32(dsm);

    const int tid  = threadIdx.x;
    const int lane = tid & 31;
    const int warp = tid >> 5;
    const int g    = lane >> 2;
    const int tg   = lane & 3;
    const int warpM = (warp & 3) * 32;
    const int warpN = (warp >> 2) * 64;
    const int row0 = blockIdx.y * BM;
    const int col0 = blockIdx.x * BN;

    int kb = 0, klen = Kd;
    if (kchunk > 0) {
        kb   = blockIdx.z * kchunk;
        klen = kchunk;
        C   += (size_t)blockIdx.z * M * Nn;
    }
    const int ntiles = klen / BK;

    // per-thread load units: idx = tid + 256*i (i=0,1): row = idx>>2, chunk = idx&3
    int arow[2], wrow[2];
    uint32_t wsz[2];
#pragma unroll
    for (int i = 0; i < 2; i++) {
        int idx = tid + 256 * i;
        int r   = idx >> 2;
        int gr  = row0 + r;
        if (flip) { gr = (gr & ~(L_ - 1)) + ((L_ - 1) - (gr & (L_ - 1))); }
        arow[i] = gr;
        int gn = col0 + r;
        wsz[i]  = (gn < Nn) ? 16u : 0u;
        wrow[i] = (gn < Nn) ? gn : 0;
    }
    const int ld_row   = tid >> 2;          // unit0 row (unit1: +64)
    const int ld_chunk = (tid & 3) * 8;     // half offset within 32

    // ldmatrix lane decomposition
    const int tquad = lane >> 3;
    const int trow  = lane & 7;
    const int a_m = ((tquad & 1) << 3) + trow;
    const int a_k = (tquad >> 1) << 3;
    const int b_n = ((tquad >> 1) << 3) + trow;
    const int b_k = (tquad & 1) << 3;

    float acc[2][8][4];
#pragma unroll
    for (int mi = 0; mi < 2; mi++)
#pragma unroll
        for (int ni = 0; ni < 8; ni++)
#pragma unroll
            for (int q = 0; q < 4; q++) acc[mi][ni][q] = 0.f;

    // ---- issue loads for tile t into stage s
    auto issue = [&](int t, int s) {
        const uint32_t st = sbase + (uint32_t)s * STG_BYTES;
        const int koff = kb + t * BK + ld_chunk;
#pragma unroll
        for (int i = 0; i < 2; i++) {
            int r = ld_row + 64 * i;
            uint32_t da = st + (uint32_t)r * (BKP * 2) + (uint32_t)ld_chunk * 2;
            CP_ASYNC16(da, A + (size_t)arow[i] * lda + koff, 16u);
        }
#pragma unroll
        for (int i = 0; i < 2; i++) {
            int r = ld_row + 64 * i;
            uint32_t db = st + (uint32_t)(BM * BKP * 2)
                        + (uint32_t)r * (BKP * 2) + (uint32_t)ld_chunk * 2;
            CP_ASYNC16(db, W + (size_t)wrow[i] * ldw + koff, wsz[i]);
        }
    };

    // prologue: stages 0..STAGES-2
#pragma unroll
    for (int s = 0; s < STAGES - 1; s++) {
        if (s < ntiles) issue(s, s);
        CP_COMMIT();
    }

    for (int t = 0; t < ntiles; t++) {
        CP_WAIT2();
        __syncthreads();

        const int tn = t + STAGES - 1;
        if (tn < ntiles) issue(tn, tn & (STAGES - 1));
        CP_COMMIT();

        const uint32_t stA = sbase + (uint32_t)(t & (STAGES - 1)) * STG_BYTES;
        const uint32_t stB = stA + (uint32_t)(BM * BKP * 2);

#pragma unroll
        for (int kk = 0; kk < 2; kk++) {
            const uint32_t kbyte = (uint32_t)(kk * 16) * 2;
            uint32_t af[2][4], bf[8][2];
#pragma unroll
            for (int mi = 0; mi < 2; mi++) {
                uint32_t addr = stA + (uint32_t)(warpM + mi * 16 + a_m) * (BKP * 2)
                              + kbyte + (uint32_t)a_k * 2;
                ldsm4(af[mi][0], af[mi][1], af[mi][2], af[mi][3], addr);
            }
#pragma unroll
            for (int nj = 0; nj < 4; nj++) {
                uint32_t addr = stB + (uint32_t)(warpN + nj * 16 + b_n) * (BKP * 2)
                              + kbyte + (uint32_t)b_k * 2;
                ldsm4(bf[2 * nj][0], bf[2 * nj][1], bf[2 * nj + 1][0], bf[2 * nj + 1][1], addr);
            }
#pragma unroll
            for (int mi = 0; mi < 2; mi++)
#pragma unroll
                for (int ni = 0; ni < 8; ni++)
                    mma_f16(acc[mi][ni], af[mi], bf[ni]);
        }
    }

    // ---- epilogue
#pragma unroll
    for (int mi = 0; mi < 2; mi++) {
        int r0 = row0 + warpM + mi * 16 + g;
#pragma unroll
        for (int ni = 0; ni < 8; ni++) {
            int cb = col0 + warpN + ni * 8 + 2 * tg;
            if (cb < Nn) {
                float v00 = acc[mi][ni][0], v01 = acc[mi][ni][1];
                float v10 = acc[mi][ni][2], v11 = acc[mi][ni][3];
                if (bias) {
                    float b0 = biasScale * bias[cb];
                    float b1 = biasScale * bias[cb + 1];
                    v00 += b0; v01 += b1; v10 += b0; v11 += b1;
                }
                if (act == 1) {  // softplus
                    v00 = (v00 > 20.f) ? v00 : log1pf(expf(v00));
                    v01 = (v01 > 20.f) ? v01 : log1pf(expf(v01));
                    v10 = (v10 > 20.f) ? v10 : log1pf(expf(v10));
                    v11 = (v11 > 20.f) ? v11 : log1pf(expf(v11));
                }
                *(float2*)(C + (size_t)r0 * Nn + cb)       = make_float2(v00, v01);
                *(float2*)(C + (size_t)(r0 + 8) * Nn + cb) = make_float2(v10, v11);
            }
        }
    }
}

// ---------------------------------------------------------------------------
// f32 -> f16 conversion (8 elems/thread)
// ---------------------------------------------------------------------------
__global__ void cvt_half_kernel(const float* __restrict__ s,
                                __half* __restrict__ d, int n)
{
    int i = (blockIdx.x * blockDim.x + threadIdx.x) * 8;
    if (i < n) {
        float4 v0 = *(const float4*)(s + i);
        float4 v1 = *(const float4*)(s + i + 4);
        __half2 h0 = __floats2half2_rn(v0.x, v0.y);
        __half2 h1 = __floats2half2_rn(v0.z, v0.w);
        __half2 h2 = __floats2half2_rn(v1.x, v1.y);
        __half2 h3 = __floats2half2_rn(v1.z, v1.w);
        *(uint4*)(d + i) = make_uint4(*(uint32_t*)&h0, *(uint32_t*)&h1,
                                      *(uint32_t*)&h2, *(uint32_t*)&h3);
    }
}

// ---------------------------------------------------------------------------
// Reduce split-K partials; writes f32 (scan) + fp16 (delta GEMM operand)
// ---------------------------------------------------------------------------
__global__ void reduce_dbl_kernel(const float* __restrict__ part,
                                  float* __restrict__ of, float* __restrict__ ob,
                                  __half* __restrict__ hf, __half* __restrict__ hb)
{
    const int NV = MTOT * DBLC / 4;
    int i = blockIdx.x * blockDim.x + threadIdx.x;
    if (i >= 2 * NV) return;
    int br = (i >= NV);
    int j  = i - br * NV;
    const float4* p = (const float4*)part + (size_t)br * SPLITK * NV + j;
    float4 s = make_float4(0.f, 0.f, 0.f, 0.f);
#pragma unroll
    for (int k = 0; k < SPLITK; k++) {
        float4 v = p[(size_t)k * NV];
        s.x += v.x; s.y += v.y; s.z += v.z; s.w += v.w;
    }
    ((float4*)(br ? ob : of))[j] = s;
    __half2 h0 = __floats2half2_rn(s.x, s.y);
    __half2 h1 = __floats2half2_rn(s.z, s.w);
    ((uint2*)(br ? hb : hf))[j] = make_uint2(*(uint32_t*)&h0, *(uint32_t*)&h1);
}

// ---------------------------------------------------------------------------
// Depthwise causal conv1d (K=4) + bias + SiLU; writes f32 + fp16 u
// ---------------------------------------------------------------------------
__global__ void conv_silu_kernel(const float* __restrict__ x0, int ld0,
                                 const float* __restrict__ w0,
                                 const float* __restrict__ b0,
                                 float* __restrict__ u0, __half* __restrict__ h0,
                                 const float* __restrict__ x1, int ld1,
                                 const float* __restrict__ w1,
                                 const float* __restrict__ b1,
                                 float* __restrict__ u1, __half* __restrict__ h1)
{
    const int br = blockIdx.z;
    const float* __restrict__ x = br ? x1 : x0;
    const float* __restrict__ w = br ? w1 : w0;
    const float* __restrict__ bi = br ? b1 : b0;
    float* __restrict__ u  = br ? u1 : u0;
    __half* __restrict__ hu = br ? h1 : h0;
    const int ldx = br ? ld1 : ld0;

    int idx = blockIdx.x * blockDim.x + threadIdx.x;
    if (idx >= MTOT * DI) return;
    int d   = idx % DI;
    int row = idx / DI;
    int l   = row & (L_ - 1);

    float acc = bi[d];
#pragma unroll
    for (int k = 0; k < KC; k++) {
        int ls = l + k - (KC - 1);
        if (ls >= 0) {
            acc = fmaf(x[(size_t)(row + k - (KC - 1)) * ldx + d], w[d * KC + k], acc);
        }
    }
    float s = 1.f / (1.f + __expf(-acc));
    float v = acc * s;
    u[idx]  = v;
    hu[idx] = __float2half_rn(v);
}

// ---------------------------------------------------------------------------
// Selective scan, both branches in one launch (blockIdx.y selects branch)
// ---------------------------------------------------------------------------
#define SCAN_TPB 128
#define SCAN_CH  16

__global__ __launch_bounds__(SCAN_TPB, 1)
void scan_kernel(const float* __restrict__ u_f, const float* __restrict__ del_f,
                 const float* __restrict__ dbl_f,
                 const float* __restrict__ u_b, const float* __restrict__ del_b,
                 const float* __restrict__ dbl_b,
                 const float* __restrict__ A_log_f, const float* __restrict__ D_f,
                 const float* __restrict__ A_log_b, const float* __restrict__ D_b,
                 float* __restrict__ y_f, float* __restrict__ y_b)
{
    const int br = blockIdx.y;
    const float* __restrict__ u    = br ? u_b   : u_f;
    const float* __restrict__ del  = br ? del_b : del_f;
    const float* __restrict__ dbl  = br ? dbl_b : dbl_f;
    const float* __restrict__ Alog = br ? A_log_b : A_log_f;
    const float* __restrict__ Dv_p = br ? D_b  : D_f;
    float* __restrict__ yout       = br ? y_b  : y_f;

    const int tid   = threadIdx.x;
    const int dpart = blockIdx.x % (DI / SCAN_TPB);
    const int bb    = blockIdx.x / (DI / SCAN_TPB);
    const int d     = dpart * SCAN_TPB + tid;
    const int dbase = dpart * SCAN_TPB;

    float a[NS];
    bool fast = true;
#pragma unroll
    for (int n = 0; n < NS; n++) {
        a[n] = expf(Alog[(size_t)d * NS + n]);
        fast = fast && (fabsf(a[n] - (float)(n + 1)) < 1e-4f * (float)(n + 1));
    }
    const float Dv = Dv_p[d];

    float h[NS];
#pragma unroll
    for (int n = 0; n < NS; n++) h[n] = 0.f;

    __shared__ float  s_del[SCAN_CH][SCAN_TPB];
    __shared__ float  s_u[SCAN_CH][SCAN_TPB];
    __shared__ float4 s_bc[SCAN_CH][8];

    for (int c0 = 0; c0 < L_; c0 += SCAN_CH) {
        __syncthreads();
#pragma unroll
        for (int k = 0; k < SCAN_CH; k++) {
            size_t off = (size_t)(bb * L_ + c0 + k) * DI + dbase + tid;
            s_del[k][tid] = del[off];
            s_u[k][tid]   = u[off];
        }
        {
            int k = tid >> 3;
            int q = tid & 7;
            size_t off = (size_t)(bb * L_ + c0 + k) * DBLC + RR + q * 4;
            s_bc[k][q] = *(const float4*)(dbl + off);
        }
        __syncthreads();

        if (fast) {
#pragma unroll 2
            for (int k = 0; k < SCAN_CH; k++) {
                float dl = s_del[k][tid];
                float uu = s_u[k][tid];
                float du = dl * uu;
                float e  = __expf(-dl);
                float4 V0 = s_bc[k][0], V1 = s_bc[k][1], V2 = s_bc[k][2], V3 = s_bc[k][3];
                float4 W0 = s_bc[k][4], W1 = s_bc[k][5], W2 = s_bc[k][6], W3 = s_bc[k][7];
                float Bv[NS] = {V0.x,V0.y,V0.z,V0.w, V1.x,V1.y,V1.z,V1.w,
                                V2.x,V2.y,V2.z,V2.w, V3.x,V3.y,V3.z,V3.w};
                float Cv[NS] = {W0.x,W0.y,W0.z,W0.w, W1.x,W1.y,W1.z,W1.w,
                                W2.x,W2.y,W2.z,W2.w, W3.x,W3.y,W3.z,W3.w};
                float p  = e;
                float yv0 = 0.f, yv1 = 0.f;
#pragma unroll
                for (int n = 0; n < NS; n++) {
                    h[n] = fmaf(p, h[n], du * Bv[n]);
                    if (n & 1) yv1 = fmaf(h[n], Cv[n], yv1);
                    else       yv0 = fmaf(h[n], Cv[n], yv0);
                    p   *= e;
                }
                float yv = fmaf(uu, Dv, yv0 + yv1);
                yout[(size_t)(bb * L_ + c0 + k) * DI + d] = yv;
            }
        } else {
            for (int k = 0; k < SCAN_CH; k++) {
                float dl = s_del[k][tid];
                float uu = s_u[k][tid];
                float du = dl * uu;
                float yv = 0.f;
                const float* bc = (const float*)s_bc[k];
#pragma unroll
                for (int n = 0; n < NS; n++) {
                    float dA = __expf(-dl * a[n]);
                    h[n] = fmaf(dA, h[n], du * bc[n]);
                    yv   = fmaf(h[n], bc[NS + n], yv);
                }
                yv = fmaf(uu, Dv, yv);
                yout[(size_t)(bb * L_ + c0 + k) * DI + d] = yv;
            }
        }
    }
}

// ---------------------------------------------------------------------------
// Gate (y * silu(z)) + RMSNorm * norm_w; writes fp16 g (GEMM operand)
// ---------------------------------------------------------------------------
__global__ __launch_bounds__(256)
void gate_rms_kernel(const float* __restrict__ yf, const float* __restrict__ yb,
                     const float* __restrict__ xz, const float* __restrict__ nw,
                     __half* __restrict__ g)
{
    const int row = blockIdx.x;
    const int l   = row & (L_ - 1);
    const int bb  = row >> 10;
    const int frow = (bb << 10) + (L_ - 1 - l);
    const int tid = threadIdx.x;

    __shared__ float sg[DI];
    __shared__ float red[8];

    float ss = 0.f;
    for (int d = tid; d < DI; d += 256) {
        float y  = yf[(size_t)row * DI + d] + yb[(size_t)frow * DI + d];
        float z  = xz[(size_t)row * (2 * DI) + DI + d];
        float sz = z / (1.f + __expf(-z));
        float gg = y * sz;
        sg[d] = gg;
        ss = fmaf(gg, gg, ss);
    }
#pragma unroll
    for (int o = 16; o; o >>= 1) ss += __shfl_xor_sync(0xFFFFFFFFu, ss, o);
    if ((tid & 31) == 0) red[tid >> 5] = ss;
    __syncthreads();
    float total = red[0] + red[1] + red[2] + red[3] + red[4] + red[5] + red[6] + red[7];
    float scale = rsqrtf(total / (float)DI + EPS);

    for (int d = tid; d < DI; d += 256) {
        g[(size_t)row * DI + d] = __float2half_rn(sg[d] * scale * nw[d]);
    }
}

// ---------------------------------------------------------------------------
// Launch
// ---------------------------------------------------------------------------
extern "C" void kernel_launch(void* const* d_in, const int* in_sizes, int n_in,
                              void* d_out, int out_size)
{
    (void)in_sizes; (void)n_in; (void)out_size;
    const float* a       = (const float*)d_in[0];
    const float* b       = (const float*)d_in[1];
    const float* Wi      = (const float*)d_in[2];
    const float* conv_w  = (const float*)d_in[3];
    const float* conv_b  = (const float*)d_in[4];
    const float* Wx      = (const float*)d_in[5];
    const float* Wdt     = (const float*)d_in[6];
    const float* bdt     = (const float*)d_in[7];
    const float* A_log   = (const float*)d_in[8];
    const float* D       = (const float*)d_in[9];
    const float* conv_w_b = (const float*)d_in[10];
    const float* conv_b_b = (const float*)d_in[11];
    const float* Wx_b    = (const float*)d_in[12];
    const float* Wdt_b   = (const float*)d_in[13];
    const float* bdt_b   = (const float*)d_in[14];
    const float* A_log_b = (const float*)d_in[15];
    const float* D_b     = (const float*)d_in[16];
    const float* Wo      = (const float*)d_in[17];
    const float* norm_w  = (const float*)d_in[18];
    float* out = (float*)d_out;

    __half *p_ha, *p_hb, *p_hWi, *p_hWo, *p_hWx, *p_hWx_b, *p_hWdt, *p_hWdt_b;
    __half *p_hu_f, *p_hu_b, *p_hdbl_f, *p_hdbl_b, *p_hg;
    float *p_xz_a, *p_xz_b, *p_u_f, *p_u_b, *p_dblp, *p_dbl_f, *p_dbl_b;
    float *p_delta_f, *p_delta_b, *p_y_f, *p_y_b;
    cudaGetSymbolAddress((void**)&p_ha, g_ha);
    cudaGetSymbolAddress((void**)&p_hb, g_hb);
    cudaGetSymbolAddress((void**)&p_hWi, g_hWi);
    cudaGetSymbolAddress((void**)&p_hWo, g_hWo);
    cudaGetSymbolAddress((void**)&p_hWx, g_hWx);
    cudaGetSymbolAddress((void**)&p_hWx_b, g_hWx_b);
    cudaGetSymbolAddress((void**)&p_hWdt, g_hWdt);
    cudaGetSymbolAddress((void**)&p_hWdt_b, g_hWdt_b);
    cudaGetSymbolAddress((void**)&p_hu_f, g_hu_f);
    cudaGetSymbolAddress((void**)&p_hu_b, g_hu_b);
    cudaGetSymbolAddress((void**)&p_hdbl_f, g_hdbl_f);
    cudaGetSymbolAddress((void**)&p_hdbl_b, g_hdbl_b);
    cudaGetSymbolAddress((void**)&p_hg, g_hg);
    cudaGetSymbolAddress((void**)&p_xz_a, g_xz_a);
    cudaGetSymbolAddress((void**)&p_xz_b, g_xz_b);
    cudaGetSymbolAddress((void**)&p_u_f, g_u_f);
    cudaGetSymbolAddress((void**)&p_u_b, g_u_b);
    cudaGetSymbolAddress((void**)&p_dblp, g_dblp);
    cudaGetSymbolAddress((void**)&p_dbl_f, g_dbl_f);
    cudaGetSymbolAddress((void**)&p_dbl_b, g_dbl_b);
    cudaGetSymbolAddress((void**)&p_delta_f, g_delta_f);
    cudaGetSymbolAddress((void**)&p_delta_b, g_delta_b);
    cudaGetSymbolAddress((void**)&p_y_f, g_y_f);
    cudaGetSymbolAddress((void**)&p_y_b, g_y_b);

    const int TPB = 256;
    cudaFuncSetAttribute(ha_linear_kernel,
                         cudaFuncAttributeMaxDynamicSharedMemorySize, SMEM_TOTAL);

    // 0. convert inputs/weights to fp16
#define CVT(src, dst, n) cvt_half_kernel<<<((n) / 8 + TPB - 1) / TPB, TPB>>>(src, dst, n)
    CVT(a,     p_ha,     MTOT * DM);
    CVT(b,     p_hb,     MTOT * DM);
    CVT(Wi,    p_hWi,    2 * DI * DM);
    CVT(Wo,    p_hWo,    DM * DI);
    CVT(Wx,    p_hWx,    DBLC * DI);
    CVT(Wx_b,  p_hWx_b,  DBLC * DI);
    CVT(Wdt,   p_hWdt,   DI * RR);
    CVT(Wdt_b, p_hWdt_b, DI * RR);
#undef CVT

    // 1. xz_a = a @ Wi^T                     [2048, 4096]
    ha_linear_kernel<<<dim3((2 * DI) / BN, MTOT / BM), TPB, SMEM_TOTAL>>>(
        p_ha, DM, p_hWi, DM, nullptr, 0.f, p_xz_a, MTOT, 2 * DI, DM, 0, 0, 0);

    // 2. xz_b = flip(b) @ Wi[:DI]^T          [2048, 2048]
    ha_linear_kernel<<<dim3(DI / BN, MTOT / BM), TPB, SMEM_TOTAL>>>(
        p_hb, DM, p_hWi, DM, nullptr, 0.f, p_xz_b, MTOT, DI, DM, 1, 0, 0);

    // 3. conv + silu (both branches, z-dim); writes f32 + fp16 u
    conv_silu_kernel<<<dim3((MTOT * DI + TPB - 1) / TPB, 1, 2), TPB>>>(
        p_xz_a, 2 * DI, conv_w, conv_b, p_u_f, p_hu_f,
        p_xz_b, DI, conv_w_b, conv_b_b, p_u_b, p_hu_b);

    // 4/5. dbl = u @ Wx^T  [2048, 96], split-K
    ha_linear_kernel<<<dim3(1, MTOT / BM, SPLITK), TPB, SMEM_TOTAL>>>(
        p_hu_f, DI, p_hWx, DI, nullptr, 0.f, p_dblp, MTOT, DBLC, DI, 0, 0, KCHUNK);
    ha_linear_kernel<<<dim3(1, MTOT / BM, SPLITK), TPB, SMEM_TOTAL>>>(
        p_hu_b, DI, p_hWx_b, DI, nullptr, 0.f, p_dblp + (size_t)SPLITK * MTOT * DBLC,
        MTOT, DBLC, DI, 0, 0, KCHUNK);

    // 6. reduce partials -> dbl (f32 + fp16)
    {
        int nthreads = 2 * MTOT * DBLC / 4;
        reduce_dbl_kernel<<<(nthreads + TPB - 1) / TPB, TPB>>>(
            p_dblp, p_dbl_f, p_dbl_b, p_hdbl_f, p_hdbl_b);
    }

    // 7. delta = softplus(dt @ Wdt^T + 2*bdt)   [2048, 2048]
    ha_linear_kernel<<<dim3(DI / BN, MTOT / BM), TPB, SMEM_TOTAL>>>(
        p_hdbl_f, DBLC, p_hWdt, RR, bdt, 2.f, p_delta_f, MTOT, DI, RR, 0, 1, 0);
    ha_linear_kernel<<<dim3(DI / BN, MTOT / BM), TPB, SMEM_TOTAL>>>(
        p_hdbl_b, DBLC, p_hWdt_b, RR, bdt_b, 2.f, p_delta_b, MTOT, DI, RR, 0, 1, 0);

    // 8. selective scans (both branches)
    scan_kernel<<<dim3(B_ * DI / SCAN_TPB, 2), SCAN_TPB>>>(
        p_u_f, p_delta_f, p_dbl_f,
        p_u_b, p_delta_b, p_dbl_b,
        A_log, D, A_log_b, D_b,
        p_y_f, p_y_b);

    // 9. gate + rmsnorm (writes fp16 g)
    gate_rms_kernel<<<MTOT, TPB>>>(p_y_f, p_y_b, p_xz_a, norm_w, p_hg);

    // 10. out = g @ Wo^T                     [2048, 1024]
    ha_linear_kernel<<<dim3(DM / BN, MTOT / BM), TPB, SMEM_TOTAL>>>(
        p_hg, DI, p_hWo, DI, nullptr, 0.f, out, MTOT, DM, DI, 0, 0, 0);
}

// round 8
// speedup vs baseline: 5.5630x; 1.1819x over previous
#include <cuda_runtime.h>
#include <cuda_bf16.h>
#include <cuda_fp16.h>
#include <math.h>
#include <stdint.h>

// Problem constants
#define B_  2
#define L_  1024
#define DM  1024
#define DI  2048
#define NS  16
#define RR  64
#define KC  4
#define MTOT (B_ * L_)      // 2048
#define EPS 1e-5f

#define DBLC (RR + 2 * NS)  // 96
#define SPLITK 8
#define KCHUNK (DI / SPLITK)  // 256

#define NCH 8               // scan chunks
#define CH  (L_ / NCH)      // 128 steps per chunk

// ---------------------------------------------------------------------------
// Scratch buffers (device globals; no allocation allowed)
// ---------------------------------------------------------------------------
__device__ __half g_ha[MTOT * DM];
__device__ __half g_hb[MTOT * DM];
__device__ __half g_hWi[(2 * DI) * DM];
__device__ __half g_hWo[DM * DI];
__device__ __half g_hWx[DBLC * DI];
__device__ __half g_hWx_b[DBLC * DI];
__device__ __half g_hWdt[DI * RR];
__device__ __half g_hWdt_b[DI * RR];
__device__ __half g_hu_f[MTOT * DI];
__device__ __half g_hu_b[MTOT * DI];
__device__ __half g_hdbl_f[MTOT * DBLC];
__device__ __half g_hdbl_b[MTOT * DBLC];
__device__ __half g_hg[MTOT * DI];

__device__ float g_xz_a[MTOT * (2 * DI)];
__device__ float g_xz_b[MTOT * DI];
__device__ float g_u_f[MTOT * DI];
__device__ float g_u_b[MTOT * DI];
__device__ float g_dblp[2 * SPLITK * MTOT * DBLC];
__device__ float g_dbl_f[MTOT * DBLC];
__device__ float g_dbl_b[MTOT * DBLC];
__device__ float g_delta_f[MTOT * DI];
__device__ float g_delta_b[MTOT * DI];
__device__ float g_y_f[MTOT * DI];
__device__ float g_y_b[MTOT * DI];
__device__ float g_wop[2 * MTOT * DM];               // Wo split-K partials

// scan chunking state: [br][b][ch][n][d] / [br][b][ch][d]
__device__ float g_hloc[2 * B_ * NCH * NS * DI];
__device__ float g_hin [2 * B_ * NCH * NS * DI];
__device__ float g_psum[2 * B_ * NCH * DI];

// ---------------------------------------------------------------------------
// fp16 tensor-core GEMM, cp.async 4-stage pipeline (unchanged from R7)
// ---------------------------------------------------------------------------
#define BM 128
#define BN 128
#define BK 32
#define BKP 40
#define STAGES 4
#define STG_BYTES ((BM + BN) * BKP * 2)
#define SMEM_TOTAL (STAGES * STG_BYTES)

__device__ __forceinline__ uint32_t smem_u32(const void* p) {
    uint32_t a;
    asm("{ .reg .u64 t; cvta.to.shared.u64 t, %1; cvt.u32.u64 %0, t; }"
        : "=r"(a) : "l"(p));
    return a;
}

__device__ __forceinline__ void ldsm4(uint32_t& r0, uint32_t& r1,
                                      uint32_t& r2, uint32_t& r3, uint32_t addr) {
    asm volatile("ldmatrix.sync.aligned.m8n8.x4.shared.b16 {%0,%1,%2,%3}, [%4];"
                 : "=r"(r0), "=r"(r1), "=r"(r2), "=r"(r3) : "r"(addr));
}

__device__ __forceinline__ void mma_f16(float c[4], const uint32_t a[4],
                                        const uint32_t b[2]) {
    asm volatile(
        "mma.sync.aligned.m16n8k16.row.col.f32.f16.f16.f32 "
        "{%0,%1,%2,%3}, {%4,%5,%6,%7}, {%8,%9}, {%0,%1,%2,%3};"
        : "+f"(c[0]), "+f"(c[1]), "+f"(c[2]), "+f"(c[3])
        : "r"(a[0]), "r"(a[1]), "r"(a[2]), "r"(a[3]), "r"(b[0]), "r"(b[1]));
}

#define CP_ASYNC16(dst, src, sz) \
    asm volatile("cp.async.cg.shared.global [%0], [%1], 16, %2;" \
                 :: "r"(dst), "l"(src), "r"(sz) : "memory")
#define CP_COMMIT() asm volatile("cp.async.commit_group;" ::: "memory")
#define CP_WAIT2()  asm volatile("cp.async.wait_group 2;" ::: "memory")

__global__ __launch_bounds__(256, 2)
void ha_linear_kernel(const __half* __restrict__ A, int lda,
                      const __half* __restrict__ W, int ldw,
                      const float* __restrict__ bias, float biasScale,
                      float* __restrict__ C,
                      int M, int Nn, int Kd, int flip, int act, int kchunk)
{
    extern __shared__ __align__(16) char dsm[];
    const uint32_t sbase = smem_u32(dsm);

    const int tid  = threadIdx.x;
    const int lane = tid & 31;
    const int warp = tid >> 5;
    const int g    = lane >> 2;
    const int tg   = lane & 3;
    const int warpM = (warp & 3) * 32;
    const int warpN = (warp >> 2) * 64;
    const int row0 = blockIdx.y * BM;
    const int col0 = blockIdx.x * BN;

    int kb = 0, klen = Kd;
    if (kchunk > 0) {
        kb   = blockIdx.z * kchunk;
        klen = kchunk;
        C   += (size_t)blockIdx.z * M * Nn;
    }
    const int ntiles = klen / BK;

    int arow[2], wrow[2];
    uint32_t wsz[2];
#pragma unroll
    for (int i = 0; i < 2; i++) {
        int idx = tid + 256 * i;
        int r   = idx >> 2;
        int gr  = row0 + r;
        if (flip) { gr = (gr & ~(L_ - 1)) + ((L_ - 1) - (gr & (L_ - 1))); }
        arow[i] = gr;
        int gn = col0 + r;
        wsz[i]  = (gn < Nn) ? 16u : 0u;
        wrow[i] = (gn < Nn) ? gn : 0;
    }
    const int ld_row   = tid >> 2;
    const int ld_chunk = (tid & 3) * 8;

    const int tquad = lane >> 3;
    const int trow  = lane & 7;
    const int a_m = ((tquad & 1) << 3) + trow;
    const int a_k = (tquad >> 1) << 3;
    const int b_n = ((tquad >> 1) << 3) + trow;
    const int b_k = (tquad & 1) << 3;

    float acc[2][8][4];
#pragma unroll
    for (int mi = 0; mi < 2; mi++)
#pragma unroll
        for (int ni = 0; ni < 8; ni++)
#pragma unroll
            for (int q = 0; q < 4; q++) acc[mi][ni][q] = 0.f;

    auto issue = [&](int t, int s) {
        const uint32_t st = sbase + (uint32_t)s * STG_BYTES;
        const int koff = kb + t * BK + ld_chunk;
#pragma unroll
        for (int i = 0; i < 2; i++) {
            int r = ld_row + 64 * i;
            uint32_t da = st + (uint32_t)r * (BKP * 2) + (uint32_t)ld_chunk * 2;
            CP_ASYNC16(da, A + (size_t)arow[i] * lda + koff, 16u);
        }
#pragma unroll
        for (int i = 0; i < 2; i++) {
            int r = ld_row + 64 * i;
            uint32_t db = st + (uint32_t)(BM * BKP * 2)
                        + (uint32_t)r * (BKP * 2) + (uint32_t)ld_chunk * 2;
            CP_ASYNC16(db, W + (size_t)wrow[i] * ldw + koff, wsz[i]);
        }
    };

#pragma unroll
    for (int s = 0; s < STAGES - 1; s++) {
        if (s < ntiles) issue(s, s);
        CP_COMMIT();
    }

    for (int t = 0; t < ntiles; t++) {
        CP_WAIT2();
        __syncthreads();

        const int tn = t + STAGES - 1;
        if (tn < ntiles) issue(tn, tn & (STAGES - 1));
        CP_COMMIT();

        const uint32_t stA = sbase + (uint32_t)(t & (STAGES - 1)) * STG_BYTES;
        const uint32_t stB = stA + (uint32_t)(BM * BKP * 2);

#pragma unroll
        for (int kk = 0; kk < 2; kk++) {
            const uint32_t kbyte = (uint32_t)(kk * 16) * 2;
            uint32_t af[2][4], bf[8][2];
#pragma unroll
            for (int mi = 0; mi < 2; mi++) {
                uint32_t addr = stA + (uint32_t)(warpM + mi * 16 + a_m) * (BKP * 2)
                              + kbyte + (uint32_t)a_k * 2;
                ldsm4(af[mi][0], af[mi][1], af[mi][2], af[mi][3], addr);
            }
#pragma unroll
            for (int nj = 0; nj < 4; nj++) {
                uint32_t addr = stB + (uint32_t)(warpN + nj * 16 + b_n) * (BKP * 2)
                              + kbyte + (uint32_t)b_k * 2;
                ldsm4(bf[2 * nj][0], bf[2 * nj][1], bf[2 * nj + 1][0], bf[2 * nj + 1][1], addr);
            }
#pragma unroll
            for (int mi = 0; mi < 2; mi++)
#pragma unroll
                for (int ni = 0; ni < 8; ni++)
                    mma_f16(acc[mi][ni], af[mi], bf[ni]);
        }
    }

#pragma unroll
    for (int mi = 0; mi < 2; mi++) {
        int r0 = row0 + warpM + mi * 16 + g;
#pragma unroll
        for (int ni = 0; ni < 8; ni++) {
            int cb = col0 + warpN + ni * 8 + 2 * tg;
            if (cb < Nn) {
                float v00 = acc[mi][ni][0], v01 = acc[mi][ni][1];
                float v10 = acc[mi][ni][2], v11 = acc[mi][ni][3];
                if (bias) {
                    float b0 = biasScale * bias[cb];
                    float b1 = biasScale * bias[cb + 1];
                    v00 += b0; v01 += b1; v10 += b0; v11 += b1;
                }
                if (act == 1) {
                    v00 = (v00 > 20.f) ? v00 : log1pf(expf(v00));
                    v01 = (v01 > 20.f) ? v01 : log1pf(expf(v01));
                    v10 = (v10 > 20.f) ? v10 : log1pf(expf(v10));
                    v11 = (v11 > 20.f) ? v11 : log1pf(expf(v11));
                }
                *(float2*)(C + (size_t)r0 * Nn + cb)       = make_float2(v00, v01);
                *(float2*)(C + (size_t)(r0 + 8) * Nn + cb) = make_float2(v10, v11);
            }
        }
    }
}

// ---------------------------------------------------------------------------
// f32 -> f16 conversion
// ---------------------------------------------------------------------------
__global__ void cvt_half_kernel(const float* __restrict__ s,
                                __half* __restrict__ d, int n)
{
    int i = (blockIdx.x * blockDim.x + threadIdx.x) * 8;
    if (i < n) {
        float4 v0 = *(const float4*)(s + i);
        float4 v1 = *(const float4*)(s + i + 4);
        __half2 h0 = __floats2half2_rn(v0.x, v0.y);
        __half2 h1 = __floats2half2_rn(v0.z, v0.w);
        __half2 h2 = __floats2half2_rn(v1.x, v1.y);
        __half2 h3 = __floats2half2_rn(v1.z, v1.w);
        *(uint4*)(d + i) = make_uint4(*(uint32_t*)&h0, *(uint32_t*)&h1,
                                      *(uint32_t*)&h2, *(uint32_t*)&h3);
    }
}

// ---------------------------------------------------------------------------
// Reduce split-K partials (dbl): f32 + fp16 out
// ---------------------------------------------------------------------------
__global__ void reduce_dbl_kernel(const float* __restrict__ part,
                                  float* __restrict__ of, float* __restrict__ ob,
                                  __half* __restrict__ hf, __half* __restrict__ hb)
{
    const int NV = MTOT * DBLC / 4;
    int i = blockIdx.x * blockDim.x + threadIdx.x;
    if (i >= 2 * NV) return;
    int br = (i >= NV);
    int j  = i - br * NV;
    const float4* p = (const float4*)part + (size_t)br * SPLITK * NV + j;
    float4 s = make_float4(0.f, 0.f, 0.f, 0.f);
#pragma unroll
    for (int k = 0; k < SPLITK; k++) {
        float4 v = p[(size_t)k * NV];
        s.x += v.x; s.y += v.y; s.z += v.z; s.w += v.w;
    }
    ((float4*)(br ? ob : of))[j] = s;
    __half2 h0 = __floats2half2_rn(s.x, s.y);
    __half2 h1 = __floats2half2_rn(s.z, s.w);
    ((uint2*)(br ? hb : hf))[j] = make_uint2(*(uint32_t*)&h0, *(uint32_t*)&h1);
}

// ---------------------------------------------------------------------------
// Reduce Wo split-K partials into out
// ---------------------------------------------------------------------------
__global__ void reduce_out_kernel(const float* __restrict__ part,
                                  float* __restrict__ out)
{
    const int NV = MTOT * DM / 4;
    int i = blockIdx.x * blockDim.x + threadIdx.x;
    if (i >= NV) return;
    float4 a = ((const float4*)part)[i];
    float4 b = ((const float4*)part)[i + NV];
    ((float4*)out)[i] = make_float4(a.x + b.x, a.y + b.y, a.z + b.z, a.w + b.w);
}

// ---------------------------------------------------------------------------
// Depthwise causal conv1d (K=4) + bias + SiLU; 8 l per thread
// ---------------------------------------------------------------------------
#define CLG 8
__global__ void conv_silu_kernel(const float* __restrict__ x0, int ld0,
                                 const float* __restrict__ w0,
                                 const float* __restrict__ b0,
                                 float* __restrict__ u0, __half* __restrict__ h0,
                                 const float* __restrict__ x1, int ld1,
                                 const float* __restrict__ w1,
                                 const float* __restrict__ b1,
                                 float* __restrict__ u1, __half* __restrict__ h1)
{
    const int br = blockIdx.z;
    const float* __restrict__ x = br ? x1 : x0;
    const float* __restrict__ w = br ? w1 : w0;
    const float* __restrict__ bi = br ? b1 : b0;
    float* __restrict__ u  = br ? u1 : u0;
    __half* __restrict__ hu = br ? h1 : h0;
    const int ldx = br ? ld1 : ld0;

    int idx = blockIdx.x * blockDim.x + threadIdx.x;
    if (idx >= (MTOT / CLG) * DI) return;
    const int d    = idx % DI;
    const int grp  = idx / DI;
    const int row0 = grp * CLG;
    const int l0   = row0 & (L_ - 1);
    const int bb0  = row0 - l0;          // batch start row

    float xv[CLG + KC - 1];
#pragma unroll
    for (int j = 0; j < CLG + KC - 1; j++) {
        int l = l0 - (KC - 1) + j;
        xv[j] = (l >= 0) ? x[(size_t)(bb0 + l) * ldx + d] : 0.f;
    }
    const float w0v = w[d * KC + 0], w1v = w[d * KC + 1],
                w2v = w[d * KC + 2], w3v = w[d * KC + 3];
    const float bv = bi[d];

#pragma unroll
    for (int j = 0; j < CLG; j++) {
        float acc = bv;
        acc = fmaf(xv[j],     w0v, acc);
        acc = fmaf(xv[j + 1], w1v, acc);
        acc = fmaf(xv[j + 2], w2v, acc);
        acc = fmaf(xv[j + 3], w3v, acc);
        float s = 1.f / (1.f + __expf(-acc));
        float v = acc * s;
        size_t o = (size_t)(row0 + j) * DI + d;
        u[o]  = v;
        hu[o] = __float2half_rn(v);
    }
}

// ---------------------------------------------------------------------------
// Chunked selective scan.
//   Phase 1: per (br,b,d,chunk): local scan from h=0 -> h_loc[16], psum.
//   Carry:   per (br,b,d): h_in[ch+1] = exp(-a*psum[ch]) * h_in[ch] + h_loc[ch]
//   Phase 2: per (br,b,d,chunk): scan from h_in, write y.
// ---------------------------------------------------------------------------
#define SCAN_TPB 128
#define SCAN_ST  16   // smem staging depth

__global__ __launch_bounds__(SCAN_TPB)
void scan_phase1(const float* __restrict__ del_f, const float* __restrict__ dbl_f,
                 const float* __restrict__ u_f,
                 const float* __restrict__ del_b, const float* __restrict__ dbl_b,
                 const float* __restrict__ u_b,
                 const float* __restrict__ Alog_f, const float* __restrict__ Alog_b,
                 float* __restrict__ hloc, float* __restrict__ psum)
{
    const int br = blockIdx.y;
    const float* __restrict__ del  = br ? del_b : del_f;
    const float* __restrict__ dbl  = br ? dbl_b : dbl_f;
    const float* __restrict__ u    = br ? u_b   : u_f;
    const float* __restrict__ Alog = br ? Alog_b : Alog_f;

    const int tid   = threadIdx.x;
    const int ch    = blockIdx.x & (NCH - 1);
    const int bb    = (blockIdx.x >> 3) & 1;
    const int dpart = blockIdx.x >> 4;
    const int d     = dpart * SCAN_TPB + tid;
    const int dbase = dpart * SCAN_TPB;
    const int rowb  = bb * L_ + ch * CH;

    float a[NS];
    bool fast = true;
#pragma unroll
    for (int n = 0; n < NS; n++) {
        a[n] = expf(Alog[(size_t)d * NS + n]);
        fast = fast && (fabsf(a[n] - (float)(n + 1)) < 1e-4f * (float)(n + 1));
    }

    float h[NS];
#pragma unroll
    for (int n = 0; n < NS; n++) h[n] = 0.f;
    float ps = 0.f;

    __shared__ float  s_del[SCAN_ST][SCAN_TPB];
    __shared__ float  s_u[SCAN_ST][SCAN_TPB];
    __shared__ float4 s_bc[SCAN_ST][8];

    for (int c0 = 0; c0 < CH; c0 += SCAN_ST) {
        __syncthreads();
#pragma unroll
        for (int k = 0; k < SCAN_ST; k++) {
            size_t off = (size_t)(rowb + c0 + k) * DI + dbase + tid;
            s_del[k][tid] = del[off];
            s_u[k][tid]   = u[off];
        }
        {
            int k = tid >> 3;
            int q = tid & 7;
            size_t off = (size_t)(rowb + c0 + k) * DBLC + RR + q * 4;
            s_bc[k][q] = *(const float4*)(dbl + off);
        }
        __syncthreads();

        if (fast) {
#pragma unroll 2
            for (int k = 0; k < SCAN_ST; k++) {
                float dl = s_del[k][tid];
                float du = dl * s_u[k][tid];
                ps += dl;
                float e = __expf(-dl);
                float4 V0 = s_bc[k][0], V1 = s_bc[k][1], V2 = s_bc[k][2], V3 = s_bc[k][3];
                float Bv[NS] = {V0.x,V0.y,V0.z,V0.w, V1.x,V1.y,V1.z,V1.w,
                                V2.x,V2.y,V2.z,V2.w, V3.x,V3.y,V3.z,V3.w};
                float p = e;
#pragma unroll
                for (int n = 0; n < NS; n++) {
                    h[n] = fmaf(p, h[n], du * Bv[n]);
                    p   *= e;
                }
            }
        } else {
            for (int k = 0; k < SCAN_ST; k++) {
                float dl = s_del[k][tid];
                float du = dl * s_u[k][tid];
                ps += dl;
                const float* bc = (const float*)s_bc[k];
#pragma unroll
                for (int n = 0; n < NS; n++) {
                    float dA = __expf(-dl * a[n]);
                    h[n] = fmaf(dA, h[n], du * bc[n]);
                }
            }
        }
    }

    const int cbase = ((br * B_ + bb) * NCH + ch);
    psum[(size_t)cbase * DI + d] = ps;
#pragma unroll
    for (int n = 0; n < NS; n++)
        hloc[((size_t)cbase * NS + n) * DI + d] = h[n];
}

__global__ void scan_carry(const float* __restrict__ hloc,
                           const float* __restrict__ psum,
                           const float* __restrict__ Alog_f,
                           const float* __restrict__ Alog_b,
                           float* __restrict__ hin)
{
    int idx = blockIdx.x * blockDim.x + threadIdx.x;
    if (idx >= 2 * B_ * DI) return;
    const int d  = idx % DI;
    const int bb = (idx / DI) % B_;
    const int br = idx / (B_ * DI);
    const float* __restrict__ Alog = br ? Alog_b : Alog_f;

    float a[NS];
    bool fast = true;
#pragma unroll
    for (int n = 0; n < NS; n++) {
        a[n] = expf(Alog[(size_t)d * NS + n]);
        fast = fast && (fabsf(a[n] - (float)(n + 1)) < 1e-4f * (float)(n + 1));
    }

    float h[NS];
#pragma unroll
    for (int n = 0; n < NS; n++) h[n] = 0.f;

    for (int ch = 0; ch < NCH; ch++) {
        const size_t cbase = ((size_t)(br * B_ + bb) * NCH + ch);
#pragma unroll
        for (int n = 0; n < NS; n++)
            hin[(cbase * NS + n) * DI + d] = h[n];
        float ps = psum[cbase * DI + d];
        if (fast) {
            float E = __expf(-ps);
            float p = E;
#pragma unroll
            for (int n = 0; n < NS; n++) {
                h[n] = fmaf(p, h[n], hloc[(cbase * NS + n) * DI + d]);
                p   *= E;
            }
        } else {
#pragma unroll
            for (int n = 0; n < NS; n++) {
                float P = __expf(-ps * a[n]);
                h[n] = fmaf(P, h[n], hloc[(cbase * NS + n) * DI + d]);
            }
        }
    }
}

__global__ __launch_bounds__(SCAN_TPB)
void scan_phase2(const float* __restrict__ del_f, const float* __restrict__ dbl_f,
                 const float* __restrict__ u_f,
                 const float* __restrict__ del_b, const float* __restrict__ dbl_b,
                 const float* __restrict__ u_b,
                 const float* __restrict__ Alog_f, const float* __restrict__ D_f,
                 const float* __restrict__ Alog_b, const float* __restrict__ D_b,
                 const float* __restrict__ hin,
                 float* __restrict__ y_f, float* __restrict__ y_b)
{
    const int br = blockIdx.y;
    const float* __restrict__ del  = br ? del_b : del_f;
    const float* __restrict__ dbl  = br ? dbl_b : dbl_f;
    const float* __restrict__ u    = br ? u_b   : u_f;
    const float* __restrict__ Alog = br ? Alog_b : Alog_f;
    const float* __restrict__ Dv_p = br ? D_b : D_f;
    float* __restrict__ yout       = br ? y_b : y_f;

    const int tid   = threadIdx.x;
    const int ch    = blockIdx.x & (NCH - 1);
    const int bb    = (blockIdx.x >> 3) & 1;
    const int dpart = blockIdx.x >> 4;
    const int d     = dpart * SCAN_TPB + tid;
    const int dbase = dpart * SCAN_TPB;
    const int rowb  = bb * L_ + ch * CH;

    float a[NS];
    bool fast = true;
#pragma unroll
    for (int n = 0; n < NS; n++) {
        a[n] = expf(Alog[(size_t)d * NS + n]);
        fast = fast && (fabsf(a[n] - (float)(n + 1)) < 1e-4f * (float)(n + 1));
    }
    const float Dv = Dv_p[d];

    const size_t cbase = ((size_t)(br * B_ + bb) * NCH + ch);
    float h[NS];
#pragma unroll
    for (int n = 0; n < NS; n++)
        h[n] = hin[(cbase * NS + n) * DI + d];

    __shared__ float  s_del[SCAN_ST][SCAN_TPB];
    __shared__ float  s_u[SCAN_ST][SCAN_TPB];
    __shared__ float4 s_bc[SCAN_ST][8];

    for (int c0 = 0; c0 < CH; c0 += SCAN_ST) {
        __syncthreads();
#pragma unroll
        for (int k = 0; k < SCAN_ST; k++) {
            size_t off = (size_t)(rowb + c0 + k) * DI + dbase + tid;
            s_del[k][tid] = del[off];
            s_u[k][tid]   = u[off];
        }
        {
            int k = tid >> 3;
            int q = tid & 7;
            size_t off = (size_t)(rowb + c0 + k) * DBLC + RR + q * 4;
            s_bc[k][q] = *(const float4*)(dbl + off);
        }
        __syncthreads();

        if (fast) {
#pragma unroll 2
            for (int k = 0; k < SCAN_ST; k++) {
                float dl = s_del[k][tid];
                float uu = s_u[k][tid];
                float du = dl * uu;
                float e  = __expf(-dl);
                float4 V0 = s_bc[k][0], V1 = s_bc[k][1], V2 = s_bc[k][2], V3 = s_bc[k][3];
                float4 W0 = s_bc[k][4], W1 = s_bc[k][5], W2 = s_bc[k][6], W3 = s_bc[k][7];
                float Bv[NS] = {V0.x,V0.y,V0.z,V0.w, V1.x,V1.y,V1.z,V1.w,
                                V2.x,V2.y,V2.z,V2.w, V3.x,V3.y,V3.z,V3.w};
                float Cv[NS] = {W0.x,W0.y,W0.z,W0.w, W1.x,W1.y,W1.z,W1.w,
                                W2.x,W2.y,W2.z,W2.w, W3.x,W3.y,W3.z,W3.w};
                float p  = e;
                float yv0 = 0.f, yv1 = 0.f;
#pragma unroll
                for (int n = 0; n < NS; n++) {
                    h[n] = fmaf(p, h[n], du * Bv[n]);
                    if (n & 1) yv1 = fmaf(h[n], Cv[n], yv1);
                    else       yv0 = fmaf(h[n], Cv[n], yv0);
                    p   *= e;
                }
                float yv = fmaf(uu, Dv, yv0 + yv1);
                yout[(size_t)(rowb + c0 + k) * DI + d] = yv;
            }
        } else {
            for (int k = 0; k < SCAN_ST; k++) {
                float dl = s_del[k][tid];
                float uu = s_u[k][tid];
                float du = dl * uu;
                float yv = 0.f;
                const float* bc = (const float*)s_bc[k];
#pragma unroll
                for (int n = 0; n < NS; n++) {
                    float dA = __expf(-dl * a[n]);
                    h[n] = fmaf(dA, h[n], du * bc[n]);
                    yv   = fmaf(h[n], bc[NS + n], yv);
                }
                yv = fmaf(uu, Dv, yv);
                yout[(size_t)(rowb + c0 + k) * DI + d] = yv;
            }
        }
    }
}

// ---------------------------------------------------------------------------
// Gate (y * silu(z)) + RMSNorm * norm_w; writes fp16 g
// ---------------------------------------------------------------------------
__global__ __launch_bounds__(256)
void gate_rms_kernel(const float* __restrict__ yf, const float* __restrict__ yb,
                     const float* __restrict__ xz, const float* __restrict__ nw,
                     __half* __restrict__ g)
{
    const int row = blockIdx.x;
    const int l   = row & (L_ - 1);
    const int bb  = row >> 10;
    const int frow = (bb << 10) + (L_ - 1 - l);
    const int tid = threadIdx.x;

    __shared__ float sg[DI];
    __shared__ float red[8];

    float ss = 0.f;
    for (int d = tid; d < DI; d += 256) {
        float y  = yf[(size_t)row * DI + d] + yb[(size_t)frow * DI + d];
        float z  = xz[(size_t)row * (2 * DI) + DI + d];
        float sz = z / (1.f + __expf(-z));
        float gg = y * sz;
        sg[d] = gg;
        ss = fmaf(gg, gg, ss);
    }
#pragma unroll
    for (int o = 16; o; o >>= 1) ss += __shfl_xor_sync(0xFFFFFFFFu, ss, o);
    if ((tid & 31) == 0) red[tid >> 5] = ss;
    __syncthreads();
    float total = red[0] + red[1] + red[2] + red[3] + red[4] + red[5] + red[6] + red[7];
    float scale = rsqrtf(total / (float)DI + EPS);

    for (int d = tid; d < DI; d += 256) {
        g[(size_t)row * DI + d] = __float2half_rn(sg[d] * scale * nw[d]);
    }
}

// ---------------------------------------------------------------------------
// Launch
// ---------------------------------------------------------------------------
extern "C" void kernel_launch(void* const* d_in, const int* in_sizes, int n_in,
                              void* d_out, int out_size)
{
    (void)in_sizes; (void)n_in; (void)out_size;
    const float* a       = (const float*)d_in[0];
    const float* b       = (const float*)d_in[1];
    const float* Wi      = (const float*)d_in[2];
    const float* conv_w  = (const float*)d_in[3];
    const float* conv_b  = (const float*)d_in[4];
    const float* Wx      = (const float*)d_in[5];
    const float* Wdt     = (const float*)d_in[6];
    const float* bdt     = (const float*)d_in[7];
    const float* A_log   = (const float*)d_in[8];
    const float* D       = (const float*)d_in[9];
    const float* conv_w_b = (const float*)d_in[10];
    const float* conv_b_b = (const float*)d_in[11];
    const float* Wx_b    = (const float*)d_in[12];
    const float* Wdt_b   = (const float*)d_in[13];
    const float* bdt_b   = (const float*)d_in[14];
    const float* A_log_b = (const float*)d_in[15];
    const float* D_b     = (const float*)d_in[16];
    const float* Wo      = (const float*)d_in[17];
    const float* norm_w  = (const float*)d_in[18];
    float* out = (float*)d_out;

    __half *p_ha, *p_hb, *p_hWi, *p_hWo, *p_hWx, *p_hWx_b, *p_hWdt, *p_hWdt_b;
    __half *p_hu_f, *p_hu_b, *p_hdbl_f, *p_hdbl_b, *p_hg;
    float *p_xz_a, *p_xz_b, *p_u_f, *p_u_b, *p_dblp, *p_dbl_f, *p_dbl_b;
    float *p_delta_f, *p_delta_b, *p_y_f, *p_y_b, *p_wop;
    float *p_hloc, *p_hin, *p_psum;
    cudaGetSymbolAddress((void**)&p_ha, g_ha);
    cudaGetSymbolAddress((void**)&p_hb, g_hb);
    cudaGetSymbolAddress((void**)&p_hWi, g_hWi);
    cudaGetSymbolAddress((void**)&p_hWo, g_hWo);
    cudaGetSymbolAddress((void**)&p_hWx, g_hWx);
    cudaGetSymbolAddress((void**)&p_hWx_b, g_hWx_b);
    cudaGetSymbolAddress((void**)&p_hWdt, g_hWdt);
    cudaGetSymbolAddress((void**)&p_hWdt_b, g_hWdt_b);
    cudaGetSymbolAddress((void**)&p_hu_f, g_hu_f);
    cudaGetSymbolAddress((void**)&p_hu_b, g_hu_b);
    cudaGetSymbolAddress((void**)&p_hdbl_f, g_hdbl_f);
    cudaGetSymbolAddress((void**)&p_hdbl_b, g_hdbl_b);
    cudaGetSymbolAddress((void**)&p_hg, g_hg);
    cudaGetSymbolAddress((void**)&p_xz_a, g_xz_a);
    cudaGetSymbolAddress((void**)&p_xz_b, g_xz_b);
    cudaGetSymbolAddress((void**)&p_u_f, g_u_f);
    cudaGetSymbolAddress((void**)&p_u_b, g_u_b);
    cudaGetSymbolAddress((void**)&p_dblp, g_dblp);
    cudaGetSymbolAddress((void**)&p_dbl_f, g_dbl_f);
    cudaGetSymbolAddress((void**)&p_dbl_b, g_dbl_b);
    cudaGetSymbolAddress((void**)&p_delta_f, g_delta_f);
    cudaGetSymbolAddress((void**)&p_delta_b, g_delta_b);
    cudaGetSymbolAddress((void**)&p_y_f, g_y_f);
    cudaGetSymbolAddress((void**)&p_y_b, g_y_b);
    cudaGetSymbolAddress((void**)&p_wop, g_wop);
    cudaGetSymbolAddress((void**)&p_hloc, g_hloc);
    cudaGetSymbolAddress((void**)&p_hin, g_hin);
    cudaGetSymbolAddress((void**)&p_psum, g_psum);

    const int TPB = 256;
    cudaFuncSetAttribute(ha_linear_kernel,
                         cudaFuncAttributeMaxDynamicSharedMemorySize, SMEM_TOTAL);

    // 0. convert inputs/weights to fp16
#define CVT(src, dst, n) cvt_half_kernel<<<((n) / 8 + TPB - 1) / TPB, TPB>>>(src, dst, n)
    CVT(a,     p_ha,     MTOT * DM);
    CVT(b,     p_hb,     MTOT * DM);
    CVT(Wi,    p_hWi,    2 * DI * DM);
    CVT(Wo,    p_hWo,    DM * DI);
    CVT(Wx,    p_hWx,    DBLC * DI);
    CVT(Wx_b,  p_hWx_b,  DBLC * DI);
    CVT(Wdt,   p_hWdt,   DI * RR);
    CVT(Wdt_b, p_hWdt_b, DI * RR);
#undef CVT

    // 1. xz_a = a @ Wi^T   [2048, 4096]
    ha_linear_kernel<<<dim3((2 * DI) / BN, MTOT / BM), TPB, SMEM_TOTAL>>>(
        p_ha, DM, p_hWi, DM, nullptr, 0.f, p_xz_a, MTOT, 2 * DI, DM, 0, 0, 0);

    // 2. xz_b = flip(b) @ Wi[:DI]^T  [2048, 2048]
    ha_linear_kernel<<<dim3(DI / BN, MTOT / BM), TPB, SMEM_TOTAL>>>(
        p_hb, DM, p_hWi, DM, nullptr, 0.f, p_xz_b, MTOT, DI, DM, 1, 0, 0);

    // 3. conv + silu (8 l/thread, both branches)
    conv_silu_kernel<<<dim3((MTOT / CLG) * DI / TPB, 1, 2), TPB>>>(
        p_xz_a, 2 * DI, conv_w, conv_b, p_u_f, p_hu_f,
        p_xz_b, DI, conv_w_b, conv_b_b, p_u_b, p_hu_b);

    // 4/5. dbl = u @ Wx^T  [2048, 96], split-K
    ha_linear_kernel<<<dim3(1, MTOT / BM, SPLITK), TPB, SMEM_TOTAL>>>(
        p_hu_f, DI, p_hWx, DI, nullptr, 0.f, p_dblp, MTOT, DBLC, DI, 0, 0, KCHUNK);
    ha_linear_kernel<<<dim3(1, MTOT / BM, SPLITK), TPB, SMEM_TOTAL>>>(
        p_hu_b, DI, p_hWx_b, DI, nullptr, 0.f, p_dblp + (size_t)SPLITK * MTOT * DBLC,
        MTOT, DBLC, DI, 0, 0, KCHUNK);

    // 6. reduce partials -> dbl (f32 + fp16)
    {
        int nthreads = 2 * MTOT * DBLC / 4;
        reduce_dbl_kernel<<<(nthreads + TPB - 1) / TPB, TPB>>>(
            p_dblp, p_dbl_f, p_dbl_b, p_hdbl_f, p_hdbl_b);
    }

    // 7. delta = softplus(dt @ Wdt^T + 2*bdt)   [2048, 2048]
    ha_linear_kernel<<<dim3(DI / BN, MTOT / BM), TPB, SMEM_TOTAL>>>(
        p_hdbl_f, DBLC, p_hWdt, RR, bdt, 2.f, p_delta_f, MTOT, DI, RR, 0, 1, 0);
    ha_linear_kernel<<<dim3(DI / BN, MTOT / BM), TPB, SMEM_TOTAL>>>(
        p_hdbl_b, DBLC, p_hWdt_b, RR, bdt_b, 2.f, p_delta_b, MTOT, DI, RR, 0, 1, 0);

    // 8. chunked selective scan (both branches)
    scan_phase1<<<dim3((DI / SCAN_TPB) * B_ * NCH, 2), SCAN_TPB>>>(
        p_delta_f, p_dbl_f, p_u_f, p_delta_b, p_dbl_b, p_u_b,
        A_log, A_log_b, p_hloc, p_psum);
    scan_carry<<<(2 * B_ * DI + TPB - 1) / TPB, TPB>>>(
        p_hloc, p_psum, A_log, A_log_b, p_hin);
    scan_phase2<<<dim3((DI / SCAN_TPB) * B_ * NCH, 2), SCAN_TPB>>>(
        p_delta_f, p_dbl_f, p_u_f, p_delta_b, p_dbl_b, p_u_b,
        A_log, D, A_log_b, D_b, p_hin, p_y_f, p_y_b);

    // 9. gate + rmsnorm (writes fp16 g)
    gate_rms_kernel<<<MTOT, TPB>>>(p_y_f, p_y_b, p_xz_a, norm_w, p_hg);

    // 10. out = g @ Wo^T  [2048, 1024], split-K x2
    ha_linear_kernel<<<dim3(DM / BN, MTOT / BM, 2), TPB, SMEM_TOTAL>>>(
        p_hg, DI, p_hWo, DI, nullptr, 0.f, p_wop, MTOT, DM, DI, 0, 0, DI / 2);
    reduce_out_kernel<<<(MTOT * DM / 4 + TPB - 1) / TPB, TPB>>>(p_wop, out);
}

// round 9
// speedup vs baseline: 5.7816x; 1.0393x over previous
#include <cuda_runtime.h>
#include <cuda_bf16.h>
#include <cuda_fp16.h>
#include <math.h>
#include <stdint.h>

// Problem constants
#define B_  2
#define L_  1024
#define DM  1024
#define DI  2048
#define NS  16
#define RR  64
#define KC  4
#define MTOT (B_ * L_)      // 2048
#define EPS 1e-5f

#define DBLC (RR + 2 * NS)  // 96
#define SPLITK 8
#define KCHUNK (DI / SPLITK)  // 256

#define NCH 8               // scan chunks
#define CH  (L_ / NCH)      // 128 steps per chunk

#define BIGSPLIT 0x40000000

// ---------------------------------------------------------------------------
// Scratch buffers (device globals; no allocation allowed)
// ---------------------------------------------------------------------------
__device__ __half g_ha[MTOT * DM];
__device__ __half g_hb[MTOT * DM];
__device__ __half g_hWi[(2 * DI) * DM];
__device__ __half g_hWo[DM * DI];
__device__ __half g_hWx[DBLC * DI];
__device__ __half g_hWx_b[DBLC * DI];
__device__ __half g_hWdt[DI * RR];
__device__ __half g_hWdt_b[DI * RR];
__device__ __half g_hu_f[MTOT * DI];
__device__ __half g_hu_b[MTOT * DI];
__device__ __half g_hdbl_f[MTOT * DBLC];
__device__ __half g_hdbl_b[MTOT * DBLC];
__device__ __half g_hg[MTOT * DI];

__device__ float g_xz_a[MTOT * (2 * DI)];
__device__ float g_xz_b[MTOT * DI];
__device__ float g_u_f[MTOT * DI];
__device__ float g_u_b[MTOT * DI];
__device__ float g_dblp[2 * SPLITK * MTOT * DBLC];
__device__ float g_dbl_f[MTOT * DBLC];
__device__ float g_dbl_b[MTOT * DBLC];
__device__ float g_delta_f[MTOT * DI];
__device__ float g_delta_b[MTOT * DI];
__device__ float g_y_f[MTOT * DI];
__device__ float g_y_b[MTOT * DI];
__device__ float g_wop[2 * MTOT * DM];

// scan chunking state
__device__ float g_hloc[2 * B_ * NCH * NS * DI];
__device__ float g_hin [2 * B_ * NCH * NS * DI];
__device__ float g_psum[2 * B_ * NCH * DI];

// ---------------------------------------------------------------------------
// fp16 tensor-core GEMM, cp.async 4-stage pipeline, DUAL-BRANCH:
//   Blocks with blockIdx.x >= splitX (or blockIdx.z >= splitZ) run set 1.
// ---------------------------------------------------------------------------
#define BM 128
#define BN 128
#define BK 32
#define BKP 40
#define STAGES 4
#define STG_BYTES ((BM + BN) * BKP * 2)
#define SMEM_TOTAL (STAGES * STG_BYTES)

__device__ __forceinline__ uint32_t smem_u32(const void* p) {
    uint32_t a;
    asm("{ .reg .u64 t; cvta.to.shared.u64 t, %1; cvt.u32.u64 %0, t; }"
        : "=r"(a) : "l"(p));
    return a;
}

__device__ __forceinline__ void ldsm4(uint32_t& r0, uint32_t& r1,
                                      uint32_t& r2, uint32_t& r3, uint32_t addr) {
    asm volatile("ldmatrix.sync.aligned.m8n8.x4.shared.b16 {%0,%1,%2,%3}, [%4];"
                 : "=r"(r0), "=r"(r1), "=r"(r2), "=r"(r3) : "r"(addr));
}

__device__ __forceinline__ void mma_f16(float c[4], const uint32_t a[4],
                                        const uint32_t b[2]) {
    asm volatile(
        "mma.sync.aligned.m16n8k16.row.col.f32.f16.f16.f32 "
        "{%0,%1,%2,%3}, {%4,%5,%6,%7}, {%8,%9}, {%0,%1,%2,%3};"
        : "+f"(c[0]), "+f"(c[1]), "+f"(c[2]), "+f"(c[3])
        : "r"(a[0]), "r"(a[1]), "r"(a[2]), "r"(a[3]), "r"(b[0]), "r"(b[1]));
}

#define CP_ASYNC16(dst, src, sz) \
    asm volatile("cp.async.cg.shared.global [%0], [%1], 16, %2;" \
                 :: "r"(dst), "l"(src), "r"(sz) : "memory")
#define CP_COMMIT() asm volatile("cp.async.commit_group;" ::: "memory")
#define CP_WAIT2()  asm volatile("cp.async.wait_group 2;" ::: "memory")

__global__ __launch_bounds__(256, 2)
void ha_linear2_kernel(
    const __half* __restrict__ A0, int lda0, const __half* __restrict__ W0, int ldw0,
    const float* __restrict__ bias0, float bs0, float* __restrict__ C0,
    int Nn0, int flip0, int act0,
    const __half* __restrict__ A1, int lda1, const __half* __restrict__ W1, int ldw1,
    const float* __restrict__ bias1, float bs1, float* __restrict__ C1,
    int Nn1, int flip1, int act1,
    int M, int Kd, int splitX, int splitZ, int kchunk)
{
    extern __shared__ __align__(16) char dsm[];
    const uint32_t sbase = smem_u32(dsm);

    int bx = blockIdx.x, bz = blockIdx.z, sel = 0;
    if (bx >= splitX) { sel = 1; bx -= splitX; }
    else if (bz >= splitZ) { sel = 1; bz -= splitZ; }

    const __half* __restrict__ A = sel ? A1 : A0;
    const __half* __restrict__ W = sel ? W1 : W0;
    const float* __restrict__ bias = sel ? bias1 : bias0;
    const float biasScale = sel ? bs1 : bs0;
    float* __restrict__ C = sel ? C1 : C0;
    const int lda  = sel ? lda1 : lda0;
    const int ldw  = sel ? ldw1 : ldw0;
    const int Nn   = sel ? Nn1 : Nn0;
    const int flip = sel ? flip1 : flip0;
    const int act  = sel ? act1 : act0;

    const int tid  = threadIdx.x;
    const int lane = tid & 31;
    const int warp = tid >> 5;
    const int g    = lane >> 2;
    const int tg   = lane & 3;
    const int warpM = (warp & 3) * 32;
    const int warpN = (warp >> 2) * 64;
    const int row0 = blockIdx.y * BM;
    const int col0 = bx * BN;

    int kb = 0, klen = Kd;
    if (kchunk > 0) {
        kb   = bz * kchunk;
        klen = kchunk;
        C   += (size_t)bz * M * Nn;
    }
    const int ntiles = klen / BK;

    int arow[2], wrow[2];
    uint32_t wsz[2];
#pragma unroll
    for (int i = 0; i < 2; i++) {
        int idx = tid + 256 * i;
        int r   = idx >> 2;
        int gr  = row0 + r;
        if (flip) { gr = (gr & ~(L_ - 1)) + ((L_ - 1) - (gr & (L_ - 1))); }
        arow[i] = gr;
        int gn = col0 + r;
        wsz[i]  = (gn < Nn) ? 16u : 0u;
        wrow[i] = (gn < Nn) ? gn : 0;
    }
    const int ld_row   = tid >> 2;
    const int ld_chunk = (tid & 3) * 8;

    const int tquad = lane >> 3;
    const int trow  = lane & 7;
    const int a_m = ((tquad & 1) << 3) + trow;
    const int a_k = (tquad >> 1) << 3;
    const int b_n = ((tquad >> 1) << 3) + trow;
    const int b_k = (tquad & 1) << 3;

    float acc[2][8][4];
#pragma unroll
    for (int mi = 0; mi < 2; mi++)
#pragma unroll
        for (int ni = 0; ni < 8; ni++)
#pragma unroll
            for (int q = 0; q < 4; q++) acc[mi][ni][q] = 0.f;

    auto issue = [&](int t, int s) {
        const uint32_t st = sbase + (uint32_t)s * STG_BYTES;
        const int koff = kb + t * BK + ld_chunk;
#pragma unroll
        for (int i = 0; i < 2; i++) {
            int r = ld_row + 64 * i;
            uint32_t da = st + (uint32_t)r * (BKP * 2) + (uint32_t)ld_chunk * 2;
            CP_ASYNC16(da, A + (size_t)arow[i] * lda + koff, 16u);
        }
#pragma unroll
        for (int i = 0; i < 2; i++) {
            int r = ld_row + 64 * i;
            uint32_t db = st + (uint32_t)(BM * BKP * 2)
                        + (uint32_t)r * (BKP * 2) + (uint32_t)ld_chunk * 2;
            CP_ASYNC16(db, W + (size_t)wrow[i] * ldw + koff, wsz[i]);
        }
    };

#pragma unroll
    for (int s = 0; s < STAGES - 1; s++) {
        if (s < ntiles) issue(s, s);
        CP_COMMIT();
    }

    for (int t = 0; t < ntiles; t++) {
        CP_WAIT2();
        __syncthreads();

        const int tn = t + STAGES - 1;
        if (tn < ntiles) issue(tn, tn & (STAGES - 1));
        CP_COMMIT();

        const uint32_t stA = sbase + (uint32_t)(t & (STAGES - 1)) * STG_BYTES;
        const uint32_t stB = stA + (uint32_t)(BM * BKP * 2);

#pragma unroll
        for (int kk = 0; kk < 2; kk++) {
            const uint32_t kbyte = (uint32_t)(kk * 16) * 2;
            uint32_t af[2][4], bf[8][2];
#pragma unroll
            for (int mi = 0; mi < 2; mi++) {
                uint32_t addr = stA + (uint32_t)(warpM + mi * 16 + a_m) * (BKP * 2)
                              + kbyte + (uint32_t)a_k * 2;
                ldsm4(af[mi][0], af[mi][1], af[mi][2], af[mi][3], addr);
            }
#pragma unroll
            for (int nj = 0; nj < 4; nj++) {
                uint32_t addr = stB + (uint32_t)(warpN + nj * 16 + b_n) * (BKP * 2)
                              + kbyte + (uint32_t)b_k * 2;
                ldsm4(bf[2 * nj][0], bf[2 * nj][1], bf[2 * nj + 1][0], bf[2 * nj + 1][1], addr);
            }
#pragma unroll
            for (int mi = 0; mi < 2; mi++)
#pragma unroll
                for (int ni = 0; ni < 8; ni++)
                    mma_f16(acc[mi][ni], af[mi], bf[ni]);
        }
    }

#pragma unroll
    for (int mi = 0; mi < 2; mi++) {
        int r0 = row0 + warpM + mi * 16 + g;
#pragma unroll
        for (int ni = 0; ni < 8; ni++) {
            int cb = col0 + warpN + ni * 8 + 2 * tg;
            if (cb < Nn) {
                float v00 = acc[mi][ni][0], v01 = acc[mi][ni][1];
                float v10 = acc[mi][ni][2], v11 = acc[mi][ni][3];
                if (bias) {
                    float b0 = biasScale * bias[cb];
                    float b1 = biasScale * bias[cb + 1];
                    v00 += b0; v01 += b1; v10 += b0; v11 += b1;
                }
                if (act == 1) {
                    v00 = (v00 > 20.f) ? v00 : log1pf(expf(v00));
                    v01 = (v01 > 20.f) ? v01 : log1pf(expf(v01));
                    v10 = (v10 > 20.f) ? v10 : log1pf(expf(v10));
                    v11 = (v11 > 20.f) ? v11 : log1pf(expf(v11));
                }
                *(float2*)(C + (size_t)r0 * Nn + cb)       = make_float2(v00, v01);
                *(float2*)(C + (size_t)(r0 + 8) * Nn + cb) = make_float2(v10, v11);
            }
        }
    }
}

// ---------------------------------------------------------------------------
// f32 -> f16 conversion, two arrays per launch
// ---------------------------------------------------------------------------
__global__ void cvt2_half_kernel(const float* __restrict__ s0, __half* __restrict__ d0, int n0,
                                 const float* __restrict__ s1, __half* __restrict__ d1, int n1)
{
    int i = (blockIdx.x * blockDim.x + threadIdx.x) * 8;
    const float* s;
    __half* d;
    if (i < n0) { s = s0 + i; d = d0 + i; }
    else {
        int j = i - n0;
        if (j >= n1) return;
        s = s1 + j; d = d1 + j;
    }
    float4 v0 = *(const float4*)s;
    float4 v1 = *(const float4*)(s + 4);
    __half2 h0 = __floats2half2_rn(v0.x, v0.y);
    __half2 h1 = __floats2half2_rn(v0.z, v0.w);
    __half2 h2 = __floats2half2_rn(v1.x, v1.y);
    __half2 h3 = __floats2half2_rn(v1.z, v1.w);
    *(uint4*)d = make_uint4(*(uint32_t*)&h0, *(uint32_t*)&h1,
                            *(uint32_t*)&h2, *(uint32_t*)&h3);
}

// ---------------------------------------------------------------------------
// Reduce split-K partials (dbl): f32 + fp16 out
// ---------------------------------------------------------------------------
__global__ void reduce_dbl_kernel(const float* __restrict__ part,
                                  float* __restrict__ of, float* __restrict__ ob,
                                  __half* __restrict__ hf, __half* __restrict__ hb)
{
    const int NV = MTOT * DBLC / 4;
    int i = blockIdx.x * blockDim.x + threadIdx.x;
    if (i >= 2 * NV) return;
    int br = (i >= NV);
    int j  = i - br * NV;
    const float4* p = (const float4*)part + (size_t)br * SPLITK * NV + j;
    float4 s = make_float4(0.f, 0.f, 0.f, 0.f);
#pragma unroll
    for (int k = 0; k < SPLITK; k++) {
        float4 v = p[(size_t)k * NV];
        s.x += v.x; s.y += v.y; s.z += v.z; s.w += v.w;
    }
    ((float4*)(br ? ob : of))[j] = s;
    __half2 h0 = __floats2half2_rn(s.x, s.y);
    __half2 h1 = __floats2half2_rn(s.z, s.w);
    ((uint2*)(br ? hb : hf))[j] = make_uint2(*(uint32_t*)&h0, *(uint32_t*)&h1);
}

// ---------------------------------------------------------------------------
// Reduce Wo split-K partials into out
// ---------------------------------------------------------------------------
__global__ void reduce_out_kernel(const float* __restrict__ part,
                                  float* __restrict__ out)
{
    const int NV = MTOT * DM / 4;
    int i = blockIdx.x * blockDim.x + threadIdx.x;
    if (i >= NV) return;
    float4 a = ((const float4*)part)[i];
    float4 b = ((const float4*)part)[i + NV];
    ((float4*)out)[i] = make_float4(a.x + b.x, a.y + b.y, a.z + b.z, a.w + b.w);
}

// ---------------------------------------------------------------------------
// Depthwise causal conv1d (K=4) + bias + SiLU; 8 l per thread
// ---------------------------------------------------------------------------
#define CLG 8
__global__ void conv_silu_kernel(const float* __restrict__ x0, int ld0,
                                 const float* __restrict__ w0,
                                 const float* __restrict__ b0,
                                 float* __restrict__ u0, __half* __restrict__ h0,
                                 const float* __restrict__ x1, int ld1,
                                 const float* __restrict__ w1,
                                 const float* __restrict__ b1,
                                 float* __restrict__ u1, __half* __restrict__ h1)
{
    const int br = blockIdx.z;
    const float* __restrict__ x = br ? x1 : x0;
    const float* __restrict__ w = br ? w1 : w0;
    const float* __restrict__ bi = br ? b1 : b0;
    float* __restrict__ u  = br ? u1 : u0;
    __half* __restrict__ hu = br ? h1 : h0;
    const int ldx = br ? ld1 : ld0;

    int idx = blockIdx.x * blockDim.x + threadIdx.x;
    if (idx >= (MTOT / CLG) * DI) return;
    const int d    = idx % DI;
    const int grp  = idx / DI;
    const int row0 = grp * CLG;
    const int l0   = row0 & (L_ - 1);
    const int bb0  = row0 - l0;

    float xv[CLG + KC - 1];
#pragma unroll
    for (int j = 0; j < CLG + KC - 1; j++) {
        int l = l0 - (KC - 1) + j;
        xv[j] = (l >= 0) ? x[(size_t)(bb0 + l) * ldx + d] : 0.f;
    }
    const float w0v = w[d * KC + 0], w1v = w[d * KC + 1],
                w2v = w[d * KC + 2], w3v = w[d * KC + 3];
    const float bv = bi[d];

#pragma unroll
    for (int j = 0; j < CLG; j++) {
        float acc = bv;
        acc = fmaf(xv[j],     w0v, acc);
        acc = fmaf(xv[j + 1], w1v, acc);
        acc = fmaf(xv[j + 2], w2v, acc);
        acc = fmaf(xv[j + 3], w3v, acc);
        float s = 1.f / (1.f + __expf(-acc));
        float v = acc * s;
        size_t o = (size_t)(row0 + j) * DI + d;
        u[o]  = v;
        hu[o] = __float2half_rn(v);
    }
}

// ---------------------------------------------------------------------------
// Chunked selective scan (phase1 / carry / phase2)
// ---------------------------------------------------------------------------
#define SCAN_TPB 128
#define SCAN_ST  16

__global__ __launch_bounds__(SCAN_TPB)
void scan_phase1(const float* __restrict__ del_f, const float* __restrict__ dbl_f,
                 const float* __restrict__ u_f,
                 const float* __restrict__ del_b, const float* __restrict__ dbl_b,
                 const float* __restrict__ u_b,
                 const float* __restrict__ Alog_f, const float* __restrict__ Alog_b,
                 float* __restrict__ hloc, float* __restrict__ psum)
{
    const int br = blockIdx.y;
    const float* __restrict__ del  = br ? del_b : del_f;
    const float* __restrict__ dbl  = br ? dbl_b : dbl_f;
    const float* __restrict__ u    = br ? u_b   : u_f;
    const float* __restrict__ Alog = br ? Alog_b : Alog_f;

    const int tid   = threadIdx.x;
    const int ch    = blockIdx.x & (NCH - 1);
    const int bb    = (blockIdx.x >> 3) & 1;
    const int dpart = blockIdx.x >> 4;
    const int d     = dpart * SCAN_TPB + tid;
    const int dbase = dpart * SCAN_TPB;
    const int rowb  = bb * L_ + ch * CH;

    float a[NS];
    bool fast = true;
#pragma unroll
    for (int n = 0; n < NS; n++) {
        a[n] = expf(Alog[(size_t)d * NS + n]);
        fast = fast && (fabsf(a[n] - (float)(n + 1)) < 1e-4f * (float)(n + 1));
    }

    float h[NS];
#pragma unroll
    for (int n = 0; n < NS; n++) h[n] = 0.f;
    float ps = 0.f;

    __shared__ float  s_del[SCAN_ST][SCAN_TPB];
    __shared__ float  s_u[SCAN_ST][SCAN_TPB];
    __shared__ float4 s_bc[SCAN_ST][8];

    for (int c0 = 0; c0 < CH; c0 += SCAN_ST) {
        __syncthreads();
#pragma unroll
        for (int k = 0; k < SCAN_ST; k++) {
            size_t off = (size_t)(rowb + c0 + k) * DI + dbase + tid;
            s_del[k][tid] = del[off];
            s_u[k][tid]   = u[off];
        }
        {
            int k = tid >> 3;
            int q = tid & 7;
            size_t off = (size_t)(rowb + c0 + k) * DBLC + RR + q * 4;
            s_bc[k][q] = *(const float4*)(dbl + off);
        }
        __syncthreads();

        if (fast) {
#pragma unroll 2
            for (int k = 0; k < SCAN_ST; k++) {
                float dl = s_del[k][tid];
                float du = dl * s_u[k][tid];
                ps += dl;
                float e = __expf(-dl);
                float4 V0 = s_bc[k][0], V1 = s_bc[k][1], V2 = s_bc[k][2], V3 = s_bc[k][3];
                float Bv[NS] = {V0.x,V0.y,V0.z,V0.w, V1.x,V1.y,V1.z,V1.w,
                                V2.x,V2.y,V2.z,V2.w, V3.x,V3.y,V3.z,V3.w};
                float p = e;
#pragma unroll
                for (int n = 0; n < NS; n++) {
                    h[n] = fmaf(p, h[n], du * Bv[n]);
                    p   *= e;
                }
            }
        } else {
            for (int k = 0; k < SCAN_ST; k++) {
                float dl = s_del[k][tid];
                float du = dl * s_u[k][tid];
                ps += dl;
                const float* bc = (const float*)s_bc[k];
#pragma unroll
                for (int n = 0; n < NS; n++) {
                    float dA = __expf(-dl * a[n]);
                    h[n] = fmaf(dA, h[n], du * bc[n]);
                }
            }
        }
    }

    const int cbase = ((br * B_ + bb) * NCH + ch);
    psum[(size_t)cbase * DI + d] = ps;
#pragma unroll
    for (int n = 0; n < NS; n++)
        hloc[((size_t)cbase * NS + n) * DI + d] = h[n];
}

__global__ void scan_carry(const float* __restrict__ hloc,
                           const float* __restrict__ psum,
                           const float* __restrict__ Alog_f,
                           const float* __restrict__ Alog_b,
                           float* __restrict__ hin)
{
    int idx = blockIdx.x * blockDim.x + threadIdx.x;
    if (idx >= 2 * B_ * DI) return;
    const int d  = idx % DI;
    const int bb = (idx / DI) % B_;
    const int br = idx / (B_ * DI);
    const float* __restrict__ Alog = br ? Alog_b : Alog_f;

    float a[NS];
    bool fast = true;
#pragma unroll
    for (int n = 0; n < NS; n++) {
        a[n] = expf(Alog[(size_t)d * NS + n]);
        fast = fast && (fabsf(a[n] - (float)(n + 1)) < 1e-4f * (float)(n + 1));
    }

    float h[NS];
#pragma unroll
    for (int n = 0; n < NS; n++) h[n] = 0.f;

    for (int ch = 0; ch < NCH; ch++) {
        const size_t cbase = ((size_t)(br * B_ + bb) * NCH + ch);
#pragma unroll
        for (int n = 0; n < NS; n++)
            hin[(cbase * NS + n) * DI + d] = h[n];
        float ps = psum[cbase * DI + d];
        if (fast) {
            float E = __expf(-ps);
            float p = E;
#pragma unroll
            for (int n = 0; n < NS; n++) {
                h[n] = fmaf(p, h[n], hloc[(cbase * NS + n) * DI + d]);
                p   *= E;
            }
        } else {
#pragma unroll
            for (int n = 0; n < NS; n++) {
                float P = __expf(-ps * a[n]);
                h[n] = fmaf(P, h[n], hloc[(cbase * NS + n) * DI + d]);
            }
        }
    }
}

__global__ __launch_bounds__(SCAN_TPB)
void scan_phase2(const float* __restrict__ del_f, const float* __restrict__ dbl_f,
                 const float* __restrict__ u_f,
                 const float* __restrict__ del_b, const float* __restrict__ dbl_b,
                 const float* __restrict__ u_b,
                 const float* __restrict__ Alog_f, const float* __restrict__ D_f,
                 const float* __restrict__ Alog_b, const float* __restrict__ D_b,
                 const float* __restrict__ hin,
                 float* __restrict__ y_f, float* __restrict__ y_b)
{
    const int br = blockIdx.y;
    const float* __restrict__ del  = br ? del_b : del_f;
    const float* __restrict__ dbl  = br ? dbl_b : dbl_f;
    const float* __restrict__ u    = br ? u_b   : u_f;
    const float* __restrict__ Alog = br ? Alog_b : Alog_f;
    const float* __restrict__ Dv_p = br ? D_b : D_f;
    float* __restrict__ yout       = br ? y_b : y_f;

    const int tid   = threadIdx.x;
    const int ch    = blockIdx.x & (NCH - 1);
    const int bb    = (blockIdx.x >> 3) & 1;
    const int dpart = blockIdx.x >> 4;
    const int d     = dpart * SCAN_TPB + tid;
    const int dbase = dpart * SCAN_TPB;
    const int rowb  = bb * L_ + ch * CH;

    float a[NS];
    bool fast = true;
#pragma unroll
    for (int n = 0; n < NS; n++) {
        a[n] = expf(Alog[(size_t)d * NS + n]);
        fast = fast && (fabsf(a[n] - (float)(n + 1)) < 1e-4f * (float)(n + 1));
    }
    const float Dv = Dv_p[d];

    const size_t cbase = ((size_t)(br * B_ + bb) * NCH + ch);
    float h[NS];
#pragma unroll
    for (int n = 0; n < NS; n++)
        h[n] = hin[(cbase * NS + n) * DI + d];

    __shared__ float  s_del[SCAN_ST][SCAN_TPB];
    __shared__ float  s_u[SCAN_ST][SCAN_TPB];
    __shared__ float4 s_bc[SCAN_ST][8];

    for (int c0 = 0; c0 < CH; c0 += SCAN_ST) {
        __syncthreads();
#pragma unroll
        for (int k = 0; k < SCAN_ST; k++) {
            size_t off = (size_t)(rowb + c0 + k) * DI + dbase + tid;
            s_del[k][tid] = del[off];
            s_u[k][tid]   = u[off];
        }
        {
            int k = tid >> 3;
            int q = tid & 7;
            size_t off = (size_t)(rowb + c0 + k) * DBLC + RR + q * 4;
            s_bc[k][q] = *(const float4*)(dbl + off);
        }
        __syncthreads();

        if (fast) {
#pragma unroll 2
            for (int k = 0; k < SCAN_ST; k++) {
                float dl = s_del[k][tid];
                float uu = s_u[k][tid];
                float du = dl * uu;
                float e  = __expf(-dl);
                float4 V0 = s_bc[k][0], V1 = s_bc[k][1], V2 = s_bc[k][2], V3 = s_bc[k][3];
                float4 W0 = s_bc[k][4], W1 = s_bc[k][5], W2 = s_bc[k][6], W3 = s_bc[k][7];
                float Bv[NS] = {V0.x,V0.y,V0.z,V0.w, V1.x,V1.y,V1.z,V1.w,
                                V2.x,V2.y,V2.z,V2.w, V3.x,V3.y,V3.z,V3.w};
                float Cv[NS] = {W0.x,W0.y,W0.z,W0.w, W1.x,W1.y,W1.z,W1.w,
                                W2.x,W2.y,W2.z,W2.w, W3.x,W3.y,W3.z,W3.w};
                float p  = e;
                float yv0 = 0.f, yv1 = 0.f;
#pragma unroll
                for (int n = 0; n < NS; n++) {
                    h[n] = fmaf(p, h[n], du * Bv[n]);
                    if (n & 1) yv1 = fmaf(h[n], Cv[n], yv1);
                    else       yv0 = fmaf(h[n], Cv[n], yv0);
                    p   *= e;
                }
                float yv = fmaf(uu, Dv, yv0 + yv1);
                yout[(size_t)(rowb + c0 + k) * DI + d] = yv;
            }
        } else {
            for (int k = 0; k < SCAN_ST; k++) {
                float dl = s_del[k][tid];
                float uu = s_u[k][tid];
                float du = dl * uu;
                float yv = 0.f;
                const float* bc = (const float*)s_bc[k];
#pragma unroll
                for (int n = 0; n < NS; n++) {
                    float dA = __expf(-dl * a[n]);
                    h[n] = fmaf(dA, h[n], du * bc[n]);
                    yv   = fmaf(h[n], bc[NS + n], yv);
                }
                yv = fmaf(uu, Dv, yv);
                yout[(size_t)(rowb + c0 + k) * DI + d] = yv;
            }
        }
    }
}

// ---------------------------------------------------------------------------
// Gate (y * silu(z)) + RMSNorm * norm_w; writes fp16 g
// ---------------------------------------------------------------------------
__global__ __launch_bounds__(256)
void gate_rms_kernel(const float* __restrict__ yf, const float* __restrict__ yb,
                     const float* __restrict__ xz, const float* __restrict__ nw,
                     __half* __restrict__ g)
{
    const int row = blockIdx.x;
    const int l   = row & (L_ - 1);
    const int bb  = row >> 10;
    const int frow = (bb << 10) + (L_ - 1 - l);
    const int tid = threadIdx.x;

    __shared__ float sg[DI];
    __shared__ float red[8];

    float ss = 0.f;
    for (int d = tid; d < DI; d += 256) {
        float y  = yf[(size_t)row * DI + d] + yb[(size_t)frow * DI + d];
        float z  = xz[(size_t)row * (2 * DI) + DI + d];
        float sz = z / (1.f + __expf(-z));
        float gg = y * sz;
        sg[d] = gg;
        ss = fmaf(gg, gg, ss);
    }
#pragma unroll
    for (int o = 16; o; o >>= 1) ss += __shfl_xor_sync(0xFFFFFFFFu, ss, o);
    if ((tid & 31) == 0) red[tid >> 5] = ss;
    __syncthreads();
    float total = red[0] + red[1] + red[2] + red[3] + red[4] + red[5] + red[6] + red[7];
    float scale = rsqrtf(total / (float)DI + EPS);

    for (int d = tid; d < DI; d += 256) {
        g[(size_t)row * DI + d] = __float2half_rn(sg[d] * scale * nw[d]);
    }
}

// ---------------------------------------------------------------------------
// Launch
// ---------------------------------------------------------------------------
extern "C" void kernel_launch(void* const* d_in, const int* in_sizes, int n_in,
                              void* d_out, int out_size)
{
    (void)in_sizes; (void)n_in; (void)out_size;
    const float* a       = (const float*)d_in[0];
    const float* b       = (const float*)d_in[1];
    const float* Wi      = (const float*)d_in[2];
    const float* conv_w  = (const float*)d_in[3];
    const float* conv_b  = (const float*)d_in[4];
    const float* Wx      = (const float*)d_in[5];
    const float* Wdt     = (const float*)d_in[6];
    const float* bdt     = (const float*)d_in[7];
    const float* A_log   = (const float*)d_in[8];
    const float* D       = (const float*)d_in[9];
    const float* conv_w_b = (const float*)d_in[10];
    const float* conv_b_b = (const float*)d_in[11];
    const float* Wx_b    = (const float*)d_in[12];
    const float* Wdt_b   = (const float*)d_in[13];
    const float* bdt_b   = (const float*)d_in[14];
    const float* A_log_b = (const float*)d_in[15];
    const float* D_b     = (const float*)d_in[16];
    const float* Wo      = (const float*)d_in[17];
    const float* norm_w  = (const float*)d_in[18];
    float* out = (float*)d_out;

    __half *p_ha, *p_hb, *p_hWi, *p_hWo, *p_hWx, *p_hWx_b, *p_hWdt, *p_hWdt_b;
    __half *p_hu_f, *p_hu_b, *p_hdbl_f, *p_hdbl_b, *p_hg;
    float *p_xz_a, *p_xz_b, *p_u_f, *p_u_b, *p_dblp, *p_dbl_f, *p_dbl_b;
    float *p_delta_f, *p_delta_b, *p_y_f, *p_y_b, *p_wop;
    float *p_hloc, *p_hin, *p_psum;
    cudaGetSymbolAddress((void**)&p_ha, g_ha);
    cudaGetSymbolAddress((void**)&p_hb, g_hb);
    cudaGetSymbolAddress((void**)&p_hWi, g_hWi);
    cudaGetSymbolAddress((void**)&p_hWo, g_hWo);
    cudaGetSymbolAddress((void**)&p_hWx, g_hWx);
    cudaGetSymbolAddress((void**)&p_hWx_b, g_hWx_b);
    cudaGetSymbolAddress((void**)&p_hWdt, g_hWdt);
    cudaGetSymbolAddress((void**)&p_hWdt_b, g_hWdt_b);
    cudaGetSymbolAddress((void**)&p_hu_f, g_hu_f);
    cudaGetSymbolAddress((void**)&p_hu_b, g_hu_b);
    cudaGetSymbolAddress((void**)&p_hdbl_f, g_hdbl_f);
    cudaGetSymbolAddress((void**)&p_hdbl_b, g_hdbl_b);
    cudaGetSymbolAddress((void**)&p_hg, g_hg);
    cudaGetSymbolAddress((void**)&p_xz_a, g_xz_a);
    cudaGetSymbolAddress((void**)&p_xz_b, g_xz_b);
    cudaGetSymbolAddress((void**)&p_u_f, g_u_f);
    cudaGetSymbolAddress((void**)&p_u_b, g_u_b);
    cudaGetSymbolAddress((void**)&p_dblp, g_dblp);
    cudaGetSymbolAddress((void**)&p_dbl_f, g_dbl_f);
    cudaGetSymbolAddress((void**)&p_dbl_b, g_dbl_b);
    cudaGetSymbolAddress((void**)&p_delta_f, g_delta_f);
    cudaGetSymbolAddress((void**)&p_delta_b, g_delta_b);
    cudaGetSymbolAddress((void**)&p_y_f, g_y_f);
    cudaGetSymbolAddress((void**)&p_y_b, g_y_b);
    cudaGetSymbolAddress((void**)&p_wop, g_wop);
    cudaGetSymbolAddress((void**)&p_hloc, g_hloc);
    cudaGetSymbolAddress((void**)&p_hin, g_hin);
    cudaGetSymbolAddress((void**)&p_psum, g_psum);

    const int TPB = 256;
    cudaFuncSetAttribute(ha_linear2_kernel,
                         cudaFuncAttributeMaxDynamicSharedMemorySize, SMEM_TOTAL);

    // 0. convert inputs/weights to fp16 (paired launches)
#define CVT2(s0, d0, n0, s1, d1, n1) \
    cvt2_half_kernel<<<(((n0) + (n1)) / 8 + TPB - 1) / TPB, TPB>>>(s0, d0, n0, s1, d1, n1)
    CVT2(a,   p_ha,   MTOT * DM,      b,     p_hb,    MTOT * DM);
    CVT2(Wi,  p_hWi,  2 * DI * DM,    Wo,    p_hWo,   DM * DI);
    CVT2(Wx,  p_hWx,  DBLC * DI,      Wx_b,  p_hWx_b, DBLC * DI);
    CVT2(Wdt, p_hWdt, DI * RR,        Wdt_b, p_hWdt_b, DI * RR);
#undef CVT2

    // 1. fused: xz_a = a @ Wi^T [2048,4096]  +  xz_b = flip(b) @ Wi[:DI]^T [2048,2048]
    ha_linear2_kernel<<<dim3(32 + 16, MTOT / BM, 1), TPB, SMEM_TOTAL>>>(
        p_ha, DM, p_hWi, DM, nullptr, 0.f, p_xz_a, 2 * DI, 0, 0,
        p_hb, DM, p_hWi, DM, nullptr, 0.f, p_xz_b, DI, 1, 0,
        MTOT, DM, /*splitX=*/32, /*splitZ=*/BIGSPLIT, 0);

    // 2. conv + silu (8 l/thread, both branches)
    conv_silu_kernel<<<dim3((MTOT / CLG) * DI / TPB, 1, 2), TPB>>>(
        p_xz_a, 2 * DI, conv_w, conv_b, p_u_f, p_hu_f,
        p_xz_b, DI, conv_w_b, conv_b_b, p_u_b, p_hu_b);

    // 3. fused dbl = u @ Wx^T [2048,96], split-K both branches (z: 0..7 f, 8..15 b)
    ha_linear2_kernel<<<dim3(1, MTOT / BM, 2 * SPLITK), TPB, SMEM_TOTAL>>>(
        p_hu_f, DI, p_hWx, DI, nullptr, 0.f, p_dblp, DBLC, 0, 0,
        p_hu_b, DI, p_hWx_b, DI, nullptr, 0.f, p_dblp + (size_t)SPLITK * MTOT * DBLC,
        DBLC, 0, 0,
        MTOT, DI, /*splitX=*/BIGSPLIT, /*splitZ=*/SPLITK, KCHUNK);

    // 4. reduce partials -> dbl (f32 + fp16)
    {
        int nthreads = 2 * MTOT * DBLC / 4;
        reduce_dbl_kernel<<<(nthreads + TPB - 1) / TPB, TPB>>>(
            p_dblp, p_dbl_f, p_dbl_b, p_hdbl_f, p_hdbl_b);
    }

    // 5. fused delta = softplus(dt @ Wdt^T + 2*bdt) [2048,2048], both branches
    ha_linear2_kernel<<<dim3(DI / BN, MTOT / BM, 2), TPB, SMEM_TOTAL>>>(
        p_hdbl_f, DBLC, p_hWdt, RR, bdt, 2.f, p_delta_f, DI, 0, 1,
        p_hdbl_b, DBLC, p_hWdt_b, RR, bdt_b, 2.f, p_delta_b, DI, 0, 1,
        MTOT, RR, /*splitX=*/BIGSPLIT, /*splitZ=*/1, 0);

    // 6. chunked selective scan (both branches)
    scan_phase1<<<dim3((DI / SCAN_TPB) * B_ * NCH, 2), SCAN_TPB>>>(
        p_delta_f, p_dbl_f, p_u_f, p_delta_b, p_dbl_b, p_u_b,
        A_log, A_log_b, p_hloc, p_psum);
    scan_carry<<<(2 * B_ * DI + TPB - 1) / TPB, TPB>>>(
        p_hloc, p_psum, A_log, A_log_b, p_hin);
    scan_phase2<<<dim3((DI / SCAN_TPB) * B_ * NCH, 2), SCAN_TPB>>>(
        p_delta_f, p_dbl_f, p_u_f, p_delta_b, p_dbl_b, p_u_b,
        A_log, D, A_log_b, D_b, p_hin, p_y_f, p_y_b);

    // 7. gate + rmsnorm (writes fp16 g)
    gate_rms_kernel<<<MTOT, TPB>>>(p_y_f, p_y_b, p_xz_a, norm_w, p_hg);

    // 8. out = g @ Wo^T [2048,1024], split-K x2
    ha_linear2_kernel<<<dim3(DM / BN, MTOT / BM, 2), TPB, SMEM_TOTAL>>>(
        p_hg, DI, p_hWo, DI, nullptr, 0.f, p_wop, DM, 0, 0,
        p_hg, DI, p_hWo, DI, nullptr, 0.f, p_wop, DM, 0, 0,
        MTOT, DI, /*splitX=*/BIGSPLIT, /*splitZ=*/BIGSPLIT, DI / 2);
    reduce_out_kernel<<<(MTOT * DM / 4 + TPB - 1) / TPB, TPB>>>(p_wop, out);
}

// round 10
// speedup vs baseline: 5.9716x; 1.0329x over previous
#include <cuda_runtime.h>
#include <cuda_bf16.h>
#include <cuda_fp16.h>
#include <math.h>
#include <stdint.h>

// Problem constants
#define B_  2
#define L_  1024
#define DM  1024
#define DI  2048
#define NS  16
#define RR  64
#define KC  4
#define MTOT (B_ * L_)      // 2048
#define EPS 1e-5f

#define DBLC (RR + 2 * NS)  // 96
#define SPLITK 8
#define KCHUNK (DI / SPLITK)  // 256

#define NCH 8               // scan chunks
#define CH  (L_ / NCH)      // 128 steps per chunk

#define BIGSPLIT 0x40000000

// ---------------------------------------------------------------------------
// Scratch buffers (device globals; no allocation allowed)
// ---------------------------------------------------------------------------
__device__ __half g_ha[MTOT * DM];
__device__ __half g_hb[MTOT * DM];
__device__ __half g_hWi[(2 * DI) * DM];
__device__ __half g_hWo[DM * DI];
__device__ __half g_hWx[DBLC * DI];
__device__ __half g_hWx_b[DBLC * DI];
__device__ __half g_hWdt[DI * RR];
__device__ __half g_hWdt_b[DI * RR];
__device__ __half g_hu_f[MTOT * DI];        // fp16 u (GEMM + scan operand)
__device__ __half g_hu_b[MTOT * DI];
__device__ __half g_hdbl_f[MTOT * DBLC];
__device__ __half g_hdbl_b[MTOT * DBLC];
__device__ __half g_hdelta_f[MTOT * DI];    // fp16 delta (scan operand)
__device__ __half g_hdelta_b[MTOT * DI];
__device__ __half g_hg[MTOT * DI];

__device__ float g_xz_a[MTOT * (2 * DI)];
__device__ float g_xz_b[MTOT * DI];
__device__ float g_dblp[2 * SPLITK * MTOT * DBLC];
__device__ float g_dbl_f[MTOT * DBLC];
__device__ float g_dbl_b[MTOT * DBLC];
__device__ float g_y_f[MTOT * DI];
__device__ float g_y_b[MTOT * DI];
__device__ float g_wop[2 * MTOT * DM];

// scan chunking state
__device__ float g_hloc[2 * B_ * NCH * NS * DI];
__device__ float g_hin [2 * B_ * NCH * NS * DI];
__device__ float g_psum[2 * B_ * NCH * DI];

// ---------------------------------------------------------------------------
// fp16 tensor-core GEMM, cp.async 4-stage pipeline, DUAL-BRANCH:
//   Blocks with blockIdx.x >= splitX (or blockIdx.z >= splitZ) run set 1.
//   act: 0 = none, 1 = softplus (f32 out), 2 = softplus + fp16 out
// ---------------------------------------------------------------------------
#define BM 128
#define BN 128
#define BK 32
#define BKP 40
#define STAGES 4
#define STG_BYTES ((BM + BN) * BKP * 2)
#define SMEM_TOTAL (STAGES * STG_BYTES)

__device__ __forceinline__ uint32_t smem_u32(const void* p) {
    uint32_t a;
    asm("{ .reg .u64 t; cvta.to.shared.u64 t, %1; cvt.u32.u64 %0, t; }"
        : "=r"(a) : "l"(p));
    return a;
}

__device__ __forceinline__ void ldsm4(uint32_t& r0, uint32_t& r1,
                                      uint32_t& r2, uint32_t& r3, uint32_t addr) {
    asm volatile("ldmatrix.sync.aligned.m8n8.x4.shared.b16 {%0,%1,%2,%3}, [%4];"
                 : "=r"(r0), "=r"(r1), "=r"(r2), "=r"(r3) : "r"(addr));
}

__device__ __forceinline__ void mma_f16(float c[4], const uint32_t a[4],
                                        const uint32_t b[2]) {
    asm volatile(
        "mma.sync.aligned.m16n8k16.row.col.f32.f16.f16.f32 "
        "{%0,%1,%2,%3}, {%4,%5,%6,%7}, {%8,%9}, {%0,%1,%2,%3};"
        : "+f"(c[0]), "+f"(c[1]), "+f"(c[2]), "+f"(c[3])
        : "r"(a[0]), "r"(a[1]), "r"(a[2]), "r"(a[3]), "r"(b[0]), "r"(b[1]));
}

#define CP_ASYNC16(dst, src, sz) \
    asm volatile("cp.async.cg.shared.global [%0], [%1], 16, %2;" \
                 :: "r"(dst), "l"(src), "r"(sz) : "memory")
#define CP_COMMIT() asm volatile("cp.async.commit_group;" ::: "memory")
#define CP_WAIT2()  asm volatile("cp.async.wait_group 2;" ::: "memory")

__global__ __launch_bounds__(256, 2)
void ha_linear2_kernel(
    const __half* __restrict__ A0, int lda0, const __half* __restrict__ W0, int ldw0,
    const float* __restrict__ bias0, float bs0, float* __restrict__ C0,
    int Nn0, int flip0, int act0,
    const __half* __restrict__ A1, int lda1, const __half* __restrict__ W1, int ldw1,
    const float* __restrict__ bias1, float bs1, float* __restrict__ C1,
    int Nn1, int flip1, int act1,
    int M, int Kd, int splitX, int splitZ, int kchunk)
{
    extern __shared__ __align__(16) char dsm[];
    const uint32_t sbase = smem_u32(dsm);

    int bx = blockIdx.x, bz = blockIdx.z, sel = 0;
    if (bx >= splitX) { sel = 1; bx -= splitX; }
    else if (bz >= splitZ) { sel = 1; bz -= splitZ; }

    const __half* __restrict__ A = sel ? A1 : A0;
    const __half* __restrict__ W = sel ? W1 : W0;
    const float* __restrict__ bias = sel ? bias1 : bias0;
    const float biasScale = sel ? bs1 : bs0;
    float* __restrict__ C = sel ? C1 : C0;
    const int lda  = sel ? lda1 : lda0;
    const int ldw  = sel ? ldw1 : ldw0;
    const int Nn   = sel ? Nn1 : Nn0;
    const int flip = sel ? flip1 : flip0;
    const int act  = sel ? act1 : act0;

    const int tid  = threadIdx.x;
    const int lane = tid & 31;
    const int warp = tid >> 5;
    const int g    = lane >> 2;
    const int tg   = lane & 3;
    const int warpM = (warp & 3) * 32;
    const int warpN = (warp >> 2) * 64;
    const int row0 = blockIdx.y * BM;
    const int col0 = bx * BN;

    int kb = 0, klen = Kd;
    if (kchunk > 0) {
        kb   = bz * kchunk;
        klen = kchunk;
        C   += (size_t)bz * M * Nn;
    }
    const int ntiles = klen / BK;

    int arow[2], wrow[2];
    uint32_t wsz[2];
#pragma unroll
    for (int i = 0; i < 2; i++) {
        int idx = tid + 256 * i;
        int r   = idx >> 2;
        int gr  = row0 + r;
        if (flip) { gr = (gr & ~(L_ - 1)) + ((L_ - 1) - (gr & (L_ - 1))); }
        arow[i] = gr;
        int gn = col0 + r;
        wsz[i]  = (gn < Nn) ? 16u : 0u;
        wrow[i] = (gn < Nn) ? gn : 0;
    }
    const int ld_row   = tid >> 2;
    const int ld_chunk = (tid & 3) * 8;

    const int tquad = lane >> 3;
    const int trow  = lane & 7;
    const int a_m = ((tquad & 1) << 3) + trow;
    const int a_k = (tquad >> 1) << 3;
    const int b_n = ((tquad >> 1) << 3) + trow;
    const int b_k = (tquad & 1) << 3;

    float acc[2][8][4];
#pragma unroll
    for (int mi = 0; mi < 2; mi++)
#pragma unroll
        for (int ni = 0; ni < 8; ni++)
#pragma unroll
            for (int q = 0; q < 4; q++) acc[mi][ni][q] = 0.f;

    auto issue = [&](int t, int s) {
        const uint32_t st = sbase + (uint32_t)s * STG_BYTES;
        const int koff = kb + t * BK + ld_chunk;
#pragma unroll
        for (int i = 0; i < 2; i++) {
            int r = ld_row + 64 * i;
            uint32_t da = st + (uint32_t)r * (BKP * 2) + (uint32_t)ld_chunk * 2;
            CP_ASYNC16(da, A + (size_t)arow[i] * lda + koff, 16u);
        }
#pragma unroll
        for (int i = 0; i < 2; i++) {
            int r = ld_row + 64 * i;
            uint32_t db = st + (uint32_t)(BM * BKP * 2)
                        + (uint32_t)r * (BKP * 2) + (uint32_t)ld_chunk * 2;
            CP_ASYNC16(db, W + (size_t)wrow[i] * ldw + koff, wsz[i]);
        }
    };

#pragma unroll
    for (int s = 0; s < STAGES - 1; s++) {
        if (s < ntiles) issue(s, s);
        CP_COMMIT();
    }

    for (int t = 0; t < ntiles; t++) {
        CP_WAIT2();
        __syncthreads();

        const int tn = t + STAGES - 1;
        if (tn < ntiles) issue(tn, tn & (STAGES - 1));
        CP_COMMIT();

        const uint32_t stA = sbase + (uint32_t)(t & (STAGES - 1)) * STG_BYTES;
        const uint32_t stB = stA + (uint32_t)(BM * BKP * 2);

#pragma unroll
        for (int kk = 0; kk < 2; kk++) {
            const uint32_t kbyte = (uint32_t)(kk * 16) * 2;
            uint32_t af[2][4], bf[8][2];
#pragma unroll
            for (int mi = 0; mi < 2; mi++) {
                uint32_t addr = stA + (uint32_t)(warpM + mi * 16 + a_m) * (BKP * 2)
                              + kbyte + (uint32_t)a_k * 2;
                ldsm4(af[mi][0], af[mi][1], af[mi][2], af[mi][3], addr);
            }
#pragma unroll
            for (int nj = 0; nj < 4; nj++) {
                uint32_t addr = stB + (uint32_t)(warpN + nj * 16 + b_n) * (BKP * 2)
                              + kbyte + (uint32_t)b_k * 2;
                ldsm4(bf[2 * nj][0], bf[2 * nj][1], bf[2 * nj + 1][0], bf[2 * nj + 1][1], addr);
            }
#pragma unroll
            for (int mi = 0; mi < 2; mi++)
#pragma unroll
                for (int ni = 0; ni < 8; ni++)
                    mma_f16(acc[mi][ni], af[mi], bf[ni]);
        }
    }

#pragma unroll
    for (int mi = 0; mi < 2; mi++) {
        int r0 = row0 + warpM + mi * 16 + g;
#pragma unroll
        for (int ni = 0; ni < 8; ni++) {
            int cb = col0 + warpN + ni * 8 + 2 * tg;
            if (cb < Nn) {
                float v00 = acc[mi][ni][0], v01 = acc[mi][ni][1];
                float v10 = acc[mi][ni][2], v11 = acc[mi][ni][3];
                if (bias) {
                    float b0 = biasScale * bias[cb];
                    float b1 = biasScale * bias[cb + 1];
                    v00 += b0; v01 += b1; v10 += b0; v11 += b1;
                }
                if (act >= 1) {  // softplus
                    v00 = (v00 > 20.f) ? v00 : log1pf(expf(v00));
                    v01 = (v01 > 20.f) ? v01 : log1pf(expf(v01));
                    v10 = (v10 > 20.f) ? v10 : log1pf(expf(v10));
                    v11 = (v11 > 20.f) ? v11 : log1pf(expf(v11));
                }
                if (act == 2) {  // fp16 store
                    __half* Ch = (__half*)C;
                    *(__half2*)(Ch + (size_t)r0 * Nn + cb)       = __floats2half2_rn(v00, v01);
                    *(__half2*)(Ch + (size_t)(r0 + 8) * Nn + cb) = __floats2half2_rn(v10, v11);
                } else {
                    *(float2*)(C + (size_t)r0 * Nn + cb)       = make_float2(v00, v01);
                    *(float2*)(C + (size_t)(r0 + 8) * Nn + cb) = make_float2(v10, v11);
                }
            }
        }
    }
}

// ---------------------------------------------------------------------------
// f32 -> f16 conversion, four arrays per launch
// ---------------------------------------------------------------------------
__global__ void cvt4_half_kernel(
    const float* __restrict__ s0, __half* __restrict__ d0, int n0,
    const float* __restrict__ s1, __half* __restrict__ d1, int n1,
    const float* __restrict__ s2, __half* __restrict__ d2, int n2,
    const float* __restrict__ s3, __half* __restrict__ d3, int n3)
{
    int i = (blockIdx.x * blockDim.x + threadIdx.x) * 8;
    const float* s;
    __half* d;
    if (i < n0) { s = s0 + i; d = d0 + i; }
    else if ((i -= n0) < n1) { s = s1 + i; d = d1 + i; }
    else if ((i -= n1) < n2) { s = s2 + i; d = d2 + i; }
    else if ((i -= n2) < n3) { s = s3 + i; d = d3 + i; }
    else return;
    float4 v0 = *(const float4*)s;
    float4 v1 = *(const float4*)(s + 4);
    __half2 h0 = __floats2half2_rn(v0.x, v0.y);
    __half2 h1 = __floats2half2_rn(v0.z, v0.w);
    __half2 h2 = __floats2half2_rn(v1.x, v1.y);
    __half2 h3 = __floats2half2_rn(v1.z, v1.w);
    *(uint4*)d = make_uint4(*(uint32_t*)&h0, *(uint32_t*)&h1,
                            *(uint32_t*)&h2, *(uint32_t*)&h3);
}

// ---------------------------------------------------------------------------
// Reduce split-K partials (dbl): f32 + fp16 out
// ---------------------------------------------------------------------------
__global__ void reduce_dbl_kernel(const float* __restrict__ part,
                                  float* __restrict__ of, float* __restrict__ ob,
                                  __half* __restrict__ hf, __half* __restrict__ hb)
{
    const int NV = MTOT * DBLC / 4;
    int i = blockIdx.x * blockDim.x + threadIdx.x;
    if (i >= 2 * NV) return;
    int br = (i >= NV);
    int j  = i - br * NV;
    const float4* p = (const float4*)part + (size_t)br * SPLITK * NV + j;
    float4 s = make_float4(0.f, 0.f, 0.f, 0.f);
#pragma unroll
    for (int k = 0; k < SPLITK; k++) {
        float4 v = p[(size_t)k * NV];
        s.x += v.x; s.y += v.y; s.z += v.z; s.w += v.w;
    }
    ((float4*)(br ? ob : of))[j] = s;
    __half2 h0 = __floats2half2_rn(s.x, s.y);
    __half2 h1 = __floats2half2_rn(s.z, s.w);
    ((uint2*)(br ? hb : hf))[j] = make_uint2(*(uint32_t*)&h0, *(uint32_t*)&h1);
}

// ---------------------------------------------------------------------------
// Reduce Wo split-K partials into out
// ---------------------------------------------------------------------------
__global__ void reduce_out_kernel(const float* __restrict__ part,
                                  float* __restrict__ out)
{
    const int NV = MTOT * DM / 4;
    int i = blockIdx.x * blockDim.x + threadIdx.x;
    if (i >= NV) return;
    float4 a = ((const float4*)part)[i];
    float4 b = ((const float4*)part)[i + NV];
    ((float4*)out)[i] = make_float4(a.x + b.x, a.y + b.y, a.z + b.z, a.w + b.w);
}

// ---------------------------------------------------------------------------
// Depthwise causal conv1d (K=4) + bias + SiLU; 8 l per thread; fp16 u out
// ---------------------------------------------------------------------------
#define CLG 8
__global__ void conv_silu_kernel(const float* __restrict__ x0, int ld0,
                                 const float* __restrict__ w0,
                                 const float* __restrict__ b0,
                                 __half* __restrict__ h0,
                                 const float* __restrict__ x1, int ld1,
                                 const float* __restrict__ w1,
                                 const float* __restrict__ b1,
                                 __half* __restrict__ h1)
{
    const int br = blockIdx.z;
    const float* __restrict__ x = br ? x1 : x0;
    const float* __restrict__ w = br ? w1 : w0;
    const float* __restrict__ bi = br ? b1 : b0;
    __half* __restrict__ hu = br ? h1 : h0;
    const int ldx = br ? ld1 : ld0;

    int idx = blockIdx.x * blockDim.x + threadIdx.x;
    if (idx >= (MTOT / CLG) * DI) return;
    const int d    = idx % DI;
    const int grp  = idx / DI;
    const int row0 = grp * CLG;
    const int l0   = row0 & (L_ - 1);
    const int bb0  = row0 - l0;

    float xv[CLG + KC - 1];
#pragma unroll
    for (int j = 0; j < CLG + KC - 1; j++) {
        int l = l0 - (KC - 1) + j;
        xv[j] = (l >= 0) ? x[(size_t)(bb0 + l) * ldx + d] : 0.f;
    }
    const float w0v = w[d * KC + 0], w1v = w[d * KC + 1],
                w2v = w[d * KC + 2], w3v = w[d * KC + 3];
    const float bv = bi[d];

#pragma unroll
    for (int j = 0; j < CLG; j++) {
        float acc = bv;
        acc = fmaf(xv[j],     w0v, acc);
        acc = fmaf(xv[j + 1], w1v, acc);
        acc = fmaf(xv[j + 2], w2v, acc);
        acc = fmaf(xv[j + 3], w3v, acc);
        float s = 1.f / (1.f + __expf(-acc));
        hu[(size_t)(row0 + j) * DI + d] = __float2half_rn(acc * s);
    }
}

// ---------------------------------------------------------------------------
// Chunked selective scan (phase1 / carry / phase2); delta & u read as fp16
// ---------------------------------------------------------------------------
#define SCAN_TPB 128
#define SCAN_ST  16

__global__ __launch_bounds__(SCAN_TPB)
void scan_phase1(const __half* __restrict__ del_f, const float* __restrict__ dbl_f,
                 const __half* __restrict__ u_f,
                 const __half* __restrict__ del_b, const float* __restrict__ dbl_b,
                 const __half* __restrict__ u_b,
                 const float* __restrict__ Alog_f, const float* __restrict__ Alog_b,
                 float* __restrict__ hloc, float* __restrict__ psum)
{
    const int br = blockIdx.y;
    const __half* __restrict__ del = br ? del_b : del_f;
    const float* __restrict__ dbl  = br ? dbl_b : dbl_f;
    const __half* __restrict__ u   = br ? u_b   : u_f;
    const float* __restrict__ Alog = br ? Alog_b : Alog_f;

    const int tid   = threadIdx.x;
    const int ch    = blockIdx.x & (NCH - 1);
    const int bb    = (blockIdx.x >> 3) & 1;
    const int dpart = blockIdx.x >> 4;
    const int d     = dpart * SCAN_TPB + tid;
    const int dbase = dpart * SCAN_TPB;
    const int rowb  = bb * L_ + ch * CH;

    float a[NS];
    bool fast = true;
#pragma unroll
    for (int n = 0; n < NS; n++) {
        a[n] = expf(Alog[(size_t)d * NS + n]);
        fast = fast && (fabsf(a[n] - (float)(n + 1)) < 1e-4f * (float)(n + 1));
    }

    float h[NS];
#pragma unroll
    for (int n = 0; n < NS; n++) h[n] = 0.f;
    float ps = 0.f;

    __shared__ float  s_del[SCAN_ST][SCAN_TPB];
    __shared__ float  s_u[SCAN_ST][SCAN_TPB];
    __shared__ float4 s_bc[SCAN_ST][8];

    for (int c0 = 0; c0 < CH; c0 += SCAN_ST) {
        __syncthreads();
#pragma unroll
        for (int k = 0; k < SCAN_ST; k++) {
            size_t off = (size_t)(rowb + c0 + k) * DI + dbase + tid;
            s_del[k][tid] = __half2float(del[off]);
            s_u[k][tid]   = __half2float(u[off]);
        }
        {
            int k = tid >> 3;
            int q = tid & 7;
            size_t off = (size_t)(rowb + c0 + k) * DBLC + RR + q * 4;
            s_bc[k][q] = *(const float4*)(dbl + off);
        }
        __syncthreads();

        if (fast) {
#pragma unroll 2
            for (int k = 0; k < SCAN_ST; k++) {
                float dl = s_del[k][tid];
                float du = dl * s_u[k][tid];
                ps += dl;
                float e = __expf(-dl);
                float4 V0 = s_bc[k][0], V1 = s_bc[k][1], V2 = s_bc[k][2], V3 = s_bc[k][3];
                float Bv[NS] = {V0.x,V0.y,V0.z,V0.w, V1.x,V1.y,V1.z,V1.w,
                                V2.x,V2.y,V2.z,V2.w, V3.x,V3.y,V3.z,V3.w};
                float p = e;
#pragma unroll
                for (int n = 0; n < NS; n++) {
                    h[n] = fmaf(p, h[n], du * Bv[n]);
                    p   *= e;
                }
            }
        } else {
            for (int k = 0; k < SCAN_ST; k++) {
                float dl = s_del[k][tid];
                float du = dl * s_u[k][tid];
                ps += dl;
                const float* bc = (const float*)s_bc[k];
#pragma unroll
                for (int n = 0; n < NS; n++) {
                    float dA = __expf(-dl * a[n]);
                    h[n] = fmaf(dA, h[n], du * bc[n]);
                }
            }
        }
    }

    const int cbase = ((br * B_ + bb) * NCH + ch);
    psum[(size_t)cbase * DI + d] = ps;
#pragma unroll
    for (int n = 0; n < NS; n++)
        hloc[((size_t)cbase * NS + n) * DI + d] = h[n];
}

__global__ void scan_carry(const float* __restrict__ hloc,
                           const float* __restrict__ psum,
                           const float* __restrict__ Alog_f,
                           const float* __restrict__ Alog_b,
                           float* __restrict__ hin)
{
    int idx = blockIdx.x * blockDim.x + threadIdx.x;
    if (idx >= 2 * B_ * DI) return;
    const int d  = idx % DI;
    const int bb = (idx / DI) % B_;
    const int br = idx / (B_ * DI);
    const float* __restrict__ Alog = br ? Alog_b : Alog_f;

    float a[NS];
    bool fast = true;
#pragma unroll
    for (int n = 0; n < NS; n++) {
        a[n] = expf(Alog[(size_t)d * NS + n]);
        fast = fast && (fabsf(a[n] - (float)(n + 1)) < 1e-4f * (float)(n + 1));
    }

    float h[NS];
#pragma unroll
    for (int n = 0; n < NS; n++) h[n] = 0.f;

    for (int ch = 0; ch < NCH; ch++) {
        const size_t cbase = ((size_t)(br * B_ + bb) * NCH + ch);
#pragma unroll
        for (int n = 0; n < NS; n++)
            hin[(cbase * NS + n) * DI + d] = h[n];
        float ps = psum[cbase * DI + d];
        if (fast) {
            float E = __expf(-ps);
            float p = E;
#pragma unroll
            for (int n = 0; n < NS; n++) {
                h[n] = fmaf(p, h[n], hloc[(cbase * NS + n) * DI + d]);
                p   *= E;
            }
        } else {
#pragma unroll
            for (int n = 0; n < NS; n++) {
                float P = __expf(-ps * a[n]);
                h[n] = fmaf(P, h[n], hloc[(cbase * NS + n) * DI + d]);
            }
        }
    }
}

__global__ __launch_bounds__(SCAN_TPB)
void scan_phase2(const __half* __restrict__ del_f, const float* __restrict__ dbl_f,
                 const __half* __restrict__ u_f,
                 const __half* __restrict__ del_b, const float* __restrict__ dbl_b,
                 const __half* __restrict__ u_b,
                 const float* __restrict__ Alog_f, const float* __restrict__ D_f,
                 const float* __restrict__ Alog_b, const float* __restrict__ D_b,
                 const float* __restrict__ hin,
                 float* __restrict__ y_f, float* __restrict__ y_b)
{
    const int br = blockIdx.y;
    const __half* __restrict__ del = br ? del_b : del_f;
    const float* __restrict__ dbl  = br ? dbl_b : dbl_f;
    const __half* __restrict__ u   = br ? u_b   : u_f;
    const float* __restrict__ Alog = br ? Alog_b : Alog_f;
    const float* __restrict__ Dv_p = br ? D_b : D_f;
    float* __restrict__ yout       = br ? y_b : y_f;

    const int tid   = threadIdx.x;
    const int ch    = blockIdx.x & (NCH - 1);
    const int bb    = (blockIdx.x >> 3) & 1;
    const int dpart = blockIdx.x >> 4;
    const int d     = dpart * SCAN_TPB + tid;
    const int dbase = dpart * SCAN_TPB;
    const int rowb  = bb * L_ + ch * CH;

    float a[NS];
    bool fast = true;
#pragma unroll
    for (int n = 0; n < NS; n++) {
        a[n] = expf(Alog[(size_t)d * NS + n]);
        fast = fast && (fabsf(a[n] - (float)(n + 1)) < 1e-4f * (float)(n + 1));
    }
    const float Dv = Dv_p[d];

    const size_t cbase = ((size_t)(br * B_ + bb) * NCH + ch);
    float h[NS];
#pragma unroll
    for (int n = 0; n < NS; n++)
        h[n] = hin[(cbase * NS + n) * DI + d];

    __shared__ float  s_del[SCAN_ST][SCAN_TPB];
    __shared__ float  s_u[SCAN_ST][SCAN_TPB];
    __shared__ float4 s_bc[SCAN_ST][8];

    for (int c0 = 0; c0 < CH; c0 += SCAN_ST) {
        __syncthreads();
#pragma unroll
        for (int k = 0; k < SCAN_ST; k++) {
            size_t off = (size_t)(rowb + c0 + k) * DI + dbase + tid;
            s_del[k][tid] = __half2float(del[off]);
            s_u[k][tid]   = __half2float(u[off]);
        }
        {
            int k = tid >> 3;
            int q = tid & 7;
            size_t off = (size_t)(rowb + c0 + k) * DBLC + RR + q * 4;
            s_bc[k][q] = *(const float4*)(dbl + off);
        }
        __syncthreads();

        if (fast) {
#pragma unroll 2
            for (int k = 0; k < SCAN_ST; k++) {
                float dl = s_del[k][tid];
                float uu = s_u[k][tid];
                float du = dl * uu;
                float e  = __expf(-dl);
                float4 V0 = s_bc[k][0], V1 = s_bc[k][1], V2 = s_bc[k][2], V3 = s_bc[k][3];
                float4 W0 = s_bc[k][4], W1 = s_bc[k][5], W2 = s_bc[k][6], W3 = s_bc[k][7];
                float Bv[NS] = {V0.x,V0.y,V0.z,V0.w, V1.x,V1.y,V1.z,V1.w,
                                V2.x,V2.y,V2.z,V2.w, V3.x,V3.y,V3.z,V3.w};
                float Cv[NS] = {W0.x,W0.y,W0.z,W0.w, W1.x,W1.y,W1.z,W1.w,
                                W2.x,W2.y,W2.z,W2.w, W3.x,W3.y,W3.z,W3.w};
                float p  = e;
                float yv0 = 0.f, yv1 = 0.f;
#pragma unroll
                for (int n = 0; n < NS; n++) {
                    h[n] = fmaf(p, h[n], du * Bv[n]);
                    if (n & 1) yv1 = fmaf(h[n], Cv[n], yv1);
                    else       yv0 = fmaf(h[n], Cv[n], yv0);
                    p   *= e;
                }
                float yv = fmaf(uu, Dv, yv0 + yv1);
                yout[(size_t)(rowb + c0 + k) * DI + d] = yv;
            }
        } else {
            for (int k = 0; k < SCAN_ST; k++) {
                float dl = s_del[k][tid];
                float uu = s_u[k][tid];
                float du = dl * uu;
                float yv = 0.f;
                const float* bc = (const float*)s_bc[k];
#pragma unroll
                for (int n = 0; n < NS; n++) {
                    float dA = __expf(-dl * a[n]);
                    h[n] = fmaf(dA, h[n], du * bc[n]);
                    yv   = fmaf(h[n], bc[NS + n], yv);
                }
                yv = fmaf(uu, Dv, yv);
                yout[(size_t)(rowb + c0 + k) * DI + d] = yv;
            }
        }
    }
}

// ---------------------------------------------------------------------------
// Gate (y * silu(z)) + RMSNorm * norm_w; writes fp16 g
// ---------------------------------------------------------------------------
__global__ __launch_bounds__(256)
void gate_rms_kernel(const float* __restrict__ yf, const float* __restrict__ yb,
                     const float* __restrict__ xz, const float* __restrict__ nw,
                     __half* __restrict__ g)
{
    const int row = blockIdx.x;
    const int l   = row & (L_ - 1);
    const int bb  = row >> 10;
    const int frow = (bb << 10) + (L_ - 1 - l);
    const int tid = threadIdx.x;

    __shared__ float sg[DI];
    __shared__ float red[8];

    float ss = 0.f;
    for (int d = tid; d < DI; d += 256) {
        float y  = yf[(size_t)row * DI + d] + yb[(size_t)frow * DI + d];
        float z  = xz[(size_t)row * (2 * DI) + DI + d];
        float sz = z / (1.f + __expf(-z));
        float gg = y * sz;
        sg[d] = gg;
        ss = fmaf(gg, gg, ss);
    }
#pragma unroll
    for (int o = 16; o; o >>= 1) ss += __shfl_xor_sync(0xFFFFFFFFu, ss, o);
    if ((tid & 31) == 0) red[tid >> 5] = ss;
    __syncthreads();
    float total = red[0] + red[1] + red[2] + red[3] + red[4] + red[5] + red[6] + red[7];
    float scale = rsqrtf(total / (float)DI + EPS);

    for (int d = tid; d < DI; d += 256) {
        g[(size_t)row * DI + d] = __float2half_rn(sg[d] * scale * nw[d]);
    }
}

// ---------------------------------------------------------------------------
// Launch
// ---------------------------------------------------------------------------
extern "C" void kernel_launch(void* const* d_in, const int* in_sizes, int n_in,
                              void* d_out, int out_size)
{
    (void)in_sizes; (void)n_in; (void)out_size;
    const float* a       = (const float*)d_in[0];
    const float* b       = (const float*)d_in[1];
    const float* Wi      = (const float*)d_in[2];
    const float* conv_w  = (const float*)d_in[3];
    const float* conv_b  = (const float*)d_in[4];
    const float* Wx      = (const float*)d_in[5];
    const float* Wdt     = (const float*)d_in[6];
    const float* bdt     = (const float*)d_in[7];
    const float* A_log   = (const float*)d_in[8];
    const float* D       = (const float*)d_in[9];
    const float* conv_w_b = (const float*)d_in[10];
    const float* conv_b_b = (const float*)d_in[11];
    const float* Wx_b    = (const float*)d_in[12];
    const float* Wdt_b   = (const float*)d_in[13];
    const float* bdt_b   = (const float*)d_in[14];
    const float* A_log_b = (const float*)d_in[15];
    const float* D_b     = (const float*)d_in[16];
    const float* Wo      = (const float*)d_in[17];
    const float* norm_w  = (const float*)d_in[18];
    float* out = (float*)d_out;

    __half *p_ha, *p_hb, *p_hWi, *p_hWo, *p_hWx, *p_hWx_b, *p_hWdt, *p_hWdt_b;
    __half *p_hu_f, *p_hu_b, *p_hdbl_f, *p_hdbl_b, *p_hdelta_f, *p_hdelta_b, *p_hg;
    float *p_xz_a, *p_xz_b, *p_dblp, *p_dbl_f, *p_dbl_b;
    float *p_y_f, *p_y_b, *p_wop;
    float *p_hloc, *p_hin, *p_psum;
    cudaGetSymbolAddress((void**)&p_ha, g_ha);
    cudaGetSymbolAddress((void**)&p_hb, g_hb);
    cudaGetSymbolAddress((void**)&p_hWi, g_hWi);
    cudaGetSymbolAddress((void**)&p_hWo, g_hWo);
    cudaGetSymbolAddress((void**)&p_hWx, g_hWx);
    cudaGetSymbolAddress((void**)&p_hWx_b, g_hWx_b);
    cudaGetSymbolAddress((void**)&p_hWdt, g_hWdt);
    cudaGetSymbolAddress((void**)&p_hWdt_b, g_hWdt_b);
    cudaGetSymbolAddress((void**)&p_hu_f, g_hu_f);
    cudaGetSymbolAddress((void**)&p_hu_b, g_hu_b);
    cudaGetSymbolAddress((void**)&p_hdbl_f, g_hdbl_f);
    cudaGetSymbolAddress((void**)&p_hdbl_b, g_hdbl_b);
    cudaGetSymbolAddress((void**)&p_hdelta_f, g_hdelta_f);
    cudaGetSymbolAddress((void**)&p_hdelta_b, g_hdelta_b);
    cudaGetSymbolAddress((void**)&p_hg, g_hg);
    cudaGetSymbolAddress((void**)&p_xz_a, g_xz_a);
    cudaGetSymbolAddress((void**)&p_xz_b, g_xz_b);
    cudaGetSymbolAddress((void**)&p_dblp, g_dblp);
    cudaGetSymbolAddress((void**)&p_dbl_f, g_dbl_f);
    cudaGetSymbolAddress((void**)&p_dbl_b, g_dbl_b);
    cudaGetSymbolAddress((void**)&p_y_f, g_y_f);
    cudaGetSymbolAddress((void**)&p_y_b, g_y_b);
    cudaGetSymbolAddress((void**)&p_wop, g_wop);
    cudaGetSymbolAddress((void**)&p_hloc, g_hloc);
    cudaGetSymbolAddress((void**)&p_hin, g_hin);
    cudaGetSymbolAddress((void**)&p_psum, g_psum);

    const int TPB = 256;
    cudaFuncSetAttribute(ha_linear2_kernel,
                         cudaFuncAttributeMaxDynamicSharedMemorySize, SMEM_TOTAL);

    // 0. convert inputs/weights to fp16 (two 4-array launches)
    {
        int nA = MTOT * DM, nB = MTOT * DM, nC = 2 * DI * DM, nD = DM * DI;
        cvt4_half_kernel<<<((nA + nB + nC + nD) / 8 + TPB - 1) / TPB, TPB>>>(
            a, p_ha, nA, b, p_hb, nB, Wi, p_hWi, nC, Wo, p_hWo, nD);
        int n0 = DBLC * DI, n1 = DBLC * DI, n2 = DI * RR, n3 = DI * RR;
        cvt4_half_kernel<<<((n0 + n1 + n2 + n3) / 8 + TPB - 1) / TPB, TPB>>>(
            Wx, p_hWx, n0, Wx_b, p_hWx_b, n1, Wdt, p_hWdt, n2, Wdt_b, p_hWdt_b, n3);
    }

    // 1. fused: xz_a = a @ Wi^T [2048,4096]  +  xz_b = flip(b) @ Wi[:DI]^T [2048,2048]
    ha_linear2_kernel<<<dim3(32 + 16, MTOT / BM, 1), TPB, SMEM_TOTAL>>>(
        p_ha, DM, p_hWi, DM, nullptr, 0.f, p_xz_a, 2 * DI, 0, 0,
        p_hb, DM, p_hWi, DM, nullptr, 0.f, p_xz_b, DI, 1, 0,
        MTOT, DM, /*splitX=*/32, /*splitZ=*/BIGSPLIT, 0);

    // 2. conv + silu (8 l/thread, both branches); fp16 u out
    conv_silu_kernel<<<dim3((MTOT / CLG) * DI / TPB, 1, 2), TPB>>>(
        p_xz_a, 2 * DI, conv_w, conv_b, p_hu_f,
        p_xz_b, DI, conv_w_b, conv_b_b, p_hu_b);

    // 3. fused dbl = u @ Wx^T [2048,96], split-K both branches
    ha_linear2_kernel<<<dim3(1, MTOT / BM, 2 * SPLITK), TPB, SMEM_TOTAL>>>(
        p_hu_f, DI, p_hWx, DI, nullptr, 0.f, p_dblp, DBLC, 0, 0,
        p_hu_b, DI, p_hWx_b, DI, nullptr, 0.f, p_dblp + (size_t)SPLITK * MTOT * DBLC,
        DBLC, 0, 0,
        MTOT, DI, /*splitX=*/BIGSPLIT, /*splitZ=*/SPLITK, KCHUNK);

    // 4. reduce partials -> dbl (f32 + fp16)
    {
        int nthreads = 2 * MTOT * DBLC / 4;
        reduce_dbl_kernel<<<(nthreads + TPB - 1) / TPB, TPB>>>(
            p_dblp, p_dbl_f, p_dbl_b, p_hdbl_f, p_hdbl_b);
    }

    // 5. fused delta = softplus(dt @ Wdt^T + 2*bdt), fp16 out, both branches
    ha_linear2_kernel<<<dim3(DI / BN, MTOT / BM, 2), TPB, SMEM_TOTAL>>>(
        p_hdbl_f, DBLC, p_hWdt, RR, bdt, 2.f, (float*)p_hdelta_f, DI, 0, 2,
        p_hdbl_b, DBLC, p_hWdt_b, RR, bdt_b, 2.f, (float*)p_hdelta_b, DI, 0, 2,
        MTOT, RR, /*splitX=*/BIGSPLIT, /*splitZ=*/1, 0);

    // 6. chunked selective scan (both branches)
    scan_phase1<<<dim3((DI / SCAN_TPB) * B_ * NCH, 2), SCAN_TPB>>>(
        p_hdelta_f, p_dbl_f, p_hu_f, p_hdelta_b, p_dbl_b, p_hu_b,
        A_log, A_log_b, p_hloc, p_psum);
    scan_carry<<<(2 * B_ * DI + TPB - 1) / TPB, TPB>>>(
        p_hloc, p_psum, A_log, A_log_b, p_hin);
    scan_phase2<<<dim3((DI / SCAN_TPB) * B_ * NCH, 2), SCAN_TPB>>>(
        p_hdelta_f, p_dbl_f, p_hu_f, p_hdelta_b, p_dbl_b, p_hu_b,
        A_log, D, A_log_b, D_b, p_hin, p_y_f, p_y_b);

    // 7. gate + rmsnorm (writes fp16 g)
    gate_rms_kernel<<<MTOT, TPB>>>(p_y_f, p_y_b, p_xz_a, norm_w, p_hg);

    // 8. out = g @ Wo^T [2048,1024], split-K x2
    ha_linear2_kernel<<<dim3(DM / BN, MTOT / BM, 2), TPB, SMEM_TOTAL>>>(
        p_hg, DI, p_hWo, DI, nullptr, 0.f, p_wop, DM, 0, 0,
        p_hg, DI, p_hWo, DI, nullptr, 0.f, p_wop, DM, 0, 0,
        MTOT, DI, /*splitX=*/BIGSPLIT, /*splitZ=*/BIGSPLIT, DI / 2);
    reduce_out_kernel<<<(MTOT * DM / 4 + TPB - 1) / TPB, TPB>>>(p_wop, out);
}

// round 11
// speedup vs baseline: 5.9798x; 1.0014x over previous
#include <cuda_runtime.h>
#include <cuda_bf16.h>
#include <cuda_fp16.h>
#include <math.h>
#include <stdint.h>

// Problem constants
#define B_  2
#define L_  1024
#define DM  1024
#define DI  2048
#define NS  16
#define RR  64
#define KC  4
#define MTOT (B_ * L_)      // 2048
#define EPS 1e-5f

#define DBLC (RR + 2 * NS)  // 96
#define SPLITK 8
#define KCHUNK (DI / SPLITK)  // 256

#define NCH 8               // scan chunks
#define CH  (L_ / NCH)      // 128 steps per chunk

#define BIGSPLIT 0x40000000

// ---------------------------------------------------------------------------
// Scratch buffers (device globals; no allocation allowed)
// ---------------------------------------------------------------------------
__device__ __half g_hA[MTOT * DM];
__device__ __half g_hB[MTOT * DM];
__device__ __half g_hWi[(2 * DI) * DM];
__device__ __half g_hWo[DM * DI];
__device__ __half g_hWx[DBLC * DI];
__device__ __half g_hWx_b[DBLC * DI];
__device__ __half g_hWdt[DI * RR];
__device__ __half g_hWdt_b[DI * RR];
__device__ __half g_hx_f[MTOT * DI];        // fp16 x (conv input), dense ld=DI
__device__ __half g_hx_b[MTOT * DI];
__device__ __half g_hu_f[MTOT * DI];        // fp16 u (GEMM + scan operand)
__device__ __half g_hu_b[MTOT * DI];
__device__ __half g_hdbl_f[MTOT * DBLC];
__device__ __half g_hdbl_b[MTOT * DBLC];
__device__ __half g_hdelta_f[MTOT * DI];    // fp16 delta (scan operand)
__device__ __half g_hdelta_b[MTOT * DI];
__device__ __half g_hg[MTOT * DI];

__device__ float g_z[MTOT * DI];            // f32 z (gate input)
__device__ float g_dblp[2 * SPLITK * MTOT * DBLC];
__device__ float g_dbl_f[MTOT * DBLC];
__device__ float g_dbl_b[MTOT * DBLC];
__device__ float g_y_f[MTOT * DI];
__device__ float g_y_b[MTOT * DI];
__device__ float g_wop[2 * MTOT * DM];

// scan chunking state
__device__ float g_hloc[2 * B_ * NCH * NS * DI];
__device__ float g_hin [2 * B_ * NCH * NS * DI];
__device__ float g_psum[2 * B_ * NCH * DI];

// ---------------------------------------------------------------------------
// fp16 tensor-core GEMM, cp.async 4-stage pipeline, DUAL-BRANCH:
//   Blocks with blockIdx.x >= splitX (or blockIdx.z >= splitZ) run set 1.
//   act: 0 = none, 1 = softplus (f32 out), 2 = softplus + fp16 out
//   Cx/NX: columns [0,NX) stored fp16 to Cx (ld NX); rest f32 to C (ld Nn-NX).
// ---------------------------------------------------------------------------
#define BM 128
#define BN 128
#define BK 32
#define BKP 40
#define STAGES 4
#define STG_BYTES ((BM + BN) * BKP * 2)
#define SMEM_TOTAL (STAGES * STG_BYTES)

__device__ __forceinline__ uint32_t smem_u32(const void* p) {
    uint32_t a;
    asm("{ .reg .u64 t; cvta.to.shared.u64 t, %1; cvt.u32.u64 %0, t; }"
        : "=r"(a) : "l"(p));
    return a;
}

__device__ __forceinline__ void ldsm4(uint32_t& r0, uint32_t& r1,
                                      uint32_t& r2, uint32_t& r3, uint32_t addr) {
    asm volatile("ldmatrix.sync.aligned.m8n8.x4.shared.b16 {%0,%1,%2,%3}, [%4];"
                 : "=r"(r0), "=r"(r1), "=r"(r2), "=r"(r3) : "r"(addr));
}

__device__ __forceinline__ void mma_f16(float c[4], const uint32_t a[4],
                                        const uint32_t b[2]) {
    asm volatile(
        "mma.sync.aligned.m16n8k16.row.col.f32.f16.f16.f32 "
        "{%0,%1,%2,%3}, {%4,%5,%6,%7}, {%8,%9}, {%0,%1,%2,%3};"
        : "+f"(c[0]), "+f"(c[1]), "+f"(c[2]), "+f"(c[3])
        : "r"(a[0]), "r"(a[1]), "r"(a[2]), "r"(a[3]), "r"(b[0]), "r"(b[1]));
}

#define CP_ASYNC16(dst, src, sz) \
    asm volatile("cp.async.cg.shared.global [%0], [%1], 16, %2;" \
                 :: "r"(dst), "l"(src), "r"(sz) : "memory")
#define CP_COMMIT() asm volatile("cp.async.commit_group;" ::: "memory")
#define CP_WAIT2()  asm volatile("cp.async.wait_group 2;" ::: "memory")

__global__ __launch_bounds__(256, 2)
void ha_linear2_kernel(
    const __half* __restrict__ A0, int lda0, const __half* __restrict__ W0, int ldw0,
    const float* __restrict__ bias0, float bs0, float* __restrict__ C0,
    __half* __restrict__ Cx0, int NX0,
    int Nn0, int flip0, int act0,
    const __half* __restrict__ A1, int lda1, const __half* __restrict__ W1, int ldw1,
    const float* __restrict__ bias1, float bs1, float* __restrict__ C1,
    __half* __restrict__ Cx1, int NX1,
    int Nn1, int flip1, int act1,
    int M, int Kd, int splitX, int splitZ, int kchunk)
{
    extern __shared__ __align__(16) char dsm[];
    const uint32_t sbase = smem_u32(dsm);

    int bx = blockIdx.x, bz = blockIdx.z, sel = 0;
    if (bx >= splitX) { sel = 1; bx -= splitX; }
    else if (bz >= splitZ) { sel = 1; bz -= splitZ; }

    const __half* __restrict__ A = sel ? A1 : A0;
    const __half* __restrict__ W = sel ? W1 : W0;
    const float* __restrict__ bias = sel ? bias1 : bias0;
    const float biasScale = sel ? bs1 : bs0;
    float* __restrict__ C = sel ? C1 : C0;
    __half* __restrict__ Cx = sel ? Cx1 : Cx0;
    const int NX   = sel ? NX1 : NX0;
    const int lda  = sel ? lda1 : lda0;
    const int ldw  = sel ? ldw1 : ldw0;
    const int Nn   = sel ? Nn1 : Nn0;
    const int flip = sel ? flip1 : flip0;
    const int act  = sel ? act1 : act0;

    const int tid  = threadIdx.x;
    const int lane = tid & 31;
    const int warp = tid >> 5;
    const int g    = lane >> 2;
    const int tg   = lane & 3;
    const int warpM = (warp & 3) * 32;
    const int warpN = (warp >> 2) * 64;
    const int row0 = blockIdx.y * BM;
    const int col0 = bx * BN;

    int kb = 0, klen = Kd;
    if (kchunk > 0) {
        kb   = bz * kchunk;
        klen = kchunk;
        C   += (size_t)bz * M * Nn;
    }
    const int ntiles = klen / BK;

    int arow[2], wrow[2];
    uint32_t wsz[2];
#pragma unroll
    for (int i = 0; i < 2; i++) {
        int idx = tid + 256 * i;
        int r   = idx >> 2;
        int gr  = row0 + r;
        if (flip) { gr = (gr & ~(L_ - 1)) + ((L_ - 1) - (gr & (L_ - 1))); }
        arow[i] = gr;
        int gn = col0 + r;
        wsz[i]  = (gn < Nn) ? 16u : 0u;
        wrow[i] = (gn < Nn) ? gn : 0;
    }
    const int ld_row   = tid >> 2;
    const int ld_chunk = (tid & 3) * 8;

    const int tquad = lane >> 3;
    const int trow  = lane & 7;
    const int a_m = ((tquad & 1) << 3) + trow;
    const int a_k = (tquad >> 1) << 3;
    const int b_n = ((tquad >> 1) << 3) + trow;
    const int b_k = (tquad & 1) << 3;

    float acc[2][8][4];
#pragma unroll
    for (int mi = 0; mi < 2; mi++)
#pragma unroll
        for (int ni = 0; ni < 8; ni++)
#pragma unroll
            for (int q = 0; q < 4; q++) acc[mi][ni][q] = 0.f;

    auto issue = [&](int t, int s) {
        const uint32_t st = sbase + (uint32_t)s * STG_BYTES;
        const int koff = kb + t * BK + ld_chunk;
#pragma unroll
        for (int i = 0; i < 2; i++) {
            int r = ld_row + 64 * i;
            uint32_t da = st + (uint32_t)r * (BKP * 2) + (uint32_t)ld_chunk * 2;
            CP_ASYNC16(da, A + (size_t)arow[i] * lda + koff, 16u);
        }
#pragma unroll
        for (int i = 0; i < 2; i++) {
            int r = ld_row + 64 * i;
            uint32_t db = st + (uint32_t)(BM * BKP * 2)
                        + (uint32_t)r * (BKP * 2) + (uint32_t)ld_chunk * 2;
            CP_ASYNC16(db, W + (size_t)wrow[i] * ldw + koff, wsz[i]);
        }
    };

#pragma unroll
    for (int s = 0; s < STAGES - 1; s++) {
        if (s < ntiles) issue(s, s);
        CP_COMMIT();
    }

    for (int t = 0; t < ntiles; t++) {
        CP_WAIT2();
        __syncthreads();

        const int tn = t + STAGES - 1;
        if (tn < ntiles) issue(tn, tn & (STAGES - 1));
        CP_COMMIT();

        const uint32_t stA = sbase + (uint32_t)(t & (STAGES - 1)) * STG_BYTES;
        const uint32_t stB = stA + (uint32_t)(BM * BKP * 2);

#pragma unroll
        for (int kk = 0; kk < 2; kk++) {
            const uint32_t kbyte = (uint32_t)(kk * 16) * 2;
            uint32_t af[2][4], bf[8][2];
#pragma unroll
            for (int mi = 0; mi < 2; mi++) {
                uint32_t addr = stA + (uint32_t)(warpM + mi * 16 + a_m) * (BKP * 2)
                              + kbyte + (uint32_t)a_k * 2;
                ldsm4(af[mi][0], af[mi][1], af[mi][2], af[mi][3], addr);
            }
#pragma unroll
            for (int nj = 0; nj < 4; nj++) {
                uint32_t addr = stB + (uint32_t)(warpN + nj * 16 + b_n) * (BKP * 2)
                              + kbyte + (uint32_t)b_k * 2;
                ldsm4(bf[2 * nj][0], bf[2 * nj][1], bf[2 * nj + 1][0], bf[2 * nj + 1][1], addr);
            }
#pragma unroll
            for (int mi = 0; mi < 2; mi++)
#pragma unroll
                for (int ni = 0; ni < 8; ni++)
                    mma_f16(acc[mi][ni], af[mi], bf[ni]);
        }
    }

    const bool isX = (Cx != nullptr) && (col0 < NX);
    const int  Nz  = Nn - NX;
#pragma unroll
    for (int mi = 0; mi < 2; mi++) {
        int r0 = row0 + warpM + mi * 16 + g;
#pragma unroll
        for (int ni = 0; ni < 8; ni++) {
            int cb = col0 + warpN + ni * 8 + 2 * tg;
            if (cb < Nn) {
                float v00 = acc[mi][ni][0], v01 = acc[mi][ni][1];
                float v10 = acc[mi][ni][2], v11 = acc[mi][ni][3];
                if (bias) {
                    float b0 = biasScale * bias[cb];
                    float b1 = biasScale * bias[cb + 1];
                    v00 += b0; v01 += b1; v10 += b0; v11 += b1;
                }
                if (act >= 1) {  // softplus
                    v00 = (v00 > 20.f) ? v00 : log1pf(expf(v00));
                    v01 = (v01 > 20.f) ? v01 : log1pf(expf(v01));
                    v10 = (v10 > 20.f) ? v10 : log1pf(expf(v10));
                    v11 = (v11 > 20.f) ? v11 : log1pf(expf(v11));
                }
                if (isX) {  // fp16 x-part
                    *(__half2*)(Cx + (size_t)r0 * NX + cb)       = __floats2half2_rn(v00, v01);
                    *(__half2*)(Cx + (size_t)(r0 + 8) * NX + cb) = __floats2half2_rn(v10, v11);
                } else if (act == 2) {  // fp16 store (delta)
                    __half* Ch = (__half*)C;
                    *(__half2*)(Ch + (size_t)r0 * Nn + cb)       = __floats2half2_rn(v00, v01);
                    *(__half2*)(Ch + (size_t)(r0 + 8) * Nn + cb) = __floats2half2_rn(v10, v11);
                } else {
                    int cz = cb - NX;
                    *(float2*)(C + (size_t)r0 * Nz + cz)       = make_float2(v00, v01);
                    *(float2*)(C + (size_t)(r0 + 8) * Nz + cz) = make_float2(v10, v11);
                }
            }
        }
    }
}

// ---------------------------------------------------------------------------
// f32 -> f16 conversion, four arrays per launch
// ---------------------------------------------------------------------------
__global__ void cvt4_half_kernel(
    const float* __restrict__ s0, __half* __restrict__ d0, int n0,
    const float* __restrict__ s1, __half* __restrict__ d1, int n1,
    const float* __restrict__ s2, __half* __restrict__ d2, int n2,
    const float* __restrict__ s3, __half* __restrict__ d3, int n3)
{
    int i = (blockIdx.x * blockDim.x + threadIdx.x) * 8;
    const float* s;
    __half* d;
    if (i < n0) { s = s0 + i; d = d0 + i; }
    else if ((i -= n0) < n1) { s = s1 + i; d = d1 + i; }
    else if ((i -= n1) < n2) { s = s2 + i; d = d2 + i; }
    else if ((i -= n2) < n3) { s = s3 + i; d = d3 + i; }
    else return;
    float4 v0 = *(const float4*)s;
    float4 v1 = *(const float4*)(s + 4);
    __half2 h0 = __floats2half2_rn(v0.x, v0.y);
    __half2 h1 = __floats2half2_rn(v0.z, v0.w);
    __half2 h2 = __floats2half2_rn(v1.x, v1.y);
    __half2 h3 = __floats2half2_rn(v1.z, v1.w);
    *(uint4*)d = make_uint4(*(uint32_t*)&h0, *(uint32_t*)&h1,
                            *(uint32_t*)&h2, *(uint32_t*)&h3);
}

// ---------------------------------------------------------------------------
// Reduce split-K partials (dbl): f32 + fp16 out
// ---------------------------------------------------------------------------
__global__ void reduce_dbl_kernel(const float* __restrict__ part,
                                  float* __restrict__ of, float* __restrict__ ob,
                                  __half* __restrict__ hf, __half* __restrict__ hb)
{
    const int NV = MTOT * DBLC / 4;
    int i = blockIdx.x * blockDim.x + threadIdx.x;
    if (i >= 2 * NV) return;
    int br = (i >= NV);
    int j  = i - br * NV;
    const float4* p = (const float4*)part + (size_t)br * SPLITK * NV + j;
    float4 s = make_float4(0.f, 0.f, 0.f, 0.f);
#pragma unroll
    for (int k = 0; k < SPLITK; k++) {
        float4 v = p[(size_t)k * NV];
        s.x += v.x; s.y += v.y; s.z += v.z; s.w += v.w;
    }
    ((float4*)(br ? ob : of))[j] = s;
    __half2 h0 = __floats2half2_rn(s.x, s.y);
    __half2 h1 = __floats2half2_rn(s.z, s.w);
    ((uint2*)(br ? hb : hf))[j] = make_uint2(*(uint32_t*)&h0, *(uint32_t*)&h1);
}

// ---------------------------------------------------------------------------
// Reduce Wo split-K partials into out
// ---------------------------------------------------------------------------
__global__ void reduce_out_kernel(const float* __restrict__ part,
                                  float* __restrict__ out)
{
    const int NV = MTOT * DM / 4;
    int i = blockIdx.x * blockDim.x + threadIdx.x;
    if (i >= NV) return;
    float4 a = ((const float4*)part)[i];
    float4 b = ((const float4*)part)[i + NV];
    ((float4*)out)[i] = make_float4(a.x + b.x, a.y + b.y, a.z + b.z, a.w + b.w);
}

// ---------------------------------------------------------------------------
// Depthwise causal conv1d (K=4) + bias + SiLU; 8 l per thread; fp16 in/out
// ---------------------------------------------------------------------------
#define CLG 8
__global__ void conv_silu_kernel(const __half* __restrict__ x0,
                                 const float* __restrict__ w0,
                                 const float* __restrict__ b0,
                                 __half* __restrict__ h0,
                                 const __half* __restrict__ x1,
                                 const float* __restrict__ w1,
                                 const float* __restrict__ b1,
                                 __half* __restrict__ h1)
{
    const int br = blockIdx.z;
    const __half* __restrict__ x = br ? x1 : x0;
    const float* __restrict__ w = br ? w1 : w0;
    const float* __restrict__ bi = br ? b1 : b0;
    __half* __restrict__ hu = br ? h1 : h0;

    int idx = blockIdx.x * blockDim.x + threadIdx.x;
    if (idx >= (MTOT / CLG) * DI) return;
    const int d    = idx % DI;
    const int grp  = idx / DI;
    const int row0 = grp * CLG;
    const int l0   = row0 & (L_ - 1);
    const int bb0  = row0 - l0;

    float xv[CLG + KC - 1];
#pragma unroll
    for (int j = 0; j < CLG + KC - 1; j++) {
        int l = l0 - (KC - 1) + j;
        xv[j] = (l >= 0) ? __half2float(x[(size_t)(bb0 + l) * DI + d]) : 0.f;
    }
    const float w0v = w[d * KC + 0], w1v = w[d * KC + 1],
                w2v = w[d * KC + 2], w3v = w[d * KC + 3];
    const float bv = bi[d];

#pragma unroll
    for (int j = 0; j < CLG; j++) {
        float acc = bv;
        acc = fmaf(xv[j],     w0v, acc);
        acc = fmaf(xv[j + 1], w1v, acc);
        acc = fmaf(xv[j + 2], w2v, acc);
        acc = fmaf(xv[j + 3], w3v, acc);
        float s = 1.f / (1.f + __expf(-acc));
        hu[(size_t)(row0 + j) * DI + d] = __float2half_rn(acc * s);
    }
}

// ---------------------------------------------------------------------------
// Chunked selective scan (phase1 / carry / phase2); delta & u read as fp16
// ---------------------------------------------------------------------------
#define SCAN_TPB 128
#define SCAN_ST  16

__global__ __launch_bounds__(SCAN_TPB)
void scan_phase1(const __half* __restrict__ del_f, const float* __restrict__ dbl_f,
                 const __half* __restrict__ u_f,
                 const __half* __restrict__ del_b, const float* __restrict__ dbl_b,
                 const __half* __restrict__ u_b,
                 const float* __restrict__ Alog_f, const float* __restrict__ Alog_b,
                 float* __restrict__ hloc, float* __restrict__ psum)
{
    const int br = blockIdx.y;
    const __half* __restrict__ del = br ? del_b : del_f;
    const float* __restrict__ dbl  = br ? dbl_b : dbl_f;
    const __half* __restrict__ u   = br ? u_b   : u_f;
    const float* __restrict__ Alog = br ? Alog_b : Alog_f;

    const int tid   = threadIdx.x;
    const int ch    = blockIdx.x & (NCH - 1);
    const int bb    = (blockIdx.x >> 3) & 1;
    const int dpart = blockIdx.x >> 4;
    const int d     = dpart * SCAN_TPB + tid;
    const int dbase = dpart * SCAN_TPB;
    const int rowb  = bb * L_ + ch * CH;

    float a[NS];
    bool fast = true;
#pragma unroll
    for (int n = 0; n < NS; n++) {
        a[n] = expf(Alog[(size_t)d * NS + n]);
        fast = fast && (fabsf(a[n] - (float)(n + 1)) < 1e-4f * (float)(n + 1));
    }

    float h[NS];
#pragma unroll
    for (int n = 0; n < NS; n++) h[n] = 0.f;
    float ps = 0.f;

    __shared__ float  s_del[SCAN_ST][SCAN_TPB];
    __shared__ float  s_u[SCAN_ST][SCAN_TPB];
    __shared__ float4 s_bc[SCAN_ST][4];   // B only

    for (int c0 = 0; c0 < CH; c0 += SCAN_ST) {
        __syncthreads();
#pragma unroll
        for (int k = 0; k < SCAN_ST; k++) {
            size_t off = (size_t)(rowb + c0 + k) * DI + dbase + tid;
            s_del[k][tid] = __half2float(del[off]);
            s_u[k][tid]   = __half2float(u[off]);
        }
        if (tid < 64) {
            int k = tid >> 2;
            int q = tid & 3;
            size_t off = (size_t)(rowb + c0 + k) * DBLC + RR + q * 4;
            s_bc[k][q] = *(const float4*)(dbl + off);
        }
        __syncthreads();

        if (fast) {
#pragma unroll 2
            for (int k = 0; k < SCAN_ST; k++) {
                float dl = s_del[k][tid];
                float du = dl * s_u[k][tid];
                ps += dl;
                float e = __expf(-dl);
                float4 V0 = s_bc[k][0], V1 = s_bc[k][1], V2 = s_bc[k][2], V3 = s_bc[k][3];
                float Bv[NS] = {V0.x,V0.y,V0.z,V0.w, V1.x,V1.y,V1.z,V1.w,
                                V2.x,V2.y,V2.z,V2.w, V3.x,V3.y,V3.z,V3.w};
                float p = e;
#pragma unroll
                for (int n = 0; n < NS; n++) {
                    h[n] = fmaf(p, h[n], du * Bv[n]);
                    p   *= e;
                }
            }
        } else {
            for (int k = 0; k < SCAN_ST; k++) {
                float dl = s_del[k][tid];
                float du = dl * s_u[k][tid];
                ps += dl;
                const float* bc = (const float*)s_bc[k];
#pragma unroll
                for (int n = 0; n < NS; n++) {
                    float dA = __expf(-dl * a[n]);
                    h[n] = fmaf(dA, h[n], du * bc[n]);
                }
            }
        }
    }

    const int cbase = ((br * B_ + bb) * NCH + ch);
    psum[(size_t)cbase * DI + d] = ps;
#pragma unroll
    for (int n = 0; n < NS; n++)
        hloc[((size_t)cbase * NS + n) * DI + d] = h[n];
}

__global__ void scan_carry(const float* __restrict__ hloc,
                           const float* __restrict__ psum,
                           const float* __restrict__ Alog_f,
                           const float* __restrict__ Alog_b,
                           float* __restrict__ hin)
{
    int idx = blockIdx.x * blockDim.x + threadIdx.x;
    if (idx >= 2 * B_ * DI) return;
    const int d  = idx % DI;
    const int bb = (idx / DI) % B_;
    const int br = idx / (B_ * DI);
    const float* __restrict__ Alog = br ? Alog_b : Alog_f;

    float a[NS];
    bool fast = true;
#pragma unroll
    for (int n = 0; n < NS; n++) {
        a[n] = expf(Alog[(size_t)d * NS + n]);
        fast = fast && (fabsf(a[n] - (float)(n + 1)) < 1e-4f * (float)(n + 1));
    }

    float h[NS];
#pragma unroll
    for (int n = 0; n < NS; n++) h[n] = 0.f;

    for (int ch = 0; ch < NCH; ch++) {
        const size_t cbase = ((size_t)(br * B_ + bb) * NCH + ch);
#pragma unroll
        for (int n = 0; n < NS; n++)
            hin[(cbase * NS + n) * DI + d] = h[n];
        float ps = psum[cbase * DI + d];
        if (fast) {
            float E = __expf(-ps);
            float p = E;
#pragma unroll
            for (int n = 0; n < NS; n++) {
                h[n] = fmaf(p, h[n], hloc[(cbase * NS + n) * DI + d]);
                p   *= E;
            }
        } else {
#pragma unroll
            for (int n = 0; n < NS; n++) {
                float P = __expf(-ps * a[n]);
                h[n] = fmaf(P, h[n], hloc[(cbase * NS + n) * DI + d]);
            }
        }
    }
}

__global__ __launch_bounds__(SCAN_TPB)
void scan_phase2(const __half* __restrict__ del_f, const float* __restrict__ dbl_f,
                 const __half* __restrict__ u_f,
                 const __half* __restrict__ del_b, const float* __restrict__ dbl_b,
                 const __half* __restrict__ u_b,
                 const float* __restrict__ Alog_f, const float* __restrict__ D_f,
                 const float* __restrict__ Alog_b, const float* __restrict__ D_b,
                 const float* __restrict__ hin,
                 float* __restrict__ y_f, float* __restrict__ y_b)
{
    const int br = blockIdx.y;
    const __half* __restrict__ del = br ? del_b : del_f;
    const float* __restrict__ dbl  = br ? dbl_b : dbl_f;
    const __half* __restrict__ u   = br ? u_b   : u_f;
    const float* __restrict__ Alog = br ? Alog_b : Alog_f;
    const float* __restrict__ Dv_p = br ? D_b : D_f;
    float* __restrict__ yout       = br ? y_b : y_f;

    const int tid   = threadIdx.x;
    const int ch    = blockIdx.x & (NCH - 1);
    const int bb    = (blockIdx.x >> 3) & 1;
    const int dpart = blockIdx.x >> 4;
    const int d     = dpart * SCAN_TPB + tid;
    const int dbase = dpart * SCAN_TPB;
    const int rowb  = bb * L_ + ch * CH;

    float a[NS];
    bool fast = true;
#pragma unroll
    for (int n = 0; n < NS; n++) {
        a[n] = expf(Alog[(size_t)d * NS + n]);
        fast = fast && (fabsf(a[n] - (float)(n + 1)) < 1e-4f * (float)(n + 1));
    }
    const float Dv = Dv_p[d];

    const size_t cbase = ((size_t)(br * B_ + bb) * NCH + ch);
    float h[NS];
#pragma unroll
    for (int n = 0; n < NS; n++)
        h[n] = hin[(cbase * NS + n) * DI + d];

    __shared__ float  s_del[SCAN_ST][SCAN_TPB];
    __shared__ float  s_u[SCAN_ST][SCAN_TPB];
    __shared__ float4 s_bc[SCAN_ST][8];

    for (int c0 = 0; c0 < CH; c0 += SCAN_ST) {
        __syncthreads();
#pragma unroll
        for (int k = 0; k < SCAN_ST; k++) {
            size_t off = (size_t)(rowb + c0 + k) * DI + dbase + tid;
            s_del[k][tid] = __half2float(del[off]);
            s_u[k][tid]   = __half2float(u[off]);
        }
        {
            int k = tid >> 3;
            int q = tid & 7;
            size_t off = (size_t)(rowb + c0 + k) * DBLC + RR + q * 4;
            s_bc[k][q] = *(const float4*)(dbl + off);
        }
        __syncthreads();

        if (fast) {
#pragma unroll 2
            for (int k = 0; k < SCAN_ST; k++) {
                float dl = s_del[k][tid];
                float uu = s_u[k][tid];
                float du = dl * uu;
                float e  = __expf(-dl);
                float4 V0 = s_bc[k][0], V1 = s_bc[k][1], V2 = s_bc[k][2], V3 = s_bc[k][3];
                float4 W0 = s_bc[k][4], W1 = s_bc[k][5], W2 = s_bc[k][6], W3 = s_bc[k][7];
                float Bv[NS] = {V0.x,V0.y,V0.z,V0.w, V1.x,V1.y,V1.z,V1.w,
                                V2.x,V2.y,V2.z,V2.w, V3.x,V3.y,V3.z,V3.w};
                float Cv[NS] = {W0.x,W0.y,W0.z,W0.w, W1.x,W1.y,W1.z,W1.w,
                                W2.x,W2.y,W2.z,W2.w, W3.x,W3.y,W3.z,W3.w};
                float p  = e;
                float yv0 = 0.f, yv1 = 0.f;
#pragma unroll
                for (int n = 0; n < NS; n++) {
                    h[n] = fmaf(p, h[n], du * Bv[n]);
                    if (n & 1) yv1 = fmaf(h[n], Cv[n], yv1);
                    else       yv0 = fmaf(h[n], Cv[n], yv0);
                    p   *= e;
                }
                float yv = fmaf(uu, Dv, yv0 + yv1);
                yout[(size_t)(rowb + c0 + k) * DI + d] = yv;
            }
        } else {
            for (int k = 0; k < SCAN_ST; k++) {
                float dl = s_del[k][tid];
                float uu = s_u[k][tid];
                float du = dl * uu;
                float yv = 0.f;
                const float* bc = (const float*)s_bc[k];
#pragma unroll
                for (int n = 0; n < NS; n++) {
                    float dA = __expf(-dl * a[n]);
                    h[n] = fmaf(dA, h[n], du * bc[n]);
                    yv   = fmaf(h[n], bc[NS + n], yv);
                }
                yv = fmaf(uu, Dv, yv);
                yout[(size_t)(rowb + c0 + k) * DI + d] = yv;
            }
        }
    }
}

// ---------------------------------------------------------------------------
// Gate (y * silu(z)) + RMSNorm * norm_w; z dense f32; writes fp16 g
// ---------------------------------------------------------------------------
__global__ __launch_bounds__(256)
void gate_rms_kernel(const float* __restrict__ yf, const float* __restrict__ yb,
                     const float* __restrict__ z, const float* __restrict__ nw,
                     __half* __restrict__ g)
{
    const int row = blockIdx.x;
    const int l   = row & (L_ - 1);
    const int bb  = row >> 10;
    const int frow = (bb << 10) + (L_ - 1 - l);
    const int tid = threadIdx.x;

    __shared__ float sg[DI];
    __shared__ float red[8];

    float ss = 0.f;
    for (int d = tid; d < DI; d += 256) {
        float y  = yf[(size_t)row * DI + d] + yb[(size_t)frow * DI + d];
        float zz = z[(size_t)row * DI + d];
        float sz = zz / (1.f + __expf(-zz));
        float gg = y * sz;
        sg[d] = gg;
        ss = fmaf(gg, gg, ss);
    }
#pragma unroll
    for (int o = 16; o; o >>= 1) ss += __shfl_xor_sync(0xFFFFFFFFu, ss, o);
    if ((tid & 31) == 0) red[tid >> 5] = ss;
    __syncthreads();
    float total = red[0] + red[1] + red[2] + red[3] + red[4] + red[5] + red[6] + red[7];
    float scale = rsqrtf(total / (float)DI + EPS);

    for (int d = tid; d < DI; d += 256) {
        g[(size_t)row * DI + d] = __float2half_rn(sg[d] * scale * nw[d]);
    }
}

// ---------------------------------------------------------------------------
// Launch
// ---------------------------------------------------------------------------
extern "C" void kernel_launch(void* const* d_in, const int* in_sizes, int n_in,
                              void* d_out, int out_size)
{
    (void)in_sizes; (void)n_in; (void)out_size;
    const float* a       = (const float*)d_in[0];
    const float* b       = (const float*)d_in[1];
    const float* Wi      = (const float*)d_in[2];
    const float* conv_w  = (const float*)d_in[3];
    const float* conv_b  = (const float*)d_in[4];
    const float* Wx      = (const float*)d_in[5];
    const float* Wdt     = (const float*)d_in[6];
    const float* bdt     = (const float*)d_in[7];
    const float* A_log   = (const float*)d_in[8];
    const float* D       = (const float*)d_in[9];
    const float* conv_w_b = (const float*)d_in[10];
    const float* conv_b_b = (const float*)d_in[11];
    const float* Wx_b    = (const float*)d_in[12];
    const float* Wdt_b   = (const float*)d_in[13];
    const float* bdt_b   = (const float*)d_in[14];
    const float* A_log_b = (const float*)d_in[15];
    const float* D_b     = (const float*)d_in[16];
    const float* Wo      = (const float*)d_in[17];
    const float* norm_w  = (const float*)d_in[18];
    float* out = (float*)d_out;

    __half *p_hA, *p_hB, *p_hWi, *p_hWo, *p_hWx, *p_hWx_b, *p_hWdt, *p_hWdt_b;
    __half *p_hx_f, *p_hx_b, *p_hu_f, *p_hu_b, *p_hdbl_f, *p_hdbl_b;
    __half *p_hdelta_f, *p_hdelta_b, *p_hg;
    float *p_z, *p_dblp, *p_dbl_f, *p_dbl_b, *p_y_f, *p_y_b, *p_wop;
    float *p_hloc, *p_hin, *p_psum;
    cudaGetSymbolAddress((void**)&p_hA, g_hA);
    cudaGetSymbolAddress((void**)&p_hB, g_hB);
    cudaGetSymbolAddress((void**)&p_hWi, g_hWi);
    cudaGetSymbolAddress((void**)&p_hWo, g_hWo);
    cudaGetSymbolAddress((void**)&p_hWx, g_hWx);
    cudaGetSymbolAddress((void**)&p_hWx_b, g_hWx_b);
    cudaGetSymbolAddress((void**)&p_hWdt, g_hWdt);
    cudaGetSymbolAddress((void**)&p_hWdt_b, g_hWdt_b);
    cudaGetSymbolAddress((void**)&p_hx_f, g_hx_f);
    cudaGetSymbolAddress((void**)&p_hx_b, g_hx_b);
    cudaGetSymbolAddress((void**)&p_hu_f, g_hu_f);
    cudaGetSymbolAddress((void**)&p_hu_b, g_hu_b);
    cudaGetSymbolAddress((void**)&p_hdbl_f, g_hdbl_f);
    cudaGetSymbolAddress((void**)&p_hdbl_b, g_hdbl_b);
    cudaGetSymbolAddress((void**)&p_hdelta_f, g_hdelta_f);
    cudaGetSymbolAddress((void**)&p_hdelta_b, g_hdelta_b);
    cudaGetSymbolAddress((void**)&p_hg, g_hg);
    cudaGetSymbolAddress((void**)&p_z, g_z);
    cudaGetSymbolAddress((void**)&p_dblp, g_dblp);
    cudaGetSymbolAddress((void**)&p_dbl_f, g_dbl_f);
    cudaGetSymbolAddress((void**)&p_dbl_b, g_dbl_b);
    cudaGetSymbolAddress((void**)&p_y_f, g_y_f);
    cudaGetSymbolAddress((void**)&p_y_b, g_y_b);
    cudaGetSymbolAddress((void**)&p_wop, g_wop);
    cudaGetSymbolAddress((void**)&p_hloc, g_hloc);
    cudaGetSymbolAddress((void**)&p_hin, g_hin);
    cudaGetSymbolAddress((void**)&p_psum, g_psum);

    const int TPB = 256;
    cudaFuncSetAttribute(ha_linear2_kernel,
                         cudaFuncAttributeMaxDynamicSharedMemorySize, SMEM_TOTAL);

    // 0. convert inputs/weights to fp16 (two 4-array launches)
    {
        int nA = MTOT * DM, nB = MTOT * DM, nC = 2 * DI * DM, nD = DM * DI;
        cvt4_half_kernel<<<((nA + nB + nC + nD) / 8 + TPB - 1) / TPB, TPB>>>(
            a, p_hA, nA, b, p_hB, nB, Wi, p_hWi, nC, Wo, p_hWo, nD);
        int n0 = DBLC * DI, n1 = DBLC * DI, n2 = DI * RR, n3 = DI * RR;
        cvt4_half_kernel<<<((n0 + n1 + n2 + n3) / 8 + TPB - 1) / TPB, TPB>>>(
            Wx, p_hWx, n0, Wx_b, p_hWx_b, n1, Wdt, p_hWdt, n2, Wdt_b, p_hWdt_b, n3);
    }

    // 1. fused xz GEMM: fwd x->fp16 + z->f32; bwd x->fp16
    ha_linear2_kernel<<<dim3(32 + 16, MTOT / BM, 1), TPB, SMEM_TOTAL>>>(
        p_hA, DM, p_hWi, DM, nullptr, 0.f, p_z, p_hx_f, DI, 2 * DI, 0, 0,
        p_hB, DM, p_hWi, DM, nullptr, 0.f, nullptr, p_hx_b, DI, DI, 1, 0,
        MTOT, DM, /*splitX=*/32, /*splitZ=*/BIGSPLIT, 0);

    // 2. conv + silu (8 l/thread, both branches); fp16 in/out
    conv_silu_kernel<<<dim3((MTOT / CLG) * DI / TPB, 1, 2), TPB>>>(
        p_hx_f, conv_w, conv_b, p_hu_f,
        p_hx_b, conv_w_b, conv_b_b, p_hu_b);

    // 3. fused dbl = u @ Wx^T [2048,96], split-K both branches
    ha_linear2_kernel<<<dim3(1, MTOT / BM, 2 * SPLITK), TPB, SMEM_TOTAL>>>(
        p_hu_f, DI, p_hWx, DI, nullptr, 0.f, p_dblp, nullptr, 0, DBLC, 0, 0,
        p_hu_b, DI, p_hWx_b, DI, nullptr, 0.f, p_dblp + (size_t)SPLITK * MTOT * DBLC,
        nullptr, 0, DBLC, 0, 0,
        MTOT, DI, /*splitX=*/BIGSPLIT, /*splitZ=*/SPLITK, KCHUNK);

    // 4. reduce partials -> dbl (f32 + fp16)
    {
        int nthreads = 2 * MTOT * DBLC / 4;
        reduce_dbl_kernel<<<(nthreads + TPB - 1) / TPB, TPB>>>(
            p_dblp, p_dbl_f, p_dbl_b, p_hdbl_f, p_hdbl_b);
    }

    // 5. fused delta = softplus(dt @ Wdt^T + 2*bdt), fp16 out, both branches
    ha_linear2_kernel<<<dim3(DI / BN, MTOT / BM, 2), TPB, SMEM_TOTAL>>>(
        p_hdbl_f, DBLC, p_hWdt, RR, bdt, 2.f, (float*)p_hdelta_f, nullptr, 0, DI, 0, 2,
        p_hdbl_b, DBLC, p_hWdt_b, RR, bdt_b, 2.f, (float*)p_hdelta_b, nullptr, 0, DI, 0, 2,
        MTOT, RR, /*splitX=*/BIGSPLIT, /*splitZ=*/1, 0);

    // 6. chunked selective scan (both branches)
    scan_phase1<<<dim3((DI / SCAN_TPB) * B_ * NCH, 2), SCAN_TPB>>>(
        p_hdelta_f, p_dbl_f, p_hu_f, p_hdelta_b, p_dbl_b, p_hu_b,
        A_log, A_log_b, p_hloc, p_psum);
    scan_carry<<<(2 * B_ * DI + TPB - 1) / TPB, TPB>>>(
        p_hloc, p_psum, A_log, A_log_b, p_hin);
    scan_phase2<<<dim3((DI / SCAN_TPB) * B_ * NCH, 2), SCAN_TPB>>>(
        p_hdelta_f, p_dbl_f, p_hu_f, p_hdelta_b, p_dbl_b, p_hu_b,
        A_log, D, A_log_b, D_b, p_hin, p_y_f, p_y_b);

    // 7. gate + rmsnorm (writes fp16 g)
    gate_rms_kernel<<<MTOT, TPB>>>(p_y_f, p_y_b, p_z, norm_w, p_hg);

    // 8. out = g @ Wo^T [2048,1024], split-K x2
    ha_linear2_kernel<<<dim3(DM / BN, MTOT / BM, 2), TPB, SMEM_TOTAL>>>(
        p_hg, DI, p_hWo, DI, nullptr, 0.f, p_wop, nullptr, 0, DM, 0, 0,
        p_hg, DI, p_hWo, DI, nullptr, 0.f, p_wop, nullptr, 0, DM, 0, 0,
        MTOT, DI, /*splitX=*/BIGSPLIT, /*splitZ=*/BIGSPLIT, DI / 2);
    reduce_out_kernel<<<(MTOT * DM / 4 + TPB - 1) / TPB, TPB>>>(p_wop, out);
}

// round 12
// speedup vs baseline: 6.0194x; 1.0066x over previous
#include <cuda_runtime.h>
#include <cuda_bf16.h>
#include <cuda_fp16.h>
#include <math.h>
#include <stdint.h>

// Problem constants
#define B_  2
#define L_  1024
#define DM  1024
#define DI  2048
#define NS  16
#define RR  64
#define KC  4
#define MTOT (B_ * L_)      // 2048
#define EPS 1e-5f

#define DBLC (RR + 2 * NS)  // 96
#define SPLITK 8
#define KCHUNK (DI / SPLITK)  // 256

#define NCH 8               // scan chunks
#define CH  (L_ / NCH)      // 128 steps per chunk

#define BIGSPLIT 0x40000000

// ---------------------------------------------------------------------------
// Scratch buffers (device globals; no allocation allowed)
// ---------------------------------------------------------------------------
__device__ __half g_hA[MTOT * DM];
__device__ __half g_hB[MTOT * DM];
__device__ __half g_hWi[(2 * DI) * DM];
__device__ __half g_hWo[DM * DI];
__device__ __half g_hWx[DBLC * DI];
__device__ __half g_hWx_b[DBLC * DI];
__device__ __half g_hWdt[DI * RR];
__device__ __half g_hWdt_b[DI * RR];
__device__ __half g_hx_f[MTOT * DI];        // fp16 x (conv input), dense ld=DI
__device__ __half g_hx_b[MTOT * DI];
__device__ __half g_hu_f[MTOT * DI];        // fp16 u (GEMM + scan operand)
__device__ __half g_hu_b[MTOT * DI];
__device__ __half g_hdbl_f[MTOT * DBLC];
__device__ __half g_hdbl_b[MTOT * DBLC];
__device__ __half g_hdelta_f[MTOT * DI];    // fp16 delta (scan operand)
__device__ __half g_hdelta_b[MTOT * DI];
__device__ __half g_hy_f[MTOT * DI];        // fp16 y
__device__ __half g_hy_b[MTOT * DI];
__device__ __half g_hg[MTOT * DI];

__device__ float g_z[MTOT * DI];            // f32 z (gate input)
__device__ float g_dblp[2 * SPLITK * MTOT * DBLC];
__device__ float g_dbl_f[MTOT * DBLC];
__device__ float g_dbl_b[MTOT * DBLC];
__device__ float g_wop[2 * MTOT * DM];

// scan chunking state
__device__ float g_hloc[2 * B_ * NCH * NS * DI];
__device__ float g_hin [2 * B_ * NCH * NS * DI];
__device__ float g_psum[2 * B_ * NCH * DI];

// ---------------------------------------------------------------------------
// fp16 tensor-core GEMM, cp.async 3-stage pipeline, DUAL-BRANCH, 2 CTA/SM:
//   Blocks with blockIdx.x >= splitX (or blockIdx.z >= splitZ) run set 1.
//   act: 0 = none, 1 = softplus (f32 out), 2 = softplus + fp16 out
//   Cx/NX: columns [0,NX) stored fp16 to Cx (ld NX); rest f32 to C (ld Nn-NX).
// ---------------------------------------------------------------------------
#define BM 128
#define BN 128
#define BK 32
#define BKP 40
#define STAGES 3
#define STG_BYTES ((BM + BN) * BKP * 2)      // 20480
#define SMEM_TOTAL (STAGES * STG_BYTES)      // 61440

__device__ __forceinline__ uint32_t smem_u32(const void* p) {
    uint32_t a;
    asm("{ .reg .u64 t; cvta.to.shared.u64 t, %1; cvt.u32.u64 %0, t; }"
        : "=r"(a) : "l"(p));
    return a;
}

__device__ __forceinline__ void ldsm4(uint32_t& r0, uint32_t& r1,
                                      uint32_t& r2, uint32_t& r3, uint32_t addr) {
    asm volatile("ldmatrix.sync.aligned.m8n8.x4.shared.b16 {%0,%1,%2,%3}, [%4];"
                 : "=r"(r0), "=r"(r1), "=r"(r2), "=r"(r3) : "r"(addr));
}

__device__ __forceinline__ void mma_f16(float c[4], const uint32_t a[4],
                                        const uint32_t b[2]) {
    asm volatile(
        "mma.sync.aligned.m16n8k16.row.col.f32.f16.f16.f32 "
        "{%0,%1,%2,%3}, {%4,%5,%6,%7}, {%8,%9}, {%0,%1,%2,%3};"
        : "+f"(c[0]), "+f"(c[1]), "+f"(c[2]), "+f"(c[3])
        : "r"(a[0]), "r"(a[1]), "r"(a[2]), "r"(a[3]), "r"(b[0]), "r"(b[1]));
}

#define CP_ASYNC16(dst, src, sz) \
    asm volatile("cp.async.cg.shared.global [%0], [%1], 16, %2;" \
                 :: "r"(dst), "l"(src), "r"(sz) : "memory")
#define CP_COMMIT() asm volatile("cp.async.commit_group;" ::: "memory")
#define CP_WAIT1()  asm volatile("cp.async.wait_group 1;" ::: "memory")

__global__ __launch_bounds__(256, 2)
void ha_linear2_kernel(
    const __half* __restrict__ A0, int lda0, const __half* __restrict__ W0, int ldw0,
    const float* __restrict__ bias0, float bs0, float* __restrict__ C0,
    __half* __restrict__ Cx0, int NX0,
    int Nn0, int flip0, int act0,
    const __half* __restrict__ A1, int lda1, const __half* __restrict__ W1, int ldw1,
    const float* __restrict__ bias1, float bs1, float* __restrict__ C1,
    __half* __restrict__ Cx1, int NX1,
    int Nn1, int flip1, int act1,
    int M, int Kd, int splitX, int splitZ, int kchunk)
{
    extern __shared__ __align__(16) char dsm[];
    const uint32_t sbase = smem_u32(dsm);

    int bx = blockIdx.x, bz = blockIdx.z, sel = 0;
    if (bx >= splitX) { sel = 1; bx -= splitX; }
    else if (bz >= splitZ) { sel = 1; bz -= splitZ; }

    const __half* __restrict__ A = sel ? A1 : A0;
    const __half* __restrict__ W = sel ? W1 : W0;
    const float* __restrict__ bias = sel ? bias1 : bias0;
    const float biasScale = sel ? bs1 : bs0;
    float* __restrict__ C = sel ? C1 : C0;
    __half* __restrict__ Cx = sel ? Cx1 : Cx0;
    const int NX   = sel ? NX1 : NX0;
    const int lda  = sel ? lda1 : lda0;
    const int ldw  = sel ? ldw1 : ldw0;
    const int Nn   = sel ? Nn1 : Nn0;
    const int flip = sel ? flip1 : flip0;
    const int act  = sel ? act1 : act0;

    const int tid  = threadIdx.x;
    const int lane = tid & 31;
    const int warp = tid >> 5;
    const int g    = lane >> 2;
    const int tg   = lane & 3;
    const int warpM = (warp & 3) * 32;
    const int warpN = (warp >> 2) * 64;
    const int row0 = blockIdx.y * BM;
    const int col0 = bx * BN;

    int kb = 0, klen = Kd;
    if (kchunk > 0) {
        kb   = bz * kchunk;
        klen = kchunk;
        C   += (size_t)bz * M * Nn;
    }
    const int ntiles = klen / BK;

    int arow[2], wrow[2];
    uint32_t wsz[2];
#pragma unroll
    for (int i = 0; i < 2; i++) {
        int idx = tid + 256 * i;
        int r   = idx >> 2;
        int gr  = row0 + r;
        if (flip) { gr = (gr & ~(L_ - 1)) + ((L_ - 1) - (gr & (L_ - 1))); }
        arow[i] = gr;
        int gn = col0 + r;
        wsz[i]  = (gn < Nn) ? 16u : 0u;
        wrow[i] = (gn < Nn) ? gn : 0;
    }
    const int ld_row   = tid >> 2;
    const int ld_chunk = (tid & 3) * 8;

    const int tquad = lane >> 3;
    const int trow  = lane & 7;
    const int a_m = ((tquad & 1) << 3) + trow;
    const int a_k = (tquad >> 1) << 3;
    const int b_n = ((tquad >> 1) << 3) + trow;
    const int b_k = (tquad & 1) << 3;

    float acc[2][8][4];
#pragma unroll
    for (int mi = 0; mi < 2; mi++)
#pragma unroll
        for (int ni = 0; ni < 8; ni++)
#pragma unroll
            for (int q = 0; q < 4; q++) acc[mi][ni][q] = 0.f;

    auto issue = [&](int t, int s) {
        const uint32_t st = sbase + (uint32_t)s * STG_BYTES;
        const int koff = kb + t * BK + ld_chunk;
#pragma unroll
        for (int i = 0; i < 2; i++) {
            int r = ld_row + 64 * i;
            uint32_t da = st + (uint32_t)r * (BKP * 2) + (uint32_t)ld_chunk * 2;
            CP_ASYNC16(da, A + (size_t)arow[i] * lda + koff, 16u);
        }
#pragma unroll
        for (int i = 0; i < 2; i++) {
            int r = ld_row + 64 * i;
            uint32_t db = st + (uint32_t)(BM * BKP * 2)
                        + (uint32_t)r * (BKP * 2) + (uint32_t)ld_chunk * 2;
            CP_ASYNC16(db, W + (size_t)wrow[i] * ldw + koff, wsz[i]);
        }
    };

    // prologue: issue stages 0..STAGES-2
#pragma unroll
    for (int s = 0; s < STAGES - 1; s++) {
        if (s < ntiles) issue(s, s);
        CP_COMMIT();
    }

    int cur = 0;              // stage of tile t
    int nxt = STAGES - 1;     // stage of tile t+STAGES-1
    for (int t = 0; t < ntiles; t++) {
        CP_WAIT1();
        __syncthreads();

        const int tn = t + STAGES - 1;
        if (tn < ntiles) issue(tn, nxt);
        CP_COMMIT();

        const uint32_t stA = sbase + (uint32_t)cur * STG_BYTES;
        const uint32_t stB = stA + (uint32_t)(BM * BKP * 2);

#pragma unroll
        for (int kk = 0; kk < 2; kk++) {
            const uint32_t kbyte = (uint32_t)(kk * 16) * 2;
            uint32_t af[2][4], bf[8][2];
#pragma unroll
            for (int mi = 0; mi < 2; mi++) {
                uint32_t addr = stA + (uint32_t)(warpM + mi * 16 + a_m) * (BKP * 2)
                              + kbyte + (uint32_t)a_k * 2;
                ldsm4(af[mi][0], af[mi][1], af[mi][2], af[mi][3], addr);
            }
#pragma unroll
            for (int nj = 0; nj < 4; nj++) {
                uint32_t addr = stB + (uint32_t)(warpN + nj * 16 + b_n) * (BKP * 2)
                              + kbyte + (uint32_t)b_k * 2;
                ldsm4(bf[2 * nj][0], bf[2 * nj][1], bf[2 * nj + 1][0], bf[2 * nj + 1][1], addr);
            }
#pragma unroll
            for (int mi = 0; mi < 2; mi++)
#pragma unroll
                for (int ni = 0; ni < 8; ni++)
                    mma_f16(acc[mi][ni], af[mi], bf[ni]);
        }

        cur = (cur + 1 == STAGES) ? 0 : cur + 1;
        nxt = (nxt + 1 == STAGES) ? 0 : nxt + 1;
    }

    const bool isX = (Cx != nullptr) && (col0 < NX);
    const int  Nz  = Nn - NX;
#pragma unroll
    for (int mi = 0; mi < 2; mi++) {
        int r0 = row0 + warpM + mi * 16 + g;
#pragma unroll
        for (int ni = 0; ni < 8; ni++) {
            int cb = col0 + warpN + ni * 8 + 2 * tg;
            if (cb < Nn) {
                float v00 = acc[mi][ni][0], v01 = acc[mi][ni][1];
                float v10 = acc[mi][ni][2], v11 = acc[mi][ni][3];
                if (bias) {
                    float b0 = biasScale * bias[cb];
                    float b1 = biasScale * bias[cb + 1];
                    v00 += b0; v01 += b1; v10 += b0; v11 += b1;
                }
                if (act >= 1) {  // softplus
                    v00 = (v00 > 20.f) ? v00 : log1pf(expf(v00));
                    v01 = (v01 > 20.f) ? v01 : log1pf(expf(v01));
                    v10 = (v10 > 20.f) ? v10 : log1pf(expf(v10));
                    v11 = (v11 > 20.f) ? v11 : log1pf(expf(v11));
                }
                if (isX) {  // fp16 x-part
                    *(__half2*)(Cx + (size_t)r0 * NX + cb)       = __floats2half2_rn(v00, v01);
                    *(__half2*)(Cx + (size_t)(r0 + 8) * NX + cb) = __floats2half2_rn(v10, v11);
                } else if (act == 2) {  // fp16 store (delta)
                    __half* Ch = (__half*)C;
                    *(__half2*)(Ch + (size_t)r0 * Nn + cb)       = __floats2half2_rn(v00, v01);
                    *(__half2*)(Ch + (size_t)(r0 + 8) * Nn + cb) = __floats2half2_rn(v10, v11);
                } else {
                    int cz = cb - NX;
                    *(float2*)(C + (size_t)r0 * Nz + cz)       = make_float2(v00, v01);
                    *(float2*)(C + (size_t)(r0 + 8) * Nz + cz) = make_float2(v10, v11);
                }
            }
        }
    }
}

// ---------------------------------------------------------------------------
// f32 -> f16 conversion, four arrays per launch
// ---------------------------------------------------------------------------
__global__ void cvt4_half_kernel(
    const float* __restrict__ s0, __half* __restrict__ d0, int n0,
    const float* __restrict__ s1, __half* __restrict__ d1, int n1,
    const float* __restrict__ s2, __half* __restrict__ d2, int n2,
    const float* __restrict__ s3, __half* __restrict__ d3, int n3)
{
    int i = (blockIdx.x * blockDim.x + threadIdx.x) * 8;
    const float* s;
    __half* d;
    if (i < n0) { s = s0 + i; d = d0 + i; }
    else if ((i -= n0) < n1) { s = s1 + i; d = d1 + i; }
    else if ((i -= n1) < n2) { s = s2 + i; d = d2 + i; }
    else if ((i -= n2) < n3) { s = s3 + i; d = d3 + i; }
    else return;
    float4 v0 = *(const float4*)s;
    float4 v1 = *(const float4*)(s + 4);
    __half2 h0 = __floats2half2_rn(v0.x, v0.y);
    __half2 h1 = __floats2half2_rn(v0.z, v0.w);
    __half2 h2 = __floats2half2_rn(v1.x, v1.y);
    __half2 h3 = __floats2half2_rn(v1.z, v1.w);
    *(uint4*)d = make_uint4(*(uint32_t*)&h0, *(uint32_t*)&h1,
                            *(uint32_t*)&h2, *(uint32_t*)&h3);
}

// ---------------------------------------------------------------------------
// Reduce split-K partials (dbl): f32 + fp16 out
// ---------------------------------------------------------------------------
__global__ void reduce_dbl_kernel(const float* __restrict__ part,
                                  float* __restrict__ of, float* __restrict__ ob,
                                  __half* __restrict__ hf, __half* __restrict__ hb)
{
    const int NV = MTOT * DBLC / 4;
    int i = blockIdx.x * blockDim.x + threadIdx.x;
    if (i >= 2 * NV) return;
    int br = (i >= NV);
    int j  = i - br * NV;
    const float4* p = (const float4*)part + (size_t)br * SPLITK * NV + j;
    float4 s = make_float4(0.f, 0.f, 0.f, 0.f);
#pragma unroll
    for (int k = 0; k < SPLITK; k++) {
        float4 v = p[(size_t)k * NV];
        s.x += v.x; s.y += v.y; s.z += v.z; s.w += v.w;
    }
    ((float4*)(br ? ob : of))[j] = s;
    __half2 h0 = __floats2half2_rn(s.x, s.y);
    __half2 h1 = __floats2half2_rn(s.z, s.w);
    ((uint2*)(br ? hb : hf))[j] = make_uint2(*(uint32_t*)&h0, *(uint32_t*)&h1);
}

// ---------------------------------------------------------------------------
// Reduce Wo split-K partials into out
// ---------------------------------------------------------------------------
__global__ void reduce_out_kernel(const float* __restrict__ part,
                                  float* __restrict__ out)
{
    const int NV = MTOT * DM / 4;
    int i = blockIdx.x * blockDim.x + threadIdx.x;
    if (i >= NV) return;
    float4 a = ((const float4*)part)[i];
    float4 b = ((const float4*)part)[i + NV];
    ((float4*)out)[i] = make_float4(a.x + b.x, a.y + b.y, a.z + b.z, a.w + b.w);
}

// ---------------------------------------------------------------------------
// Depthwise causal conv1d (K=4) + bias + SiLU; 8 l per thread; fp16 in/out
// ---------------------------------------------------------------------------
#define CLG 8
__global__ void conv_silu_kernel(const __half* __restrict__ x0,
                                 const float* __restrict__ w0,
                                 const float* __restrict__ b0,
                                 __half* __restrict__ h0,
                                 const __half* __restrict__ x1,
                                 const float* __restrict__ w1,
                                 const float* __restrict__ b1,
                                 __half* __restrict__ h1)
{
    const int br = blockIdx.z;
    const __half* __restrict__ x = br ? x1 : x0;
    const float* __restrict__ w = br ? w1 : w0;
    const float* __restrict__ bi = br ? b1 : b0;
    __half* __restrict__ hu = br ? h1 : h0;

    int idx = blockIdx.x * blockDim.x + threadIdx.x;
    if (idx >= (MTOT / CLG) * DI) return;
    const int d    = idx % DI;
    const int grp  = idx / DI;
    const int row0 = grp * CLG;
    const int l0   = row0 & (L_ - 1);
    const int bb0  = row0 - l0;

    float xv[CLG + KC - 1];
#pragma unroll
    for (int j = 0; j < CLG + KC - 1; j++) {
        int l = l0 - (KC - 1) + j;
        xv[j] = (l >= 0) ? __half2float(x[(size_t)(bb0 + l) * DI + d]) : 0.f;
    }
    const float w0v = w[d * KC + 0], w1v = w[d * KC + 1],
                w2v = w[d * KC + 2], w3v = w[d * KC + 3];
    const float bv = bi[d];

#pragma unroll
    for (int j = 0; j < CLG; j++) {
        float acc = bv;
        acc = fmaf(xv[j],     w0v, acc);
        acc = fmaf(xv[j + 1], w1v, acc);
        acc = fmaf(xv[j + 2], w2v, acc);
        acc = fmaf(xv[j + 3], w3v, acc);
        float s = 1.f / (1.f + __expf(-acc));
        hu[(size_t)(row0 + j) * DI + d] = __float2half_rn(acc * s);
    }
}

// ---------------------------------------------------------------------------
// Chunked selective scan (phase1 / carry / phase2); fp16 delta/u/y
// ---------------------------------------------------------------------------
#define SCAN_TPB 128
#define SCAN_ST  16

__global__ __launch_bounds__(SCAN_TPB)
void scan_phase1(const __half* __restrict__ del_f, const float* __restrict__ dbl_f,
                 const __half* __restrict__ u_f,
                 const __half* __restrict__ del_b, const float* __restrict__ dbl_b,
                 const __half* __restrict__ u_b,
                 const float* __restrict__ Alog_f, const float* __restrict__ Alog_b,
                 float* __restrict__ hloc, float* __restrict__ psum)
{
    const int br = blockIdx.y;
    const __half* __restrict__ del = br ? del_b : del_f;
    const float* __restrict__ dbl  = br ? dbl_b : dbl_f;
    const __half* __restrict__ u   = br ? u_b   : u_f;
    const float* __restrict__ Alog = br ? Alog_b : Alog_f;

    const int tid   = threadIdx.x;
    const int ch    = blockIdx.x & (NCH - 1);
    const int bb    = (blockIdx.x >> 3) & 1;
    const int dpart = blockIdx.x >> 4;
    const int d     = dpart * SCAN_TPB + tid;
    const int dbase = dpart * SCAN_TPB;
    const int rowb  = bb * L_ + ch * CH;

    float a[NS];
    bool fast = true;
#pragma unroll
    for (int n = 0; n < NS; n++) {
        a[n] = expf(Alog[(size_t)d * NS + n]);
        fast = fast && (fabsf(a[n] - (float)(n + 1)) < 1e-4f * (float)(n + 1));
    }

    float h[NS];
#pragma unroll
    for (int n = 0; n < NS; n++) h[n] = 0.f;
    float ps = 0.f;

    __shared__ float  s_del[SCAN_ST][SCAN_TPB];
    __shared__ float  s_u[SCAN_ST][SCAN_TPB];
    __shared__ float4 s_bc[SCAN_ST][4];   // B only

    for (int c0 = 0; c0 < CH; c0 += SCAN_ST) {
        __syncthreads();
#pragma unroll
        for (int k = 0; k < SCAN_ST; k++) {
            size_t off = (size_t)(rowb + c0 + k) * DI + dbase + tid;
            s_del[k][tid] = __half2float(del[off]);
            s_u[k][tid]   = __half2float(u[off]);
        }
        if (tid < 64) {
            int k = tid >> 2;
            int q = tid & 3;
            size_t off = (size_t)(rowb + c0 + k) * DBLC + RR + q * 4;
            s_bc[k][q] = *(const float4*)(dbl + off);
        }
        __syncthreads();

        if (fast) {
#pragma unroll 2
            for (int k = 0; k < SCAN_ST; k++) {
                float dl = s_del[k][tid];
                float du = dl * s_u[k][tid];
                ps += dl;
                float e = __expf(-dl);
                float4 V0 = s_bc[k][0], V1 = s_bc[k][1], V2 = s_bc[k][2], V3 = s_bc[k][3];
                float Bv[NS] = {V0.x,V0.y,V0.z,V0.w, V1.x,V1.y,V1.z,V1.w,
                                V2.x,V2.y,V2.z,V2.w, V3.x,V3.y,V3.z,V3.w};
                float p = e;
#pragma unroll
                for (int n = 0; n < NS; n++) {
                    h[n] = fmaf(p, h[n], du * Bv[n]);
                    p   *= e;
                }
            }
        } else {
            for (int k = 0; k < SCAN_ST; k++) {
                float dl = s_del[k][tid];
                float du = dl * s_u[k][tid];
                ps += dl;
                const float* bc = (const float*)s_bc[k];
#pragma unroll
                for (int n = 0; n < NS; n++) {
                    float dA = __expf(-dl * a[n]);
                    h[n] = fmaf(dA, h[n], du * bc[n]);
                }
            }
        }
    }

    const int cbase = ((br * B_ + bb) * NCH + ch);
    psum[(size_t)cbase * DI + d] = ps;
#pragma unroll
    for (int n = 0; n < NS; n++)
        hloc[((size_t)cbase * NS + n) * DI + d] = h[n];
}

__global__ void scan_carry(const float* __restrict__ hloc,
                           const float* __restrict__ psum,
                           const float* __restrict__ Alog_f,
                           const float* __restrict__ Alog_b,
                           float* __restrict__ hin)
{
    int idx = blockIdx.x * blockDim.x + threadIdx.x;
    if (idx >= 2 * B_ * DI) return;
    const int d  = idx % DI;
    const int bb = (idx / DI) % B_;
    const int br = idx / (B_ * DI);
    const float* __restrict__ Alog = br ? Alog_b : Alog_f;

    float a[NS];
    bool fast = true;
#pragma unroll
    for (int n = 0; n < NS; n++) {
        a[n] = expf(Alog[(size_t)d * NS + n]);
        fast = fast && (fabsf(a[n] - (float)(n + 1)) < 1e-4f * (float)(n + 1));
    }

    float h[NS];
#pragma unroll
    for (int n = 0; n < NS; n++) h[n] = 0.f;

    for (int ch = 0; ch < NCH; ch++) {
        const size_t cbase = ((size_t)(br * B_ + bb) * NCH + ch);
#pragma unroll
        for (int n = 0; n < NS; n++)
            hin[(cbase * NS + n) * DI + d] = h[n];
        float ps = psum[cbase * DI + d];
        if (fast) {
            float E = __expf(-ps);
            float p = E;
#pragma unroll
            for (int n = 0; n < NS; n++) {
                h[n] = fmaf(p, h[n], hloc[(cbase * NS + n) * DI + d]);
                p   *= E;
            }
        } else {
#pragma unroll
            for (int n = 0; n < NS; n++) {
                float P = __expf(-ps * a[n]);
                h[n] = fmaf(P, h[n], hloc[(cbase * NS + n) * DI + d]);
            }
        }
    }
}

__global__ __launch_bounds__(SCAN_TPB)
void scan_phase2(const __half* __restrict__ del_f, const float* __restrict__ dbl_f,
                 const __half* __restrict__ u_f,
                 const __half* __restrict__ del_b, const float* __restrict__ dbl_b,
                 const __half* __restrict__ u_b,
                 const float* __restrict__ Alog_f, const float* __restrict__ D_f,
                 const float* __restrict__ Alog_b, const float* __restrict__ D_b,
                 const float* __restrict__ hin,
                 __half* __restrict__ y_f, __half* __restrict__ y_b)
{
    const int br = blockIdx.y;
    const __half* __restrict__ del = br ? del_b : del_f;
    const float* __restrict__ dbl  = br ? dbl_b : dbl_f;
    const __half* __restrict__ u   = br ? u_b   : u_f;
    const float* __restrict__ Alog = br ? Alog_b : Alog_f;
    const float* __restrict__ Dv_p = br ? D_b : D_f;
    __half* __restrict__ yout      = br ? y_b : y_f;

    const int tid   = threadIdx.x;
    const int ch    = blockIdx.x & (NCH - 1);
    const int bb    = (blockIdx.x >> 3) & 1;
    const int dpart = blockIdx.x >> 4;
    const int d     = dpart * SCAN_TPB + tid;
    const int dbase = dpart * SCAN_TPB;
    const int rowb  = bb * L_ + ch * CH;

    float a[NS];
    bool fast = true;
#pragma unroll
    for (int n = 0; n < NS; n++) {
        a[n] = expf(Alog[(size_t)d * NS + n]);
        fast = fast && (fabsf(a[n] - (float)(n + 1)) < 1e-4f * (float)(n + 1));
    }
    const float Dv = Dv_p[d];

    const size_t cbase = ((size_t)(br * B_ + bb) * NCH + ch);
    float h[NS];
#pragma unroll
    for (int n = 0; n < NS; n++)
        h[n] = hin[(cbase * NS + n) * DI + d];

    __shared__ float  s_del[SCAN_ST][SCAN_TPB];
    __shared__ float  s_u[SCAN_ST][SCAN_TPB];
    __shared__ float4 s_bc[SCAN_ST][8];

    for (int c0 = 0; c0 < CH; c0 += SCAN_ST) {
        __syncthreads();
#pragma unroll
        for (int k = 0; k < SCAN_ST; k++) {
            size_t off = (size_t)(rowb + c0 + k) * DI + dbase + tid;
            s_del[k][tid] = __half2float(del[off]);
            s_u[k][tid]   = __half2float(u[off]);
        }
        {
            int k = tid >> 3;
            int q = tid & 7;
            size_t off = (size_t)(rowb + c0 + k) * DBLC + RR + q * 4;
            s_bc[k][q] = *(const float4*)(dbl + off);
        }
        __syncthreads();

        if (fast) {
#pragma unroll 2
            for (int k = 0; k < SCAN_ST; k++) {
                float dl = s_del[k][tid];
                float uu = s_u[k][tid];
                float du = dl * uu;
                float e  = __expf(-dl);
                float4 V0 = s_bc[k][0], V1 = s_bc[k][1], V2 = s_bc[k][2], V3 = s_bc[k][3];
                float4 W0 = s_bc[k][4], W1 = s_bc[k][5], W2 = s_bc[k][6], W3 = s_bc[k][7];
                float Bv[NS] = {V0.x,V0.y,V0.z,V0.w, V1.x,V1.y,V1.z,V1.w,
                                V2.x,V2.y,V2.z,V2.w, V3.x,V3.y,V3.z,V3.w};
                float Cv[NS] = {W0.x,W0.y,W0.z,W0.w, W1.x,W1.y,W1.z,W1.w,
                                W2.x,W2.y,W2.z,W2.w, W3.x,W3.y,W3.z,W3.w};
                float p  = e;
                float yv0 = 0.f, yv1 = 0.f;
#pragma unroll
                for (int n = 0; n < NS; n++) {
                    h[n] = fmaf(p, h[n], du * Bv[n]);
                    if (n & 1) yv1 = fmaf(h[n], Cv[n], yv1);
                    else       yv0 = fmaf(h[n], Cv[n], yv0);
                    p   *= e;
                }
                float yv = fmaf(uu, Dv, yv0 + yv1);
                yout[(size_t)(rowb + c0 + k) * DI + d] = __float2half_rn(yv);
            }
        } else {
            for (int k = 0; k < SCAN_ST; k++) {
                float dl = s_del[k][tid];
                float uu = s_u[k][tid];
                float du = dl * uu;
                float yv = 0.f;
                const float* bc = (const float*)s_bc[k];
#pragma unroll
                for (int n = 0; n < NS; n++) {
                    float dA = __expf(-dl * a[n]);
                    h[n] = fmaf(dA, h[n], du * bc[n]);
                    yv   = fmaf(h[n], bc[NS + n], yv);
                }
                yv = fmaf(uu, Dv, yv);
                yout[(size_t)(rowb + c0 + k) * DI + d] = __float2half_rn(yv);
            }
        }
    }
}

// ---------------------------------------------------------------------------
// Gate (y * silu(z)) + RMSNorm * norm_w; fp16 y in, f32 z, fp16 g out
// ---------------------------------------------------------------------------
__global__ __launch_bounds__(256)
void gate_rms_kernel(const __half* __restrict__ yf, const __half* __restrict__ yb,
                     const float* __restrict__ z, const float* __restrict__ nw,
                     __half* __restrict__ g)
{
    const int row = blockIdx.x;
    const int l   = row & (L_ - 1);
    const int bb  = row >> 10;
    const int frow = (bb << 10) + (L_ - 1 - l);
    const int tid = threadIdx.x;

    __shared__ float sg[DI];
    __shared__ float red[8];

    float ss = 0.f;
    for (int d = tid; d < DI; d += 256) {
        float y  = __half2float(yf[(size_t)row * DI + d])
                 + __half2float(yb[(size_t)frow * DI + d]);
        float zz = z[(size_t)row * DI + d];
        float sz = zz / (1.f + __expf(-zz));
        float gg = y * sz;
        sg[d] = gg;
        ss = fmaf(gg, gg, ss);
    }
#pragma unroll
    for (int o = 16; o; o >>= 1) ss += __shfl_xor_sync(0xFFFFFFFFu, ss, o);
    if ((tid & 31) == 0) red[tid >> 5] = ss;
    __syncthreads();
    float total = red[0] + red[1] + red[2] + red[3] + red[4] + red[5] + red[6] + red[7];
    float scale = rsqrtf(total / (float)DI + EPS);

    for (int d = tid; d < DI; d += 256) {
        g[(size_t)row * DI + d] = __float2half_rn(sg[d] * scale * nw[d]);
    }
}

// ---------------------------------------------------------------------------
// Launch
// ---------------------------------------------------------------------------
extern "C" void kernel_launch(void* const* d_in, const int* in_sizes, int n_in,
                              void* d_out, int out_size)
{
    (void)in_sizes; (void)n_in; (void)out_size;
    const float* a       = (const float*)d_in[0];
    const float* b       = (const float*)d_in[1];
    const float* Wi      = (const float*)d_in[2];
    const float* conv_w  = (const float*)d_in[3];
    const float* conv_b  = (const float*)d_in[4];
    const float* Wx      = (const float*)d_in[5];
    const float* Wdt     = (const float*)d_in[6];
    const float* bdt     = (const float*)d_in[7];
    const float* A_log   = (const float*)d_in[8];
    const float* D       = (const float*)d_in[9];
    const float* conv_w_b = (const float*)d_in[10];
    const float* conv_b_b = (const float*)d_in[11];
    const float* Wx_b    = (const float*)d_in[12];
    const float* Wdt_b   = (const float*)d_in[13];
    const float* bdt_b   = (const float*)d_in[14];
    const float* A_log_b = (const float*)d_in[15];
    const float* D_b     = (const float*)d_in[16];
    const float* Wo      = (const float*)d_in[17];
    const float* norm_w  = (const float*)d_in[18];
    float* out = (float*)d_out;

    __half *p_hA, *p_hB, *p_hWi, *p_hWo, *p_hWx, *p_hWx_b, *p_hWdt, *p_hWdt_b;
    __half *p_hx_f, *p_hx_b, *p_hu_f, *p_hu_b, *p_hdbl_f, *p_hdbl_b;
    __half *p_hdelta_f, *p_hdelta_b, *p_hy_f, *p_hy_b, *p_hg;
    float *p_z, *p_dblp, *p_dbl_f, *p_dbl_b, *p_wop;
    float *p_hloc, *p_hin, *p_psum;
    cudaGetSymbolAddress((void**)&p_hA, g_hA);
    cudaGetSymbolAddress((void**)&p_hB, g_hB);
    cudaGetSymbolAddress((void**)&p_hWi, g_hWi);
    cudaGetSymbolAddress((void**)&p_hWo, g_hWo);
    cudaGetSymbolAddress((void**)&p_hWx, g_hWx);
    cudaGetSymbolAddress((void**)&p_hWx_b, g_hWx_b);
    cudaGetSymbolAddress((void**)&p_hWdt, g_hWdt);
    cudaGetSymbolAddress((void**)&p_hWdt_b, g_hWdt_b);
    cudaGetSymbolAddress((void**)&p_hx_f, g_hx_f);
    cudaGetSymbolAddress((void**)&p_hx_b, g_hx_b);
    cudaGetSymbolAddress((void**)&p_hu_f, g_hu_f);
    cudaGetSymbolAddress((void**)&p_hu_b, g_hu_b);
    cudaGetSymbolAddress((void**)&p_hdbl_f, g_hdbl_f);
    cudaGetSymbolAddress((void**)&p_hdbl_b, g_hdbl_b);
    cudaGetSymbolAddress((void**)&p_hdelta_f, g_hdelta_f);
    cudaGetSymbolAddress((void**)&p_hdelta_b, g_hdelta_b);
    cudaGetSymbolAddress((void**)&p_hy_f, g_hy_f);
    cudaGetSymbolAddress((void**)&p_hy_b, g_hy_b);
    cudaGetSymbolAddress((void**)&p_hg, g_hg);
    cudaGetSymbolAddress((void**)&p_z, g_z);
    cudaGetSymbolAddress((void**)&p_dblp, g_dblp);
    cudaGetSymbolAddress((void**)&p_dbl_f, g_dbl_f);
    cudaGetSymbolAddress((void**)&p_dbl_b, g_dbl_b);
    cudaGetSymbolAddress((void**)&p_wop, g_wop);
    cudaGetSymbolAddress((void**)&p_hloc, g_hloc);
    cudaGetSymbolAddress((void**)&p_hin, g_hin);
    cudaGetSymbolAddress((void**)&p_psum, g_psum);

    const int TPB = 256;
    cudaFuncSetAttribute(ha_linear2_kernel,
                         cudaFuncAttributeMaxDynamicSharedMemorySize, SMEM_TOTAL);

    // 0. convert inputs/weights to fp16 (two 4-array launches)
    {
        int nA = MTOT * DM, nB = MTOT * DM, nC = 2 * DI * DM, nD = DM * DI;
        cvt4_half_kernel<<<((nA + nB + nC + nD) / 8 + TPB - 1) / TPB, TPB>>>(
            a, p_hA, nA, b, p_hB, nB, Wi, p_hWi, nC, Wo, p_hWo, nD);
        int n0 = DBLC * DI, n1 = DBLC * DI, n2 = DI * RR, n3 = DI * RR;
        cvt4_half_kernel<<<((n0 + n1 + n2 + n3) / 8 + TPB - 1) / TPB, TPB>>>(
            Wx, p_hWx, n0, Wx_b, p_hWx_b, n1, Wdt, p_hWdt, n2, Wdt_b, p_hWdt_b, n3);
    }

    // 1. fused xz GEMM: fwd x->fp16 + z->f32; bwd x->fp16
    ha_linear2_kernel<<<dim3(32 + 16, MTOT / BM, 1), TPB, SMEM_TOTAL>>>(
        p_hA, DM, p_hWi, DM, nullptr, 0.f, p_z, p_hx_f, DI, 2 * DI, 0, 0,
        p_hB, DM, p_hWi, DM, nullptr, 0.f, nullptr, p_hx_b, DI, DI, 1, 0,
        MTOT, DM, /*splitX=*/32, /*splitZ=*/BIGSPLIT, 0);

    // 2. conv + silu (8 l/thread, both branches); fp16 in/out
    conv_silu_kernel<<<dim3((MTOT / CLG) * DI / TPB, 1, 2), TPB>>>(
        p_hx_f, conv_w, conv_b, p_hu_f,
        p_hx_b, conv_w_b, conv_b_b, p_hu_b);

    // 3. fused dbl = u @ Wx^T [2048,96], split-K both branches
    ha_linear2_kernel<<<dim3(1, MTOT / BM, 2 * SPLITK), TPB, SMEM_TOTAL>>>(
        p_hu_f, DI, p_hWx, DI, nullptr, 0.f, p_dblp, nullptr, 0, DBLC, 0, 0,
        p_hu_b, DI, p_hWx_b, DI, nullptr, 0.f, p_dblp + (size_t)SPLITK * MTOT * DBLC,
        nullptr, 0, DBLC, 0, 0,
        MTOT, DI, /*splitX=*/BIGSPLIT, /*splitZ=*/SPLITK, KCHUNK);

    // 4. reduce partials -> dbl (f32 + fp16)
    {
        int nthreads = 2 * MTOT * DBLC / 4;
        reduce_dbl_kernel<<<(nthreads + TPB - 1) / TPB, TPB>>>(
            p_dblp, p_dbl_f, p_dbl_b, p_hdbl_f, p_hdbl_b);
    }

    // 5. fused delta = softplus(dt @ Wdt^T + 2*bdt), fp16 out, both branches
    ha_linear2_kernel<<<dim3(DI / BN, MTOT / BM, 2), TPB, SMEM_TOTAL>>>(
        p_hdbl_f, DBLC, p_hWdt, RR, bdt, 2.f, (float*)p_hdelta_f, nullptr, 0, DI, 0, 2,
        p_hdbl_b, DBLC, p_hWdt_b, RR, bdt_b, 2.f, (float*)p_hdelta_b, nullptr, 0, DI, 0, 2,
        MTOT, RR, /*splitX=*/BIGSPLIT, /*splitZ=*/1, 0);

    // 6. chunked selective scan (both branches)
    scan_phase1<<<dim3((DI / SCAN_TPB) * B_ * NCH, 2), SCAN_TPB>>>(
        p_hdelta_f, p_dbl_f, p_hu_f, p_hdelta_b, p_dbl_b, p_hu_b,
        A_log, A_log_b, p_hloc, p_psum);
    scan_carry<<<(2 * B_ * DI + TPB - 1) / TPB, TPB>>>(
        p_hloc, p_psum, A_log, A_log_b, p_hin);
    scan_phase2<<<dim3((DI / SCAN_TPB) * B_ * NCH, 2), SCAN_TPB>>>(
        p_hdelta_f, p_dbl_f, p_hu_f, p_hdelta_b, p_dbl_b, p_hu_b,
        A_log, D, A_log_b, D_b, p_hin, p_hy_f, p_hy_b);

    // 7. gate + rmsnorm (fp16 y in, writes fp16 g)
    gate_rms_kernel<<<MTOT, TPB>>>(p_hy_f, p_hy_b, p_z, norm_w, p_hg);

    // 8. out = g @ Wo^T [2048,1024], split-K x2
    ha_linear2_kernel<<<dim3(DM / BN, MTOT / BM, 2), TPB, SMEM_TOTAL>>>(
        p_hg, DI, p_hWo, DI, nullptr, 0.f, p_wop, nullptr, 0, DM, 0, 0,
        p_hg, DI, p_hWo, DI, nullptr, 0.f, p_wop, nullptr, 0, DM, 0, 0,
        MTOT, DI, /*splitX=*/BIGSPLIT, /*splitZ=*/BIGSPLIT, DI / 2);
    reduce_out_kernel<<<(MTOT * DM / 4 + TPB - 1) / TPB, TPB>>>(p_wop, out);
}

// round 13
// speedup vs baseline: 6.4896x; 1.0781x over previous
#include <cuda_runtime.h>
#include <cuda_bf16.h>
#include <cuda_fp16.h>
#include <math.h>
#include <stdint.h>

// Problem constants
#define B_  2
#define L_  1024
#define DM  1024
#define DI  2048
#define NS  16
#define RR  64
#define KC  4
#define MTOT (B_ * L_)      // 2048
#define EPS 1e-5f

#define DBLC (RR + 2 * NS)  // 96
#define SPLITK 8
#define KCHUNK (DI / SPLITK)  // 256

#define NCH 8               // scan chunks
#define CH  (L_ / NCH)      // 128 steps per chunk

#define BIGSPLIT 0x40000000

// ---------------------------------------------------------------------------
// Scratch buffers (device globals; no allocation allowed)
// ---------------------------------------------------------------------------
__device__ __half g_hA[MTOT * DM];
__device__ __half g_hB[MTOT * DM];
__device__ __half g_hWi[(2 * DI) * DM];
__device__ __half g_hWo[DM * DI];
__device__ __half g_hWx[DBLC * DI];
__device__ __half g_hWx_b[DBLC * DI];
__device__ __half g_hWdt[DI * RR];
__device__ __half g_hWdt_b[DI * RR];
__device__ __half g_hx_f[MTOT * DI];        // fp16 x (conv input)
__device__ __half g_hx_b[MTOT * DI];
__device__ __half g_hu_f[MTOT * DI];        // fp16 u (GEMM + scan operand)
__device__ __half g_hu_b[MTOT * DI];
__device__ __half g_hdbl_f[MTOT * DBLC];
__device__ __half g_hdbl_b[MTOT * DBLC];
__device__ __half g_hdelta_f[MTOT * DI];    // fp16 delta (scan operand)
__device__ __half g_hdelta_b[MTOT * DI];
__device__ __half g_hy_f[MTOT * DI];        // fp16 y
__device__ __half g_hy_b[MTOT * DI];
__device__ __half g_hg[MTOT * DI];

__device__ float g_z[MTOT * DI];            // f32 z (gate input)
__device__ float g_dblp[2 * SPLITK * MTOT * DBLC];
__device__ float g_dbl_f[MTOT * DBLC];
__device__ float g_dbl_b[MTOT * DBLC];
__device__ float g_wop[2 * MTOT * DM];

// scan chunking state
__device__ float g_hloc[2 * B_ * NCH * NS * DI];
__device__ float g_psum[2 * B_ * NCH * DI];

// ---------------------------------------------------------------------------
// fp16 tensor-core GEMM, cp.async 3-stage pipeline, DUAL-BRANCH
// ---------------------------------------------------------------------------
#define BM 128
#define BN 128
#define BK 32
#define BKP 40
#define STAGES 3
#define STG_BYTES ((BM + BN) * BKP * 2)
#define SMEM_TOTAL (STAGES * STG_BYTES)

__device__ __forceinline__ uint32_t smem_u32(const void* p) {
    uint32_t a;
    asm("{ .reg .u64 t; cvta.to.shared.u64 t, %1; cvt.u32.u64 %0, t; }"
        : "=r"(a) : "l"(p));
    return a;
}

__device__ __forceinline__ void ldsm4(uint32_t& r0, uint32_t& r1,
                                      uint32_t& r2, uint32_t& r3, uint32_t addr) {
    asm volatile("ldmatrix.sync.aligned.m8n8.x4.shared.b16 {%0,%1,%2,%3}, [%4];"
                 : "=r"(r0), "=r"(r1), "=r"(r2), "=r"(r3) : "r"(addr));
}

__device__ __forceinline__ void mma_f16(float c[4], const uint32_t a[4],
                                        const uint32_t b[2]) {
    asm volatile(
        "mma.sync.aligned.m16n8k16.row.col.f32.f16.f16.f32 "
        "{%0,%1,%2,%3}, {%4,%5,%6,%7}, {%8,%9}, {%0,%1,%2,%3};"
        : "+f"(c[0]), "+f"(c[1]), "+f"(c[2]), "+f"(c[3])
        : "r"(a[0]), "r"(a[1]), "r"(a[2]), "r"(a[3]), "r"(b[0]), "r"(b[1]));
}

#define CP_ASYNC16(dst, src, sz) \
    asm volatile("cp.async.cg.shared.global [%0], [%1], 16, %2;" \
                 :: "r"(dst), "l"(src), "r"(sz) : "memory")
#define CP_COMMIT() asm volatile("cp.async.commit_group;" ::: "memory")
#define CP_WAIT1()  asm volatile("cp.async.wait_group 1;" ::: "memory")

__global__ __launch_bounds__(256, 2)
void ha_linear2_kernel(
    const __half* __restrict__ A0, int lda0, const __half* __restrict__ W0, int ldw0,
    const float* __restrict__ bias0, float bs0, float* __restrict__ C0,
    __half* __restrict__ Cx0, int NX0,
    int Nn0, int flip0, int act0,
    const __half* __restrict__ A1, int lda1, const __half* __restrict__ W1, int ldw1,
    const float* __restrict__ bias1, float bs1, float* __restrict__ C1,
    __half* __restrict__ Cx1, int NX1,
    int Nn1, int flip1, int act1,
    int M, int Kd, int splitX, int splitZ, int kchunk)
{
    extern __shared__ __align__(16) char dsm[];
    const uint32_t sbase = smem_u32(dsm);

    int bx = blockIdx.x, bz = blockIdx.z, sel = 0;
    if (bx >= splitX) { sel = 1; bx -= splitX; }
    else if (bz >= splitZ) { sel = 1; bz -= splitZ; }

    const __half* __restrict__ A = sel ? A1 : A0;
    const __half* __restrict__ W = sel ? W1 : W0;
    const float* __restrict__ bias = sel ? bias1 : bias0;
    const float biasScale = sel ? bs1 : bs0;
    float* __restrict__ C = sel ? C1 : C0;
    __half* __restrict__ Cx = sel ? Cx1 : Cx0;
    const int NX   = sel ? NX1 : NX0;
    const int lda  = sel ? lda1 : lda0;
    const int ldw  = sel ? ldw1 : ldw0;
    const int Nn   = sel ? Nn1 : Nn0;
    const int flip = sel ? flip1 : flip0;
    const int act  = sel ? act1 : act0;

    const int tid  = threadIdx.x;
    const int lane = tid & 31;
    const int warp = tid >> 5;
    const int g    = lane >> 2;
    const int tg   = lane & 3;
    const int warpM = (warp & 3) * 32;
    const int warpN = (warp >> 2) * 64;
    const int row0 = blockIdx.y * BM;
    const int col0 = bx * BN;

    int kb = 0, klen = Kd;
    if (kchunk > 0) {
        kb   = bz * kchunk;
        klen = kchunk;
        C   += (size_t)bz * M * Nn;
    }
    const int ntiles = klen / BK;

    int arow[2], wrow[2];
    uint32_t wsz[2];
#pragma unroll
    for (int i = 0; i < 2; i++) {
        int idx = tid + 256 * i;
        int r   = idx >> 2;
        int gr  = row0 + r;
        if (flip) { gr = (gr & ~(L_ - 1)) + ((L_ - 1) - (gr & (L_ - 1))); }
        arow[i] = gr;
        int gn = col0 + r;
        wsz[i]  = (gn < Nn) ? 16u : 0u;
        wrow[i] = (gn < Nn) ? gn : 0;
    }
    const int ld_row   = tid >> 2;
    const int ld_chunk = (tid & 3) * 8;

    const int tquad = lane >> 3;
    const int trow  = lane & 7;
    const int a_m = ((tquad & 1) << 3) + trow;
    const int a_k = (tquad >> 1) << 3;
    const int b_n = ((tquad >> 1) << 3) + trow;
    const int b_k = (tquad & 1) << 3;

    float acc[2][8][4];
#pragma unroll
    for (int mi = 0; mi < 2; mi++)
#pragma unroll
        for (int ni = 0; ni < 8; ni++)
#pragma unroll
            for (int q = 0; q < 4; q++) acc[mi][ni][q] = 0.f;

    auto issue = [&](int t, int s) {
        const uint32_t st = sbase + (uint32_t)s * STG_BYTES;
        const int koff = kb + t * BK + ld_chunk;
#pragma unroll
        for (int i = 0; i < 2; i++) {
            int r = ld_row + 64 * i;
            uint32_t da = st + (uint32_t)r * (BKP * 2) + (uint32_t)ld_chunk * 2;
            CP_ASYNC16(da, A + (size_t)arow[i] * lda + koff, 16u);
        }
#pragma unroll
        for (int i = 0; i < 2; i++) {
            int r = ld_row + 64 * i;
            uint32_t db = st + (uint32_t)(BM * BKP * 2)
                        + (uint32_t)r * (BKP * 2) + (uint32_t)ld_chunk * 2;
            CP_ASYNC16(db, W + (size_t)wrow[i] * ldw + koff, wsz[i]);
        }
    };

#pragma unroll
    for (int s = 0; s < STAGES - 1; s++) {
        if (s < ntiles) issue(s, s);
        CP_COMMIT();
    }

    int cur = 0;
    int nxt = STAGES - 1;
    for (int t = 0; t < ntiles; t++) {
        CP_WAIT1();
        __syncthreads();

        const int tn = t + STAGES - 1;
        if (tn < ntiles) issue(tn, nxt);
        CP_COMMIT();

        const uint32_t stA = sbase + (uint32_t)cur * STG_BYTES;
        const uint32_t stB = stA + (uint32_t)(BM * BKP * 2);

#pragma unroll
        for (int kk = 0; kk < 2; kk++) {
            const uint32_t kbyte = (uint32_t)(kk * 16) * 2;
            uint32_t af[2][4], bf[8][2];
#pragma unroll
            for (int mi = 0; mi < 2; mi++) {
                uint32_t addr = stA + (uint32_t)(warpM + mi * 16 + a_m) * (BKP * 2)
                              + kbyte + (uint32_t)a_k * 2;
                ldsm4(af[mi][0], af[mi][1], af[mi][2], af[mi][3], addr);
            }
#pragma unroll
            for (int nj = 0; nj < 4; nj++) {
                uint32_t addr = stB + (uint32_t)(warpN + nj * 16 + b_n) * (BKP * 2)
                              + kbyte + (uint32_t)b_k * 2;
                ldsm4(bf[2 * nj][0], bf[2 * nj][1], bf[2 * nj + 1][0], bf[2 * nj + 1][1], addr);
            }
#pragma unroll
            for (int mi = 0; mi < 2; mi++)
#pragma unroll
                for (int ni = 0; ni < 8; ni++)
                    mma_f16(acc[mi][ni], af[mi], bf[ni]);
        }

        cur = (cur + 1 == STAGES) ? 0 : cur + 1;
        nxt = (nxt + 1 == STAGES) ? 0 : nxt + 1;
    }

    const bool isX = (Cx != nullptr) && (col0 < NX);
    const int  Nz  = Nn - NX;
#pragma unroll
    for (int mi = 0; mi < 2; mi++) {
        int r0 = row0 + warpM + mi * 16 + g;
#pragma unroll
        for (int ni = 0; ni < 8; ni++) {
            int cb = col0 + warpN + ni * 8 + 2 * tg;
            if (cb < Nn) {
                float v00 = acc[mi][ni][0], v01 = acc[mi][ni][1];
                float v10 = acc[mi][ni][2], v11 = acc[mi][ni][3];
                if (bias) {
                    float b0 = biasScale * bias[cb];
                    float b1 = biasScale * bias[cb + 1];
                    v00 += b0; v01 += b1; v10 += b0; v11 += b1;
                }
                if (act >= 1) {
                    v00 = (v00 > 20.f) ? v00 : log1pf(expf(v00));
                    v01 = (v01 > 20.f) ? v01 : log1pf(expf(v01));
                    v10 = (v10 > 20.f) ? v10 : log1pf(expf(v10));
                    v11 = (v11 > 20.f) ? v11 : log1pf(expf(v11));
                }
                if (isX) {
                    *(__half2*)(Cx + (size_t)r0 * NX + cb)       = __floats2half2_rn(v00, v01);
                    *(__half2*)(Cx + (size_t)(r0 + 8) * NX + cb) = __floats2half2_rn(v10, v11);
                } else if (act == 2) {
                    __half* Ch = (__half*)C;
                    *(__half2*)(Ch + (size_t)r0 * Nn + cb)       = __floats2half2_rn(v00, v01);
                    *(__half2*)(Ch + (size_t)(r0 + 8) * Nn + cb) = __floats2half2_rn(v10, v11);
                } else {
                    int cz = cb - NX;
                    *(float2*)(C + (size_t)r0 * Nz + cz)       = make_float2(v00, v01);
                    *(float2*)(C + (size_t)(r0 + 8) * Nz + cz) = make_float2(v10, v11);
                }
            }
        }
    }
}

// ---------------------------------------------------------------------------
// f32 -> f16 conversion, eight arrays per launch
// ---------------------------------------------------------------------------
__global__ void cvt8_half_kernel(
    const float* __restrict__ s0, __half* __restrict__ d0, int n0,
    const float* __restrict__ s1, __half* __restrict__ d1, int n1,
    const float* __restrict__ s2, __half* __restrict__ d2, int n2,
    const float* __restrict__ s3, __half* __restrict__ d3, int n3,
    const float* __restrict__ s4, __half* __restrict__ d4, int n4,
    const float* __restrict__ s5, __half* __restrict__ d5, int n5,
    const float* __restrict__ s6, __half* __restrict__ d6, int n6,
    const float* __restrict__ s7, __half* __restrict__ d7, int n7)
{
    int i = (blockIdx.x * blockDim.x + threadIdx.x) * 8;
    const float* s;
    __half* d;
    if (i < n0) { s = s0 + i; d = d0 + i; }
    else if ((i -= n0) < n1) { s = s1 + i; d = d1 + i; }
    else if ((i -= n1) < n2) { s = s2 + i; d = d2 + i; }
    else if ((i -= n2) < n3) { s = s3 + i; d = d3 + i; }
    else if ((i -= n3) < n4) { s = s4 + i; d = d4 + i; }
    else if ((i -= n4) < n5) { s = s5 + i; d = d5 + i; }
    else if ((i -= n5) < n6) { s = s6 + i; d = d6 + i; }
    else if ((i -= n6) < n7) { s = s7 + i; d = d7 + i; }
    else return;
    float4 v0 = *(const float4*)s;
    float4 v1 = *(const float4*)(s + 4);
    __half2 h0 = __floats2half2_rn(v0.x, v0.y);
    __half2 h1 = __floats2half2_rn(v0.z, v0.w);
    __half2 h2 = __floats2half2_rn(v1.x, v1.y);
    __half2 h3 = __floats2half2_rn(v1.z, v1.w);
    *(uint4*)d = make_uint4(*(uint32_t*)&h0, *(uint32_t*)&h1,
                            *(uint32_t*)&h2, *(uint32_t*)&h3);
}

// ---------------------------------------------------------------------------
// Reduce split-K partials (dbl): f32 + fp16 out
// ---------------------------------------------------------------------------
__global__ void reduce_dbl_kernel(const float* __restrict__ part,
                                  float* __restrict__ of, float* __restrict__ ob,
                                  __half* __restrict__ hf, __half* __restrict__ hb)
{
    const int NV = MTOT * DBLC / 4;
    int i = blockIdx.x * blockDim.x + threadIdx.x;
    if (i >= 2 * NV) return;
    int br = (i >= NV);
    int j  = i - br * NV;
    const float4* p = (const float4*)part + (size_t)br * SPLITK * NV + j;
    float4 s = make_float4(0.f, 0.f, 0.f, 0.f);
#pragma unroll
    for (int k = 0; k < SPLITK; k++) {
        float4 v = p[(size_t)k * NV];
        s.x += v.x; s.y += v.y; s.z += v.z; s.w += v.w;
    }
    ((float4*)(br ? ob : of))[j] = s;
    __half2 h0 = __floats2half2_rn(s.x, s.y);
    __half2 h1 = __floats2half2_rn(s.z, s.w);
    ((uint2*)(br ? hb : hf))[j] = make_uint2(*(uint32_t*)&h0, *(uint32_t*)&h1);
}

// ---------------------------------------------------------------------------
// Reduce Wo split-K partials into out
// ---------------------------------------------------------------------------
__global__ void reduce_out_kernel(const float* __restrict__ part,
                                  float* __restrict__ out)
{
    const int NV = MTOT * DM / 4;
    int i = blockIdx.x * blockDim.x + threadIdx.x;
    if (i >= NV) return;
    float4 a = ((const float4*)part)[i];
    float4 b = ((const float4*)part)[i + NV];
    ((float4*)out)[i] = make_float4(a.x + b.x, a.y + b.y, a.z + b.z, a.w + b.w);
}

// ---------------------------------------------------------------------------
// Depthwise causal conv1d (K=4) + bias + SiLU; 8 l x 2 d per thread; half2 I/O
// ---------------------------------------------------------------------------
#define CLG 8
__global__ void conv_silu_kernel(const __half* __restrict__ x0,
                                 const float* __restrict__ w0,
                                 const float* __restrict__ b0,
                                 __half* __restrict__ h0,
                                 const __half* __restrict__ x1,
                                 const float* __restrict__ w1,
                                 const float* __restrict__ b1,
                                 __half* __restrict__ h1)
{
    const int br = blockIdx.z;
    const __half* __restrict__ x = br ? x1 : x0;
    const float* __restrict__ w = br ? w1 : w0;
    const float* __restrict__ bi = br ? b1 : b0;
    __half* __restrict__ hu = br ? h1 : h0;

    int idx = blockIdx.x * blockDim.x + threadIdx.x;
    if (idx >= (MTOT / CLG) * (DI / 2)) return;
    const int d    = (idx % (DI / 2)) * 2;
    const int grp  = idx / (DI / 2);
    const int row0 = grp * CLG;
    const int l0   = row0 & (L_ - 1);
    const int bb0  = row0 - l0;

    float2 xv[CLG + KC - 1];
#pragma unroll
    for (int j = 0; j < CLG + KC - 1; j++) {
        int l = l0 - (KC - 1) + j;
        if (l >= 0) {
            __half2 hv = *(const __half2*)(x + (size_t)(bb0 + l) * DI + d);
            xv[j] = __half22float2(hv);
        } else {
            xv[j] = make_float2(0.f, 0.f);
        }
    }
    const float w00 = w[d * KC + 0], w01 = w[d * KC + 1],
                w02 = w[d * KC + 2], w03 = w[d * KC + 3];
    const float w10 = w[(d + 1) * KC + 0], w11 = w[(d + 1) * KC + 1],
                w12 = w[(d + 1) * KC + 2], w13 = w[(d + 1) * KC + 3];
    const float bv0 = bi[d], bv1 = bi[d + 1];

#pragma unroll
    for (int j = 0; j < CLG; j++) {
        float a0 = bv0, a1 = bv1;
        a0 = fmaf(xv[j].x,     w00, a0);  a1 = fmaf(xv[j].y,     w10, a1);
        a0 = fmaf(xv[j + 1].x, w01, a0);  a1 = fmaf(xv[j + 1].y, w11, a1);
        a0 = fmaf(xv[j + 2].x, w02, a0);  a1 = fmaf(xv[j + 2].y, w12, a1);
        a0 = fmaf(xv[j + 3].x, w03, a0);  a1 = fmaf(xv[j + 3].y, w13, a1);
        float s0 = 1.f / (1.f + __expf(-a0));
        float s1 = 1.f / (1.f + __expf(-a1));
        *(__half2*)(hu + (size_t)(row0 + j) * DI + d) =
            __floats2half2_rn(a0 * s0, a1 * s1);
    }
}

// ---------------------------------------------------------------------------
// Chunked selective scan (phase1 / phase2 with inline carry); fp16 delta/u/y
// ---------------------------------------------------------------------------
#define SCAN_TPB 128
#define SCAN_ST  16

__global__ __launch_bounds__(SCAN_TPB)
void scan_phase1(const __half* __restrict__ del_f, const float* __restrict__ dbl_f,
                 const __half* __restrict__ u_f,
                 const __half* __restrict__ del_b, const float* __restrict__ dbl_b,
                 const __half* __restrict__ u_b,
                 const float* __restrict__ Alog_f, const float* __restrict__ Alog_b,
                 float* __restrict__ hloc, float* __restrict__ psum)
{
    const int br = blockIdx.y;
    const __half* __restrict__ del = br ? del_b : del_f;
    const float* __restrict__ dbl  = br ? dbl_b : dbl_f;
    const __half* __restrict__ u   = br ? u_b   : u_f;
    const float* __restrict__ Alog = br ? Alog_b : Alog_f;

    const int tid   = threadIdx.x;
    const int ch    = blockIdx.x & (NCH - 1);
    const int bb    = (blockIdx.x >> 3) & 1;
    const int dpart = blockIdx.x >> 4;
    const int d     = dpart * SCAN_TPB + tid;
    const int dbase = dpart * SCAN_TPB;
    const int rowb  = bb * L_ + ch * CH;

    float a[NS];
    bool fast = true;
#pragma unroll
    for (int n = 0; n < NS; n++) {
        a[n] = expf(Alog[(size_t)d * NS + n]);
        fast = fast && (fabsf(a[n] - (float)(n + 1)) < 1e-4f * (float)(n + 1));
    }

    float h[NS];
#pragma unroll
    for (int n = 0; n < NS; n++) h[n] = 0.f;
    float ps = 0.f;

    __shared__ float  s_del[SCAN_ST][SCAN_TPB];
    __shared__ float  s_u[SCAN_ST][SCAN_TPB];
    __shared__ float4 s_bc[SCAN_ST][4];   // B only

    const int v_k = tid >> 6;        // 0..1
    const int v_j = (tid & 63) * 2;  // even half index

    for (int c0 = 0; c0 < CH; c0 += SCAN_ST) {
        __syncthreads();
#pragma unroll
        for (int kk = 0; kk < SCAN_ST; kk += 2) {
            int k = kk + v_k;
            size_t off = (size_t)(rowb + c0 + k) * DI + dbase + v_j;
            float2 fd = __half22float2(*(const __half2*)(del + off));
            float2 fu = __half22float2(*(const __half2*)(u + off));
            *(float2*)&s_del[k][v_j] = fd;
            *(float2*)&s_u[k][v_j]   = fu;
        }
        if (tid < 64) {
            int k = tid >> 2;
            int q = tid & 3;
            size_t off = (size_t)(rowb + c0 + k) * DBLC + RR + q * 4;
            s_bc[k][q] = *(const float4*)(dbl + off);
        }
        __syncthreads();

        if (fast) {
#pragma unroll 2
            for (int k = 0; k < SCAN_ST; k++) {
                float dl = s_del[k][tid];
                float du = dl * s_u[k][tid];
                ps += dl;
                float e = __expf(-dl);
                float4 V0 = s_bc[k][0], V1 = s_bc[k][1], V2 = s_bc[k][2], V3 = s_bc[k][3];
                float Bv[NS] = {V0.x,V0.y,V0.z,V0.w, V1.x,V1.y,V1.z,V1.w,
                                V2.x,V2.y,V2.z,V2.w, V3.x,V3.y,V3.z,V3.w};
                float p = e;
#pragma unroll
                for (int n = 0; n < NS; n++) {
                    h[n] = fmaf(p, h[n], du * Bv[n]);
                    p   *= e;
                }
            }
        } else {
            for (int k = 0; k < SCAN_ST; k++) {
                float dl = s_del[k][tid];
                float du = dl * s_u[k][tid];
                ps += dl;
                const float* bc = (const float*)s_bc[k];
#pragma unroll
                for (int n = 0; n < NS; n++) {
                    float dA = __expf(-dl * a[n]);
                    h[n] = fmaf(dA, h[n], du * bc[n]);
                }
            }
        }
    }

    const int cbase = ((br * B_ + bb) * NCH + ch);
    psum[(size_t)cbase * DI + d] = ps;
#pragma unroll
    for (int n = 0; n < NS; n++)
        hloc[((size_t)cbase * NS + n) * DI + d] = h[n];
}

__global__ __launch_bounds__(SCAN_TPB)
void scan_phase2(const __half* __restrict__ del_f, const float* __restrict__ dbl_f,
                 const __half* __restrict__ u_f,
                 const __half* __restrict__ del_b, const float* __restrict__ dbl_b,
                 const __half* __restrict__ u_b,
                 const float* __restrict__ Alog_f, const float* __restrict__ D_f,
                 const float* __restrict__ Alog_b, const float* __restrict__ D_b,
                 const float* __restrict__ hloc, const float* __restrict__ psum,
                 __half* __restrict__ y_f, __half* __restrict__ y_b)
{
    const int br = blockIdx.y;
    const __half* __restrict__ del = br ? del_b : del_f;
    const float* __restrict__ dbl  = br ? dbl_b : dbl_f;
    const __half* __restrict__ u   = br ? u_b   : u_f;
    const float* __restrict__ Alog = br ? Alog_b : Alog_f;
    const float* __restrict__ Dv_p = br ? D_b : D_f;
    __half* __restrict__ yout      = br ? y_b : y_f;

    const int tid   = threadIdx.x;
    const int ch    = blockIdx.x & (NCH - 1);
    const int bb    = (blockIdx.x >> 3) & 1;
    const int dpart = blockIdx.x >> 4;
    const int d     = dpart * SCAN_TPB + tid;
    const int dbase = dpart * SCAN_TPB;
    const int rowb  = bb * L_ + ch * CH;

    float a[NS];
    bool fast = true;
#pragma unroll
    for (int n = 0; n < NS; n++) {
        a[n] = expf(Alog[(size_t)d * NS + n]);
        fast = fast && (fabsf(a[n] - (float)(n + 1)) < 1e-4f * (float)(n + 1));
    }
    const float Dv = Dv_p[d];

    // inline carry: accumulate h_in from preceding chunks
    float h[NS];
#pragma unroll
    for (int n = 0; n < NS; n++) h[n] = 0.f;
    for (int c = 0; c < ch; c++) {
        const size_t cb = ((size_t)(br * B_ + bb) * NCH + c);
        float ps = psum[cb * DI + d];
        if (fast) {
            float E = __expf(-ps);
            float p = E;
#pragma unroll
            for (int n = 0; n < NS; n++) {
                h[n] = fmaf(p, h[n], hloc[(cb * NS + n) * DI + d]);
                p   *= E;
            }
        } else {
#pragma unroll
            for (int n = 0; n < NS; n++) {
                float P = __expf(-ps * a[n]);
                h[n] = fmaf(P, h[n], hloc[(cb * NS + n) * DI + d]);
            }
        }
    }

    __shared__ float  s_del[SCAN_ST][SCAN_TPB];
    __shared__ float  s_u[SCAN_ST][SCAN_TPB];
    __shared__ float4 s_bc[SCAN_ST][8];

    const int v_k = tid >> 6;
    const int v_j = (tid & 63) * 2;

    for (int c0 = 0; c0 < CH; c0 += SCAN_ST) {
        __syncthreads();
#pragma unroll
        for (int kk = 0; kk < SCAN_ST; kk += 2) {
            int k = kk + v_k;
            size_t off = (size_t)(rowb + c0 + k) * DI + dbase + v_j;
            float2 fd = __half22float2(*(const __half2*)(del + off));
            float2 fu = __half22float2(*(const __half2*)(u + off));
            *(float2*)&s_del[k][v_j] = fd;
            *(float2*)&s_u[k][v_j]   = fu;
        }
        {
            int k = tid >> 3;
            int q = tid & 7;
            size_t off = (size_t)(rowb + c0 + k) * DBLC + RR + q * 4;
            s_bc[k][q] = *(const float4*)(dbl + off);
        }
        __syncthreads();

        if (fast) {
#pragma unroll 2
            for (int k = 0; k < SCAN_ST; k++) {
                float dl = s_del[k][tid];
                float uu = s_u[k][tid];
                float du = dl * uu;
                float e  = __expf(-dl);
                float4 V0 = s_bc[k][0], V1 = s_bc[k][1], V2 = s_bc[k][2], V3 = s_bc[k][3];
                float4 W0 = s_bc[k][4], W1 = s_bc[k][5], W2 = s_bc[k][6], W3 = s_bc[k][7];
                float Bv[NS] = {V0.x,V0.y,V0.z,V0.w, V1.x,V1.y,V1.z,V1.w,
                                V2.x,V2.y,V2.z,V2.w, V3.x,V3.y,V3.z,V3.w};
                float Cv[NS] = {W0.x,W0.y,W0.z,W0.w, W1.x,W1.y,W1.z,W1.w,
                                W2.x,W2.y,W2.z,W2.w, W3.x,W3.y,W3.z,W3.w};
                float p  = e;
                float yv0 = 0.f, yv1 = 0.f;
#pragma unroll
                for (int n = 0; n < NS; n++) {
                    h[n] = fmaf(p, h[n], du * Bv[n]);
                    if (n & 1) yv1 = fmaf(h[n], Cv[n], yv1);
                    else       yv0 = fmaf(h[n], Cv[n], yv0);
                    p   *= e;
                }
                float yv = fmaf(uu, Dv, yv0 + yv1);
                yout[(size_t)(rowb + c0 + k) * DI + d] = __float2half_rn(yv);
            }
        } else {
            for (int k = 0; k < SCAN_ST; k++) {
                float dl = s_del[k][tid];
                float uu = s_u[k][tid];
                float du = dl * uu;
                float yv = 0.f;
                const float* bc = (const float*)s_bc[k];
#pragma unroll
                for (int n = 0; n < NS; n++) {
                    float dA = __expf(-dl * a[n]);
                    h[n] = fmaf(dA, h[n], du * bc[n]);
                    yv   = fmaf(h[n], bc[NS + n], yv);
                }
                yv = fmaf(uu, Dv, yv);
                yout[(size_t)(rowb + c0 + k) * DI + d] = __float2half_rn(yv);
            }
        }
    }
}

// ---------------------------------------------------------------------------
// Gate (y * silu(z)) + RMSNorm * norm_w; vectorized half2/float2
// ---------------------------------------------------------------------------
__global__ __launch_bounds__(256)
void gate_rms_kernel(const __half* __restrict__ yf, const __half* __restrict__ yb,
                     const float* __restrict__ z, const float* __restrict__ nw,
                     __half* __restrict__ g)
{
    const int row = blockIdx.x;
    const int l   = row & (L_ - 1);
    const int bb  = row >> 10;
    const int frow = (bb << 10) + (L_ - 1 - l);
    const int tid = threadIdx.x;

    __shared__ float sg[DI];
    __shared__ float red[8];

    float ss = 0.f;
#pragma unroll
    for (int it = 0; it < DI / 512; it++) {
        int d = (tid + it * 256) * 2;
        float2 y0 = __half22float2(*(const __half2*)(yf + (size_t)row * DI + d));
        float2 y1 = __half22float2(*(const __half2*)(yb + (size_t)frow * DI + d));
        float2 zz = *(const float2*)(z + (size_t)row * DI + d);
        float sz0 = zz.x / (1.f + __expf(-zz.x));
        float sz1 = zz.y / (1.f + __expf(-zz.y));
        float g0 = (y0.x + y1.x) * sz0;
        float g1 = (y0.y + y1.y) * sz1;
        *(float2*)&sg[d] = make_float2(g0, g1);
        ss = fmaf(g0, g0, ss);
        ss = fmaf(g1, g1, ss);
    }
#pragma unroll
    for (int o = 16; o; o >>= 1) ss += __shfl_xor_sync(0xFFFFFFFFu, ss, o);
    if ((tid & 31) == 0) red[tid >> 5] = ss;
    __syncthreads();
    float total = red[0] + red[1] + red[2] + red[3] + red[4] + red[5] + red[6] + red[7];
    float scale = rsqrtf(total / (float)DI + EPS);

#pragma unroll
    for (int it = 0; it < DI / 512; it++) {
        int d = (tid + it * 256) * 2;
        float2 gv = *(const float2*)&sg[d];
        float2 nv = *(const float2*)(nw + d);
        *(__half2*)(g + (size_t)row * DI + d) =
            __floats2half2_rn(gv.x * scale * nv.x, gv.y * scale * nv.y);
    }
}

// ---------------------------------------------------------------------------
// Launch
// ---------------------------------------------------------------------------
extern "C" void kernel_launch(void* const* d_in, const int* in_sizes, int n_in,
                              void* d_out, int out_size)
{
    (void)in_sizes; (void)n_in; (void)out_size;
    const float* a       = (const float*)d_in[0];
    const float* b       = (const float*)d_in[1];
    const float* Wi      = (const float*)d_in[2];
    const float* conv_w  = (const float*)d_in[3];
    const float* conv_b  = (const float*)d_in[4];
    const float* Wx      = (const float*)d_in[5];
    const float* Wdt     = (const float*)d_in[6];
    const float* bdt     = (const float*)d_in[7];
    const float* A_log   = (const float*)d_in[8];
    const float* D       = (const float*)d_in[9];
    const float* conv_w_b = (const float*)d_in[10];
    const float* conv_b_b = (const float*)d_in[11];
    const float* Wx_b    = (const float*)d_in[12];
    const float* Wdt_b   = (const float*)d_in[13];
    const float* bdt_b   = (const float*)d_in[14];
    const float* A_log_b = (const float*)d_in[15];
    const float* D_b     = (const float*)d_in[16];
    const float* Wo      = (const float*)d_in[17];
    const float* norm_w  = (const float*)d_in[18];
    float* out = (float*)d_out;

    __half *p_hA, *p_hB, *p_hWi, *p_hWo, *p_hWx, *p_hWx_b, *p_hWdt, *p_hWdt_b;
    __half *p_hx_f, *p_hx_b, *p_hu_f, *p_hu_b, *p_hdbl_f, *p_hdbl_b;
    __half *p_hdelta_f, *p_hdelta_b, *p_hy_f, *p_hy_b, *p_hg;
    float *p_z, *p_dblp, *p_dbl_f, *p_dbl_b, *p_wop;
    float *p_hloc, *p_psum;
    cudaGetSymbolAddress((void**)&p_hA, g_hA);
    cudaGetSymbolAddress((void**)&p_hB, g_hB);
    cudaGetSymbolAddress((void**)&p_hWi, g_hWi);
    cudaGetSymbolAddress((void**)&p_hWo, g_hWo);
    cudaGetSymbolAddress((void**)&p_hWx, g_hWx);
    cudaGetSymbolAddress((void**)&p_hWx_b, g_hWx_b);
    cudaGetSymbolAddress((void**)&p_hWdt, g_hWdt);
    cudaGetSymbolAddress((void**)&p_hWdt_b, g_hWdt_b);
    cudaGetSymbolAddress((void**)&p_hx_f, g_hx_f);
    cudaGetSymbolAddress((void**)&p_hx_b, g_hx_b);
    cudaGetSymbolAddress((void**)&p_hu_f, g_hu_f);
    cudaGetSymbolAddress((void**)&p_hu_b, g_hu_b);
    cudaGetSymbolAddress((void**)&p_hdbl_f, g_hdbl_f);
    cudaGetSymbolAddress((void**)&p_hdbl_b, g_hdbl_b);
    cudaGetSymbolAddress((void**)&p_hdelta_f, g_hdelta_f);
    cudaGetSymbolAddress((void**)&p_hdelta_b, g_hdelta_b);
    cudaGetSymbolAddress((void**)&p_hy_f, g_hy_f);
    cudaGetSymbolAddress((void**)&p_hy_b, g_hy_b);
    cudaGetSymbolAddress((void**)&p_hg, g_hg);
    cudaGetSymbolAddress((void**)&p_z, g_z);
    cudaGetSymbolAddress((void**)&p_dblp, g_dblp);
    cudaGetSymbolAddress((void**)&p_dbl_f, g_dbl_f);
    cudaGetSymbolAddress((void**)&p_dbl_b, g_dbl_b);
    cudaGetSymbolAddress((void**)&p_wop, g_wop);
    cudaGetSymbolAddress((void**)&p_hloc, g_hloc);
    cudaGetSymbolAddress((void**)&p_psum, g_psum);

    const int TPB = 256;
    cudaFuncSetAttribute(ha_linear2_kernel,
                         cudaFuncAttributeMaxDynamicSharedMemorySize, SMEM_TOTAL);

    // 0. convert inputs/weights to fp16 (one 8-array launch)
    {
        int nA = MTOT * DM, nB = MTOT * DM, nC = 2 * DI * DM, nD = DM * DI;
        int n0 = DBLC * DI, n1 = DBLC * DI, n2 = DI * RR, n3 = DI * RR;
        int ntot = nA + nB + nC + nD + n0 + n1 + n2 + n3;
        cvt8_half_kernel<<<(ntot / 8 + TPB - 1) / TPB, TPB>>>(
            a, p_hA, nA, b, p_hB, nB, Wi, p_hWi, nC, Wo, p_hWo, nD,
            Wx, p_hWx, n0, Wx_b, p_hWx_b, n1, Wdt, p_hWdt, n2, Wdt_b, p_hWdt_b, n3);
    }

    // 1. fused xz GEMM: fwd x->fp16 + z->f32; bwd x->fp16
    ha_linear2_kernel<<<dim3(32 + 16, MTOT / BM, 1), TPB, SMEM_TOTAL>>>(
        p_hA, DM, p_hWi, DM, nullptr, 0.f, p_z, p_hx_f, DI, 2 * DI, 0, 0,
        p_hB, DM, p_hWi, DM, nullptr, 0.f, nullptr, p_hx_b, DI, DI, 1, 0,
        MTOT, DM, /*splitX=*/32, /*splitZ=*/BIGSPLIT, 0);

    // 2. conv + silu (8 l x 2 d per thread, both branches)
    conv_silu_kernel<<<dim3((MTOT / CLG) * (DI / 2) / TPB, 1, 2), TPB>>>(
        p_hx_f, conv_w, conv_b, p_hu_f,
        p_hx_b, conv_w_b, conv_b_b, p_hu_b);

    // 3. fused dbl = u @ Wx^T [2048,96], split-K both branches
    ha_linear2_kernel<<<dim3(1, MTOT / BM, 2 * SPLITK), TPB, SMEM_TOTAL>>>(
        p_hu_f, DI, p_hWx, DI, nullptr, 0.f, p_dblp, nullptr, 0, DBLC, 0, 0,
        p_hu_b, DI, p_hWx_b, DI, nullptr, 0.f, p_dblp + (size_t)SPLITK * MTOT * DBLC,
        nullptr, 0, DBLC, 0, 0,
        MTOT, DI, /*splitX=*/BIGSPLIT, /*splitZ=*/SPLITK, KCHUNK);

    // 4. reduce partials -> dbl (f32 + fp16)
    {
        int nthreads = 2 * MTOT * DBLC / 4;
        reduce_dbl_kernel<<<(nthreads + TPB - 1) / TPB, TPB>>>(
            p_dblp, p_dbl_f, p_dbl_b, p_hdbl_f, p_hdbl_b);
    }

    // 5. fused delta = softplus(dt @ Wdt^T + 2*bdt), fp16 out, both branches
    ha_linear2_kernel<<<dim3(DI / BN, MTOT / BM, 2), TPB, SMEM_TOTAL>>>(
        p_hdbl_f, DBLC, p_hWdt, RR, bdt, 2.f, (float*)p_hdelta_f, nullptr, 0, DI, 0, 2,
        p_hdbl_b, DBLC, p_hWdt_b, RR, bdt_b, 2.f, (float*)p_hdelta_b, nullptr, 0, DI, 0, 2,
        MTOT, RR, /*splitX=*/BIGSPLIT, /*splitZ=*/1, 0);

    // 6. chunked selective scan (both branches); carry inlined in phase2
    scan_phase1<<<dim3((DI / SCAN_TPB) * B_ * NCH, 2), SCAN_TPB>>>(
        p_hdelta_f, p_dbl_f, p_hu_f, p_hdelta_b, p_dbl_b, p_hu_b,
        A_log, A_log_b, p_hloc, p_psum);
    scan_phase2<<<dim3((DI / SCAN_TPB) * B_ * NCH, 2), SCAN_TPB>>>(
        p_hdelta_f, p_dbl_f, p_hu_f, p_hdelta_b, p_dbl_b, p_hu_b,
        A_log, D, A_log_b, D_b, p_hloc, p_psum, p_hy_f, p_hy_b);

    // 7. gate + rmsnorm (vectorized)
    gate_rms_kernel<<<MTOT, TPB>>>(p_hy_f, p_hy_b, p_z, norm_w, p_hg);

    // 8. out = g @ Wo^T [2048,1024], split-K x2
    ha_linear2_kernel<<<dim3(DM / BN, MTOT / BM, 2), TPB, SMEM_TOTAL>>>(
        p_hg, DI, p_hWo, DI, nullptr, 0.f, p_wop, nullptr, 0, DM, 0, 0,
        p_hg, DI, p_hWo, DI, nullptr, 0.f, p_wop, nullptr, 0, DM, 0, 0,
        MTOT, DI, /*splitX=*/BIGSPLIT, /*splitZ=*/BIGSPLIT, DI / 2);
    reduce_out_kernel<<<(MTOT * DM / 4 + TPB - 1) / TPB, TPB>>>(p_wop, out);
}

// round 14
// speedup vs baseline: 6.5921x; 1.0158x over previous
#include <cuda_runtime.h>
#include <cuda_bf16.h>
#include <cuda_fp16.h>
#include <math.h>
#include <stdint.h>

// Problem constants
#define B_  2
#define L_  1024
#define DM  1024
#define DI  2048
#define NS  16
#define RR  64
#define KC  4
#define MTOT (B_ * L_)      // 2048
#define EPS 1e-5f

#define DBLC (RR + 2 * NS)  // 96
#define SPLITK 8
#define KCHUNK (DI / SPLITK)  // 256
#define WOSPLIT 4

#define NCH 8               // scan chunks
#define CH  (L_ / NCH)      // 128 steps per chunk

#define BIGSPLIT 0x40000000

// ---------------------------------------------------------------------------
// Scratch buffers (device globals; no allocation allowed)
// ---------------------------------------------------------------------------
__device__ __half g_hA[MTOT * DM];
__device__ __half g_hB[MTOT * DM];
__device__ __half g_hWi[(2 * DI) * DM];
__device__ __half g_hWo[DM * DI];
__device__ __half g_hWx[DBLC * DI];
__device__ __half g_hWx_b[DBLC * DI];
__device__ __half g_hWdt[DI * RR];
__device__ __half g_hWdt_b[DI * RR];
__device__ __half g_hx_f[MTOT * DI];        // fp16 x (conv input)
__device__ __half g_hx_b[MTOT * DI];
__device__ __half g_hu_f[MTOT * DI];        // fp16 u (GEMM + scan operand)
__device__ __half g_hu_b[MTOT * DI];
__device__ __half g_hdbl_f[MTOT * DBLC];
__device__ __half g_hdbl_b[MTOT * DBLC];
__device__ __half g_hdelta_f[MTOT * DI];    // fp16 delta (scan operand)
__device__ __half g_hdelta_b[MTOT * DI];
__device__ __half g_hy_f[MTOT * DI];        // fp16 y
__device__ __half g_hy_b[MTOT * DI];
__device__ __half g_hg[MTOT * DI];

__device__ float g_z[MTOT * DI];            // f32 z (gate input)
__device__ float g_dblp[2 * SPLITK * MTOT * DBLC];
__device__ float g_dbl_f[MTOT * DBLC];
__device__ float g_dbl_b[MTOT * DBLC];
__device__ float g_wop[WOSPLIT * MTOT * DM];

// scan chunking state
__device__ float g_hloc[2 * B_ * NCH * NS * DI];
__device__ float g_psum[2 * B_ * NCH * DI];

// ---------------------------------------------------------------------------
// fp16 tensor-core GEMM, cp.async 3-stage pipeline, DUAL-BRANCH
// ---------------------------------------------------------------------------
#define BM 128
#define BN 128
#define BK 32
#define BKP 40
#define STAGES 3
#define STG_BYTES ((BM + BN) * BKP * 2)
#define SMEM_TOTAL (STAGES * STG_BYTES)

__device__ __forceinline__ uint32_t smem_u32(const void* p) {
    uint32_t a;
    asm("{ .reg .u64 t; cvta.to.shared.u64 t, %1; cvt.u32.u64 %0, t; }"
        : "=r"(a) : "l"(p));
    return a;
}

__device__ __forceinline__ void ldsm4(uint32_t& r0, uint32_t& r1,
                                      uint32_t& r2, uint32_t& r3, uint32_t addr) {
    asm volatile("ldmatrix.sync.aligned.m8n8.x4.shared.b16 {%0,%1,%2,%3}, [%4];"
                 : "=r"(r0), "=r"(r1), "=r"(r2), "=r"(r3) : "r"(addr));
}

__device__ __forceinline__ void mma_f16(float c[4], const uint32_t a[4],
                                        const uint32_t b[2]) {
    asm volatile(
        "mma.sync.aligned.m16n8k16.row.col.f32.f16.f16.f32 "
        "{%0,%1,%2,%3}, {%4,%5,%6,%7}, {%8,%9}, {%0,%1,%2,%3};"
        : "+f"(c[0]), "+f"(c[1]), "+f"(c[2]), "+f"(c[3])
        : "r"(a[0]), "r"(a[1]), "r"(a[2]), "r"(a[3]), "r"(b[0]), "r"(b[1]));
}

#define CP_ASYNC16(dst, src, sz) \
    asm volatile("cp.async.cg.shared.global [%0], [%1], 16, %2;" \
                 :: "r"(dst), "l"(src), "r"(sz) : "memory")
#define CP_COMMIT() asm volatile("cp.async.commit_group;" ::: "memory")
#define CP_WAIT1()  asm volatile("cp.async.wait_group 1;" ::: "memory")

__global__ __launch_bounds__(256, 2)
void ha_linear2_kernel(
    const __half* __restrict__ A0, int lda0, const __half* __restrict__ W0, int ldw0,
    const float* __restrict__ bias0, float bs0, float* __restrict__ C0,
    __half* __restrict__ Cx0, int NX0,
    int Nn0, int flip0, int act0,
    const __half* __restrict__ A1, int lda1, const __half* __restrict__ W1, int ldw1,
    const float* __restrict__ bias1, float bs1, float* __restrict__ C1,
    __half* __restrict__ Cx1, int NX1,
    int Nn1, int flip1, int act1,
    int M, int Kd, int splitX, int splitZ, int kchunk)
{
    extern __shared__ __align__(16) char dsm[];
    const uint32_t sbase = smem_u32(dsm);

    int bx = blockIdx.x, bz = blockIdx.z, sel = 0;
    if (bx >= splitX) { sel = 1; bx -= splitX; }
    else if (bz >= splitZ) { sel = 1; bz -= splitZ; }

    const __half* __restrict__ A = sel ? A1 : A0;
    const __half* __restrict__ W = sel ? W1 : W0;
    const float* __restrict__ bias = sel ? bias1 : bias0;
    const float biasScale = sel ? bs1 : bs0;
    float* __restrict__ C = sel ? C1 : C0;
    __half* __restrict__ Cx = sel ? Cx1 : Cx0;
    const int NX   = sel ? NX1 : NX0;
    const int lda  = sel ? lda1 : lda0;
    const int ldw  = sel ? ldw1 : ldw0;
    const int Nn   = sel ? Nn1 : Nn0;
    const int flip = sel ? flip1 : flip0;
    const int act  = sel ? act1 : act0;

    const int tid  = threadIdx.x;
    const int lane = tid & 31;
    const int warp = tid >> 5;
    const int g    = lane >> 2;
    const int tg   = lane & 3;
    const int warpM = (warp & 3) * 32;
    const int warpN = (warp >> 2) * 64;
    const int row0 = blockIdx.y * BM;
    const int col0 = bx * BN;

    int kb = 0, klen = Kd;
    if (kchunk > 0) {
        kb   = bz * kchunk;
        klen = kchunk;
        C   += (size_t)bz * M * Nn;
    }
    const int ntiles = klen / BK;

    int arow[2], wrow[2];
    uint32_t wsz[2];
#pragma unroll
    for (int i = 0; i < 2; i++) {
        int idx = tid + 256 * i;
        int r   = idx >> 2;
        int gr  = row0 + r;
        if (flip) { gr = (gr & ~(L_ - 1)) + ((L_ - 1) - (gr & (L_ - 1))); }
        arow[i] = gr;
        int gn = col0 + r;
        wsz[i]  = (gn < Nn) ? 16u : 0u;
        wrow[i] = (gn < Nn) ? gn : 0;
    }
    const int ld_row   = tid >> 2;
    const int ld_chunk = (tid & 3) * 8;

    const int tquad = lane >> 3;
    const int trow  = lane & 7;
    const int a_m = ((tquad & 1) << 3) + trow;
    const int a_k = (tquad >> 1) << 3;
    const int b_n = ((tquad >> 1) << 3) + trow;
    const int b_k = (tquad & 1) << 3;

    float acc[2][8][4];
#pragma unroll
    for (int mi = 0; mi < 2; mi++)
#pragma unroll
        for (int ni = 0; ni < 8; ni++)
#pragma unroll
            for (int q = 0; q < 4; q++) acc[mi][ni][q] = 0.f;

    auto issue = [&](int t, int s) {
        const uint32_t st = sbase + (uint32_t)s * STG_BYTES;
        const int koff = kb + t * BK + ld_chunk;
#pragma unroll
        for (int i = 0; i < 2; i++) {
            int r = ld_row + 64 * i;
            uint32_t da = st + (uint32_t)r * (BKP * 2) + (uint32_t)ld_chunk * 2;
            CP_ASYNC16(da, A + (size_t)arow[i] * lda + koff, 16u);
        }
#pragma unroll
        for (int i = 0; i < 2; i++) {
            int r = ld_row + 64 * i;
            uint32_t db = st + (uint32_t)(BM * BKP * 2)
                        + (uint32_t)r * (BKP * 2) + (uint32_t)ld_chunk * 2;
            CP_ASYNC16(db, W + (size_t)wrow[i] * ldw + koff, wsz[i]);
        }
    };

#pragma unroll
    for (int s = 0; s < STAGES - 1; s++) {
        if (s < ntiles) issue(s, s);
        CP_COMMIT();
    }

    int cur = 0;
    int nxt = STAGES - 1;
    for (int t = 0; t < ntiles; t++) {
        CP_WAIT1();
        __syncthreads();

        const int tn = t + STAGES - 1;
        if (tn < ntiles) issue(tn, nxt);
        CP_COMMIT();

        const uint32_t stA = sbase + (uint32_t)cur * STG_BYTES;
        const uint32_t stB = stA + (uint32_t)(BM * BKP * 2);

#pragma unroll
        for (int kk = 0; kk < 2; kk++) {
            const uint32_t kbyte = (uint32_t)(kk * 16) * 2;
            uint32_t af[2][4], bf[8][2];
#pragma unroll
            for (int mi = 0; mi < 2; mi++) {
                uint32_t addr = stA + (uint32_t)(warpM + mi * 16 + a_m) * (BKP * 2)
                              + kbyte + (uint32_t)a_k * 2;
                ldsm4(af[mi][0], af[mi][1], af[mi][2], af[mi][3], addr);
            }
#pragma unroll
            for (int nj = 0; nj < 4; nj++) {
                uint32_t addr = stB + (uint32_t)(warpN + nj * 16 + b_n) * (BKP * 2)
                              + kbyte + (uint32_t)b_k * 2;
                ldsm4(bf[2 * nj][0], bf[2 * nj][1], bf[2 * nj + 1][0], bf[2 * nj + 1][1], addr);
            }
#pragma unroll
            for (int mi = 0; mi < 2; mi++)
#pragma unroll
                for (int ni = 0; ni < 8; ni++)
                    mma_f16(acc[mi][ni], af[mi], bf[ni]);
        }

        cur = (cur + 1 == STAGES) ? 0 : cur + 1;
        nxt = (nxt + 1 == STAGES) ? 0 : nxt + 1;
    }

    const bool isX = (Cx != nullptr) && (col0 < NX);
    const int  Nz  = Nn - NX;
#pragma unroll
    for (int mi = 0; mi < 2; mi++) {
        int r0 = row0 + warpM + mi * 16 + g;
#pragma unroll
        for (int ni = 0; ni < 8; ni++) {
            int cb = col0 + warpN + ni * 8 + 2 * tg;
            if (cb < Nn) {
                float v00 = acc[mi][ni][0], v01 = acc[mi][ni][1];
                float v10 = acc[mi][ni][2], v11 = acc[mi][ni][3];
                if (bias) {
                    float b0 = biasScale * bias[cb];
                    float b1 = biasScale * bias[cb + 1];
                    v00 += b0; v01 += b1; v10 += b0; v11 += b1;
                }
                if (act >= 1) {
                    v00 = (v00 > 20.f) ? v00 : log1pf(expf(v00));
                    v01 = (v01 > 20.f) ? v01 : log1pf(expf(v01));
                    v10 = (v10 > 20.f) ? v10 : log1pf(expf(v10));
                    v11 = (v11 > 20.f) ? v11 : log1pf(expf(v11));
                }
                if (isX) {
                    *(__half2*)(Cx + (size_t)r0 * NX + cb)       = __floats2half2_rn(v00, v01);
                    *(__half2*)(Cx + (size_t)(r0 + 8) * NX + cb) = __floats2half2_rn(v10, v11);
                } else if (act == 2) {
                    __half* Ch = (__half*)C;
                    *(__half2*)(Ch + (size_t)r0 * Nn + cb)       = __floats2half2_rn(v00, v01);
                    *(__half2*)(Ch + (size_t)(r0 + 8) * Nn + cb) = __floats2half2_rn(v10, v11);
                } else {
                    int cz = cb - NX;
                    *(float2*)(C + (size_t)r0 * Nz + cz)       = make_float2(v00, v01);
                    *(float2*)(C + (size_t)(r0 + 8) * Nz + cz) = make_float2(v10, v11);
                }
            }
        }
    }
}

// ---------------------------------------------------------------------------
// f32 -> f16 conversion, eight arrays per launch
// ---------------------------------------------------------------------------
__global__ void cvt8_half_kernel(
    const float* __restrict__ s0, __half* __restrict__ d0, int n0,
    const float* __restrict__ s1, __half* __restrict__ d1, int n1,
    const float* __restrict__ s2, __half* __restrict__ d2, int n2,
    const float* __restrict__ s3, __half* __restrict__ d3, int n3,
    const float* __restrict__ s4, __half* __restrict__ d4, int n4,
    const float* __restrict__ s5, __half* __restrict__ d5, int n5,
    const float* __restrict__ s6, __half* __restrict__ d6, int n6,
    const float* __restrict__ s7, __half* __restrict__ d7, int n7)
{
    int i = (blockIdx.x * blockDim.x + threadIdx.x) * 8;
    const float* s;
    __half* d;
    if (i < n0) { s = s0 + i; d = d0 + i; }
    else if ((i -= n0) < n1) { s = s1 + i; d = d1 + i; }
    else if ((i -= n1) < n2) { s = s2 + i; d = d2 + i; }
    else if ((i -= n2) < n3) { s = s3 + i; d = d3 + i; }
    else if ((i -= n3) < n4) { s = s4 + i; d = d4 + i; }
    else if ((i -= n4) < n5) { s = s5 + i; d = d5 + i; }
    else if ((i -= n5) < n6) { s = s6 + i; d = d6 + i; }
    else if ((i -= n6) < n7) { s = s7 + i; d = d7 + i; }
    else return;
    float4 v0 = *(const float4*)s;
    float4 v1 = *(const float4*)(s + 4);
    __half2 h0 = __floats2half2_rn(v0.x, v0.y);
    __half2 h1 = __floats2half2_rn(v0.z, v0.w);
    __half2 h2 = __floats2half2_rn(v1.x, v1.y);
    __half2 h3 = __floats2half2_rn(v1.z, v1.w);
    *(uint4*)d = make_uint4(*(uint32_t*)&h0, *(uint32_t*)&h1,
                            *(uint32_t*)&h2, *(uint32_t*)&h3);
}

// ---------------------------------------------------------------------------
// Reduce split-K partials (dbl): f32 + fp16 out
// ---------------------------------------------------------------------------
__global__ void reduce_dbl_kernel(const float* __restrict__ part,
                                  float* __restrict__ of, float* __restrict__ ob,
                                  __half* __restrict__ hf, __half* __restrict__ hb)
{
    const int NV = MTOT * DBLC / 4;
    int i = blockIdx.x * blockDim.x + threadIdx.x;
    if (i >= 2 * NV) return;
    int br = (i >= NV);
    int j  = i - br * NV;
    const float4* p = (const float4*)part + (size_t)br * SPLITK * NV + j;
    float4 s = make_float4(0.f, 0.f, 0.f, 0.f);
#pragma unroll
    for (int k = 0; k < SPLITK; k++) {
        float4 v = p[(size_t)k * NV];
        s.x += v.x; s.y += v.y; s.z += v.z; s.w += v.w;
    }
    ((float4*)(br ? ob : of))[j] = s;
    __half2 h0 = __floats2half2_rn(s.x, s.y);
    __half2 h1 = __floats2half2_rn(s.z, s.w);
    ((uint2*)(br ? hb : hf))[j] = make_uint2(*(uint32_t*)&h0, *(uint32_t*)&h1);
}

// ---------------------------------------------------------------------------
// Reduce Wo split-K partials into out (WOSPLIT partials)
// ---------------------------------------------------------------------------
__global__ void reduce_out_kernel(const float* __restrict__ part,
                                  float* __restrict__ out)
{
    const int NV = MTOT * DM / 4;
    int i = blockIdx.x * blockDim.x + threadIdx.x;
    if (i >= NV) return;
    float4 s = make_float4(0.f, 0.f, 0.f, 0.f);
#pragma unroll
    for (int k = 0; k < WOSPLIT; k++) {
        float4 v = ((const float4*)part)[i + (size_t)k * NV];
        s.x += v.x; s.y += v.y; s.z += v.z; s.w += v.w;
    }
    ((float4*)out)[i] = s;
}

// ---------------------------------------------------------------------------
// Depthwise causal conv1d (K=4) + bias + SiLU; 8 l x 2 d per thread; half2 I/O
// ---------------------------------------------------------------------------
#define CLG 8
__global__ void conv_silu_kernel(const __half* __restrict__ x0,
                                 const float* __restrict__ w0,
                                 const float* __restrict__ b0,
                                 __half* __restrict__ h0,
                                 const __half* __restrict__ x1,
                                 const float* __restrict__ w1,
                                 const float* __restrict__ b1,
                                 __half* __restrict__ h1)
{
    const int br = blockIdx.z;
    const __half* __restrict__ x = br ? x1 : x0;
    const float* __restrict__ w = br ? w1 : w0;
    const float* __restrict__ bi = br ? b1 : b0;
    __half* __restrict__ hu = br ? h1 : h0;

    int idx = blockIdx.x * blockDim.x + threadIdx.x;
    if (idx >= (MTOT / CLG) * (DI / 2)) return;
    const int d    = (idx % (DI / 2)) * 2;
    const int grp  = idx / (DI / 2);
    const int row0 = grp * CLG;
    const int l0   = row0 & (L_ - 1);
    const int bb0  = row0 - l0;

    float2 xv[CLG + KC - 1];
#pragma unroll
    for (int j = 0; j < CLG + KC - 1; j++) {
        int l = l0 - (KC - 1) + j;
        if (l >= 0) {
            __half2 hv = *(const __half2*)(x + (size_t)(bb0 + l) * DI + d);
            xv[j] = __half22float2(hv);
        } else {
            xv[j] = make_float2(0.f, 0.f);
        }
    }
    const float w00 = w[d * KC + 0], w01 = w[d * KC + 1],
                w02 = w[d * KC + 2], w03 = w[d * KC + 3];
    const float w10 = w[(d + 1) * KC + 0], w11 = w[(d + 1) * KC + 1],
                w12 = w[(d + 1) * KC + 2], w13 = w[(d + 1) * KC + 3];
    const float bv0 = bi[d], bv1 = bi[d + 1];

#pragma unroll
    for (int j = 0; j < CLG; j++) {
        float a0 = bv0, a1 = bv1;
        a0 = fmaf(xv[j].x,     w00, a0);  a1 = fmaf(xv[j].y,     w10, a1);
        a0 = fmaf(xv[j + 1].x, w01, a0);  a1 = fmaf(xv[j + 1].y, w11, a1);
        a0 = fmaf(xv[j + 2].x, w02, a0);  a1 = fmaf(xv[j + 2].y, w12, a1);
        a0 = fmaf(xv[j + 3].x, w03, a0);  a1 = fmaf(xv[j + 3].y, w13, a1);
        float s0 = 1.f / (1.f + __expf(-a0));
        float s1 = 1.f / (1.f + __expf(-a1));
        *(__half2*)(hu + (size_t)(row0 + j) * DI + d) =
            __floats2half2_rn(a0 * s0, a1 * s1);
    }
}

// ---------------------------------------------------------------------------
// Chunked selective scan (phase1 / phase2 with inline carry)
//   delta/u loaded directly to registers (coalesced); B/C staged in smem.
// ---------------------------------------------------------------------------
#define SCAN_TPB 128
#define SCAN_ST  16

__global__ __launch_bounds__(SCAN_TPB)
void scan_phase1(const __half* __restrict__ del_f, const float* __restrict__ dbl_f,
                 const __half* __restrict__ u_f,
                 const __half* __restrict__ del_b, const float* __restrict__ dbl_b,
                 const __half* __restrict__ u_b,
                 const float* __restrict__ Alog_f, const float* __restrict__ Alog_b,
                 float* __restrict__ hloc, float* __restrict__ psum)
{
    const int br = blockIdx.y;
    const __half* __restrict__ del = br ? del_b : del_f;
    const float* __restrict__ dbl  = br ? dbl_b : dbl_f;
    const __half* __restrict__ u   = br ? u_b   : u_f;
    const float* __restrict__ Alog = br ? Alog_b : Alog_f;

    const int tid   = threadIdx.x;
    const int ch    = blockIdx.x & (NCH - 1);
    const int bb    = (blockIdx.x >> 3) & 1;
    const int dpart = blockIdx.x >> 4;
    const int d     = dpart * SCAN_TPB + tid;
    const int rowb  = bb * L_ + ch * CH;

    bool fast = true;
#pragma unroll
    for (int n = 0; n < NS; n++) {
        float an = expf(Alog[(size_t)d * NS + n]);
        fast = fast && (fabsf(an - (float)(n + 1)) < 1e-4f * (float)(n + 1));
    }

    float h[NS];
#pragma unroll
    for (int n = 0; n < NS; n++) h[n] = 0.f;
    float ps = 0.f;

    __shared__ float4 s_bc[SCAN_ST][4];   // B only

    for (int c0 = 0; c0 < CH; c0 += SCAN_ST) {
        float rdel[SCAN_ST], ru[SCAN_ST];
#pragma unroll
        for (int k = 0; k < SCAN_ST; k++) {
            size_t off = (size_t)(rowb + c0 + k) * DI + d;
            rdel[k] = __half2float(del[off]);
            ru[k]   = __half2float(u[off]);
        }
        __syncthreads();
        if (tid < 64) {
            int k = tid >> 2;
            int q = tid & 3;
            size_t off = (size_t)(rowb + c0 + k) * DBLC + RR + q * 4;
            s_bc[k][q] = *(const float4*)(dbl + off);
        }
        __syncthreads();

        if (fast) {
#pragma unroll
            for (int k = 0; k < SCAN_ST; k++) {
                float dl = rdel[k];
                float du = dl * ru[k];
                ps += dl;
                float e = __expf(-dl);
                float4 V0 = s_bc[k][0], V1 = s_bc[k][1], V2 = s_bc[k][2], V3 = s_bc[k][3];
                float Bv[NS] = {V0.x,V0.y,V0.z,V0.w, V1.x,V1.y,V1.z,V1.w,
                                V2.x,V2.y,V2.z,V2.w, V3.x,V3.y,V3.z,V3.w};
                float p = e;
#pragma unroll
                for (int n = 0; n < NS; n++) {
                    h[n] = fmaf(p, h[n], du * Bv[n]);
                    p   *= e;
                }
            }
        } else {
#pragma unroll
            for (int k = 0; k < SCAN_ST; k++) {
                float dl = rdel[k];
                float du = dl * ru[k];
                ps += dl;
                const float* bc = (const float*)s_bc[k];
#pragma unroll
                for (int n = 0; n < NS; n++) {
                    float an = expf(Alog[(size_t)d * NS + n]);
                    float dA = __expf(-dl * an);
                    h[n] = fmaf(dA, h[n], du * bc[n]);
                }
            }
        }
    }

    const int cbase = ((br * B_ + bb) * NCH + ch);
    psum[(size_t)cbase * DI + d] = ps;
#pragma unroll
    for (int n = 0; n < NS; n++)
        hloc[((size_t)cbase * NS + n) * DI + d] = h[n];
}

__global__ __launch_bounds__(SCAN_TPB)
void scan_phase2(const __half* __restrict__ del_f, const float* __restrict__ dbl_f,
                 const __half* __restrict__ u_f,
                 const __half* __restrict__ del_b, const float* __restrict__ dbl_b,
                 const __half* __restrict__ u_b,
                 const float* __restrict__ Alog_f, const float* __restrict__ D_f,
                 const float* __restrict__ Alog_b, const float* __restrict__ D_b,
                 const float* __restrict__ hloc, const float* __restrict__ psum,
                 __half* __restrict__ y_f, __half* __restrict__ y_b)
{
    const int br = blockIdx.y;
    const __half* __restrict__ del = br ? del_b : del_f;
    const float* __restrict__ dbl  = br ? dbl_b : dbl_f;
    const __half* __restrict__ u   = br ? u_b   : u_f;
    const float* __restrict__ Alog = br ? Alog_b : Alog_f;
    const float* __restrict__ Dv_p = br ? D_b : D_f;
    __half* __restrict__ yout      = br ? y_b : y_f;

    const int tid   = threadIdx.x;
    const int ch    = blockIdx.x & (NCH - 1);
    const int bb    = (blockIdx.x >> 3) & 1;
    const int dpart = blockIdx.x >> 4;
    const int d     = dpart * SCAN_TPB + tid;
    const int rowb  = bb * L_ + ch * CH;

    bool fast = true;
#pragma unroll
    for (int n = 0; n < NS; n++) {
        float an = expf(Alog[(size_t)d * NS + n]);
        fast = fast && (fabsf(an - (float)(n + 1)) < 1e-4f * (float)(n + 1));
    }
    const float Dv = Dv_p[d];

    // inline carry: accumulate h_in from preceding chunks
    float h[NS];
#pragma unroll
    for (int n = 0; n < NS; n++) h[n] = 0.f;
    for (int c = 0; c < ch; c++) {
        const size_t cb = ((size_t)(br * B_ + bb) * NCH + c);
        float ps = psum[cb * DI + d];
        if (fast) {
            float E = __expf(-ps);
            float p = E;
#pragma unroll
            for (int n = 0; n < NS; n++) {
                h[n] = fmaf(p, h[n], hloc[(cb * NS + n) * DI + d]);
                p   *= E;
            }
        } else {
#pragma unroll
            for (int n = 0; n < NS; n++) {
                float an = expf(Alog[(size_t)d * NS + n]);
                float P = __expf(-ps * an);
                h[n] = fmaf(P, h[n], hloc[(cb * NS + n) * DI + d]);
            }
        }
    }

    __shared__ float4 s_bc[SCAN_ST][8];

    for (int c0 = 0; c0 < CH; c0 += SCAN_ST) {
        float rdel[SCAN_ST], ru[SCAN_ST];
#pragma unroll
        for (int k = 0; k < SCAN_ST; k++) {
            size_t off = (size_t)(rowb + c0 + k) * DI + d;
            rdel[k] = __half2float(del[off]);
            ru[k]   = __half2float(u[off]);
        }
        __syncthreads();
        {
            int k = tid >> 3;
            int q = tid & 7;
            size_t off = (size_t)(rowb + c0 + k) * DBLC + RR + q * 4;
            s_bc[k][q] = *(const float4*)(dbl + off);
        }
        __syncthreads();

        if (fast) {
#pragma unroll
            for (int k = 0; k < SCAN_ST; k++) {
                float dl = rdel[k];
                float uu = ru[k];
                float du = dl * uu;
                float e  = __expf(-dl);
                float4 V0 = s_bc[k][0], V1 = s_bc[k][1], V2 = s_bc[k][2], V3 = s_bc[k][3];
                float4 W0 = s_bc[k][4], W1 = s_bc[k][5], W2 = s_bc[k][6], W3 = s_bc[k][7];
                float Bv[NS] = {V0.x,V0.y,V0.z,V0.w, V1.x,V1.y,V1.z,V1.w,
                                V2.x,V2.y,V2.z,V2.w, V3.x,V3.y,V3.z,V3.w};
                float Cv[NS] = {W0.x,W0.y,W0.z,W0.w, W1.x,W1.y,W1.z,W1.w,
                                W2.x,W2.y,W2.z,W2.w, W3.x,W3.y,W3.z,W3.w};
                float p  = e;
                float yv0 = 0.f, yv1 = 0.f;
#pragma unroll
                for (int n = 0; n < NS; n++) {
                    h[n] = fmaf(p, h[n], du * Bv[n]);
                    if (n & 1) yv1 = fmaf(h[n], Cv[n], yv1);
                    else       yv0 = fmaf(h[n], Cv[n], yv0);
                    p   *= e;
                }
                float yv = fmaf(uu, Dv, yv0 + yv1);
                yout[(size_t)(rowb + c0 + k) * DI + d] = __float2half_rn(yv);
            }
        } else {
#pragma unroll
            for (int k = 0; k < SCAN_ST; k++) {
                float dl = rdel[k];
                float uu = ru[k];
                float du = dl * uu;
                float yv = 0.f;
                const float* bc = (const float*)s_bc[k];
#pragma unroll
                for (int n = 0; n < NS; n++) {
                    float an = expf(Alog[(size_t)d * NS + n]);
                    float dA = __expf(-dl * an);
                    h[n] = fmaf(dA, h[n], du * bc[n]);
                    yv   = fmaf(h[n], bc[NS + n], yv);
                }
                yv = fmaf(uu, Dv, yv);
                yout[(size_t)(rowb + c0 + k) * DI + d] = __float2half_rn(yv);
            }
        }
    }
}

// ---------------------------------------------------------------------------
// Gate (y * silu(z)) + RMSNorm * norm_w; vectorized half2/float2
// ---------------------------------------------------------------------------
__global__ __launch_bounds__(256)
void gate_rms_kernel(const __half* __restrict__ yf, const __half* __restrict__ yb,
                     const float* __restrict__ z, const float* __restrict__ nw,
                     __half* __restrict__ g)
{
    const int row = blockIdx.x;
    const int l   = row & (L_ - 1);
    const int bb  = row >> 10;
    const int frow = (bb << 10) + (L_ - 1 - l);
    const int tid = threadIdx.x;

    __shared__ float sg[DI];
    __shared__ float red[8];

    float ss = 0.f;
#pragma unroll
    for (int it = 0; it < DI / 512; it++) {
        int d = (tid + it * 256) * 2;
        float2 y0 = __half22float2(*(const __half2*)(yf + (size_t)row * DI + d));
        float2 y1 = __half22float2(*(const __half2*)(yb + (size_t)frow * DI + d));
        float2 zz = *(const float2*)(z + (size_t)row * DI + d);
        float sz0 = zz.x / (1.f + __expf(-zz.x));
        float sz1 = zz.y / (1.f + __expf(-zz.y));
        float g0 = (y0.x + y1.x) * sz0;
        float g1 = (y0.y + y1.y) * sz1;
        *(float2*)&sg[d] = make_float2(g0, g1);
        ss = fmaf(g0, g0, ss);
        ss = fmaf(g1, g1, ss);
    }
#pragma unroll
    for (int o = 16; o; o >>= 1) ss += __shfl_xor_sync(0xFFFFFFFFu, ss, o);
    if ((tid & 31) == 0) red[tid >> 5] = ss;
    __syncthreads();
    float total = red[0] + red[1] + red[2] + red[3] + red[4] + red[5] + red[6] + red[7];
    float scale = rsqrtf(total / (float)DI + EPS);

#pragma unroll
    for (int it = 0; it < DI / 512; it++) {
        int d = (tid + it * 256) * 2;
        float2 gv = *(const float2*)&sg[d];
        float2 nv = *(const float2*)(nw + d);
        *(__half2*)(g + (size_t)row * DI + d) =
            __floats2half2_rn(gv.x * scale * nv.x, gv.y * scale * nv.y);
    }
}

// ---------------------------------------------------------------------------
// Launch
// ---------------------------------------------------------------------------
extern "C" void kernel_launch(void* const* d_in, const int* in_sizes, int n_in,
                              void* d_out, int out_size)
{
    (void)in_sizes; (void)n_in; (void)out_size;
    const float* a       = (const float*)d_in[0];
    const float* b       = (const float*)d_in[1];
    const float* Wi      = (const float*)d_in[2];
    const float* conv_w  = (const float*)d_in[3];
    const float* conv_b  = (const float*)d_in[4];
    const float* Wx      = (const float*)d_in[5];
    const float* Wdt     = (const float*)d_in[6];
    const float* bdt     = (const float*)d_in[7];
    const float* A_log   = (const float*)d_in[8];
    const float* D       = (const float*)d_in[9];
    const float* conv_w_b = (const float*)d_in[10];
    const float* conv_b_b = (const float*)d_in[11];
    const float* Wx_b    = (const float*)d_in[12];
    const float* Wdt_b   = (const float*)d_in[13];
    const float* bdt_b   = (const float*)d_in[14];
    const float* A_log_b = (const float*)d_in[15];
    const float* D_b     = (const float*)d_in[16];
    const float* Wo      = (const float*)d_in[17];
    const float* norm_w  = (const float*)d_in[18];
    float* out = (float*)d_out;

    __half *p_hA, *p_hB, *p_hWi, *p_hWo, *p_hWx, *p_hWx_b, *p_hWdt, *p_hWdt_b;
    __half *p_hx_f, *p_hx_b, *p_hu_f, *p_hu_b, *p_hdbl_f, *p_hdbl_b;
    __half *p_hdelta_f, *p_hdelta_b, *p_hy_f, *p_hy_b, *p_hg;
    float *p_z, *p_dblp, *p_dbl_f, *p_dbl_b, *p_wop;
    float *p_hloc, *p_psum;
    cudaGetSymbolAddress((void**)&p_hA, g_hA);
    cudaGetSymbolAddress((void**)&p_hB, g_hB);
    cudaGetSymbolAddress((void**)&p_hWi, g_hWi);
    cudaGetSymbolAddress((void**)&p_hWo, g_hWo);
    cudaGetSymbolAddress((void**)&p_hWx, g_hWx);
    cudaGetSymbolAddress((void**)&p_hWx_b, g_hWx_b);
    cudaGetSymbolAddress((void**)&p_hWdt, g_hWdt);
    cudaGetSymbolAddress((void**)&p_hWdt_b, g_hWdt_b);
    cudaGetSymbolAddress((void**)&p_hx_f, g_hx_f);
    cudaGetSymbolAddress((void**)&p_hx_b, g_hx_b);
    cudaGetSymbolAddress((void**)&p_hu_f, g_hu_f);
    cudaGetSymbolAddress((void**)&p_hu_b, g_hu_b);
    cudaGetSymbolAddress((void**)&p_hdbl_f, g_hdbl_f);
    cudaGetSymbolAddress((void**)&p_hdbl_b, g_hdbl_b);
    cudaGetSymbolAddress((void**)&p_hdelta_f, g_hdelta_f);
    cudaGetSymbolAddress((void**)&p_hdelta_b, g_hdelta_b);
    cudaGetSymbolAddress((void**)&p_hy_f, g_hy_f);
    cudaGetSymbolAddress((void**)&p_hy_b, g_hy_b);
    cudaGetSymbolAddress((void**)&p_hg, g_hg);
    cudaGetSymbolAddress((void**)&p_z, g_z);
    cudaGetSymbolAddress((void**)&p_dblp, g_dblp);
    cudaGetSymbolAddress((void**)&p_dbl_f, g_dbl_f);
    cudaGetSymbolAddress((void**)&p_dbl_b, g_dbl_b);
    cudaGetSymbolAddress((void**)&p_wop, g_wop);
    cudaGetSymbolAddress((void**)&p_hloc, g_hloc);
    cudaGetSymbolAddress((void**)&p_psum, g_psum);

    const int TPB = 256;
    cudaFuncSetAttribute(ha_linear2_kernel,
                         cudaFuncAttributeMaxDynamicSharedMemorySize, SMEM_TOTAL);

    // 0. convert inputs/weights to fp16 (one 8-array launch)
    {
        int nA = MTOT * DM, nB = MTOT * DM, nC = 2 * DI * DM, nD = DM * DI;
        int n0 = DBLC * DI, n1 = DBLC * DI, n2 = DI * RR, n3 = DI * RR;
        int ntot = nA + nB + nC + nD + n0 + n1 + n2 + n3;
        cvt8_half_kernel<<<(ntot / 8 + TPB - 1) / TPB, TPB>>>(
            a, p_hA, nA, b, p_hB, nB, Wi, p_hWi, nC, Wo, p_hWo, nD,
            Wx, p_hWx, n0, Wx_b, p_hWx_b, n1, Wdt, p_hWdt, n2, Wdt_b, p_hWdt_b, n3);
    }

    // 1. fused xz GEMM: fwd x->fp16 + z->f32; bwd x->fp16
    ha_linear2_kernel<<<dim3(32 + 16, MTOT / BM, 1), TPB, SMEM_TOTAL>>>(
        p_hA, DM, p_hWi, DM, nullptr, 0.f, p_z, p_hx_f, DI, 2 * DI, 0, 0,
        p_hB, DM, p_hWi, DM, nullptr, 0.f, nullptr, p_hx_b, DI, DI, 1, 0,
        MTOT, DM, /*splitX=*/32, /*splitZ=*/BIGSPLIT, 0);

    // 2. conv + silu (8 l x 2 d per thread, both branches)
    conv_silu_kernel<<<dim3((MTOT / CLG) * (DI / 2) / TPB, 1, 2), TPB>>>(
        p_hx_f, conv_w, conv_b, p_hu_f,
        p_hx_b, conv_w_b, conv_b_b, p_hu_b);

    // 3. fused dbl = u @ Wx^T [2048,96], split-K both branches
    ha_linear2_kernel<<<dim3(1, MTOT / BM, 2 * SPLITK), TPB, SMEM_TOTAL>>>(
        p_hu_f, DI, p_hWx, DI, nullptr, 0.f, p_dblp, nullptr, 0, DBLC, 0, 0,
        p_hu_b, DI, p_hWx_b, DI, nullptr, 0.f, p_dblp + (size_t)SPLITK * MTOT * DBLC,
        nullptr, 0, DBLC, 0, 0,
        MTOT, DI, /*splitX=*/BIGSPLIT, /*splitZ=*/SPLITK, KCHUNK);

    // 4. reduce partials -> dbl (f32 + fp16)
    {
        int nthreads = 2 * MTOT * DBLC / 4;
        reduce_dbl_kernel<<<(nthreads + TPB - 1) / TPB, TPB>>>(
            p_dblp, p_dbl_f, p_dbl_b, p_hdbl_f, p_hdbl_b);
    }

    // 5. fused delta = softplus(dt @ Wdt^T + 2*bdt), fp16 out, both branches
    ha_linear2_kernel<<<dim3(DI / BN, MTOT / BM, 2), TPB, SMEM_TOTAL>>>(
        p_hdbl_f, DBLC, p_hWdt, RR, bdt, 2.f, (float*)p_hdelta_f, nullptr, 0, DI, 0, 2,
        p_hdbl_b, DBLC, p_hWdt_b, RR, bdt_b, 2.f, (float*)p_hdelta_b, nullptr, 0, DI, 0, 2,
        MTOT, RR, /*splitX=*/BIGSPLIT, /*splitZ=*/1, 0);

    // 6. chunked selective scan (both branches); carry inlined in phase2
    scan_phase1<<<dim3((DI / SCAN_TPB) * B_ * NCH, 2), SCAN_TPB>>>(
        p_hdelta_f, p_dbl_f, p_hu_f, p_hdelta_b, p_dbl_b, p_hu_b,
        A_log, A_log_b, p_hloc, p_psum);
    scan_phase2<<<dim3((DI / SCAN_TPB) * B_ * NCH, 2), SCAN_TPB>>>(
        p_hdelta_f, p_dbl_f, p_hu_f, p_hdelta_b, p_dbl_b, p_hu_b,
        A_log, D, A_log_b, D_b, p_hloc, p_psum, p_hy_f, p_hy_b);

    // 7. gate + rmsnorm (vectorized)
    gate_rms_kernel<<<MTOT, TPB>>>(p_hy_f, p_hy_b, p_z, norm_w, p_hg);

    // 8. out = g @ Wo^T [2048,1024], split-K x4
    ha_linear2_kernel<<<dim3(DM / BN, MTOT / BM, WOSPLIT), TPB, SMEM_TOTAL>>>(
        p_hg, DI, p_hWo, DI, nullptr, 0.f, p_wop, nullptr, 0, DM, 0, 0,
        p_hg, DI, p_hWo, DI, nullptr, 0.f, p_wop, nullptr, 0, DM, 0, 0,
        MTOT, DI, /*splitX=*/BIGSPLIT, /*splitZ=*/BIGSPLIT, DI / WOSPLIT);
    reduce_out_kernel<<<(MTOT * DM / 4 + TPB - 1) / TPB, TPB>>>(p_wop, out);
}

// round 15
// speedup vs baseline: 6.6780x; 1.0130x over previous
#include <cuda_runtime.h>
#include <cuda_bf16.h>
#include <cuda_fp16.h>
#include <math.h>
#include <stdint.h>

// Problem constants
#define B_  2
#define L_  1024
#define DM  1024
#define DI  2048
#define NS  16
#define RR  64
#define KC  4
#define MTOT (B_ * L_)      // 2048
#define EPS 1e-5f

#define DBLC (RR + 2 * NS)  // 96
#define SPLITK 8
#define KCHUNK (DI / SPLITK)  // 256
#define WOSPLIT 4

#define NCH 8               // scan chunks
#define CH  (L_ / NCH)      // 128 steps per chunk

#define BIGSPLIT 0x40000000

// ---------------------------------------------------------------------------
// Scratch buffers (device globals; no allocation allowed)
// ---------------------------------------------------------------------------
__device__ __half g_hA[MTOT * DM];
__device__ __half g_hB[MTOT * DM];
__device__ __half g_hWi[(2 * DI) * DM];
__device__ __half g_hWo[DM * DI];
__device__ __half g_hWx[DBLC * DI];
__device__ __half g_hWx_b[DBLC * DI];
__device__ __half g_hWdt[DI * RR];
__device__ __half g_hWdt_b[DI * RR];
__device__ __half g_hx_f[MTOT * DI];        // fp16 x (conv input)
__device__ __half g_hx_b[MTOT * DI];
__device__ __half g_hz[MTOT * DI];          // fp16 z (gate input)
__device__ __half g_hu_f[MTOT * DI];        // fp16 u (GEMM + scan operand)
__device__ __half g_hu_b[MTOT * DI];
__device__ __half g_hdbl_f[MTOT * DBLC];
__device__ __half g_hdbl_b[MTOT * DBLC];
__device__ __half g_hdelta_f[MTOT * DI];    // fp16 delta (scan operand)
__device__ __half g_hdelta_b[MTOT * DI];
__device__ __half g_hy_f[MTOT * DI];        // fp16 y
__device__ __half g_hy_b[MTOT * DI];
__device__ __half g_hg[MTOT * DI];

__device__ float g_dblp[2 * SPLITK * MTOT * DBLC];
__device__ float g_dbl_f[MTOT * DBLC];
__device__ float g_dbl_b[MTOT * DBLC];
__device__ float g_wop[WOSPLIT * MTOT * DM];

// scan chunking state
__device__ float g_hloc[2 * B_ * NCH * NS * DI];
__device__ float g_psum[2 * B_ * NCH * DI];

// ---------------------------------------------------------------------------
// fp16 tensor-core GEMM, cp.async 3-stage pipeline, DUAL-BRANCH
//   act: 0 = none(f32 C), 1 = softplus(f32 C), 2 = softplus(fp16 C),
//        3 = none(fp16 C)
//   Cx/NX: cols [0,NX) stored fp16 to Cx (ld NX); rest to C (ld Nn-NX).
// ---------------------------------------------------------------------------
#define BM 128
#define BN 128
#define BK 32
#define BKP 40
#define STAGES 3
#define STG_BYTES ((BM + BN) * BKP * 2)
#define SMEM_TOTAL (STAGES * STG_BYTES)

__device__ __forceinline__ uint32_t smem_u32(const void* p) {
    uint32_t a;
    asm("{ .reg .u64 t; cvta.to.shared.u64 t, %1; cvt.u32.u64 %0, t; }"
        : "=r"(a) : "l"(p));
    return a;
}

__device__ __forceinline__ void ldsm4(uint32_t& r0, uint32_t& r1,
                                      uint32_t& r2, uint32_t& r3, uint32_t addr) {
    asm volatile("ldmatrix.sync.aligned.m8n8.x4.shared.b16 {%0,%1,%2,%3}, [%4];"
                 : "=r"(r0), "=r"(r1), "=r"(r2), "=r"(r3) : "r"(addr));
}

__device__ __forceinline__ void mma_f16(float c[4], const uint32_t a[4],
                                        const uint32_t b[2]) {
    asm volatile(
        "mma.sync.aligned.m16n8k16.row.col.f32.f16.f16.f32 "
        "{%0,%1,%2,%3}, {%4,%5,%6,%7}, {%8,%9}, {%0,%1,%2,%3};"
        : "+f"(c[0]), "+f"(c[1]), "+f"(c[2]), "+f"(c[3])
        : "r"(a[0]), "r"(a[1]), "r"(a[2]), "r"(a[3]), "r"(b[0]), "r"(b[1]));
}

#define CP_ASYNC16(dst, src, sz) \
    asm volatile("cp.async.cg.shared.global [%0], [%1], 16, %2;" \
                 :: "r"(dst), "l"(src), "r"(sz) : "memory")
#define CP_COMMIT() asm volatile("cp.async.commit_group;" ::: "memory")
#define CP_WAIT1()  asm volatile("cp.async.wait_group 1;" ::: "memory")

__global__ __launch_bounds__(256, 2)
void ha_linear2_kernel(
    const __half* __restrict__ A0, int lda0, const __half* __restrict__ W0, int ldw0,
    const float* __restrict__ bias0, float bs0, float* __restrict__ C0,
    __half* __restrict__ Cx0, int NX0,
    int Nn0, int flip0, int act0,
    const __half* __restrict__ A1, int lda1, const __half* __restrict__ W1, int ldw1,
    const float* __restrict__ bias1, float bs1, float* __restrict__ C1,
    __half* __restrict__ Cx1, int NX1,
    int Nn1, int flip1, int act1,
    int M, int Kd, int splitX, int splitZ, int kchunk)
{
    extern __shared__ __align__(16) char dsm[];
    const uint32_t sbase = smem_u32(dsm);

    int bx = blockIdx.x, bz = blockIdx.z, sel = 0;
    if (bx >= splitX) { sel = 1; bx -= splitX; }
    else if (bz >= splitZ) { sel = 1; bz -= splitZ; }

    const __half* __restrict__ A = sel ? A1 : A0;
    const __half* __restrict__ W = sel ? W1 : W0;
    const float* __restrict__ bias = sel ? bias1 : bias0;
    const float biasScale = sel ? bs1 : bs0;
    float* __restrict__ C = sel ? C1 : C0;
    __half* __restrict__ Cx = sel ? Cx1 : Cx0;
    const int NX   = sel ? NX1 : NX0;
    const int lda  = sel ? lda1 : lda0;
    const int ldw  = sel ? ldw1 : ldw0;
    const int Nn   = sel ? Nn1 : Nn0;
    const int flip = sel ? flip1 : flip0;
    const int act  = sel ? act1 : act0;

    const int tid  = threadIdx.x;
    const int lane = tid & 31;
    const int warp = tid >> 5;
    const int g    = lane >> 2;
    const int tg   = lane & 3;
    const int warpM = (warp & 3) * 32;
    const int warpN = (warp >> 2) * 64;
    const int row0 = blockIdx.y * BM;
    const int col0 = bx * BN;

    int kb = 0, klen = Kd;
    if (kchunk > 0) {
        kb   = bz * kchunk;
        klen = kchunk;
        C   += (size_t)bz * M * Nn;
    }
    const int ntiles = klen / BK;

    int arow[2], wrow[2];
    uint32_t wsz[2];
#pragma unroll
    for (int i = 0; i < 2; i++) {
        int idx = tid + 256 * i;
        int r   = idx >> 2;
        int gr  = row0 + r;
        if (flip) { gr = (gr & ~(L_ - 1)) + ((L_ - 1) - (gr & (L_ - 1))); }
        arow[i] = gr;
        int gn = col0 + r;
        wsz[i]  = (gn < Nn) ? 16u : 0u;
        wrow[i] = (gn < Nn) ? gn : 0;
    }
    const int ld_row   = tid >> 2;
    const int ld_chunk = (tid & 3) * 8;

    const int tquad = lane >> 3;
    const int trow  = lane & 7;
    const int a_m = ((tquad & 1) << 3) + trow;
    const int a_k = (tquad >> 1) << 3;
    const int b_n = ((tquad >> 1) << 3) + trow;
    const int b_k = (tquad & 1) << 3;

    float acc[2][8][4];
#pragma unroll
    for (int mi = 0; mi < 2; mi++)
#pragma unroll
        for (int ni = 0; ni < 8; ni++)
#pragma unroll
            for (int q = 0; q < 4; q++) acc[mi][ni][q] = 0.f;

    auto issue = [&](int t, int s) {
        const uint32_t st = sbase + (uint32_t)s * STG_BYTES;
        const int koff = kb + t * BK + ld_chunk;
#pragma unroll
        for (int i = 0; i < 2; i++) {
            int r = ld_row + 64 * i;
            uint32_t da = st + (uint32_t)r * (BKP * 2) + (uint32_t)ld_chunk * 2;
            CP_ASYNC16(da, A + (size_t)arow[i] * lda + koff, 16u);
        }
#pragma unroll
        for (int i = 0; i < 2; i++) {
            int r = ld_row + 64 * i;
            uint32_t db = st + (uint32_t)(BM * BKP * 2)
                        + (uint32_t)r * (BKP * 2) + (uint32_t)ld_chunk * 2;
            CP_ASYNC16(db, W + (size_t)wrow[i] * ldw + koff, wsz[i]);
        }
    };

#pragma unroll
    for (int s = 0; s < STAGES - 1; s++) {
        if (s < ntiles) issue(s, s);
        CP_COMMIT();
    }

    int cur = 0;
    int nxt = STAGES - 1;
    for (int t = 0; t < ntiles; t++) {
        CP_WAIT1();
        __syncthreads();

        const int tn = t + STAGES - 1;
        if (tn < ntiles) issue(tn, nxt);
        CP_COMMIT();

        const uint32_t stA = sbase + (uint32_t)cur * STG_BYTES;
        const uint32_t stB = stA + (uint32_t)(BM * BKP * 2);

#pragma unroll
        for (int kk = 0; kk < 2; kk++) {
            const uint32_t kbyte = (uint32_t)(kk * 16) * 2;
            uint32_t af[2][4], bf[8][2];
#pragma unroll
            for (int mi = 0; mi < 2; mi++) {
                uint32_t addr = stA + (uint32_t)(warpM + mi * 16 + a_m) * (BKP * 2)
                              + kbyte + (uint32_t)a_k * 2;
                ldsm4(af[mi][0], af[mi][1], af[mi][2], af[mi][3], addr);
            }
#pragma unroll
            for (int nj = 0; nj < 4; nj++) {
                uint32_t addr = stB + (uint32_t)(warpN + nj * 16 + b_n) * (BKP * 2)
                              + kbyte + (uint32_t)b_k * 2;
                ldsm4(bf[2 * nj][0], bf[2 * nj][1], bf[2 * nj + 1][0], bf[2 * nj + 1][1], addr);
            }
#pragma unroll
            for (int mi = 0; mi < 2; mi++)
#pragma unroll
                for (int ni = 0; ni < 8; ni++)
                    mma_f16(acc[mi][ni], af[mi], bf[ni]);
        }

        cur = (cur + 1 == STAGES) ? 0 : cur + 1;
        nxt = (nxt + 1 == STAGES) ? 0 : nxt + 1;
    }

    const bool isX = (Cx != nullptr) && (col0 < NX);
    const int  Nz  = Nn - NX;
#pragma unroll
    for (int mi = 0; mi < 2; mi++) {
        int r0 = row0 + warpM + mi * 16 + g;
#pragma unroll
        for (int ni = 0; ni < 8; ni++) {
            int cb = col0 + warpN + ni * 8 + 2 * tg;
            if (cb < Nn) {
                float v00 = acc[mi][ni][0], v01 = acc[mi][ni][1];
                float v10 = acc[mi][ni][2], v11 = acc[mi][ni][3];
                if (bias) {
                    float b0 = biasScale * bias[cb];
                    float b1 = biasScale * bias[cb + 1];
                    v00 += b0; v01 += b1; v10 += b0; v11 += b1;
                }
                if (act == 1 || act == 2) {
                    v00 = (v00 > 20.f) ? v00 : log1pf(expf(v00));
                    v01 = (v01 > 20.f) ? v01 : log1pf(expf(v01));
                    v10 = (v10 > 20.f) ? v10 : log1pf(expf(v10));
                    v11 = (v11 > 20.f) ? v11 : log1pf(expf(v11));
                }
                if (isX) {
                    *(__half2*)(Cx + (size_t)r0 * NX + cb)       = __floats2half2_rn(v00, v01);
                    *(__half2*)(Cx + (size_t)(r0 + 8) * NX + cb) = __floats2half2_rn(v10, v11);
                } else if (act == 2) {           // fp16 store, ld Nn
                    __half* Ch = (__half*)C;
                    *(__half2*)(Ch + (size_t)r0 * Nn + cb)       = __floats2half2_rn(v00, v01);
                    *(__half2*)(Ch + (size_t)(r0 + 8) * Nn + cb) = __floats2half2_rn(v10, v11);
                } else if (act == 3) {           // fp16 store, ld Nz (z half)
                    __half* Ch = (__half*)C;
                    int cz = cb - NX;
                    *(__half2*)(Ch + (size_t)r0 * Nz + cz)       = __floats2half2_rn(v00, v01);
                    *(__half2*)(Ch + (size_t)(r0 + 8) * Nz + cz) = __floats2half2_rn(v10, v11);
                } else {
                    int cz = cb - NX;
                    *(float2*)(C + (size_t)r0 * Nz + cz)       = make_float2(v00, v01);
                    *(float2*)(C + (size_t)(r0 + 8) * Nz + cz) = make_float2(v10, v11);
                }
            }
        }
    }
}

// ---------------------------------------------------------------------------
// f32 -> f16 conversion, eight arrays per launch
// ---------------------------------------------------------------------------
__global__ void cvt8_half_kernel(
    const float* __restrict__ s0, __half* __restrict__ d0, int n0,
    const float* __restrict__ s1, __half* __restrict__ d1, int n1,
    const float* __restrict__ s2, __half* __restrict__ d2, int n2,
    const float* __restrict__ s3, __half* __restrict__ d3, int n3,
    const float* __restrict__ s4, __half* __restrict__ d4, int n4,
    const float* __restrict__ s5, __half* __restrict__ d5, int n5,
    const float* __restrict__ s6, __half* __restrict__ d6, int n6,
    const float* __restrict__ s7, __half* __restrict__ d7, int n7)
{
    int i = (blockIdx.x * blockDim.x + threadIdx.x) * 8;
    const float* s;
    __half* d;
    if (i < n0) { s = s0 + i; d = d0 + i; }
    else if ((i -= n0) < n1) { s = s1 + i; d = d1 + i; }
    else if ((i -= n1) < n2) { s = s2 + i; d = d2 + i; }
    else if ((i -= n2) < n3) { s = s3 + i; d = d3 + i; }
    else if ((i -= n3) < n4) { s = s4 + i; d = d4 + i; }
    else if ((i -= n4) < n5) { s = s5 + i; d = d5 + i; }
    else if ((i -= n5) < n6) { s = s6 + i; d = d6 + i; }
    else if ((i -= n6) < n7) { s = s7 + i; d = d7 + i; }
    else return;
    float4 v0 = *(const float4*)s;
    float4 v1 = *(const float4*)(s + 4);
    __half2 h0 = __floats2half2_rn(v0.x, v0.y);
    __half2 h1 = __floats2half2_rn(v0.z, v0.w);
    __half2 h2 = __floats2half2_rn(v1.x, v1.y);
    __half2 h3 = __floats2half2_rn(v1.z, v1.w);
    *(uint4*)d = make_uint4(*(uint32_t*)&h0, *(uint32_t*)&h1,
                            *(uint32_t*)&h2, *(uint32_t*)&h3);
}

// ---------------------------------------------------------------------------
// Reduce split-K partials (dbl): f32 + fp16 out
// ---------------------------------------------------------------------------
__global__ void reduce_dbl_kernel(const float* __restrict__ part,
                                  float* __restrict__ of, float* __restrict__ ob,
                                  __half* __restrict__ hf, __half* __restrict__ hb)
{
    const int NV = MTOT * DBLC / 4;
    int i = blockIdx.x * blockDim.x + threadIdx.x;
    if (i >= 2 * NV) return;
    int br = (i >= NV);
    int j  = i - br * NV;
    const float4* p = (const float4*)part + (size_t)br * SPLITK * NV + j;
    float4 s = make_float4(0.f, 0.f, 0.f, 0.f);
#pragma unroll
    for (int k = 0; k < SPLITK; k++) {
        float4 v = p[(size_t)k * NV];
        s.x += v.x; s.y += v.y; s.z += v.z; s.w += v.w;
    }
    ((float4*)(br ? ob : of))[j] = s;
    __half2 h0 = __floats2half2_rn(s.x, s.y);
    __half2 h1 = __floats2half2_rn(s.z, s.w);
    ((uint2*)(br ? hb : hf))[j] = make_uint2(*(uint32_t*)&h0, *(uint32_t*)&h1);
}

// ---------------------------------------------------------------------------
// Reduce Wo split-K partials into out (WOSPLIT partials)
// ---------------------------------------------------------------------------
__global__ void reduce_out_kernel(const float* __restrict__ part,
                                  float* __restrict__ out)
{
    const int NV = MTOT * DM / 4;
    int i = blockIdx.x * blockDim.x + threadIdx.x;
    if (i >= NV) return;
    float4 s = make_float4(0.f, 0.f, 0.f, 0.f);
#pragma unroll
    for (int k = 0; k < WOSPLIT; k++) {
        float4 v = ((const float4*)part)[i + (size_t)k * NV];
        s.x += v.x; s.y += v.y; s.z += v.z; s.w += v.w;
    }
    ((float4*)out)[i] = s;
}

// ---------------------------------------------------------------------------
// Depthwise causal conv1d (K=4) + bias + SiLU; 8 l x 2 d per thread; half2 I/O
// ---------------------------------------------------------------------------
#define CLG 8
__global__ void conv_silu_kernel(const __half* __restrict__ x0,
                                 const float* __restrict__ w0,
                                 const float* __restrict__ b0,
                                 __half* __restrict__ h0,
                                 const __half* __restrict__ x1,
                                 const float* __restrict__ w1,
                                 const float* __restrict__ b1,
                                 __half* __restrict__ h1)
{
    const int br = blockIdx.z;
    const __half* __restrict__ x = br ? x1 : x0;
    const float* __restrict__ w = br ? w1 : w0;
    const float* __restrict__ bi = br ? b1 : b0;
    __half* __restrict__ hu = br ? h1 : h0;

    int idx = blockIdx.x * blockDim.x + threadIdx.x;
    if (idx >= (MTOT / CLG) * (DI / 2)) return;
    const int d    = (idx % (DI / 2)) * 2;
    const int grp  = idx / (DI / 2);
    const int row0 = grp * CLG;
    const int l0   = row0 & (L_ - 1);
    const int bb0  = row0 - l0;

    float2 xv[CLG + KC - 1];
#pragma unroll
    for (int j = 0; j < CLG + KC - 1; j++) {
        int l = l0 - (KC - 1) + j;
        if (l >= 0) {
            __half2 hv = *(const __half2*)(x + (size_t)(bb0 + l) * DI + d);
            xv[j] = __half22float2(hv);
        } else {
            xv[j] = make_float2(0.f, 0.f);
        }
    }
    const float w00 = w[d * KC + 0], w01 = w[d * KC + 1],
                w02 = w[d * KC + 2], w03 = w[d * KC + 3];
    const float w10 = w[(d + 1) * KC + 0], w11 = w[(d + 1) * KC + 1],
                w12 = w[(d + 1) * KC + 2], w13 = w[(d + 1) * KC + 3];
    const float bv0 = bi[d], bv1 = bi[d + 1];

#pragma unroll
    for (int j = 0; j < CLG; j++) {
        float a0 = bv0, a1 = bv1;
        a0 = fmaf(xv[j].x,     w00, a0);  a1 = fmaf(xv[j].y,     w10, a1);
        a0 = fmaf(xv[j + 1].x, w01, a0);  a1 = fmaf(xv[j + 1].y, w11, a1);
        a0 = fmaf(xv[j + 2].x, w02, a0);  a1 = fmaf(xv[j + 2].y, w12, a1);
        a0 = fmaf(xv[j + 3].x, w03, a0);  a1 = fmaf(xv[j + 3].y, w13, a1);
        float s0 = 1.f / (1.f + __expf(-a0));
        float s1 = 1.f / (1.f + __expf(-a1));
        *(__half2*)(hu + (size_t)(row0 + j) * DI + d) =
            __floats2half2_rn(a0 * s0, a1 * s1);
    }
}

// ---------------------------------------------------------------------------
// Chunked selective scan (phase1 / phase2 with inline carry)
//   phase1: chunks 0..NCH-2 only (chunk NCH-1 state never consumed)
// ---------------------------------------------------------------------------
#define SCAN_TPB 128
#define SCAN_ST  16

__global__ __launch_bounds__(SCAN_TPB)
void scan_phase1(const __half* __restrict__ del_f, const float* __restrict__ dbl_f,
                 const __half* __restrict__ u_f,
                 const __half* __restrict__ del_b, const float* __restrict__ dbl_b,
                 const __half* __restrict__ u_b,
                 const float* __restrict__ Alog_f, const float* __restrict__ Alog_b,
                 float* __restrict__ hloc, float* __restrict__ psum)
{
    const int br = blockIdx.y;
    const __half* __restrict__ del = br ? del_b : del_f;
    const float* __restrict__ dbl  = br ? dbl_b : dbl_f;
    const __half* __restrict__ u   = br ? u_b   : u_f;
    const float* __restrict__ Alog = br ? Alog_b : Alog_f;

    const int tid   = threadIdx.x;
    const int ch    = blockIdx.x % (NCH - 1);          // 0..6
    const int bb    = (blockIdx.x / (NCH - 1)) & 1;
    const int dpart = blockIdx.x / (2 * (NCH - 1));
    const int d     = dpart * SCAN_TPB + tid;
    const int rowb  = bb * L_ + ch * CH;

    bool fast = true;
#pragma unroll
    for (int n = 0; n < NS; n++) {
        float an = expf(Alog[(size_t)d * NS + n]);
        fast = fast && (fabsf(an - (float)(n + 1)) < 1e-4f * (float)(n + 1));
    }

    float h[NS];
#pragma unroll
    for (int n = 0; n < NS; n++) h[n] = 0.f;
    float ps = 0.f;

    __shared__ float4 s_bc[SCAN_ST][4];   // B only

    for (int c0 = 0; c0 < CH; c0 += SCAN_ST) {
        float rdel[SCAN_ST], ru[SCAN_ST];
#pragma unroll
        for (int k = 0; k < SCAN_ST; k++) {
            size_t off = (size_t)(rowb + c0 + k) * DI + d;
            rdel[k] = __half2float(del[off]);
            ru[k]   = __half2float(u[off]);
        }
        __syncthreads();
        if (tid < 64) {
            int k = tid >> 2;
            int q = tid & 3;
            size_t off = (size_t)(rowb + c0 + k) * DBLC + RR + q * 4;
            s_bc[k][q] = *(const float4*)(dbl + off);
        }
        __syncthreads();

        if (fast) {
#pragma unroll
            for (int k = 0; k < SCAN_ST; k++) {
                float dl = rdel[k];
                float du = dl * ru[k];
                ps += dl;
                float e = __expf(-dl);
                float4 V0 = s_bc[k][0], V1 = s_bc[k][1], V2 = s_bc[k][2], V3 = s_bc[k][3];
                float Bv[NS] = {V0.x,V0.y,V0.z,V0.w, V1.x,V1.y,V1.z,V1.w,
                                V2.x,V2.y,V2.z,V2.w, V3.x,V3.y,V3.z,V3.w};
                float p = e;
#pragma unroll
                for (int n = 0; n < NS; n++) {
                    h[n] = fmaf(p, h[n], du * Bv[n]);
                    p   *= e;
                }
            }
        } else {
#pragma unroll
            for (int k = 0; k < SCAN_ST; k++) {
                float dl = rdel[k];
                float du = dl * ru[k];
                ps += dl;
                const float* bc = (const float*)s_bc[k];
#pragma unroll
                for (int n = 0; n < NS; n++) {
                    float an = expf(Alog[(size_t)d * NS + n]);
                    float dA = __expf(-dl * an);
                    h[n] = fmaf(dA, h[n], du * bc[n]);
                }
            }
        }
    }

    const int cbase = ((br * B_ + bb) * NCH + ch);
    psum[(size_t)cbase * DI + d] = ps;
#pragma unroll
    for (int n = 0; n < NS; n++)
        hloc[((size_t)cbase * NS + n) * DI + d] = h[n];
}

__global__ __launch_bounds__(SCAN_TPB)
void scan_phase2(const __half* __restrict__ del_f, const float* __restrict__ dbl_f,
                 const __half* __restrict__ u_f,
                 const __half* __restrict__ del_b, const float* __restrict__ dbl_b,
                 const __half* __restrict__ u_b,
                 const float* __restrict__ Alog_f, const float* __restrict__ D_f,
                 const float* __restrict__ Alog_b, const float* __restrict__ D_b,
                 const float* __restrict__ hloc, const float* __restrict__ psum,
                 __half* __restrict__ y_f, __half* __restrict__ y_b)
{
    const int br = blockIdx.y;
    const __half* __restrict__ del = br ? del_b : del_f;
    const float* __restrict__ dbl  = br ? dbl_b : dbl_f;
    const __half* __restrict__ u   = br ? u_b   : u_f;
    const float* __restrict__ Alog = br ? Alog_b : Alog_f;
    const float* __restrict__ Dv_p = br ? D_b : D_f;
    __half* __restrict__ yout      = br ? y_b : y_f;

    const int tid   = threadIdx.x;
    const int ch    = blockIdx.x & (NCH - 1);
    const int bb    = (blockIdx.x >> 3) & 1;
    const int dpart = blockIdx.x >> 4;
    const int d     = dpart * SCAN_TPB + tid;
    const int rowb  = bb * L_ + ch * CH;

    bool fast = true;
#pragma unroll
    for (int n = 0; n < NS; n++) {
        float an = expf(Alog[(size_t)d * NS + n]);
        fast = fast && (fabsf(an - (float)(n + 1)) < 1e-4f * (float)(n + 1));
    }
    const float Dv = Dv_p[d];

    // inline carry: accumulate h_in from preceding chunks
    float h[NS];
#pragma unroll
    for (int n = 0; n < NS; n++) h[n] = 0.f;
    for (int c = 0; c < ch; c++) {
        const size_t cb = ((size_t)(br * B_ + bb) * NCH + c);
        float ps = psum[cb * DI + d];
        if (fast) {
            float E = __expf(-ps);
            float p = E;
#pragma unroll
            for (int n = 0; n < NS; n++) {
                h[n] = fmaf(p, h[n], hloc[(cb * NS + n) * DI + d]);
                p   *= E;
            }
        } else {
#pragma unroll
            for (int n = 0; n < NS; n++) {
                float an = expf(Alog[(size_t)d * NS + n]);
                float P = __expf(-ps * an);
                h[n] = fmaf(P, h[n], hloc[(cb * NS + n) * DI + d]);
            }
        }
    }

    __shared__ float4 s_bc[SCAN_ST][8];

    for (int c0 = 0; c0 < CH; c0 += SCAN_ST) {
        float rdel[SCAN_ST], ru[SCAN_ST];
#pragma unroll
        for (int k = 0; k < SCAN_ST; k++) {
            size_t off = (size_t)(rowb + c0 + k) * DI + d;
            rdel[k] = __half2float(del[off]);
            ru[k]   = __half2float(u[off]);
        }
        __syncthreads();
        {
            int k = tid >> 3;
            int q = tid & 7;
            size_t off = (size_t)(rowb + c0 + k) * DBLC + RR + q * 4;
            s_bc[k][q] = *(const float4*)(dbl + off);
        }
        __syncthreads();

        if (fast) {
#pragma unroll
            for (int k = 0; k < SCAN_ST; k++) {
                float dl = rdel[k];
                float uu = ru[k];
                float du = dl * uu;
                float e  = __expf(-dl);
                float4 V0 = s_bc[k][0], V1 = s_bc[k][1], V2 = s_bc[k][2], V3 = s_bc[k][3];
                float4 W0 = s_bc[k][4], W1 = s_bc[k][5], W2 = s_bc[k][6], W3 = s_bc[k][7];
                float Bv[NS] = {V0.x,V0.y,V0.z,V0.w, V1.x,V1.y,V1.z,V1.w,
                                V2.x,V2.y,V2.z,V2.w, V3.x,V3.y,V3.z,V3.w};
                float Cv[NS] = {W0.x,W0.y,W0.z,W0.w, W1.x,W1.y,W1.z,W1.w,
                                W2.x,W2.y,W2.z,W2.w, W3.x,W3.y,W3.z,W3.w};
                float p  = e;
                float yv0 = 0.f, yv1 = 0.f;
#pragma unroll
                for (int n = 0; n < NS; n++) {
                    h[n] = fmaf(p, h[n], du * Bv[n]);
                    if (n & 1) yv1 = fmaf(h[n], Cv[n], yv1);
                    else       yv0 = fmaf(h[n], Cv[n], yv0);
                    p   *= e;
                }
                float yv = fmaf(uu, Dv, yv0 + yv1);
                yout[(size_t)(rowb + c0 + k) * DI + d] = __float2half_rn(yv);
            }
        } else {
#pragma unroll
            for (int k = 0; k < SCAN_ST; k++) {
                float dl = rdel[k];
                float uu = ru[k];
                float du = dl * uu;
                float yv = 0.f;
                const float* bc = (const float*)s_bc[k];
#pragma unroll
                for (int n = 0; n < NS; n++) {
                    float an = expf(Alog[(size_t)d * NS + n]);
                    float dA = __expf(-dl * an);
                    h[n] = fmaf(dA, h[n], du * bc[n]);
                    yv   = fmaf(h[n], bc[NS + n], yv);
                }
                yv = fmaf(uu, Dv, yv);
                yout[(size_t)(rowb + c0 + k) * DI + d] = __float2half_rn(yv);
            }
        }
    }
}

// ---------------------------------------------------------------------------
// Gate (y * silu(z)) + RMSNorm * norm_w; vectorized half2
// ---------------------------------------------------------------------------
__global__ __launch_bounds__(256)
void gate_rms_kernel(const __half* __restrict__ yf, const __half* __restrict__ yb,
                     const __half* __restrict__ z, const float* __restrict__ nw,
                     __half* __restrict__ g)
{
    const int row = blockIdx.x;
    const int l   = row & (L_ - 1);
    const int bb  = row >> 10;
    const int frow = (bb << 10) + (L_ - 1 - l);
    const int tid = threadIdx.x;

    __shared__ float sg[DI];
    __shared__ float red[8];

    float ss = 0.f;
#pragma unroll
    for (int it = 0; it < DI / 512; it++) {
        int d = (tid + it * 256) * 2;
        float2 y0 = __half22float2(*(const __half2*)(yf + (size_t)row * DI + d));
        float2 y1 = __half22float2(*(const __half2*)(yb + (size_t)frow * DI + d));
        float2 zz = __half22float2(*(const __half2*)(z + (size_t)row * DI + d));
        float sz0 = zz.x / (1.f + __expf(-zz.x));
        float sz1 = zz.y / (1.f + __expf(-zz.y));
        float g0 = (y0.x + y1.x) * sz0;
        float g1 = (y0.y + y1.y) * sz1;
        *(float2*)&sg[d] = make_float2(g0, g1);
        ss = fmaf(g0, g0, ss);
        ss = fmaf(g1, g1, ss);
    }
#pragma unroll
    for (int o = 16; o; o >>= 1) ss += __shfl_xor_sync(0xFFFFFFFFu, ss, o);
    if ((tid & 31) == 0) red[tid >> 5] = ss;
    __syncthreads();
    float total = red[0] + red[1] + red[2] + red[3] + red[4] + red[5] + red[6] + red[7];
    float scale = rsqrtf(total / (float)DI + EPS);

#pragma unroll
    for (int it = 0; it < DI / 512; it++) {
        int d = (tid + it * 256) * 2;
        float2 gv = *(const float2*)&sg[d];
        float2 nv = *(const float2*)(nw + d);
        *(__half2*)(g + (size_t)row * DI + d) =
            __floats2half2_rn(gv.x * scale * nv.x, gv.y * scale * nv.y);
    }
}

// ---------------------------------------------------------------------------
// Launch
// ---------------------------------------------------------------------------
extern "C" void kernel_launch(void* const* d_in, const int* in_sizes, int n_in,
                              void* d_out, int out_size)
{
    (void)in_sizes; (void)n_in; (void)out_size;
    const float* a       = (const float*)d_in[0];
    const float* b       = (const float*)d_in[1];
    const float* Wi      = (const float*)d_in[2];
    const float* conv_w  = (const float*)d_in[3];
    const float* conv_b  = (const float*)d_in[4];
    const float* Wx      = (const float*)d_in[5];
    const float* Wdt     = (const float*)d_in[6];
    const float* bdt     = (const float*)d_in[7];
    const float* A_log   = (const float*)d_in[8];
    const float* D       = (const float*)d_in[9];
    const float* conv_w_b = (const float*)d_in[10];
    const float* conv_b_b = (const float*)d_in[11];
    const float* Wx_b    = (const float*)d_in[12];
    const float* Wdt_b   = (const float*)d_in[13];
    const float* bdt_b   = (const float*)d_in[14];
    const float* A_log_b = (const float*)d_in[15];
    const float* D_b     = (const float*)d_in[16];
    const float* Wo      = (const float*)d_in[17];
    const float* norm_w  = (const float*)d_in[18];
    float* out = (float*)d_out;

    __half *p_hA, *p_hB, *p_hWi, *p_hWo, *p_hWx, *p_hWx_b, *p_hWdt, *p_hWdt_b;
    __half *p_hx_f, *p_hx_b, *p_hz, *p_hu_f, *p_hu_b, *p_hdbl_f, *p_hdbl_b;
    __half *p_hdelta_f, *p_hdelta_b, *p_hy_f, *p_hy_b, *p_hg;
    float *p_dblp, *p_dbl_f, *p_dbl_b, *p_wop;
    float *p_hloc, *p_psum;
    cudaGetSymbolAddress((void**)&p_hA, g_hA);
    cudaGetSymbolAddress((void**)&p_hB, g_hB);
    cudaGetSymbolAddress((void**)&p_hWi, g_hWi);
    cudaGetSymbolAddress((void**)&p_hWo, g_hWo);
    cudaGetSymbolAddress((void**)&p_hWx, g_hWx);
    cudaGetSymbolAddress((void**)&p_hWx_b, g_hWx_b);
    cudaGetSymbolAddress((void**)&p_hWdt, g_hWdt);
    cudaGetSymbolAddress((void**)&p_hWdt_b, g_hWdt_b);
    cudaGetSymbolAddress((void**)&p_hx_f, g_hx_f);
    cudaGetSymbolAddress((void**)&p_hx_b, g_hx_b);
    cudaGetSymbolAddress((void**)&p_hz, g_hz);
    cudaGetSymbolAddress((void**)&p_hu_f, g_hu_f);
    cudaGetSymbolAddress((void**)&p_hu_b, g_hu_b);
    cudaGetSymbolAddress((void**)&p_hdbl_f, g_hdbl_f);
    cudaGetSymbolAddress((void**)&p_hdbl_b, g_hdbl_b);
    cudaGetSymbolAddress((void**)&p_hdelta_f, g_hdelta_f);
    cudaGetSymbolAddress((void**)&p_hdelta_b, g_hdelta_b);
    cudaGetSymbolAddress((void**)&p_hy_f, g_hy_f);
    cudaGetSymbolAddress((void**)&p_hy_b, g_hy_b);
    cudaGetSymbolAddress((void**)&p_hg, g_hg);
    cudaGetSymbolAddress((void**)&p_dblp, g_dblp);
    cudaGetSymbolAddress((void**)&p_dbl_f, g_dbl_f);
    cudaGetSymbolAddress((void**)&p_dbl_b, g_dbl_b);
    cudaGetSymbolAddress((void**)&p_wop, g_wop);
    cudaGetSymbolAddress((void**)&p_hloc, g_hloc);
    cudaGetSymbolAddress((void**)&p_psum, g_psum);

    const int TPB = 256;
    cudaFuncSetAttribute(ha_linear2_kernel,
                         cudaFuncAttributeMaxDynamicSharedMemorySize, SMEM_TOTAL);

    // 0. convert inputs/weights to fp16 (one 8-array launch)
    {
        int nA = MTOT * DM, nB = MTOT * DM, nC = 2 * DI * DM, nD = DM * DI;
        int n0 = DBLC * DI, n1 = DBLC * DI, n2 = DI * RR, n3 = DI * RR;
        int ntot = nA + nB + nC + nD + n0 + n1 + n2 + n3;
        cvt8_half_kernel<<<(ntot / 8 + TPB - 1) / TPB, TPB>>>(
            a, p_hA, nA, b, p_hB, nB, Wi, p_hWi, nC, Wo, p_hWo, nD,
            Wx, p_hWx, n0, Wx_b, p_hWx_b, n1, Wdt, p_hWdt, n2, Wdt_b, p_hWdt_b, n3);
    }

    // 1. fused xz GEMM: fwd x->fp16 + z->fp16; bwd x->fp16
    ha_linear2_kernel<<<dim3(32 + 16, MTOT / BM, 1), TPB, SMEM_TOTAL>>>(
        p_hA, DM, p_hWi, DM, nullptr, 0.f, (float*)p_hz, p_hx_f, DI, 2 * DI, 0, 3,
        p_hB, DM, p_hWi, DM, nullptr, 0.f, nullptr, p_hx_b, DI, DI, 1, 0,
        MTOT, DM, /*splitX=*/32, /*splitZ=*/BIGSPLIT, 0);

    // 2. conv + silu (8 l x 2 d per thread, both branches)
    conv_silu_kernel<<<dim3((MTOT / CLG) * (DI / 2) / TPB, 1, 2), TPB>>>(
        p_hx_f, conv_w, conv_b, p_hu_f,
        p_hx_b, conv_w_b, conv_b_b, p_hu_b);

    // 3. fused dbl = u @ Wx^T [2048,96], split-K both branches
    ha_linear2_kernel<<<dim3(1, MTOT / BM, 2 * SPLITK), TPB, SMEM_TOTAL>>>(
        p_hu_f, DI, p_hWx, DI, nullptr, 0.f, p_dblp, nullptr, 0, DBLC, 0, 0,
        p_hu_b, DI, p_hWx_b, DI, nullptr, 0.f, p_dblp + (size_t)SPLITK * MTOT * DBLC,
        nullptr, 0, DBLC, 0, 0,
        MTOT, DI, /*splitX=*/BIGSPLIT, /*splitZ=*/SPLITK, KCHUNK);

    // 4. reduce partials -> dbl (f32 + fp16)
    {
        int nthreads = 2 * MTOT * DBLC / 4;
        reduce_dbl_kernel<<<(nthreads + TPB - 1) / TPB, TPB>>>(
            p_dblp, p_dbl_f, p_dbl_b, p_hdbl_f, p_hdbl_b);
    }

    // 5. fused delta = softplus(dt @ Wdt^T + 2*bdt), fp16 out, both branches
    ha_linear2_kernel<<<dim3(DI / BN, MTOT / BM, 2), TPB, SMEM_TOTAL>>>(
        p_hdbl_f, DBLC, p_hWdt, RR, bdt, 2.f, (float*)p_hdelta_f, nullptr, 0, DI, 0, 2,
        p_hdbl_b, DBLC, p_hWdt_b, RR, bdt_b, 2.f, (float*)p_hdelta_b, nullptr, 0, DI, 0, 2,
        MTOT, RR, /*splitX=*/BIGSPLIT, /*splitZ=*/1, 0);

    // 6. chunked selective scan; phase1 skips last chunk (state unused)
    scan_phase1<<<dim3((DI / SCAN_TPB) * B_ * (NCH - 1), 2), SCAN_TPB>>>(
        p_hdelta_f, p_dbl_f, p_hu_f, p_hdelta_b, p_dbl_b, p_hu_b,
        A_log, A_log_b, p_hloc, p_psum);
    scan_phase2<<<dim3((DI / SCAN_TPB) * B_ * NCH, 2), SCAN_TPB>>>(
        p_hdelta_f, p_dbl_f, p_hu_f, p_hdelta_b, p_dbl_b, p_hu_b,
        A_log, D, A_log_b, D_b, p_hloc, p_psum, p_hy_f, p_hy_b);

    // 7. gate + rmsnorm (fp16 z)
    gate_rms_kernel<<<MTOT, TPB>>>(p_hy_f, p_hy_b, p_hz, norm_w, p_hg);

    // 8. out = g @ Wo^T [2048,1024], split-K x4
    ha_linear2_kernel<<<dim3(DM / BN, MTOT / BM, WOSPLIT), TPB, SMEM_TOTAL>>>(
        p_hg, DI, p_hWo, DI, nullptr, 0.f, p_wop, nullptr, 0, DM, 0, 0,
        p_hg, DI, p_hWo, DI, nullptr, 0.f, p_wop, nullptr, 0, DM, 0, 0,
        MTOT, DI, /*splitX=*/BIGSPLIT, /*splitZ=*/BIGSPLIT, DI / WOSPLIT);
    reduce_out_kernel<<<(MTOT * DM / 4 + TPB - 1) / TPB, TPB>>>(p_wop, out);
}